// round 1
// baseline (speedup 1.0000x reference)
#include <cuda_runtime.h>
#include <math.h>

// ---------------- problem constants ----------------
#define BATCH 4
#define CCH   48
#define HH_   64
#define WW_   64
#define HW    4096
#define HID   96
#define NSET  32
#define HEADS 8
#define DHEAD 6
#define INTERC 24

// ---------------- scratch layout (one big __device__ buffer) ----------------
#define OFF_XN    0LL
#define OFF_XM    (OFF_XN   + (long long)BATCH*CCH*HW)
#define OFF_T1    (OFF_XM   + (long long)BATCH*CCH*HW)
#define OFF_T2    (OFF_T1   + (long long)BATCH*HID*HW)
#define OFF_X1    (OFF_T2   + (long long)BATCH*HID*HW)
#define OFF_UF    (OFF_X1   + (long long)BATCH*HID*HW)
#define OFF_ATT   (OFF_UF   + (long long)BATCH*HID*HW)
#define OFF_QKVT  (OFF_ATT  + (long long)BATCH*NSET*HW)
#define OFF_QKV   (OFF_QKVT + (long long)BATCH*3*CCH*HW)
#define OFF_X2    (OFF_QKV  + (long long)BATCH*3*CCH*HW)
#define OFF_M     (OFF_X2   + (long long)BATCH*HID*HW)
#define OFF_MDIN  (OFF_M    + (long long)BATCH*HID*HW)
#define OFF_MDTA  (OFF_MDIN + (long long)BATCH*CCH*HW)
#define OFF_GAP   (OFF_MDTA + (long long)BATCH*CCH*HW)
#define OFF_CA1   (OFF_GAP  + BATCH*CCH)
#define OFF_CA2   (OFF_CA1  + BATCH*CCH)
#define OFF_NORMS (OFF_CA2  + BATCH*CCH)
#define OFF_ATTN  (OFF_NORMS + 2*BATCH*CCH)
#define SCRATCH_TOTAL (OFF_ATTN + BATCH*HEADS*DHEAD*DHEAD)

__device__ float g_scratch[SCRATCH_TOTAL];

// ---------------- gap: mean over HW per (b,c) ----------------
__global__ void gap_k(const float* __restrict__ x, float* __restrict__ gap)
{
    int bc = blockIdx.x;                 // 0..191
    const float* xb = x + (size_t)bc * HW;
    __shared__ float red[256];
    float s = 0.f;
    for (int i = threadIdx.x; i < HW; i += 256) s += xb[i];
    red[threadIdx.x] = s; __syncthreads();
    for (int st = 128; st; st >>= 1) {
        if (threadIdx.x < st) red[threadIdx.x] += red[threadIdx.x + st];
        __syncthreads();
    }
    if (threadIdx.x == 0) gap[bc] = red[0] * (1.f / HW);
}

// ---------------- channel attention 1x1 convs on pooled vector ----------------
__global__ void ca_k(const float* __restrict__ gap,
                     const float* __restrict__ w1, const float* __restrict__ b1,
                     const float* __restrict__ w2, const float* __restrict__ b2,
                     float* __restrict__ ca1, float* __restrict__ ca2)
{
    int t = threadIdx.x;
    if (t >= BATCH * CCH) return;
    int b = t / CCH, o = t % CCH;
    float s1 = b1[o], s2 = b2[o];
    for (int c = 0; c < CCH; c++) {
        float g = gap[b * CCH + c];
        s1 += w1[o * CCH + c] * g;
        s2 += w2[o * CCH + c] * g;
    }
    ca1[t] = s1; ca2[t] = s2;
}

// ---------------- LayerNorm2d (over channels) -> xn, xm ----------------
__global__ __launch_bounds__(256) void ln_k(const float* __restrict__ x,
        const float* __restrict__ n1w, const float* __restrict__ n1b,
        const float* __restrict__ n2w, const float* __restrict__ n2b,
        float* __restrict__ xn, float* __restrict__ xm)
{
    int pg = blockIdx.x * 256 + threadIdx.x;   // B*HW
    int b = pg >> 12, p = pg & 4095;
    const float* xb = x + (size_t)b * CCH * HW + p;
    float v[CCH];
    float s = 0.f, s2 = 0.f;
#pragma unroll
    for (int c = 0; c < CCH; c++) { float t = xb[(size_t)c * HW]; v[c] = t; s += t; s2 += t * t; }
    float mu = s * (1.f / CCH);
    float var = s2 * (1.f / CCH) - mu * mu;
    float r = rsqrtf(var + 1e-6f);
    float* xnb = xn + (size_t)b * CCH * HW + p;
    float* xmb = xm + (size_t)b * CCH * HW + p;
#pragma unroll
    for (int c = 0; c < CCH; c++) {
        float y = (v[c] - mu) * r;
        xnb[(size_t)c * HW] = n1w[c] * y + n1b[c];
        xmb[(size_t)c * HW] = n2w[c] * y + n2b[c];
    }
}

// ---------------- generic 1x1 conv ----------------
template <int INC, int OUTC, bool HASB>
__global__ __launch_bounds__(128) void conv1x1_k(const float* __restrict__ in,
        const float* __restrict__ w, const float* __restrict__ bias,
        float* __restrict__ out)
{
    __shared__ float ws[OUTC * INC];
    __shared__ float bs[OUTC];
    int tid = threadIdx.x;
    for (int i = tid; i < OUTC * INC; i += 128) ws[i] = w[i];
    if (HASB) for (int i = tid; i < OUTC; i += 128) bs[i] = bias[i];
    __syncthreads();
    int pg = blockIdx.x * 128 + tid;
    int b = pg >> 12, p = pg & 4095;
    const float* inb = in + (size_t)b * INC * HW + p;
    float xv[INC];
#pragma unroll
    for (int c = 0; c < INC; c++) xv[c] = inb[(size_t)c * HW];
    float* outb = out + (size_t)b * OUTC * HW + p;
    for (int o = 0; o < OUTC; o++) {
        float acc = HASB ? bs[o] : 0.f;
#pragma unroll
        for (int c = 0; c < INC; c++) acc += ws[o * INC + c] * xv[c];
        outb[(size_t)o * HW] = acc;
    }
}

// ---------------- depthwise 3x3, pad 1 ----------------
template <int CH>
__global__ void dw3x3_k(const float* __restrict__ in, const float* __restrict__ w,
                        float* __restrict__ out)
{
    int idx = blockIdx.x * 256 + threadIdx.x;     // B*CH*HW
    int p = idx & 4095; int bc = idx >> 12; int c = bc % CH;
    int h = p >> 6, wq = p & 63;
    const float* inp = in + (size_t)bc * HW;
    const float* wc = w + c * 9;
    float acc = 0.f;
#pragma unroll
    for (int kh = 0; kh < 3; kh++) {
        int hh = h + kh - 1;
        if (hh < 0 || hh > 63) continue;
#pragma unroll
        for (int kw = 0; kw < 3; kw++) {
            int ww = wq + kw - 1;
            if (ww < 0 || ww > 63) continue;
            acc += wc[kh * 3 + kw] * inp[hh * 64 + ww];
        }
    }
    out[idx] = acc;
}

// ---------------- attention-coefficient mixer ----------------
// grouped 3x3 (24 groups, 2in/1out) + SimpleGate + 1x1 (12->32), att = gamma*a + att(c211)
__global__ __launch_bounds__(256) void attmix_k(const float* __restrict__ xn,
        const float* __restrict__ wA, const float* __restrict__ bA,
        const float* __restrict__ wB, const float* __restrict__ bB,
        const float* __restrict__ gam, float* __restrict__ att)
{
    __shared__ float swA[INTERC * 18], sbA[INTERC], swB[NSET * 12], sbB[NSET], sgam[NSET];
    int tid = threadIdx.x;
    for (int i = tid; i < INTERC * 18; i += 256) swA[i] = wA[i];
    for (int i = tid; i < INTERC; i += 256) sbA[i] = bA[i];
    for (int i = tid; i < NSET * 12; i += 256) swB[i] = wB[i];
    for (int i = tid; i < NSET; i += 256) { sbB[i] = bB[i]; sgam[i] = gam[i]; }
    __syncthreads();
    int pg = blockIdx.x * 256 + tid;
    int b = pg >> 12, p = pg & 4095;
    int h = p >> 6, w = p & 63;
    const float* xb = xn + (size_t)b * CCH * HW;
    float av[INTERC];
#pragma unroll
    for (int o = 0; o < INTERC; o++) {
        float acc = sbA[o];
#pragma unroll
        for (int t = 0; t < 2; t++) {
            const float* ch = xb + (size_t)(o * 2 + t) * HW;
#pragma unroll
            for (int kk = 0; kk < 9; kk++) {
                int hh = h + kk / 3 - 1, ww = w + kk % 3 - 1;
                if (hh >= 0 && hh < 64 && ww >= 0 && ww < 64)
                    acc += swA[o * 18 + t * 9 + kk] * ch[hh * 64 + ww];
            }
        }
        av[o] = acc;
    }
    float sg[12];
#pragma unroll
    for (int i = 0; i < 12; i++) sg[i] = av[i] * av[i + 12];
    for (int n = 0; n < NSET; n++) {
        float s = sbB[n];
#pragma unroll
        for (int i = 0; i < 12; i++) s += swB[n * 12 + i] * sg[i];
        size_t oi = ((size_t)b * NSET + n) * HW + p;
        att[oi] = sgam[n] * s + att[oi];
    }
}

// ---------------- KBA: per-pixel dynamic kernels ----------------
// out[p, g*4+c] = bias + sum_{n,j} a[p,n]*kw[n, g,c,j]*ufpatch[p,g,j];
// x2 = out*ga1 + uf.  2 pixels/thread, kw broadcast from shared, n split in halves of 16.
__global__ __launch_bounds__(128) void kba_k(const float* __restrict__ uf,
        const float* __restrict__ att, const float* __restrict__ kw,
        const float* __restrict__ kb, const float* __restrict__ ga1,
        float* __restrict__ x2out)
{
    __shared__ float kwsh[16 * 144];     // [n16][c4*36]
    __shared__ float kbsh[16 * 4];
    __shared__ float ush[36 * 256];      // [j][px*128 + tid]
    int tid = threadIdx.x;
    int tileBase = blockIdx.x * 256;               // over B*HW (grid.x = 64)
    int p0g = tileBase + tid;
    int p1g = tileBase + 128 + tid;
    int b = p0g >> 12;
    int p0 = p0g & 4095, p1 = p1g & 4095;
    int h0 = p0 >> 6, w0 = p0 & 63;
    int h1 = p1 >> 6, w1 = p1 & 63;
    const float* attb = att + (size_t)b * NSET * HW;

    for (int gi = 0; gi < 4; gi++) {
        int g = blockIdx.y * 4 + gi;
        // stage uf patches for this group (thread-private slots)
        const float* ufb = uf + ((size_t)b * HID + g * 4) * HW;
#pragma unroll
        for (int ci = 0; ci < 4; ci++) {
#pragma unroll
            for (int kk = 0; kk < 9; kk++) {
                int dh = kk / 3 - 1, dw = kk % 3 - 1;
                int j = ci * 9 + kk;
                int ha = h0 + dh, wa = w0 + dw;
                ush[j * 256 + tid] = (ha >= 0 && ha < 64 && wa >= 0 && wa < 64)
                                     ? ufb[(size_t)ci * HW + ha * 64 + wa] : 0.f;
                int hb = h1 + dh, wb = w1 + dw;
                ush[j * 256 + 128 + tid] = (hb >= 0 && hb < 64 && wb >= 0 && wb < 64)
                                     ? ufb[(size_t)ci * HW + hb * 64 + wb] : 0.f;
            }
        }
        float o0[4] = {0.f, 0.f, 0.f, 0.f};
        float o1[4] = {0.f, 0.f, 0.f, 0.f};
        for (int half = 0; half < 2; half++) {
            __syncthreads();
            for (int idx = tid; idx < 16 * 144; idx += 128) {
                int n = idx / 144, m = idx % 144;
                kwsh[idx] = kw[(size_t)(half * 16 + n) * 3456 + g * 144 + m];
            }
            if (tid < 64) {
                int n = tid / 4, c = tid % 4;
                kbsh[tid] = kb[(half * 16 + n) * HID + g * 4 + c];
            }
            __syncthreads();
            float a0[16], a1[16];
#pragma unroll
            for (int n = 0; n < 16; n++) {
                a0[n] = attb[(size_t)(half * 16 + n) * HW + p0];
                a1[n] = attb[(size_t)(half * 16 + n) * HW + p1];
            }
#pragma unroll
            for (int c = 0; c < 4; c++) {
                float s0 = 0.f, s1 = 0.f;
#pragma unroll
                for (int n = 0; n < 16; n++) {
                    float kv = kbsh[n * 4 + c];
                    s0 += a0[n] * kv; s1 += a1[n] * kv;
                }
                for (int j = 0; j < 36; j++) {
                    float t0 = 0.f, t1 = 0.f;
#pragma unroll
                    for (int n = 0; n < 16; n++) {
                        float wv = kwsh[n * 144 + c * 36 + j];
                        t0 += a0[n] * wv; t1 += a1[n] * wv;
                    }
                    s0 += t0 * ush[j * 256 + tid];
                    s1 += t1 * ush[j * 256 + 128 + tid];
                }
                o0[c] += s0; o1[c] += s1;
            }
        }
#pragma unroll
        for (int c = 0; c < 4; c++) {
            int ch = g * 4 + c;
            float ga = ga1[ch];
            float cen0 = ush[(c * 9 + 4) * 256 + tid];
            float cen1 = ush[(c * 9 + 4) * 256 + 128 + tid];
            x2out[((size_t)b * HID + ch) * HW + p0] = o0[c] * ga + cen0;
            x2out[((size_t)b * HID + ch) * HW + p1] = o1[c] * ga + cen1;
        }
        __syncthreads();   // before ush/kwsh reuse next group
    }
}

// ---------------- MDTA: row L2 norms over HW for q and k ----------------
__global__ void rownorm_k(const float* __restrict__ qkv, float* __restrict__ norms)
{
    int r = blockIdx.x;                      // 0..383  (q rows then k rows)
    int which = r / (BATCH * CCH);
    int idx = r % (BATCH * CCH);
    int b = idx / CCH, c = idx % CCH;
    const float* ptr = qkv + ((size_t)b * 3 * CCH + which * CCH + c) * HW;
    __shared__ float red[256];
    float s = 0.f;
    for (int i = threadIdx.x; i < HW; i += 256) { float v = ptr[i]; s += v * v; }
    red[threadIdx.x] = s; __syncthreads();
    for (int st = 128; st; st >>= 1) {
        if (threadIdx.x < st) red[threadIdx.x] += red[threadIdx.x + st];
        __syncthreads();
    }
    if (threadIdx.x == 0) norms[r] = sqrtf(red[0]);
}

// ---------------- MDTA: 6x6 attention logits + softmax per (b,h) ----------------
__global__ __launch_bounds__(256) void attn_k(const float* __restrict__ qkv,
        const float* __restrict__ norms, const float* __restrict__ temp,
        float* __restrict__ attn)
{
    int bh = blockIdx.x; int b = bh >> 3, h = bh & 7;
    int warp = threadIdx.x >> 5, lane = threadIdx.x & 31;
    __shared__ float S[36];
    const float* qb = qkv + ((size_t)b * 3 * CCH + h * DHEAD) * HW;
    const float* kb = qkv + ((size_t)b * 3 * CCH + CCH + h * DHEAD) * HW;
    for (int pi = warp; pi < 36; pi += 8) {
        int i = pi / 6, j = pi % 6;
        const float* qi = qb + (size_t)i * HW;
        const float* kj = kb + (size_t)j * HW;
        float s = 0.f;
        for (int t = lane; t < HW; t += 32) s += qi[t] * kj[t];
#pragma unroll
        for (int off = 16; off; off >>= 1) s += __shfl_down_sync(0xffffffffu, s, off);
        if (lane == 0) S[pi] = s;
    }
    __syncthreads();
    if (threadIdx.x < 6) {
        int i = threadIdx.x;
        float nq = fmaxf(norms[b * CCH + h * DHEAD + i], 1e-12f);
        float tv = temp[h];
        float row[6]; float mx = -1e30f;
#pragma unroll
        for (int j = 0; j < 6; j++) {
            float nk = fmaxf(norms[BATCH * CCH + b * CCH + h * DHEAD + j], 1e-12f);
            row[j] = tv * S[i * 6 + j] / (nq * nk);
            mx = fmaxf(mx, row[j]);
        }
        float sum = 0.f;
#pragma unroll
        for (int j = 0; j < 6; j++) { row[j] = expf(row[j] - mx); sum += row[j]; }
        float inv = 1.f / sum;
#pragma unroll
        for (int j = 0; j < 6; j++)
            attn[((size_t)(b * 8 + h) * 6 + i) * 6 + j] = row[j] * inv;
    }
}

// ---------------- MDTA: attn @ v ----------------
__global__ void av_k(const float* __restrict__ qkv, const float* __restrict__ attn,
                     float* __restrict__ out)
{
    int idx = blockIdx.x * 256 + threadIdx.x;    // B*C*HW
    int p = idx & 4095; int bc = idx >> 12; int b = bc / CCH; int c = bc % CCH;
    int h = c / DHEAD, i = c % DHEAD;
    const float* ar = attn + ((size_t)(b * 8 + h) * 6 + i) * 6;
    const float* vb = qkv + ((size_t)b * 3 * CCH + 2 * CCH + h * DHEAD) * HW + p;
    float acc = 0.f;
#pragma unroll
    for (int j = 0; j < 6; j++) acc += ar[j] * vb[(size_t)j * HW];
    out[idx] = acc;
}

// ---------------- gelu(x1) * x2 ----------------
__global__ void gelumul_k(const float* __restrict__ x1, const float* __restrict__ x2,
                          float* __restrict__ m)
{
    int idx = blockIdx.x * 256 + threadIdx.x;
    float v = x1[idx];
    float ge = 0.5f * v * (1.f + erff(v * 0.70710678118654752f));
    m[idx] = ge * x2[idx];
}

// ---------------- final: kproj(m) fused with residual combine ----------------
__global__ __launch_bounds__(128) void final_k(const float* __restrict__ x,
        const float* __restrict__ m, const float* __restrict__ mdta,
        const float* __restrict__ kproj,
        const float* __restrict__ ca1, const float* __restrict__ ca2,
        float* __restrict__ out)
{
    __shared__ float wp[CCH * HID];
    int tid = threadIdx.x;
    for (int i = tid; i < CCH * HID; i += 128) wp[i] = kproj[i];
    __syncthreads();
    int pg = blockIdx.x * 128 + tid;
    int b = pg >> 12, p = pg & 4095;
    const float* mb = m + (size_t)b * HID * HW + p;
    float mv[HID];
#pragma unroll
    for (int c = 0; c < HID; c++) mv[c] = mb[(size_t)c * HW];
    for (int o = 0; o < CCH; o++) {
        float acc = 0.f;
#pragma unroll
        for (int c = 0; c < HID; c++) acc += wp[o * HID + c] * mv[c];
        size_t oi = ((size_t)b * CCH + o) * HW + p;
        out[oi] = x[oi] + ca1[b * CCH + o] * acc + ca2[b * CCH + o] * mdta[oi];
    }
}

// ---------------- host launcher ----------------
extern "C" void kernel_launch(void* const* d_in, const int* in_sizes, int n_in,
                              void* d_out, int out_size)
{
    const float* x       = (const float*)d_in[0];
    const float* n1w     = (const float*)d_in[1];
    const float* n1b     = (const float*)d_in[2];
    const float* n2w     = (const float*)d_in[3];
    const float* n2b     = (const float*)d_in[4];
    const float* kdw1    = (const float*)d_in[5];
    const float* kdw2    = (const float*)d_in[6];
    const float* kc1a    = (const float*)d_in[7];
    const float* kc1b    = (const float*)d_in[8];
    const float* kproj   = (const float*)d_in[9];
    const float* c2a_w   = (const float*)d_in[10];
    const float* c2a_b   = (const float*)d_in[11];
    const float* c2b_w   = (const float*)d_in[12];
    const float* c2b_b   = (const float*)d_in[13];
    const float* c211_w  = (const float*)d_in[14];
    const float* c211_b  = (const float*)d_in[15];
    const float* kw      = (const float*)d_in[16];
    const float* kb      = (const float*)d_in[17];
    const float* attg    = (const float*)d_in[18];
    const float* ga1     = (const float*)d_in[19];
    const float* temp    = (const float*)d_in[20];
    const float* qkv_w   = (const float*)d_in[21];
    const float* qkv_dww = (const float*)d_in[22];
    const float* mproj_w = (const float*)d_in[23];
    const float* ca1_w   = (const float*)d_in[24];
    const float* ca1_b   = (const float*)d_in[25];
    const float* ca2_w   = (const float*)d_in[26];
    const float* ca2_b   = (const float*)d_in[27];
    float* out = (float*)d_out;

    float* S = nullptr;
    cudaGetSymbolAddress((void**)&S, g_scratch);
    float* xn   = S + OFF_XN;
    float* xm   = S + OFF_XM;
    float* t1   = S + OFF_T1;
    float* t2   = S + OFF_T2;
    float* x1   = S + OFF_X1;
    float* uf   = S + OFF_UF;
    float* att  = S + OFF_ATT;
    float* qkvt = S + OFF_QKVT;
    float* qkv  = S + OFF_QKV;
    float* x2   = S + OFF_X2;
    float* m    = S + OFF_M;
    float* mdin = S + OFF_MDIN;
    float* mdta = S + OFF_MDTA;
    float* gap  = S + OFF_GAP;
    float* ca1  = S + OFF_CA1;
    float* ca2  = S + OFF_CA2;
    float* nrm  = S + OFF_NORMS;
    float* attn = S + OFF_ATTN;

    const int PIX = BATCH * HW;              // 16384

    // channel attention scalars
    gap_k<<<BATCH * CCH, 256>>>(x, gap);
    ca_k<<<1, 256>>>(gap, ca1_w, ca1_b, ca2_w, ca2_b, ca1, ca2);

    // layernorms
    ln_k<<<PIX / 256, 256>>>(x, n1w, n1b, n2w, n2b, xn, xm);

    // KBA branch inputs
    conv1x1_k<CCH, HID, false><<<PIX / 128, 128>>>(xn, kdw1, nullptr, t1);
    conv1x1_k<CCH, HID, false><<<PIX / 128, 128>>>(xn, kc1a, nullptr, t2);
    conv1x1_k<CCH, NSET, true><<<PIX / 128, 128>>>(xn, c211_w, c211_b, att);
    dw3x3_k<HID><<<BATCH * HID * HW / 256, 256>>>(t1, kdw2, x1);
    dw3x3_k<HID><<<BATCH * HID * HW / 256, 256>>>(t2, kc1b, uf);
    attmix_k<<<PIX / 256, 256>>>(xn, c2a_w, c2a_b, c2b_w, c2b_b, attg, att);

    // MDTA branch
    conv1x1_k<CCH, 3 * CCH, false><<<PIX / 128, 128>>>(xm, qkv_w, nullptr, qkvt);
    dw3x3_k<3 * CCH><<<BATCH * 3 * CCH * HW / 256, 256>>>(qkvt, qkv_dww, qkv);
    rownorm_k<<<2 * BATCH * CCH, 256>>>(qkv, nrm);
    attn_k<<<BATCH * HEADS, 256>>>(qkv, nrm, temp, attn);
    av_k<<<BATCH * CCH * HW / 256, 256>>>(qkv, attn, mdin);
    conv1x1_k<CCH, CCH, false><<<PIX / 128, 128>>>(mdin, mproj_w, nullptr, mdta);

    // KBA core
    {
        dim3 grid(PIX / 256, 6);
        kba_k<<<grid, 128>>>(uf, att, kw, kb, ga1, x2);
    }
    gelumul_k<<<BATCH * HID * HW / 256, 256>>>(x1, x2, m);

    // projection + residual combine
    final_k<<<PIX / 128, 128>>>(x, m, mdta, kproj, ca1, ca2, out);
}

// round 2
// speedup vs baseline: 1.1540x; 1.1540x over previous
#include <cuda_runtime.h>
#include <math.h>

// ---------------- problem constants ----------------
#define BATCH 4
#define CCH   48
#define HW    4096
#define HID   96
#define NSET  32
#define HEADS 8
#define DHEAD 6
#define INTERC 24

typedef unsigned long long u64;
__device__ __forceinline__ u64 pk2(float lo, float hi){ u64 r; asm("mov.b64 %0,{%1,%2};":"=l"(r):"f"(lo),"f"(hi)); return r; }
__device__ __forceinline__ u64 dup2(float v){ return pk2(v, v); }
__device__ __forceinline__ void up2(u64 v, float& lo, float& hi){ asm("mov.b64 {%0,%1},%2;":"=f"(lo),"=f"(hi):"l"(v)); }
__device__ __forceinline__ u64 fma2_(u64 a, u64 b, u64 c){ u64 d; asm("fma.rn.f32x2 %0,%1,%2,%3;":"=l"(d):"l"(a),"l"(b),"l"(c)); return d; }

// ---------------- scratch layout ----------------
#define OFF_XN    0LL
#define OFF_XM    (OFF_XN   + (long long)BATCH*CCH*HW)
#define OFF_T1    (OFF_XM   + (long long)BATCH*CCH*HW)
#define OFF_T2    (OFF_T1   + (long long)BATCH*HID*HW)
#define OFF_X1    (OFF_T2   + (long long)BATCH*HID*HW)
#define OFF_UF    (OFF_X1   + (long long)BATCH*HID*HW)
#define OFF_ATT   (OFF_UF   + (long long)BATCH*HID*HW)
#define OFF_QKVT  (OFF_ATT  + (long long)BATCH*NSET*HW)
#define OFF_QKV   (OFF_QKVT + (long long)BATCH*3*CCH*HW)
#define OFF_X2    (OFF_QKV  + (long long)BATCH*3*CCH*HW)
#define OFF_M     (OFF_X2   + (long long)BATCH*HID*HW)
#define OFF_MDIN  (OFF_M    + (long long)BATCH*HID*HW)
#define OFF_MDTA  (OFF_MDIN + (long long)BATCH*CCH*HW)
#define OFF_GAP   (OFF_MDTA + (long long)BATCH*CCH*HW)
#define OFF_CA1   (OFF_GAP  + BATCH*CCH)
#define OFF_CA2   (OFF_CA1  + BATCH*CCH)
#define OFF_NORMS (OFF_CA2  + BATCH*CCH)
#define OFF_ATTN  (OFF_NORMS + 2*BATCH*CCH)
#define SCRATCH_TOTAL (OFF_ATTN + BATCH*HEADS*DHEAD*DHEAD)

__device__ float g_scratch[SCRATCH_TOTAL];

// ---------------- gap ----------------
__global__ void gap_k(const float* __restrict__ x, float* __restrict__ gap)
{
    int bc = blockIdx.x;
    const float* xb = x + (size_t)bc * HW;
    __shared__ float red[256];
    float s = 0.f;
    for (int i = threadIdx.x; i < HW; i += 256) s += xb[i];
    red[threadIdx.x] = s; __syncthreads();
    for (int st = 128; st; st >>= 1) {
        if (threadIdx.x < st) red[threadIdx.x] += red[threadIdx.x + st];
        __syncthreads();
    }
    if (threadIdx.x == 0) gap[bc] = red[0] * (1.f / HW);
}

// ---------------- channel attention ----------------
__global__ void ca_k(const float* __restrict__ gap,
                     const float* __restrict__ w1, const float* __restrict__ b1,
                     const float* __restrict__ w2, const float* __restrict__ b2,
                     float* __restrict__ ca1, float* __restrict__ ca2)
{
    int t = threadIdx.x;
    if (t >= BATCH * CCH) return;
    int b = t / CCH, o = t % CCH;
    float s1 = b1[o], s2 = b2[o];
    for (int c = 0; c < CCH; c++) {
        float g = gap[b * CCH + c];
        s1 += w1[o * CCH + c] * g;
        s2 += w2[o * CCH + c] * g;
    }
    ca1[t] = s1; ca2[t] = s2;
}

// ---------------- LayerNorm2d ----------------
__global__ __launch_bounds__(256) void ln_k(const float* __restrict__ x,
        const float* __restrict__ n1w, const float* __restrict__ n1b,
        const float* __restrict__ n2w, const float* __restrict__ n2b,
        float* __restrict__ xn, float* __restrict__ xm)
{
    int pg = blockIdx.x * 256 + threadIdx.x;
    int b = pg >> 12, p = pg & 4095;
    const float* xb = x + (size_t)b * CCH * HW + p;
    float v[CCH];
    float s = 0.f, s2 = 0.f;
#pragma unroll
    for (int c = 0; c < CCH; c++) { float t = xb[(size_t)c * HW]; v[c] = t; s += t; s2 += t * t; }
    float mu = s * (1.f / CCH);
    float var = s2 * (1.f / CCH) - mu * mu;
    float r = rsqrtf(var + 1e-6f);
    float* xnb = xn + (size_t)b * CCH * HW + p;
    float* xmb = xm + (size_t)b * CCH * HW + p;
#pragma unroll
    for (int c = 0; c < CCH; c++) {
        float y = (v[c] - mu) * r;
        xnb[(size_t)c * HW] = n1w[c] * y + n1b[c];
        xmb[(size_t)c * HW] = n2w[c] * y + n2b[c];
    }
}

// ---------------- packed 1x1 conv: 2 px/thread, out-channel split ----------------
template <int INC, int OUTC, int OSPL, bool HASB>
__global__ __launch_bounds__(128) void conv1x1p_k(const float* __restrict__ in,
        const float* __restrict__ w, const float* __restrict__ bias,
        float* __restrict__ out)
{
    __shared__ u64 ws2[OSPL * INC];
    __shared__ u64 bs2[OSPL];
    int tid = threadIdx.x;
    int o0 = blockIdx.y * OSPL;
    for (int i = tid; i < OSPL * INC; i += 128)
        ws2[i] = dup2(w[(o0 + i / INC) * INC + i % INC]);
    if (HASB) for (int i = tid; i < OSPL; i += 128) bs2[i] = dup2(bias[o0 + i]);
    __syncthreads();
    int p2 = blockIdx.x * 256 + tid * 2;
    int b = p2 >> 12, pp = p2 & 4095;
    const float* inb = in + (size_t)b * INC * HW + pp;
    u64 xv[INC];
#pragma unroll
    for (int c = 0; c < INC; c++) xv[c] = *(const u64*)(inb + (size_t)c * HW);
    float* outb = out + ((size_t)b * OUTC + o0) * HW + pp;
    for (int o = 0; o < OSPL; o++) {
        u64 acc = HASB ? bs2[o] : 0ULL;
#pragma unroll
        for (int c = 0; c < INC; c++) acc = fma2_(ws2[o * INC + c], xv[c], acc);
        *(u64*)(outb + (size_t)o * HW) = acc;
    }
}

// ---------------- depthwise 3x3, pad 1 ----------------
template <int CH>
__global__ void dw3x3_k(const float* __restrict__ in, const float* __restrict__ w,
                        float* __restrict__ out)
{
    int idx = blockIdx.x * 256 + threadIdx.x;
    int p = idx & 4095; int bc = idx >> 12; int c = bc % CH;
    int h = p >> 6, wq = p & 63;
    const float* inp = in + (size_t)bc * HW;
    const float* wc = w + c * 9;
    float acc = 0.f;
#pragma unroll
    for (int kh = 0; kh < 3; kh++) {
        int hh = h + kh - 1;
        if (hh < 0 || hh > 63) continue;
#pragma unroll
        for (int kw = 0; kw < 3; kw++) {
            int ww = wq + kw - 1;
            if (ww < 0 || ww > 63) continue;
            acc += wc[kh * 3 + kw] * inp[hh * 64 + ww];
        }
    }
    out[idx] = acc;
}

// ---------------- attention-coefficient mixer ----------------
__global__ __launch_bounds__(256) void attmix_k(const float* __restrict__ xn,
        const float* __restrict__ wA, const float* __restrict__ bA,
        const float* __restrict__ wB, const float* __restrict__ bB,
        const float* __restrict__ gam, float* __restrict__ att)
{
    __shared__ float swA[INTERC * 18], sbA[INTERC], swB[NSET * 12], sbB[NSET], sgam[NSET];
    int tid = threadIdx.x;
    for (int i = tid; i < INTERC * 18; i += 256) swA[i] = wA[i];
    for (int i = tid; i < INTERC; i += 256) sbA[i] = bA[i];
    for (int i = tid; i < NSET * 12; i += 256) swB[i] = wB[i];
    for (int i = tid; i < NSET; i += 256) { sbB[i] = bB[i]; sgam[i] = gam[i]; }
    __syncthreads();
    int pg = blockIdx.x * 256 + tid;
    int b = pg >> 12, p = pg & 4095;
    int h = p >> 6, w = p & 63;
    const float* xb = xn + (size_t)b * CCH * HW;
    float av[INTERC];
#pragma unroll
    for (int o = 0; o < INTERC; o++) {
        float acc = sbA[o];
#pragma unroll
        for (int t = 0; t < 2; t++) {
            const float* ch = xb + (size_t)(o * 2 + t) * HW;
#pragma unroll
            for (int kk = 0; kk < 9; kk++) {
                int hh = h + kk / 3 - 1, ww = w + kk % 3 - 1;
                if (hh >= 0 && hh < 64 && ww >= 0 && ww < 64)
                    acc += swA[o * 18 + t * 9 + kk] * ch[hh * 64 + ww];
            }
        }
        av[o] = acc;
    }
    float sg[12];
#pragma unroll
    for (int i = 0; i < 12; i++) sg[i] = av[i] * av[i + 12];
    for (int n = 0; n < NSET; n++) {
        float s = sbB[n];
#pragma unroll
        for (int i = 0; i < 12; i++) s += swB[n * 12 + i] * sg[i];
        size_t oi = ((size_t)b * NSET + n) * HW + p;
        att[oi] = sgam[n] * s + att[oi];
    }
}

// ---------------- KBA core: f32x2 packed, 2 px/thread ----------------
__global__ __launch_bounds__(128) void kba_k(const float* __restrict__ uf,
        const float* __restrict__ att, const float* __restrict__ kw,
        const float* __restrict__ kb, const float* __restrict__ ga1,
        float* __restrict__ x2out)
{
    __shared__ u64 kwsh[16 * 144];       // duplicated f32x2 weights
    __shared__ u64 kbsh[16 * 4];
    __shared__ u64 ush[36 * 128];        // [j][tid] = packed pixel pair
    float* ushf = (float*)ush;
    int tid = threadIdx.x;
    int p2 = blockIdx.x * 256 + tid * 2;         // two adjacent pixels, same row
    int b = p2 >> 12, pp = p2 & 4095;
    int h = pp >> 6, w = pp & 63;                // w even
    const float* attb = att + (size_t)b * NSET * HW + pp;

    for (int gi = 0; gi < 4; gi++) {
        int g = blockIdx.y * 4 + gi;
        const float* ufb = uf + ((size_t)b * HID + g * 4) * HW;
        // stage per-pixel patches (thread-private slots -> no cross-thread hazard)
#pragma unroll
        for (int ci = 0; ci < 4; ci++) {
#pragma unroll
            for (int kk = 0; kk < 9; kk++) {
                int dh = kk / 3 - 1, dw = kk % 3 - 1;
                int j = ci * 9 + kk;
                int hh = h + dh;
                float v0 = 0.f, v1 = 0.f;
                if (hh >= 0 && hh < 64) {
                    const float* row = ufb + (size_t)ci * HW + hh * 64;
                    int wa = w + dw;
                    if (wa >= 0 && wa < 64) v0 = row[wa];
                    int wb = w + 1 + dw;
                    if (wb >= 0 && wb < 64) v1 = row[wb];
                }
                ushf[j * 256 + 2 * tid]     = v0;
                ushf[j * 256 + 2 * tid + 1] = v1;
            }
        }
        u64 o2[4] = {0ULL, 0ULL, 0ULL, 0ULL};
        for (int half = 0; half < 2; half++) {
            __syncthreads();     // protect kwsh refill vs previous readers
            for (int idx = tid; idx < 16 * 144; idx += 128) {
                int n = idx / 144, m2 = idx % 144;
                kwsh[idx] = dup2(kw[(size_t)(half * 16 + n) * 3456 + g * 144 + m2]);
            }
            if (tid < 64)
                kbsh[tid] = dup2(kb[(half * 16 + tid / 4) * HID + g * 4 + (tid & 3)]);
            __syncthreads();
            u64 a2[16];
#pragma unroll
            for (int n = 0; n < 16; n++)
                a2[n] = *(const u64*)(attb + (size_t)(half * 16 + n) * HW);
#pragma unroll
            for (int c = 0; c < 4; c++) {
                u64 s = o2[c];
#pragma unroll
                for (int n = 0; n < 16; n++) s = fma2_(a2[n], kbsh[n * 4 + c], s);
                for (int j = 0; j < 36; j++) {
                    u64 t = 0ULL;
#pragma unroll
                    for (int n = 0; n < 16; n++)
                        t = fma2_(a2[n], kwsh[n * 144 + c * 36 + j], t);
                    s = fma2_(t, ush[j * 128 + tid], s);
                }
                o2[c] = s;
            }
        }
#pragma unroll
        for (int c = 0; c < 4; c++) {
            int ch = g * 4 + c;
            float ga = ga1[ch];
            float lo, hi; up2(o2[c], lo, hi);
            float c0 = ushf[(c * 9 + 4) * 256 + 2 * tid];
            float c1 = ushf[(c * 9 + 4) * 256 + 2 * tid + 1];
            *(u64*)(x2out + ((size_t)b * HID + ch) * HW + pp) = pk2(lo * ga + c0, hi * ga + c1);
        }
        __syncthreads();    // ush restage next group happens before next kwsh sync anyway; keep for safety of center reads
    }
}

// ---------------- MDTA: row L2 norms ----------------
__global__ void rownorm_k(const float* __restrict__ qkv, float* __restrict__ norms)
{
    int r = blockIdx.x;
    int which = r / (BATCH * CCH);
    int idx = r % (BATCH * CCH);
    int b = idx / CCH, c = idx % CCH;
    const float* ptr = qkv + ((size_t)b * 3 * CCH + which * CCH + c) * HW;
    __shared__ float red[256];
    float s = 0.f;
    for (int i = threadIdx.x; i < HW; i += 256) { float v = ptr[i]; s += v * v; }
    red[threadIdx.x] = s; __syncthreads();
    for (int st = 128; st; st >>= 1) {
        if (threadIdx.x < st) red[threadIdx.x] += red[threadIdx.x + st];
        __syncthreads();
    }
    if (threadIdx.x == 0) norms[r] = sqrtf(red[0]);
}

// ---------------- MDTA: 6x6 attention + softmax ----------------
__global__ __launch_bounds__(256) void attn_k(const float* __restrict__ qkv,
        const float* __restrict__ norms, const float* __restrict__ temp,
        float* __restrict__ attn)
{
    int bh = blockIdx.x; int b = bh >> 3, h = bh & 7;
    int warp = threadIdx.x >> 5, lane = threadIdx.x & 31;
    __shared__ float S[36];
    const float* qb = qkv + ((size_t)b * 3 * CCH + h * DHEAD) * HW;
    const float* kb = qkv + ((size_t)b * 3 * CCH + CCH + h * DHEAD) * HW;
    for (int pi = warp; pi < 36; pi += 8) {
        int i = pi / 6, j = pi % 6;
        const float* qi = qb + (size_t)i * HW;
        const float* kj = kb + (size_t)j * HW;
        float s = 0.f;
        for (int t = lane; t < HW; t += 32) s += qi[t] * kj[t];
#pragma unroll
        for (int off = 16; off; off >>= 1) s += __shfl_down_sync(0xffffffffu, s, off);
        if (lane == 0) S[pi] = s;
    }
    __syncthreads();
    if (threadIdx.x < 6) {
        int i = threadIdx.x;
        float nq = fmaxf(norms[b * CCH + h * DHEAD + i], 1e-12f);
        float tv = temp[h];
        float row[6]; float mx = -1e30f;
#pragma unroll
        for (int j = 0; j < 6; j++) {
            float nk = fmaxf(norms[BATCH * CCH + b * CCH + h * DHEAD + j], 1e-12f);
            row[j] = tv * S[i * 6 + j] / (nq * nk);
            mx = fmaxf(mx, row[j]);
        }
        float sum = 0.f;
#pragma unroll
        for (int j = 0; j < 6; j++) { row[j] = expf(row[j] - mx); sum += row[j]; }
        float inv = 1.f / sum;
#pragma unroll
        for (int j = 0; j < 6; j++)
            attn[((size_t)(b * 8 + h) * 6 + i) * 6 + j] = row[j] * inv;
    }
}

// ---------------- MDTA: attn @ v ----------------
__global__ void av_k(const float* __restrict__ qkv, const float* __restrict__ attn,
                     float* __restrict__ out)
{
    int idx = blockIdx.x * 256 + threadIdx.x;
    int p = idx & 4095; int bc = idx >> 12; int b = bc / CCH; int c = bc % CCH;
    int h = c / DHEAD, i = c % DHEAD;
    const float* ar = attn + ((size_t)(b * 8 + h) * 6 + i) * 6;
    const float* vb = qkv + ((size_t)b * 3 * CCH + 2 * CCH + h * DHEAD) * HW + p;
    float acc = 0.f;
#pragma unroll
    for (int j = 0; j < 6; j++) acc += ar[j] * vb[(size_t)j * HW];
    out[idx] = acc;
}

// ---------------- gelu(x1) * x2 ----------------
__global__ void gelumul_k(const float* __restrict__ x1, const float* __restrict__ x2,
                          float* __restrict__ m)
{
    int idx = blockIdx.x * 256 + threadIdx.x;
    float v = x1[idx];
    float ge = 0.5f * v * (1.f + erff(v * 0.70710678118654752f));
    m[idx] = ge * x2[idx];
}

// ---------------- final: kproj + residual combine (packed) ----------------
__global__ __launch_bounds__(128) void final_k(const float* __restrict__ x,
        const float* __restrict__ m, const float* __restrict__ mdta,
        const float* __restrict__ kproj,
        const float* __restrict__ ca1, const float* __restrict__ ca2,
        float* __restrict__ out)
{
    __shared__ u64 wp2[24 * HID];
    int tid = threadIdx.x;
    int o0 = blockIdx.y * 24;
    for (int i = tid; i < 24 * HID; i += 128)
        wp2[i] = dup2(kproj[(o0 + i / HID) * HID + i % HID]);
    __syncthreads();
    int p2 = blockIdx.x * 256 + tid * 2;
    int b = p2 >> 12, pp = p2 & 4095;
    const float* mb = m + (size_t)b * HID * HW + pp;
    u64 acc[24];
#pragma unroll
    for (int o = 0; o < 24; o++) acc[o] = 0ULL;
    for (int c = 0; c < HID; c++) {
        u64 mv = *(const u64*)(mb + (size_t)c * HW);
#pragma unroll
        for (int o = 0; o < 24; o++) acc[o] = fma2_(wp2[o * HID + c], mv, acc[o]);
    }
#pragma unroll
    for (int o = 0; o < 24; o++) {
        int oc = o0 + o;
        size_t oi = ((size_t)b * CCH + oc) * HW + pp;
        float a1 = ca1[b * CCH + oc], a2 = ca2[b * CCH + oc];
        float lo, hi; up2(acc[o], lo, hi);
        float x0 = x[oi], x1v = x[oi + 1];
        float d0 = mdta[oi], d1 = mdta[oi + 1];
        *(u64*)(out + oi) = pk2(x0 + a1 * lo + a2 * d0, x1v + a1 * hi + a2 * d1);
    }
}

// ---------------- host launcher ----------------
extern "C" void kernel_launch(void* const* d_in, const int* in_sizes, int n_in,
                              void* d_out, int out_size)
{
    const float* x       = (const float*)d_in[0];
    const float* n1w     = (const float*)d_in[1];
    const float* n1b     = (const float*)d_in[2];
    const float* n2w     = (const float*)d_in[3];
    const float* n2b     = (const float*)d_in[4];
    const float* kdw1    = (const float*)d_in[5];
    const float* kdw2    = (const float*)d_in[6];
    const float* kc1a    = (const float*)d_in[7];
    const float* kc1b    = (const float*)d_in[8];
    const float* kproj   = (const float*)d_in[9];
    const float* c2a_w   = (const float*)d_in[10];
    const float* c2a_b   = (const float*)d_in[11];
    const float* c2b_w   = (const float*)d_in[12];
    const float* c2b_b   = (const float*)d_in[13];
    const float* c211_w  = (const float*)d_in[14];
    const float* c211_b  = (const float*)d_in[15];
    const float* kw      = (const float*)d_in[16];
    const float* kb      = (const float*)d_in[17];
    const float* attg    = (const float*)d_in[18];
    const float* ga1     = (const float*)d_in[19];
    const float* temp    = (const float*)d_in[20];
    const float* qkv_w   = (const float*)d_in[21];
    const float* qkv_dww = (const float*)d_in[22];
    const float* mproj_w = (const float*)d_in[23];
    const float* ca1_w   = (const float*)d_in[24];
    const float* ca1_b   = (const float*)d_in[25];
    const float* ca2_w   = (const float*)d_in[26];
    const float* ca2_b   = (const float*)d_in[27];
    float* out = (float*)d_out;

    float* S = nullptr;
    cudaGetSymbolAddress((void**)&S, g_scratch);
    float* xn   = S + OFF_XN;
    float* xm   = S + OFF_XM;
    float* t1   = S + OFF_T1;
    float* t2   = S + OFF_T2;
    float* x1   = S + OFF_X1;
    float* uf   = S + OFF_UF;
    float* att  = S + OFF_ATT;
    float* qkvt = S + OFF_QKVT;
    float* qkv  = S + OFF_QKV;
    float* x2   = S + OFF_X2;
    float* m    = S + OFF_M;
    float* mdin = S + OFF_MDIN;
    float* mdta = S + OFF_MDTA;
    float* gap  = S + OFF_GAP;
    float* ca1  = S + OFF_CA1;
    float* ca2  = S + OFF_CA2;
    float* nrm  = S + OFF_NORMS;
    float* attn = S + OFF_ATTN;

    const int PIX = BATCH * HW;              // 16384
    const int XB = PIX / 256;                // 64 (2 px per thread, 128 threads)

    gap_k<<<BATCH * CCH, 256>>>(x, gap);
    ca_k<<<1, 256>>>(gap, ca1_w, ca1_b, ca2_w, ca2_b, ca1, ca2);

    ln_k<<<PIX / 256, 256>>>(x, n1w, n1b, n2w, n2b, xn, xm);

    // KBA branch inputs (packed 1x1 convs)
    conv1x1p_k<CCH, HID, 24, false><<<dim3(XB, 4), 128>>>(xn, kdw1, nullptr, t1);
    conv1x1p_k<CCH, HID, 24, false><<<dim3(XB, 4), 128>>>(xn, kc1a, nullptr, t2);
    conv1x1p_k<CCH, NSET, 8, true><<<dim3(XB, 4), 128>>>(xn, c211_w, c211_b, att);
    dw3x3_k<HID><<<BATCH * HID * HW / 256, 256>>>(t1, kdw2, x1);
    dw3x3_k<HID><<<BATCH * HID * HW / 256, 256>>>(t2, kc1b, uf);
    attmix_k<<<PIX / 256, 256>>>(xn, c2a_w, c2a_b, c2b_w, c2b_b, attg, att);

    // MDTA branch
    conv1x1p_k<CCH, 3 * CCH, 24, false><<<dim3(XB, 6), 128>>>(xm, qkv_w, nullptr, qkvt);
    dw3x3_k<3 * CCH><<<BATCH * 3 * CCH * HW / 256, 256>>>(qkvt, qkv_dww, qkv);
    rownorm_k<<<2 * BATCH * CCH, 256>>>(qkv, nrm);
    attn_k<<<BATCH * HEADS, 256>>>(qkv, nrm, temp, attn);
    av_k<<<BATCH * CCH * HW / 256, 256>>>(qkv, attn, mdin);
    conv1x1p_k<CCH, CCH, 12, false><<<dim3(XB, 4), 128>>>(mdin, mproj_w, nullptr, mdta);

    // KBA core
    kba_k<<<dim3(XB, 6), 128>>>(uf, att, kw, kb, ga1, x2);
    gelumul_k<<<BATCH * HID * HW / 256, 256>>>(x1, x2, m);

    // projection + residual
    final_k<<<dim3(XB, 2), 128>>>(x, m, mdta, kproj, ca1, ca2, out);
}

// round 3
// speedup vs baseline: 1.2838x; 1.1125x over previous
#include <cuda_runtime.h>
#include <math.h>

// ---------------- problem constants ----------------
#define BATCH 4
#define CCH   48
#define HW    4096
#define HID   96
#define NSET  32
#define HEADS 8
#define DHEAD 6
#define INTERC 24

typedef unsigned long long u64;
__device__ __forceinline__ u64 pk2(float lo, float hi){ u64 r; asm("mov.b64 %0,{%1,%2};":"=l"(r):"f"(lo),"f"(hi)); return r; }
__device__ __forceinline__ u64 dup2(float v){ return pk2(v, v); }
__device__ __forceinline__ void up2(u64 v, float& lo, float& hi){ asm("mov.b64 {%0,%1},%2;":"=f"(lo),"=f"(hi):"l"(v)); }
__device__ __forceinline__ u64 fma2_(u64 a, u64 b, u64 c){ u64 d; asm("fma.rn.f32x2 %0,%1,%2,%3;":"=l"(d):"l"(a),"l"(b),"l"(c)); return d; }
__device__ __forceinline__ u64 add2_(u64 a, u64 b){ u64 d; asm("add.rn.f32x2 %0,%1,%2;":"=l"(d):"l"(a),"l"(b)); return d; }

// ---------------- scratch layout ----------------
#define OFF_XN    0LL
#define OFF_XM    (OFF_XN   + (long long)BATCH*CCH*HW)
#define OFF_T1    (OFF_XM   + (long long)BATCH*CCH*HW)
#define OFF_T2    (OFF_T1   + (long long)BATCH*HID*HW)
#define OFF_X1    (OFF_T2   + (long long)BATCH*HID*HW)
#define OFF_UF    (OFF_X1   + (long long)BATCH*HID*HW)
#define OFF_ATT   (OFF_UF   + (long long)BATCH*HID*HW)
#define OFF_QKVT  (OFF_ATT  + (long long)BATCH*NSET*HW)
#define OFF_QKV   (OFF_QKVT + (long long)BATCH*3*CCH*HW)
#define OFF_X2    (OFF_QKV  + (long long)BATCH*3*CCH*HW)
#define OFF_M     (OFF_X2   + (long long)BATCH*HID*HW)
#define OFF_MDIN  (OFF_M    + (long long)BATCH*HID*HW)
#define OFF_MDTA  (OFF_MDIN + (long long)BATCH*CCH*HW)
#define OFF_GAP   (OFF_MDTA + (long long)BATCH*CCH*HW)
#define OFF_CA1   (OFF_GAP  + BATCH*CCH)
#define OFF_CA2   (OFF_CA1  + BATCH*CCH)
#define OFF_NORMS (OFF_CA2  + BATCH*CCH)
#define OFF_ATTN  (OFF_NORMS + 2*BATCH*CCH)
#define SCRATCH_TOTAL (OFF_ATTN + BATCH*HEADS*DHEAD*DHEAD)

__device__ float g_scratch[SCRATCH_TOTAL];

// ---------------- gap ----------------
__global__ void gap_k(const float* __restrict__ x, float* __restrict__ gap)
{
    int bc = blockIdx.x;
    const float* xb = x + (size_t)bc * HW;
    __shared__ float red[256];
    float s = 0.f;
    for (int i = threadIdx.x; i < HW; i += 256) s += xb[i];
    red[threadIdx.x] = s; __syncthreads();
    for (int st = 128; st; st >>= 1) {
        if (threadIdx.x < st) red[threadIdx.x] += red[threadIdx.x + st];
        __syncthreads();
    }
    if (threadIdx.x == 0) gap[bc] = red[0] * (1.f / HW);
}

// ---------------- channel attention ----------------
__global__ void ca_k(const float* __restrict__ gap,
                     const float* __restrict__ w1, const float* __restrict__ b1,
                     const float* __restrict__ w2, const float* __restrict__ b2,
                     float* __restrict__ ca1, float* __restrict__ ca2)
{
    int t = threadIdx.x;
    if (t >= BATCH * CCH) return;
    int b = t / CCH, o = t % CCH;
    float s1 = b1[o], s2 = b2[o];
    for (int c = 0; c < CCH; c++) {
        float g = gap[b * CCH + c];
        s1 += w1[o * CCH + c] * g;
        s2 += w2[o * CCH + c] * g;
    }
    ca1[t] = s1; ca2[t] = s2;
}

// ---------------- LayerNorm2d ----------------
__global__ __launch_bounds__(256) void ln_k(const float* __restrict__ x,
        const float* __restrict__ n1w, const float* __restrict__ n1b,
        const float* __restrict__ n2w, const float* __restrict__ n2b,
        float* __restrict__ xn, float* __restrict__ xm)
{
    int pg = blockIdx.x * 256 + threadIdx.x;
    int b = pg >> 12, p = pg & 4095;
    const float* xb = x + (size_t)b * CCH * HW + p;
    float v[CCH];
    float s = 0.f, s2 = 0.f;
#pragma unroll
    for (int c = 0; c < CCH; c++) { float t = xb[(size_t)c * HW]; v[c] = t; s += t; s2 += t * t; }
    float mu = s * (1.f / CCH);
    float var = s2 * (1.f / CCH) - mu * mu;
    float r = rsqrtf(var + 1e-6f);
    float* xnb = xn + (size_t)b * CCH * HW + p;
    float* xmb = xm + (size_t)b * CCH * HW + p;
#pragma unroll
    for (int c = 0; c < CCH; c++) {
        float y = (v[c] - mu) * r;
        xnb[(size_t)c * HW] = n1w[c] * y + n1b[c];
        xmb[(size_t)c * HW] = n2w[c] * y + n2b[c];
    }
}

// ---------------- generic packed 1x1 conv (chunked input) ----------------
template <int INC, int OUTC, int OSPL, bool HASB>
__global__ __launch_bounds__(128) void conv1x1p_k(const float* __restrict__ in,
        const float* __restrict__ w, const float* __restrict__ bias,
        float* __restrict__ out)
{
    __shared__ u64 ws2[OSPL * INC];
    __shared__ u64 bs2[OSPL > 0 ? OSPL : 1];
    int tid = threadIdx.x;
    int o0 = blockIdx.y * OSPL;
    for (int i = tid; i < OSPL * INC; i += 128)
        ws2[i] = dup2(w[(o0 + i / INC) * INC + i % INC]);
    if (HASB) for (int i = tid; i < OSPL; i += 128) bs2[i] = dup2(bias[o0 + i]);
    __syncthreads();
    int p2 = blockIdx.x * 256 + tid * 2;
    int b = p2 >> 12, pp = p2 & 4095;
    const float* inb = in + (size_t)b * INC * HW + pp;
    u64 acc[OSPL];
#pragma unroll
    for (int o = 0; o < OSPL; o++) acc[o] = HASB ? bs2[o] : 0ULL;
    for (int cc = 0; cc < INC; cc += 16) {
        u64 xv[16];
#pragma unroll
        for (int c = 0; c < 16; c++) xv[c] = *(const u64*)(inb + (size_t)(cc + c) * HW);
#pragma unroll
        for (int o = 0; o < OSPL; o++) {
            u64 a = acc[o];
#pragma unroll
            for (int c = 0; c < 16; c++) a = fma2_(ws2[o * INC + cc + c], xv[c], a);
            acc[o] = a;
        }
    }
    float* outb = out + ((size_t)b * OUTC + o0) * HW + pp;
#pragma unroll
    for (int o = 0; o < OSPL; o++) *(u64*)(outb + (size_t)o * HW) = acc[o];
}

// ---------------- fused: 3 conv1x1s reading xn (kdw1->t1, kc1a->t2, c211->att) ----------------
__global__ __launch_bounds__(128) void fused3_k(const float* __restrict__ xn,
        const float* __restrict__ w1, const float* __restrict__ w2,
        const float* __restrict__ w3, const float* __restrict__ b3,
        float* __restrict__ t1, float* __restrict__ t2, float* __restrict__ att)
{
    __shared__ u64 ws2[16 * CCH];
    __shared__ u64 bs2[16];
    int tid = threadIdx.x;
    int y = blockIdx.y;                 // 0..13
    const float* w; float* outp; int ol; int outc; bool hasb;
    if (y < 6)       { w = w1; outp = t1;  ol = y * 16;        outc = HID;  hasb = false; }
    else if (y < 12) { w = w2; outp = t2;  ol = (y - 6) * 16;  outc = HID;  hasb = false; }
    else             { w = w3; outp = att; ol = (y - 12) * 16; outc = NSET; hasb = true;  }
    for (int i = tid; i < 16 * CCH; i += 128)
        ws2[i] = dup2(w[(ol + i / CCH) * CCH + i % CCH]);
    if (hasb) { if (tid < 16) bs2[tid] = dup2(b3[ol + tid]); }
    __syncthreads();
    int p2 = blockIdx.x * 256 + tid * 2;
    int b = p2 >> 12, pp = p2 & 4095;
    const float* inb = xn + (size_t)b * CCH * HW + pp;
    u64 acc[16];
#pragma unroll
    for (int o = 0; o < 16; o++) acc[o] = hasb ? bs2[o] : 0ULL;
    for (int cc = 0; cc < CCH; cc += 16) {
        u64 xv[16];
#pragma unroll
        for (int c = 0; c < 16; c++) xv[c] = *(const u64*)(inb + (size_t)(cc + c) * HW);
#pragma unroll
        for (int o = 0; o < 16; o++) {
            u64 a = acc[o];
#pragma unroll
            for (int c = 0; c < 16; c++) a = fma2_(ws2[o * CCH + cc + c], xv[c], a);
            acc[o] = a;
        }
    }
    float* outb = outp + ((size_t)b * outc + ol) * HW + pp;
#pragma unroll
    for (int o = 0; o < 16; o++) *(u64*)(outb + (size_t)o * HW) = acc[o];
}

// ---------------- depthwise 3x3, pad 1, 2 px/thread ----------------
__global__ void dw3x3_k(const float* __restrict__ in, const float* __restrict__ w,
                        float* __restrict__ out, int CH)
{
    int idx2 = (blockIdx.x * 256 + threadIdx.x) * 2;
    int p = idx2 & 4095; int bc = idx2 >> 12; int c = bc % CH;
    int h = p >> 6, w0 = p & 63;        // w0 even
    const float* inp = in + (size_t)bc * HW;
    const float* wc = w + c * 9;
    float wk[9];
#pragma unroll
    for (int i = 0; i < 9; i++) wk[i] = __ldg(wc + i);
    float a0 = 0.f, a1 = 0.f;
#pragma unroll
    for (int kh = 0; kh < 3; kh++) {
        int hh = h + kh - 1;
        if (hh < 0 || hh > 63) continue;
        const float* r = inp + hh * 64;
        float vm1 = (w0 > 0)  ? r[w0 - 1] : 0.f;
        float v0  = r[w0];
        float v1  = r[w0 + 1];
        float v2  = (w0 < 62) ? r[w0 + 2] : 0.f;
        a0 += wk[kh * 3 + 0] * vm1 + wk[kh * 3 + 1] * v0 + wk[kh * 3 + 2] * v1;
        a1 += wk[kh * 3 + 0] * v0  + wk[kh * 3 + 1] * v1 + wk[kh * 3 + 2] * v2;
    }
    *(u64*)(out + idx2) = pk2(a0, a1);
}

// ---------------- attention-coefficient mixer ----------------
__global__ __launch_bounds__(256) void attmix_k(const float* __restrict__ xn,
        const float* __restrict__ wA, const float* __restrict__ bA,
        const float* __restrict__ wB, const float* __restrict__ bB,
        const float* __restrict__ gam, float* __restrict__ att)
{
    __shared__ float swA[INTERC * 18], sbA[INTERC], swB[NSET * 12], sbB[NSET], sgam[NSET];
    int tid = threadIdx.x;
    for (int i = tid; i < INTERC * 18; i += 256) swA[i] = wA[i];
    for (int i = tid; i < INTERC; i += 256) sbA[i] = bA[i];
    for (int i = tid; i < NSET * 12; i += 256) swB[i] = wB[i];
    for (int i = tid; i < NSET; i += 256) { sbB[i] = bB[i]; sgam[i] = gam[i]; }
    __syncthreads();
    int pg = blockIdx.x * 256 + tid;
    int b = pg >> 12, p = pg & 4095;
    int h = p >> 6, w = p & 63;
    const float* xb = xn + (size_t)b * CCH * HW;
    float av[INTERC];
#pragma unroll
    for (int o = 0; o < INTERC; o++) {
        float acc = sbA[o];
#pragma unroll
        for (int t = 0; t < 2; t++) {
            const float* ch = xb + (size_t)(o * 2 + t) * HW;
#pragma unroll
            for (int kk = 0; kk < 9; kk++) {
                int hh = h + kk / 3 - 1, ww = w + kk % 3 - 1;
                if (hh >= 0 && hh < 64 && ww >= 0 && ww < 64)
                    acc += swA[o * 18 + t * 9 + kk] * ch[hh * 64 + ww];
            }
        }
        av[o] = acc;
    }
    float sg[12];
#pragma unroll
    for (int i = 0; i < 12; i++) sg[i] = av[i] * av[i + 12];
    for (int n = 0; n < NSET; n++) {
        float s = sbB[n];
#pragma unroll
        for (int i = 0; i < 12; i++) s += swB[n * 12 + i] * sg[i];
        size_t oi = ((size_t)b * NSET + n) * HW + p;
        att[oi] = sgam[n] * s + att[oi];
    }
}

// ---------------- KBA core: f32x2, hoisted att, LDS.128 j-pairs ----------------
extern __shared__ u64 kba_sm[];
__global__ __launch_bounds__(128) void kba_k(const float* __restrict__ uf,
        const float* __restrict__ att, const float* __restrict__ kw,
        const float* __restrict__ kb, const float* __restrict__ ga1,
        float* __restrict__ x2out)
{
    u64* kwsh = kba_sm;                    // [32][144]
    u64* ush  = kba_sm + 32 * 144;         // [36][128]
    u64* kbsh = kba_sm + 32 * 144 + 36 * 128;  // [32][4]
    float* ushf = (float*)ush;
    int tid = threadIdx.x;
    int p2 = blockIdx.x * 256 + tid * 2;
    int b = p2 >> 12, pp = p2 & 4095;
    int h = pp >> 6, w = pp & 63;
    const float* attb = att + (size_t)b * NSET * HW + pp;
    u64 a2[32];
#pragma unroll
    for (int n = 0; n < 32; n++) a2[n] = *(const u64*)(attb + (size_t)n * HW);

    for (int gi = 0; gi < 4; gi++) {
        int g = blockIdx.y * 4 + gi;
        const float* ufb = uf + ((size_t)b * HID + g * 4) * HW;
        // stage uf patches (thread-private slots, no cross-thread access)
#pragma unroll
        for (int ci = 0; ci < 4; ci++) {
#pragma unroll
            for (int kk = 0; kk < 9; kk++) {
                int dh = kk / 3 - 1, dw = kk % 3 - 1;
                int j = ci * 9 + kk;
                int hh = h + dh;
                float v0 = 0.f, v1 = 0.f;
                if (hh >= 0 && hh < 64) {
                    const float* row = ufb + (size_t)ci * HW + hh * 64;
                    int wa = w + dw;
                    if (wa >= 0 && wa < 64) v0 = row[wa];
                    int wb = w + 1 + dw;
                    if (wb >= 0 && wb < 64) v1 = row[wb];
                }
                ush[j * 128 + tid] = pk2(v0, v1);
            }
        }
        // stage weights for this group
        for (int idx = tid; idx < 32 * 144; idx += 128) {
            int n = idx / 144, m2 = idx % 144;
            kwsh[idx] = dup2(kw[(size_t)n * 3456 + g * 144 + m2]);
        }
        kbsh[tid] = dup2(kb[(tid >> 2) * HID + g * 4 + (tid & 3)]);
        __syncthreads();

#pragma unroll
        for (int c = 0; c < 4; c++) {
            u64 s0 = 0ULL, s1 = 0ULL, s2 = 0ULL, s3 = 0ULL;
#pragma unroll
            for (int n = 0; n < 32; n += 4) {
                s0 = fma2_(a2[n + 0], kbsh[(n + 0) * 4 + c], s0);
                s1 = fma2_(a2[n + 1], kbsh[(n + 1) * 4 + c], s1);
                s2 = fma2_(a2[n + 2], kbsh[(n + 2) * 4 + c], s2);
                s3 = fma2_(a2[n + 3], kbsh[(n + 3) * 4 + c], s3);
            }
            const u64* kwc = kwsh + c * 36;
            for (int j = 0; j < 36; j += 2) {
                u64 tA0 = 0ULL, tA1 = 0ULL, tB0 = 0ULL, tB1 = 0ULL;
#pragma unroll
                for (int n = 0; n < 32; n += 2) {
                    ulonglong2 kv0 = *(const ulonglong2*)(kwc + n * 144 + j);
                    ulonglong2 kv1 = *(const ulonglong2*)(kwc + (n + 1) * 144 + j);
                    tA0 = fma2_(a2[n],     kv0.x, tA0);
                    tB0 = fma2_(a2[n],     kv0.y, tB0);
                    tA1 = fma2_(a2[n + 1], kv1.x, tA1);
                    tB1 = fma2_(a2[n + 1], kv1.y, tB1);
                }
                u64 tA = add2_(tA0, tA1), tB = add2_(tB0, tB1);
                s0 = fma2_(tA, ush[j * 128 + tid], s0);
                s1 = fma2_(tB, ush[(j + 1) * 128 + tid], s1);
            }
            u64 o = add2_(add2_(s0, s1), add2_(s2, s3));
            int ch = g * 4 + c;
            float ga = ga1[ch];
            float lo, hi; up2(o, lo, hi);
            float c0 = ushf[(c * 9 + 4) * 256 + 2 * tid];
            float c1 = ushf[(c * 9 + 4) * 256 + 2 * tid + 1];
            *(u64*)(x2out + ((size_t)b * HID + ch) * HW + pp) = pk2(lo * ga + c0, hi * ga + c1);
        }
        __syncthreads();   // kwsh/kbsh overwrite protection for next group
    }
}

// ---------------- MDTA: row L2 norms ----------------
__global__ void rownorm_k(const float* __restrict__ qkv, float* __restrict__ norms)
{
    int r = blockIdx.x;
    int which = r / (BATCH * CCH);
    int idx = r % (BATCH * CCH);
    int b = idx / CCH, c = idx % CCH;
    const float* ptr = qkv + ((size_t)b * 3 * CCH + which * CCH + c) * HW;
    __shared__ float red[256];
    float s = 0.f;
    for (int i = threadIdx.x; i < HW; i += 256) { float v = ptr[i]; s += v * v; }
    red[threadIdx.x] = s; __syncthreads();
    for (int st = 128; st; st >>= 1) {
        if (threadIdx.x < st) red[threadIdx.x] += red[threadIdx.x + st];
        __syncthreads();
    }
    if (threadIdx.x == 0) norms[r] = sqrtf(red[0]);
}

// ---------------- MDTA: 6x6 attention + softmax ----------------
__global__ __launch_bounds__(256) void attn_k(const float* __restrict__ qkv,
        const float* __restrict__ norms, const float* __restrict__ temp,
        float* __restrict__ attn)
{
    int bh = blockIdx.x; int b = bh >> 3, h = bh & 7;
    int warp = threadIdx.x >> 5, lane = threadIdx.x & 31;
    __shared__ float S[36];
    const float* qb = qkv + ((size_t)b * 3 * CCH + h * DHEAD) * HW;
    const float* kb = qkv + ((size_t)b * 3 * CCH + CCH + h * DHEAD) * HW;
    for (int pi = warp; pi < 36; pi += 8) {
        int i = pi / 6, j = pi % 6;
        const float* qi = qb + (size_t)i * HW;
        const float* kj = kb + (size_t)j * HW;
        float s = 0.f;
        for (int t = lane; t < HW; t += 32) s += qi[t] * kj[t];
#pragma unroll
        for (int off = 16; off; off >>= 1) s += __shfl_down_sync(0xffffffffu, s, off);
        if (lane == 0) S[pi] = s;
    }
    __syncthreads();
    if (threadIdx.x < 6) {
        int i = threadIdx.x;
        float nq = fmaxf(norms[b * CCH + h * DHEAD + i], 1e-12f);
        float tv = temp[h];
        float row[6]; float mx = -1e30f;
#pragma unroll
        for (int j = 0; j < 6; j++) {
            float nk = fmaxf(norms[BATCH * CCH + b * CCH + h * DHEAD + j], 1e-12f);
            row[j] = tv * S[i * 6 + j] / (nq * nk);
            mx = fmaxf(mx, row[j]);
        }
        float sum = 0.f;
#pragma unroll
        for (int j = 0; j < 6; j++) { row[j] = expf(row[j] - mx); sum += row[j]; }
        float inv = 1.f / sum;
#pragma unroll
        for (int j = 0; j < 6; j++)
            attn[((size_t)(b * 8 + h) * 6 + i) * 6 + j] = row[j] * inv;
    }
}

// ---------------- MDTA: attn @ v ----------------
__global__ void av_k(const float* __restrict__ qkv, const float* __restrict__ attn,
                     float* __restrict__ out)
{
    int idx = blockIdx.x * 256 + threadIdx.x;
    int p = idx & 4095; int bc = idx >> 12; int b = bc / CCH; int c = bc % CCH;
    int h = c / DHEAD, i = c % DHEAD;
    const float* ar = attn + ((size_t)(b * 8 + h) * 6 + i) * 6;
    const float* vb = qkv + ((size_t)b * 3 * CCH + 2 * CCH + h * DHEAD) * HW + p;
    float acc = 0.f;
#pragma unroll
    for (int j = 0; j < 6; j++) acc += ar[j] * vb[(size_t)j * HW];
    out[idx] = acc;
}

// ---------------- gelu(x1) * x2 ----------------
__global__ void gelumul_k(const float* __restrict__ x1, const float* __restrict__ x2,
                          float* __restrict__ m)
{
    int idx = blockIdx.x * 256 + threadIdx.x;
    float v = x1[idx];
    float ge = 0.5f * v * (1.f + erff(v * 0.70710678118654752f));
    m[idx] = ge * x2[idx];
}

// ---------------- final: kproj + residual combine (packed, chunked) ----------------
__global__ __launch_bounds__(128) void final_k(const float* __restrict__ x,
        const float* __restrict__ m, const float* __restrict__ mdta,
        const float* __restrict__ kproj,
        const float* __restrict__ ca1, const float* __restrict__ ca2,
        float* __restrict__ out)
{
    __shared__ u64 wp2[8 * HID];
    int tid = threadIdx.x;
    int o0 = blockIdx.y * 8;
    for (int i = tid; i < 8 * HID; i += 128)
        wp2[i] = dup2(kproj[(o0 + i / HID) * HID + i % HID]);
    __syncthreads();
    int p2 = blockIdx.x * 256 + tid * 2;
    int b = p2 >> 12, pp = p2 & 4095;
    const float* mb = m + (size_t)b * HID * HW + pp;
    u64 acc[8];
#pragma unroll
    for (int o = 0; o < 8; o++) acc[o] = 0ULL;
    for (int cc = 0; cc < HID; cc += 16) {
        u64 xv[16];
#pragma unroll
        for (int c = 0; c < 16; c++) xv[c] = *(const u64*)(mb + (size_t)(cc + c) * HW);
#pragma unroll
        for (int o = 0; o < 8; o++) {
            u64 a = acc[o];
#pragma unroll
            for (int c = 0; c < 16; c++) a = fma2_(wp2[o * HID + cc + c], xv[c], a);
            acc[o] = a;
        }
    }
#pragma unroll
    for (int o = 0; o < 8; o++) {
        int oc = o0 + o;
        size_t oi = ((size_t)b * CCH + oc) * HW + pp;
        float a1 = ca1[b * CCH + oc], a2 = ca2[b * CCH + oc];
        float lo, hi; up2(acc[o], lo, hi);
        float x0 = x[oi], x1v = x[oi + 1];
        float d0 = mdta[oi], d1 = mdta[oi + 1];
        *(u64*)(out + oi) = pk2(x0 + a1 * lo + a2 * d0, x1v + a1 * hi + a2 * d1);
    }
}

// ---------------- host launcher ----------------
extern "C" void kernel_launch(void* const* d_in, const int* in_sizes, int n_in,
                              void* d_out, int out_size)
{
    const float* x       = (const float*)d_in[0];
    const float* n1w     = (const float*)d_in[1];
    const float* n1b     = (const float*)d_in[2];
    const float* n2w     = (const float*)d_in[3];
    const float* n2b     = (const float*)d_in[4];
    const float* kdw1    = (const float*)d_in[5];
    const float* kdw2    = (const float*)d_in[6];
    const float* kc1a    = (const float*)d_in[7];
    const float* kc1b    = (const float*)d_in[8];
    const float* kproj   = (const float*)d_in[9];
    const float* c2a_w   = (const float*)d_in[10];
    const float* c2a_b   = (const float*)d_in[11];
    const float* c2b_w   = (const float*)d_in[12];
    const float* c2b_b   = (const float*)d_in[13];
    const float* c211_w  = (const float*)d_in[14];
    const float* c211_b  = (const float*)d_in[15];
    const float* kw      = (const float*)d_in[16];
    const float* kb      = (const float*)d_in[17];
    const float* attg    = (const float*)d_in[18];
    const float* ga1     = (const float*)d_in[19];
    const float* temp    = (const float*)d_in[20];
    const float* qkv_w   = (const float*)d_in[21];
    const float* qkv_dww = (const float*)d_in[22];
    const float* mproj_w = (const float*)d_in[23];
    const float* ca1_w   = (const float*)d_in[24];
    const float* ca1_b   = (const float*)d_in[25];
    const float* ca2_w   = (const float*)d_in[26];
    const float* ca2_b   = (const float*)d_in[27];
    float* out = (float*)d_out;

    float* S = nullptr;
    cudaGetSymbolAddress((void**)&S, g_scratch);
    float* xn   = S + OFF_XN;
    float* xm   = S + OFF_XM;
    float* t1   = S + OFF_T1;
    float* t2   = S + OFF_T2;
    float* x1   = S + OFF_X1;
    float* uf   = S + OFF_UF;
    float* att  = S + OFF_ATT;
    float* qkvt = S + OFF_QKVT;
    float* qkv  = S + OFF_QKV;
    float* x2   = S + OFF_X2;
    float* m    = S + OFF_M;
    float* mdin = S + OFF_MDIN;
    float* mdta = S + OFF_MDTA;
    float* gap  = S + OFF_GAP;
    float* ca1  = S + OFF_CA1;
    float* ca2  = S + OFF_CA2;
    float* nrm  = S + OFF_NORMS;
    float* attn = S + OFF_ATTN;

    const int PIX = BATCH * HW;              // 16384
    const int XB = PIX / 256;                // 64

    static int kba_smem_set = 0;
    const int KBA_SMEM = (32 * 144 + 36 * 128 + 32 * 4) * sizeof(u64);
    cudaFuncSetAttribute(kba_k, cudaFuncAttributeMaxDynamicSharedMemorySize, KBA_SMEM);
    (void)kba_smem_set;

    gap_k<<<BATCH * CCH, 256>>>(x, gap);
    ca_k<<<1, 256>>>(gap, ca1_w, ca1_b, ca2_w, ca2_b, ca1, ca2);

    ln_k<<<PIX / 256, 256>>>(x, n1w, n1b, n2w, n2b, xn, xm);

    // fused 1x1 convs from xn: t1, t2, att(c211+bias)
    fused3_k<<<dim3(XB, 14), 128>>>(xn, kdw1, kc1a, c211_w, c211_b, t1, t2, att);
    dw3x3_k<<<BATCH * HID * HW / 512, 256>>>(t1, kdw2, x1, HID);
    dw3x3_k<<<BATCH * HID * HW / 512, 256>>>(t2, kc1b, uf, HID);
    attmix_k<<<PIX / 256, 256>>>(xn, c2a_w, c2a_b, c2b_w, c2b_b, attg, att);

    // MDTA branch
    conv1x1p_k<CCH, 3 * CCH, 12, false><<<dim3(XB, 12), 128>>>(xm, qkv_w, nullptr, qkvt);
    dw3x3_k<<<BATCH * 3 * CCH * HW / 512, 256>>>(qkvt, qkv_dww, qkv, 3 * CCH);
    rownorm_k<<<2 * BATCH * CCH, 256>>>(qkv, nrm);
    attn_k<<<BATCH * HEADS, 256>>>(qkv, nrm, temp, attn);
    av_k<<<BATCH * CCH * HW / 256, 256>>>(qkv, attn, mdin);
    conv1x1p_k<CCH, CCH, 12, false><<<dim3(XB, 4), 128>>>(mdin, mproj_w, nullptr, mdta);

    // KBA core
    kba_k<<<dim3(XB, 6), 128, KBA_SMEM>>>(uf, att, kw, kb, ga1, x2);
    gelumul_k<<<BATCH * HID * HW / 256, 256>>>(x1, x2, m);

    // projection + residual
    final_k<<<dim3(XB, 6), 128>>>(x, m, mdta, kproj, ca1, ca2, out);
}

// round 4
// speedup vs baseline: 1.3974x; 1.0885x over previous
#include <cuda_runtime.h>
#include <math.h>

// ---------------- problem constants ----------------
#define BATCH 4
#define CCH   48
#define HW    4096
#define HID   96
#define NSET  32
#define HEADS 8
#define DHEAD 6
#define INTERC 24

typedef unsigned long long u64;
__device__ __forceinline__ u64 pk2(float lo, float hi){ u64 r; asm("mov.b64 %0,{%1,%2};":"=l"(r):"f"(lo),"f"(hi)); return r; }
__device__ __forceinline__ u64 dup2(float v){ return pk2(v, v); }
__device__ __forceinline__ void up2(u64 v, float& lo, float& hi){ asm("mov.b64 {%0,%1},%2;":"=f"(lo),"=f"(hi):"l"(v)); }
__device__ __forceinline__ u64 fma2_(u64 a, u64 b, u64 c){ u64 d; asm("fma.rn.f32x2 %0,%1,%2,%3;":"=l"(d):"l"(a),"l"(b),"l"(c)); return d; }
__device__ __forceinline__ u64 add2_(u64 a, u64 b){ u64 d; asm("add.rn.f32x2 %0,%1,%2;":"=l"(d):"l"(a),"l"(b)); return d; }

// ---------------- scratch layout ----------------
#define OFF_XN    0LL
#define OFF_XM    (OFF_XN   + (long long)BATCH*CCH*HW)
#define OFF_T1    (OFF_XM   + (long long)BATCH*CCH*HW)
#define OFF_T2    (OFF_T1   + (long long)BATCH*HID*HW)
#define OFF_X1    (OFF_T2   + (long long)BATCH*HID*HW)
#define OFF_UF    (OFF_X1   + (long long)BATCH*HID*HW)
#define OFF_ATT   (OFF_UF   + (long long)BATCH*HID*HW)
#define OFF_QKVT  (OFF_ATT  + (long long)BATCH*NSET*HW)
#define OFF_QKV   (OFF_QKVT + (long long)BATCH*3*CCH*HW)
#define OFF_X2    (OFF_QKV  + (long long)BATCH*3*CCH*HW)
#define OFF_M     (OFF_X2   + (long long)BATCH*HID*HW)
#define OFF_GAP   (OFF_M    + (long long)BATCH*HID*HW)
#define OFF_CA1   (OFF_GAP  + BATCH*CCH)
#define OFF_CA2   (OFF_CA1  + BATCH*CCH)
#define OFF_ATTN  (OFF_CA2  + BATCH*CCH)
#define SCRATCH_TOTAL (OFF_ATTN + BATCH*HEADS*DHEAD*DHEAD)

__device__ float g_scratch[SCRATCH_TOTAL];

// ---------------- gap ----------------
__global__ void gap_k(const float* __restrict__ x, float* __restrict__ gap)
{
    int bc = blockIdx.x;
    const float* xb = x + (size_t)bc * HW;
    __shared__ float red[256];
    float s = 0.f;
    for (int i = threadIdx.x; i < HW; i += 256) s += xb[i];
    red[threadIdx.x] = s; __syncthreads();
    for (int st = 128; st; st >>= 1) {
        if (threadIdx.x < st) red[threadIdx.x] += red[threadIdx.x + st];
        __syncthreads();
    }
    if (threadIdx.x == 0) gap[bc] = red[0] * (1.f / HW);
}

// ---------------- channel attention ----------------
__global__ void ca_k(const float* __restrict__ gap,
                     const float* __restrict__ w1, const float* __restrict__ b1,
                     const float* __restrict__ w2, const float* __restrict__ b2,
                     float* __restrict__ ca1, float* __restrict__ ca2)
{
    int t = threadIdx.x;
    if (t >= BATCH * CCH) return;
    int b = t / CCH, o = t % CCH;
    float s1 = b1[o], s2 = b2[o];
    for (int c = 0; c < CCH; c++) {
        float g = gap[b * CCH + c];
        s1 += w1[o * CCH + c] * g;
        s2 += w2[o * CCH + c] * g;
    }
    ca1[t] = s1; ca2[t] = s2;
}

// ---------------- LayerNorm2d ----------------
__global__ __launch_bounds__(128) void ln_k(const float* __restrict__ x,
        const float* __restrict__ n1w, const float* __restrict__ n1b,
        const float* __restrict__ n2w, const float* __restrict__ n2b,
        float* __restrict__ xn, float* __restrict__ xm)
{
    int pg = blockIdx.x * 128 + threadIdx.x;
    int b = pg >> 12, p = pg & 4095;
    const float* xb = x + (size_t)b * CCH * HW + p;
    float v[CCH];
    float s = 0.f, s2 = 0.f;
#pragma unroll
    for (int c = 0; c < CCH; c++) { float t = xb[(size_t)c * HW]; v[c] = t; s += t; s2 += t * t; }
    float mu = s * (1.f / CCH);
    float var = s2 * (1.f / CCH) - mu * mu;
    float r = rsqrtf(var + 1e-6f);
    float* xnb = xn + (size_t)b * CCH * HW + p;
    float* xmb = xm + (size_t)b * CCH * HW + p;
#pragma unroll
    for (int c = 0; c < CCH; c++) {
        float y = (v[c] - mu) * r;
        xnb[(size_t)c * HW] = n1w[c] * y + n1b[c];
        xmb[(size_t)c * HW] = n2w[c] * y + n2b[c];
    }
}

// ---------------- 4px packed 1x1 conv ----------------
template <int INC, int OUTC, int OSPL, bool HASB>
__global__ __launch_bounds__(128) void conv1x1q_k(const float* __restrict__ in,
        const float* __restrict__ w, const float* __restrict__ bias,
        float* __restrict__ out)
{
    __shared__ __align__(16) u64 ws2[OSPL * INC];
    __shared__ u64 bs2[OSPL];
    int tid = threadIdx.x;
    int o0 = blockIdx.y * OSPL;
    for (int i = tid; i < OSPL * INC; i += 128)
        ws2[i] = dup2(w[(o0 + i / INC) * INC + i % INC]);
    if (HASB) for (int i = tid; i < OSPL; i += 128) bs2[i] = dup2(bias[o0 + i]);
    __syncthreads();
    int p4 = (blockIdx.x * 128 + tid) * 4;
    int b = p4 >> 12, pp = p4 & 4095;
    const float* inb = in + (size_t)b * INC * HW + pp;
    u64 acc[OSPL][2];
#pragma unroll
    for (int o = 0; o < OSPL; o++) { acc[o][0] = HASB ? bs2[o] : 0ULL; acc[o][1] = acc[o][0]; }
    for (int cc = 0; cc < INC; cc += 8) {
        u64 xv[8][2];
#pragma unroll
        for (int c = 0; c < 8; c++) {
            ulonglong2 t = *(const ulonglong2*)(inb + (size_t)(cc + c) * HW);
            xv[c][0] = t.x; xv[c][1] = t.y;
        }
#pragma unroll
        for (int o = 0; o < OSPL; o++) {
#pragma unroll
            for (int c = 0; c < 8; c += 2) {
                ulonglong2 wv = *(const ulonglong2*)&ws2[o * INC + cc + c];
                acc[o][0] = fma2_(wv.x, xv[c][0], acc[o][0]);
                acc[o][1] = fma2_(wv.x, xv[c][1], acc[o][1]);
                acc[o][0] = fma2_(wv.y, xv[c + 1][0], acc[o][0]);
                acc[o][1] = fma2_(wv.y, xv[c + 1][1], acc[o][1]);
            }
        }
    }
    float* outb = out + ((size_t)b * OUTC + o0) * HW + pp;
#pragma unroll
    for (int o = 0; o < OSPL; o++) {
        ulonglong2 t; t.x = acc[o][0]; t.y = acc[o][1];
        *(ulonglong2*)(outb + (size_t)o * HW) = t;
    }
}

// ---------------- fused 3x conv1x1 from xn, 4px ----------------
__global__ __launch_bounds__(128) void fused3q_k(const float* __restrict__ xn,
        const float* __restrict__ w1, const float* __restrict__ w2,
        const float* __restrict__ w3, const float* __restrict__ b3,
        float* __restrict__ t1, float* __restrict__ t2, float* __restrict__ att)
{
    __shared__ __align__(16) u64 ws2[16 * CCH];
    __shared__ u64 bs2[16];
    int tid = threadIdx.x;
    int y = blockIdx.y;
    const float* w; float* outp; int ol; int outc; bool hasb;
    if (y < 6)       { w = w1; outp = t1;  ol = y * 16;        outc = HID;  hasb = false; }
    else if (y < 12) { w = w2; outp = t2;  ol = (y - 6) * 16;  outc = HID;  hasb = false; }
    else             { w = w3; outp = att; ol = (y - 12) * 16; outc = NSET; hasb = true;  }
    for (int i = tid; i < 16 * CCH; i += 128)
        ws2[i] = dup2(w[(ol + i / CCH) * CCH + i % CCH]);
    if (hasb) { if (tid < 16) bs2[tid] = dup2(b3[ol + tid]); }
    __syncthreads();
    int p4 = (blockIdx.x * 128 + tid) * 4;
    int b = p4 >> 12, pp = p4 & 4095;
    const float* inb = xn + (size_t)b * CCH * HW + pp;
    u64 acc[16][2];
#pragma unroll
    for (int o = 0; o < 16; o++) { acc[o][0] = hasb ? bs2[o] : 0ULL; acc[o][1] = acc[o][0]; }
    for (int cc = 0; cc < CCH; cc += 8) {
        u64 xv[8][2];
#pragma unroll
        for (int c = 0; c < 8; c++) {
            ulonglong2 t = *(const ulonglong2*)(inb + (size_t)(cc + c) * HW);
            xv[c][0] = t.x; xv[c][1] = t.y;
        }
#pragma unroll
        for (int o = 0; o < 16; o++) {
#pragma unroll
            for (int c = 0; c < 8; c += 2) {
                ulonglong2 wv = *(const ulonglong2*)&ws2[o * CCH + cc + c];
                acc[o][0] = fma2_(wv.x, xv[c][0], acc[o][0]);
                acc[o][1] = fma2_(wv.x, xv[c][1], acc[o][1]);
                acc[o][0] = fma2_(wv.y, xv[c + 1][0], acc[o][0]);
                acc[o][1] = fma2_(wv.y, xv[c + 1][1], acc[o][1]);
            }
        }
    }
    float* outb = outp + ((size_t)b * outc + ol) * HW + pp;
#pragma unroll
    for (int o = 0; o < 16; o++) {
        ulonglong2 t; t.x = acc[o][0]; t.y = acc[o][1];
        *(ulonglong2*)(outb + (size_t)o * HW) = t;
    }
}

// ---------------- depthwise 3x3, 4px/thread ----------------
__global__ void dw3x3q_k(const float* __restrict__ in, const float* __restrict__ w,
                         float* __restrict__ out, int CH)
{
    int idx4 = (blockIdx.x * 256 + threadIdx.x) * 4;
    int p = idx4 & 4095; int bc = idx4 >> 12; int c = bc % CH;
    int h = p >> 6, w0 = p & 63;            // w0 multiple of 4
    const float* inp = in + (size_t)bc * HW;
    const float* wc = w + c * 9;
    float wk[9];
#pragma unroll
    for (int i = 0; i < 9; i++) wk[i] = __ldg(wc + i);
    float a[4] = {0.f, 0.f, 0.f, 0.f};
#pragma unroll
    for (int kh = 0; kh < 3; kh++) {
        int hh = h + kh - 1;
        if (hh < 0 || hh > 63) continue;
        const float* r = inp + hh * 64;
        float4 v14 = *(const float4*)(r + w0);
        float vm1 = (w0 > 0)  ? r[w0 - 1] : 0.f;
        float v5  = (w0 < 60) ? r[w0 + 4] : 0.f;
        float v[6] = {vm1, v14.x, v14.y, v14.z, v14.w, v5};
        float k0 = wk[kh * 3], k1 = wk[kh * 3 + 1], k2 = wk[kh * 3 + 2];
#pragma unroll
        for (int px = 0; px < 4; px++)
            a[px] += k0 * v[px] + k1 * v[px + 1] + k2 * v[px + 2];
    }
    ulonglong2 t; t.x = pk2(a[0], a[1]); t.y = pk2(a[2], a[3]);
    *(ulonglong2*)(out + idx4) = t;
}

// ---------------- attention-coefficient mixer (1px, wider grid) ----------------
__global__ __launch_bounds__(128) void attmix_k(const float* __restrict__ xn,
        const float* __restrict__ wA, const float* __restrict__ bA,
        const float* __restrict__ wB, const float* __restrict__ bB,
        const float* __restrict__ gam, float* __restrict__ att)
{
    __shared__ float swA[INTERC * 18], sbA[INTERC], swB[NSET * 12], sbB[NSET], sgam[NSET];
    int tid = threadIdx.x;
    for (int i = tid; i < INTERC * 18; i += 128) swA[i] = wA[i];
    for (int i = tid; i < INTERC; i += 128) sbA[i] = bA[i];
    for (int i = tid; i < NSET * 12; i += 128) swB[i] = wB[i];
    for (int i = tid; i < NSET; i += 128) { sbB[i] = bB[i]; sgam[i] = gam[i]; }
    __syncthreads();
    int pg = blockIdx.x * 128 + tid;
    int b = pg >> 12, p = pg & 4095;
    int h = p >> 6, w = p & 63;
    const float* xb = xn + (size_t)b * CCH * HW;
    float av[INTERC];
#pragma unroll
    for (int o = 0; o < INTERC; o++) {
        float acc = sbA[o];
#pragma unroll
        for (int t = 0; t < 2; t++) {
            const float* ch = xb + (size_t)(o * 2 + t) * HW;
#pragma unroll
            for (int kk = 0; kk < 9; kk++) {
                int hh = h + kk / 3 - 1, ww = w + kk % 3 - 1;
                if (hh >= 0 && hh < 64 && ww >= 0 && ww < 64)
                    acc += swA[o * 18 + t * 9 + kk] * ch[hh * 64 + ww];
            }
        }
        av[o] = acc;
    }
    float sg[12];
#pragma unroll
    for (int i = 0; i < 12; i++) sg[i] = av[i] * av[i + 12];
    for (int n = 0; n < NSET; n++) {
        float s = sbB[n];
#pragma unroll
        for (int i = 0; i < 12; i++) s += swB[n * 12 + i] * sg[i];
        size_t oi = ((size_t)b * NSET + n) * HW + p;
        att[oi] = sgam[n] * s + att[oi];
    }
}

// ---------------- KBA core (unchanged from R3) ----------------
extern __shared__ u64 kba_sm[];
__global__ __launch_bounds__(128) void kba_k(const float* __restrict__ uf,
        const float* __restrict__ att, const float* __restrict__ kw,
        const float* __restrict__ kb, const float* __restrict__ ga1,
        float* __restrict__ x2out)
{
    u64* kwsh = kba_sm;
    u64* ush  = kba_sm + 32 * 144;
    u64* kbsh = kba_sm + 32 * 144 + 36 * 128;
    float* ushf = (float*)ush;
    int tid = threadIdx.x;
    int p2 = blockIdx.x * 256 + tid * 2;
    int b = p2 >> 12, pp = p2 & 4095;
    int h = pp >> 6, w = pp & 63;
    const float* attb = att + (size_t)b * NSET * HW + pp;
    u64 a2[32];
#pragma unroll
    for (int n = 0; n < 32; n++) a2[n] = *(const u64*)(attb + (size_t)n * HW);

    for (int gi = 0; gi < 4; gi++) {
        int g = blockIdx.y * 4 + gi;
        const float* ufb = uf + ((size_t)b * HID + g * 4) * HW;
#pragma unroll
        for (int ci = 0; ci < 4; ci++) {
#pragma unroll
            for (int kk = 0; kk < 9; kk++) {
                int dh = kk / 3 - 1, dw = kk % 3 - 1;
                int j = ci * 9 + kk;
                int hh = h + dh;
                float v0 = 0.f, v1 = 0.f;
                if (hh >= 0 && hh < 64) {
                    const float* row = ufb + (size_t)ci * HW + hh * 64;
                    int wa = w + dw;
                    if (wa >= 0 && wa < 64) v0 = row[wa];
                    int wb = w + 1 + dw;
                    if (wb >= 0 && wb < 64) v1 = row[wb];
                }
                ush[j * 128 + tid] = pk2(v0, v1);
            }
        }
        for (int idx = tid; idx < 32 * 144; idx += 128) {
            int n = idx / 144, m2 = idx % 144;
            kwsh[idx] = dup2(kw[(size_t)n * 3456 + g * 144 + m2]);
        }
        kbsh[tid] = dup2(kb[(tid >> 2) * HID + g * 4 + (tid & 3)]);
        __syncthreads();

#pragma unroll
        for (int c = 0; c < 4; c++) {
            u64 s0 = 0ULL, s1 = 0ULL, s2 = 0ULL, s3 = 0ULL;
#pragma unroll
            for (int n = 0; n < 32; n += 4) {
                s0 = fma2_(a2[n + 0], kbsh[(n + 0) * 4 + c], s0);
                s1 = fma2_(a2[n + 1], kbsh[(n + 1) * 4 + c], s1);
                s2 = fma2_(a2[n + 2], kbsh[(n + 2) * 4 + c], s2);
                s3 = fma2_(a2[n + 3], kbsh[(n + 3) * 4 + c], s3);
            }
            const u64* kwc = kwsh + c * 36;
            for (int j = 0; j < 36; j += 2) {
                u64 tA0 = 0ULL, tA1 = 0ULL, tB0 = 0ULL, tB1 = 0ULL;
#pragma unroll
                for (int n = 0; n < 32; n += 2) {
                    ulonglong2 kv0 = *(const ulonglong2*)(kwc + n * 144 + j);
                    ulonglong2 kv1 = *(const ulonglong2*)(kwc + (n + 1) * 144 + j);
                    tA0 = fma2_(a2[n],     kv0.x, tA0);
                    tB0 = fma2_(a2[n],     kv0.y, tB0);
                    tA1 = fma2_(a2[n + 1], kv1.x, tA1);
                    tB1 = fma2_(a2[n + 1], kv1.y, tB1);
                }
                u64 tA = add2_(tA0, tA1), tB = add2_(tB0, tB1);
                s0 = fma2_(tA, ush[j * 128 + tid], s0);
                s1 = fma2_(tB, ush[(j + 1) * 128 + tid], s1);
            }
            u64 o = add2_(add2_(s0, s1), add2_(s2, s3));
            int ch = g * 4 + c;
            float ga = ga1[ch];
            float lo, hi; up2(o, lo, hi);
            float c0 = ushf[(c * 9 + 4) * 256 + 2 * tid];
            float c1 = ushf[(c * 9 + 4) * 256 + 2 * tid + 1];
            *(u64*)(x2out + ((size_t)b * HID + ch) * HW + pp) = pk2(lo * ga + c0, hi * ga + c1);
        }
        __syncthreads();
    }
}

// ---------------- MDTA: fused norms + 6x6 attention + softmax ----------------
__global__ __launch_bounds__(256) void attn_k(const float* __restrict__ qkv,
        const float* __restrict__ temp, float* __restrict__ attn)
{
    int bh = blockIdx.x; int b = bh >> 3, h = bh & 7;
    int warp = threadIdx.x >> 5, lane = threadIdx.x & 31;
    __shared__ float S[36], NQ[6], NK[6];
    const float* qb = qkv + ((size_t)b * 3 * CCH + h * DHEAD) * HW;
    const float* kb = qkv + ((size_t)b * 3 * CCH + CCH + h * DHEAD) * HW;
    for (int pi = warp; pi < 48; pi += 8) {
        const float* pa; const float* pb;
        if (pi < 36)      { pa = qb + (size_t)(pi / 6) * HW; pb = kb + (size_t)(pi % 6) * HW; }
        else if (pi < 42) { pa = qb + (size_t)(pi - 36) * HW; pb = pa; }
        else              { pa = kb + (size_t)(pi - 42) * HW; pb = pa; }
        float s = 0.f;
        for (int t = lane * 4; t < HW; t += 128) {
            float4 va = *(const float4*)(pa + t);
            float4 vb = *(const float4*)(pb + t);
            s += va.x * vb.x + va.y * vb.y + va.z * vb.z + va.w * vb.w;
        }
#pragma unroll
        for (int off = 16; off; off >>= 1) s += __shfl_down_sync(0xffffffffu, s, off);
        if (lane == 0) {
            if (pi < 36) S[pi] = s;
            else if (pi < 42) NQ[pi - 36] = sqrtf(s);
            else NK[pi - 42] = sqrtf(s);
        }
    }
    __syncthreads();
    if (threadIdx.x < 6) {
        int i = threadIdx.x;
        float nq = fmaxf(NQ[i], 1e-12f);
        float tv = temp[h];
        float row[6]; float mx = -1e30f;
#pragma unroll
        for (int j = 0; j < 6; j++) {
            float nk = fmaxf(NK[j], 1e-12f);
            row[j] = tv * S[i * 6 + j] / (nq * nk);
            mx = fmaxf(mx, row[j]);
        }
        float sum = 0.f;
#pragma unroll
        for (int j = 0; j < 6; j++) { row[j] = expf(row[j] - mx); sum += row[j]; }
        float inv = 1.f / sum;
#pragma unroll
        for (int j = 0; j < 6; j++)
            attn[((size_t)(b * 8 + h) * 6 + i) * 6 + j] = row[j] * inv;
    }
}

// ---------------- MDTA: fused (attn @ v) + mproj, 4px ----------------
__global__ __launch_bounds__(128) void mdta_k(const float* __restrict__ qkv,
        const float* __restrict__ attn, const float* __restrict__ mproj,
        float* __restrict__ out)
{
    __shared__ float scoef[288];
    __shared__ u64 ws2[8 * CCH];
    int tid = threadIdx.x;
    int o0 = blockIdx.y * 8;
    int p4 = (blockIdx.x * 128 + tid) * 4;
    int b = p4 >> 12, pp = p4 & 4095;        // b uniform per block (512 px/block)
    int bblk = (blockIdx.x * 512) >> 12;
    for (int i = tid; i < 288; i += 128) scoef[i] = attn[bblk * 288 + i];
    for (int i = tid; i < 8 * CCH; i += 128)
        ws2[i] = dup2(mproj[(o0 + i / CCH) * CCH + i % CCH]);
    __syncthreads();
    u64 acc[8][2];
#pragma unroll
    for (int o = 0; o < 8; o++) { acc[o][0] = 0ULL; acc[o][1] = 0ULL; }
    const float* vb = qkv + ((size_t)b * 3 * CCH + 2 * CCH) * HW + pp;
#pragma unroll
    for (int h = 0; h < 8; h++) {
        u64 v[6][2];
#pragma unroll
        for (int j = 0; j < 6; j++) {
            ulonglong2 t = *(const ulonglong2*)(vb + (size_t)(h * 6 + j) * HW);
            v[j][0] = t.x; v[j][1] = t.y;
        }
#pragma unroll
        for (int i = 0; i < 6; i++) {
            int c = h * 6 + i;
            u64 md0 = 0ULL, md1 = 0ULL;
#pragma unroll
            for (int j = 0; j < 6; j++) {
                u64 cf = dup2(scoef[c * 6 + j]);
                md0 = fma2_(cf, v[j][0], md0);
                md1 = fma2_(cf, v[j][1], md1);
            }
#pragma unroll
            for (int o = 0; o < 8; o++) {
                u64 wv = ws2[o * CCH + c];
                acc[o][0] = fma2_(wv, md0, acc[o][0]);
                acc[o][1] = fma2_(wv, md1, acc[o][1]);
            }
        }
    }
    float* outb = out + ((size_t)b * CCH + o0) * HW + pp;
#pragma unroll
    for (int o = 0; o < 8; o++) {
        ulonglong2 t; t.x = acc[o][0]; t.y = acc[o][1];
        *(ulonglong2*)(outb + (size_t)o * HW) = t;
    }
}

// ---------------- gelu(x1)*x2, 4px ----------------
__global__ void gelumul_k(const float* __restrict__ x1, const float* __restrict__ x2,
                          float* __restrict__ m)
{
    int idx4 = (blockIdx.x * 256 + threadIdx.x) * 4;
    float4 v = *(const float4*)(x1 + idx4);
    float4 u = *(const float4*)(x2 + idx4);
    float4 r;
    r.x = 0.5f * v.x * (1.f + erff(v.x * 0.70710678118654752f)) * u.x;
    r.y = 0.5f * v.y * (1.f + erff(v.y * 0.70710678118654752f)) * u.y;
    r.z = 0.5f * v.z * (1.f + erff(v.z * 0.70710678118654752f)) * u.z;
    r.w = 0.5f * v.w * (1.f + erff(v.w * 0.70710678118654752f)) * u.w;
    *(float4*)(m + idx4) = r;
}

// ---------------- final: kproj + residual combine, 4px ----------------
__global__ __launch_bounds__(128) void final_k(const float* __restrict__ x,
        const float* __restrict__ m, const float* __restrict__ mdta,
        const float* __restrict__ kproj,
        const float* __restrict__ ca1, const float* __restrict__ ca2,
        float* __restrict__ out)
{
    __shared__ __align__(16) u64 wp2[8 * HID];
    int tid = threadIdx.x;
    int o0 = blockIdx.y * 8;
    for (int i = tid; i < 8 * HID; i += 128)
        wp2[i] = dup2(kproj[(o0 + i / HID) * HID + i % HID]);
    __syncthreads();
    int p4 = (blockIdx.x * 128 + tid) * 4;
    int b = p4 >> 12, pp = p4 & 4095;
    const float* mb = m + (size_t)b * HID * HW + pp;
    u64 acc[8][2];
#pragma unroll
    for (int o = 0; o < 8; o++) { acc[o][0] = 0ULL; acc[o][1] = 0ULL; }
    for (int cc = 0; cc < HID; cc += 8) {
        u64 xv[8][2];
#pragma unroll
        for (int c = 0; c < 8; c++) {
            ulonglong2 t = *(const ulonglong2*)(mb + (size_t)(cc + c) * HW);
            xv[c][0] = t.x; xv[c][1] = t.y;
        }
#pragma unroll
        for (int o = 0; o < 8; o++) {
#pragma unroll
            for (int c = 0; c < 8; c += 2) {
                ulonglong2 wv = *(const ulonglong2*)&wp2[o * HID + cc + c];
                acc[o][0] = fma2_(wv.x, xv[c][0], acc[o][0]);
                acc[o][1] = fma2_(wv.x, xv[c][1], acc[o][1]);
                acc[o][0] = fma2_(wv.y, xv[c + 1][0], acc[o][0]);
                acc[o][1] = fma2_(wv.y, xv[c + 1][1], acc[o][1]);
            }
        }
    }
#pragma unroll
    for (int o = 0; o < 8; o++) {
        int oc = o0 + o;
        size_t oi = ((size_t)b * CCH + oc) * HW + pp;
        u64 a1 = dup2(ca1[b * CCH + oc]), a2 = dup2(ca2[b * CCH + oc]);
        ulonglong2 xv = *(const ulonglong2*)(x + oi);
        ulonglong2 dv = *(const ulonglong2*)(mdta + oi);
        ulonglong2 r;
        r.x = fma2_(a1, acc[o][0], fma2_(a2, dv.x, xv.x));
        r.y = fma2_(a1, acc[o][1], fma2_(a2, dv.y, xv.y));
        *(ulonglong2*)(out + oi) = r;
    }
}

// ---------------- host launcher ----------------
extern "C" void kernel_launch(void* const* d_in, const int* in_sizes, int n_in,
                              void* d_out, int out_size)
{
    const float* x       = (const float*)d_in[0];
    const float* n1w     = (const float*)d_in[1];
    const float* n1b     = (const float*)d_in[2];
    const float* n2w     = (const float*)d_in[3];
    const float* n2b     = (const float*)d_in[4];
    const float* kdw1    = (const float*)d_in[5];
    const float* kdw2    = (const float*)d_in[6];
    const float* kc1a    = (const float*)d_in[7];
    const float* kc1b    = (const float*)d_in[8];
    const float* kproj   = (const float*)d_in[9];
    const float* c2a_w   = (const float*)d_in[10];
    const float* c2a_b   = (const float*)d_in[11];
    const float* c2b_w   = (const float*)d_in[12];
    const float* c2b_b   = (const float*)d_in[13];
    const float* c211_w  = (const float*)d_in[14];
    const float* c211_b  = (const float*)d_in[15];
    const float* kw      = (const float*)d_in[16];
    const float* kb      = (const float*)d_in[17];
    const float* attg    = (const float*)d_in[18];
    const float* ga1     = (const float*)d_in[19];
    const float* temp    = (const float*)d_in[20];
    const float* qkv_w   = (const float*)d_in[21];
    const float* qkv_dww = (const float*)d_in[22];
    const float* mproj_w = (const float*)d_in[23];
    const float* ca1_w   = (const float*)d_in[24];
    const float* ca1_b   = (const float*)d_in[25];
    const float* ca2_w   = (const float*)d_in[26];
    const float* ca2_b   = (const float*)d_in[27];
    float* out = (float*)d_out;

    float* S = nullptr;
    cudaGetSymbolAddress((void**)&S, g_scratch);
    float* xn   = S + OFF_XN;
    float* xm   = S + OFF_XM;
    float* t1   = S + OFF_T1;
    float* t2   = S + OFF_T2;
    float* x1   = S + OFF_X1;
    float* uf   = S + OFF_UF;
    float* att  = S + OFF_ATT;
    float* qkvt = S + OFF_QKVT;
    float* qkv  = S + OFF_QKV;
    float* x2   = S + OFF_X2;
    float* m    = S + OFF_M;
    float* gap  = S + OFF_GAP;
    float* ca1  = S + OFF_CA1;
    float* ca2  = S + OFF_CA2;
    float* attn = S + OFF_ATTN;
    float* mdta = qkvt;                     // reuse qkvt after qkv dwconv consumed it

    const int PIX = BATCH * HW;             // 16384
    const int XB4 = PIX / 512;              // 32 (4px * 128 thr)

    const int KBA_SMEM = (32 * 144 + 36 * 128 + 32 * 4) * sizeof(u64);
    cudaFuncSetAttribute(kba_k, cudaFuncAttributeMaxDynamicSharedMemorySize, KBA_SMEM);

    gap_k<<<BATCH * CCH, 256>>>(x, gap);
    ca_k<<<1, 256>>>(gap, ca1_w, ca1_b, ca2_w, ca2_b, ca1, ca2);

    ln_k<<<PIX / 128, 128>>>(x, n1w, n1b, n2w, n2b, xn, xm);

    // KBA branch
    fused3q_k<<<dim3(XB4, 14), 128>>>(xn, kdw1, kc1a, c211_w, c211_b, t1, t2, att);
    dw3x3q_k<<<BATCH * HID * HW / 1024, 256>>>(t1, kdw2, x1, HID);
    dw3x3q_k<<<BATCH * HID * HW / 1024, 256>>>(t2, kc1b, uf, HID);
    attmix_k<<<PIX / 128, 128>>>(xn, c2a_w, c2a_b, c2b_w, c2b_b, attg, att);

    // MDTA branch
    conv1x1q_k<CCH, 3 * CCH, 12, false><<<dim3(XB4, 12), 128>>>(xm, qkv_w, nullptr, qkvt);
    dw3x3q_k<<<BATCH * 3 * CCH * HW / 1024, 256>>>(qkvt, qkv_dww, qkv, 3 * CCH);
    attn_k<<<BATCH * HEADS, 256>>>(qkv, temp, attn);
    mdta_k<<<dim3(XB4, 6), 128>>>(qkv, attn, mproj_w, mdta);

    // KBA core
    kba_k<<<dim3(PIX / 256, 6), 128, KBA_SMEM>>>(uf, att, kw, kb, ga1, x2);
    gelumul_k<<<BATCH * HID * HW / 1024, 256>>>(x1, x2, m);

    // projection + residual
    final_k<<<dim3(XB4, 6), 128>>>(x, m, mdta, kproj, ca1, ca2, out);
}

// round 5
// speedup vs baseline: 1.4370x; 1.0284x over previous
#include <cuda_runtime.h>
#include <math.h>

// ---------------- problem constants ----------------
#define BATCH 4
#define CCH   48
#define HW    4096
#define HID   96
#define NSET  32
#define HEADS 8
#define DHEAD 6
#define INTERC 24

typedef unsigned long long u64;
__device__ __forceinline__ u64 pk2(float lo, float hi){ u64 r; asm("mov.b64 %0,{%1,%2};":"=l"(r):"f"(lo),"f"(hi)); return r; }
__device__ __forceinline__ u64 dup2(float v){ return pk2(v, v); }
__device__ __forceinline__ void up2(u64 v, float& lo, float& hi){ asm("mov.b64 {%0,%1},%2;":"=f"(lo),"=f"(hi):"l"(v)); }
__device__ __forceinline__ u64 fma2_(u64 a, u64 b, u64 c){ u64 d; asm("fma.rn.f32x2 %0,%1,%2,%3;":"=l"(d):"l"(a),"l"(b),"l"(c)); return d; }
__device__ __forceinline__ u64 add2_(u64 a, u64 b){ u64 d; asm("add.rn.f32x2 %0,%1,%2;":"=l"(d):"l"(a),"l"(b)); return d; }

// ---------------- scratch layout ----------------
#define OFF_XN    0LL
#define OFF_XM    (OFF_XN   + (long long)BATCH*CCH*HW)
#define OFF_T1    (OFF_XM   + (long long)BATCH*CCH*HW)
#define OFF_T2    (OFF_T1   + (long long)BATCH*HID*HW)
#define OFF_X1    (OFF_T2   + (long long)BATCH*HID*HW)
#define OFF_UF    (OFF_X1   + (long long)BATCH*HID*HW)
#define OFF_ATT   (OFF_UF   + (long long)BATCH*HID*HW)
#define OFF_QKVT  (OFF_ATT  + (long long)BATCH*NSET*HW)
#define OFF_QKV   (OFF_QKVT + (long long)BATCH*3*CCH*HW)
#define OFF_M     (OFF_QKV  + (long long)BATCH*3*CCH*HW)
#define OFF_GAP   (OFF_M    + (long long)BATCH*HID*HW)
#define OFF_CA1   (OFF_GAP  + BATCH*CCH)
#define OFF_CA2   (OFF_CA1  + BATCH*CCH)
#define OFF_ATTN  (OFF_CA2  + BATCH*CCH)
#define SCRATCH_TOTAL (OFF_ATTN + BATCH*HEADS*DHEAD*DHEAD)

__device__ float g_scratch[SCRATCH_TOTAL];

// ---------------- gap ----------------
__global__ void gap_k(const float* __restrict__ x, float* __restrict__ gap)
{
    int bc = blockIdx.x;
    const float* xb = x + (size_t)bc * HW;
    __shared__ float red[256];
    float s = 0.f;
    for (int i = threadIdx.x; i < HW; i += 256) s += xb[i];
    red[threadIdx.x] = s; __syncthreads();
    for (int st = 128; st; st >>= 1) {
        if (threadIdx.x < st) red[threadIdx.x] += red[threadIdx.x + st];
        __syncthreads();
    }
    if (threadIdx.x == 0) gap[bc] = red[0] * (1.f / HW);
}

// ---------------- channel attention ----------------
__global__ void ca_k(const float* __restrict__ gap,
                     const float* __restrict__ w1, const float* __restrict__ b1,
                     const float* __restrict__ w2, const float* __restrict__ b2,
                     float* __restrict__ ca1, float* __restrict__ ca2)
{
    int t = threadIdx.x;
    if (t >= BATCH * CCH) return;
    int b = t / CCH, o = t % CCH;
    float s1 = b1[o], s2 = b2[o];
    for (int c = 0; c < CCH; c++) {
        float g = gap[b * CCH + c];
        s1 += w1[o * CCH + c] * g;
        s2 += w2[o * CCH + c] * g;
    }
    ca1[t] = s1; ca2[t] = s2;
}

// ---------------- LayerNorm2d ----------------
__global__ __launch_bounds__(128) void ln_k(const float* __restrict__ x,
        const float* __restrict__ n1w, const float* __restrict__ n1b,
        const float* __restrict__ n2w, const float* __restrict__ n2b,
        float* __restrict__ xn, float* __restrict__ xm)
{
    int pg = blockIdx.x * 128 + threadIdx.x;
    int b = pg >> 12, p = pg & 4095;
    const float* xb = x + (size_t)b * CCH * HW + p;
    float v[CCH];
    float s = 0.f, s2 = 0.f;
#pragma unroll
    for (int c = 0; c < CCH; c++) { float t = xb[(size_t)c * HW]; v[c] = t; s += t; s2 += t * t; }
    float mu = s * (1.f / CCH);
    float var = s2 * (1.f / CCH) - mu * mu;
    float r = rsqrtf(var + 1e-6f);
    float* xnb = xn + (size_t)b * CCH * HW + p;
    float* xmb = xm + (size_t)b * CCH * HW + p;
#pragma unroll
    for (int c = 0; c < CCH; c++) {
        float y = (v[c] - mu) * r;
        xnb[(size_t)c * HW] = n1w[c] * y + n1b[c];
        xmb[(size_t)c * HW] = n2w[c] * y + n2b[c];
    }
}

// ---------------- 4px packed 1x1 conv, OSPL out-channels ----------------
template <int INC, int OUTC, int OSPL, bool HASB>
__global__ __launch_bounds__(128) void conv1x1q_k(const float* __restrict__ in,
        const float* __restrict__ w, const float* __restrict__ bias,
        float* __restrict__ out)
{
    __shared__ __align__(16) u64 ws2[OSPL * INC];
    __shared__ u64 bs2[OSPL];
    int tid = threadIdx.x;
    int o0 = blockIdx.y * OSPL;
    for (int i = tid; i < OSPL * INC; i += 128)
        ws2[i] = dup2(w[(o0 + i / INC) * INC + i % INC]);
    if (HASB) for (int i = tid; i < OSPL; i += 128) bs2[i] = dup2(bias[o0 + i]);
    __syncthreads();
    int p4 = (blockIdx.x * 128 + tid) * 4;
    int b = p4 >> 12, pp = p4 & 4095;
    const float* inb = in + (size_t)b * INC * HW + pp;
    u64 acc[OSPL][2];
#pragma unroll
    for (int o = 0; o < OSPL; o++) { acc[o][0] = HASB ? bs2[o] : 0ULL; acc[o][1] = acc[o][0]; }
    for (int cc = 0; cc < INC; cc += 8) {
        u64 xv[8][2];
#pragma unroll
        for (int c = 0; c < 8; c++) {
            ulonglong2 t = *(const ulonglong2*)(inb + (size_t)(cc + c) * HW);
            xv[c][0] = t.x; xv[c][1] = t.y;
        }
#pragma unroll
        for (int o = 0; o < OSPL; o++) {
#pragma unroll
            for (int c = 0; c < 8; c += 2) {
                ulonglong2 wv = *(const ulonglong2*)&ws2[o * INC + cc + c];
                acc[o][0] = fma2_(wv.x, xv[c][0], acc[o][0]);
                acc[o][1] = fma2_(wv.x, xv[c][1], acc[o][1]);
                acc[o][0] = fma2_(wv.y, xv[c + 1][0], acc[o][0]);
                acc[o][1] = fma2_(wv.y, xv[c + 1][1], acc[o][1]);
            }
        }
    }
    float* outb = out + ((size_t)b * OUTC + o0) * HW + pp;
#pragma unroll
    for (int o = 0; o < OSPL; o++) {
        ulonglong2 t; t.x = acc[o][0]; t.y = acc[o][1];
        *(ulonglong2*)(outb + (size_t)o * HW) = t;
    }
}

// ---------------- fused 3x conv1x1 from xn, 4px, OSPL=8, y=28 ----------------
__global__ __launch_bounds__(128) void fused3q_k(const float* __restrict__ xn,
        const float* __restrict__ w1, const float* __restrict__ w2,
        const float* __restrict__ w3, const float* __restrict__ b3,
        float* __restrict__ t1, float* __restrict__ t2, float* __restrict__ att)
{
    __shared__ __align__(16) u64 ws2[8 * CCH];
    __shared__ u64 bs2[8];
    int tid = threadIdx.x;
    int y = blockIdx.y;                // 0..27
    const float* w; float* outp; int ol; int outc; bool hasb;
    if (y < 12)      { w = w1; outp = t1;  ol = y * 8;         outc = HID;  hasb = false; }
    else if (y < 24) { w = w2; outp = t2;  ol = (y - 12) * 8;  outc = HID;  hasb = false; }
    else             { w = w3; outp = att; ol = (y - 24) * 8;  outc = NSET; hasb = true;  }
    for (int i = tid; i < 8 * CCH; i += 128)
        ws2[i] = dup2(w[(ol + i / CCH) * CCH + i % CCH]);
    if (hasb) { if (tid < 8) bs2[tid] = dup2(b3[ol + tid]); }
    __syncthreads();
    int p4 = (blockIdx.x * 128 + tid) * 4;
    int b = p4 >> 12, pp = p4 & 4095;
    const float* inb = xn + (size_t)b * CCH * HW + pp;
    u64 acc[8][2];
#pragma unroll
    for (int o = 0; o < 8; o++) { acc[o][0] = hasb ? bs2[o] : 0ULL; acc[o][1] = acc[o][0]; }
    for (int cc = 0; cc < CCH; cc += 8) {
        u64 xv[8][2];
#pragma unroll
        for (int c = 0; c < 8; c++) {
            ulonglong2 t = *(const ulonglong2*)(inb + (size_t)(cc + c) * HW);
            xv[c][0] = t.x; xv[c][1] = t.y;
        }
#pragma unroll
        for (int o = 0; o < 8; o++) {
#pragma unroll
            for (int c = 0; c < 8; c += 2) {
                ulonglong2 wv = *(const ulonglong2*)&ws2[o * CCH + cc + c];
                acc[o][0] = fma2_(wv.x, xv[c][0], acc[o][0]);
                acc[o][1] = fma2_(wv.x, xv[c][1], acc[o][1]);
                acc[o][0] = fma2_(wv.y, xv[c + 1][0], acc[o][0]);
                acc[o][1] = fma2_(wv.y, xv[c + 1][1], acc[o][1]);
            }
        }
    }
    float* outb = outp + ((size_t)b * outc + ol) * HW + pp;
#pragma unroll
    for (int o = 0; o < 8; o++) {
        ulonglong2 t; t.x = acc[o][0]; t.y = acc[o][1];
        *(ulonglong2*)(outb + (size_t)o * HW) = t;
    }
}

// ---------------- depthwise 3x3, 4px/thread ----------------
__global__ void dw3x3q_k(const float* __restrict__ in, const float* __restrict__ w,
                         float* __restrict__ out, int CH)
{
    int idx4 = (blockIdx.x * 256 + threadIdx.x) * 4;
    int p = idx4 & 4095; int bc = idx4 >> 12; int c = bc % CH;
    int h = p >> 6, w0 = p & 63;
    const float* inp = in + (size_t)bc * HW;
    const float* wc = w + c * 9;
    float wk[9];
#pragma unroll
    for (int i = 0; i < 9; i++) wk[i] = __ldg(wc + i);
    float a[4] = {0.f, 0.f, 0.f, 0.f};
#pragma unroll
    for (int kh = 0; kh < 3; kh++) {
        int hh = h + kh - 1;
        if (hh < 0 || hh > 63) continue;
        const float* r = inp + hh * 64;
        float4 v14 = *(const float4*)(r + w0);
        float vm1 = (w0 > 0)  ? r[w0 - 1] : 0.f;
        float v5  = (w0 < 60) ? r[w0 + 4] : 0.f;
        float v[6] = {vm1, v14.x, v14.y, v14.z, v14.w, v5};
        float k0 = wk[kh * 3], k1 = wk[kh * 3 + 1], k2 = wk[kh * 3 + 2];
#pragma unroll
        for (int px = 0; px < 4; px++)
            a[px] += k0 * v[px] + k1 * v[px + 1] + k2 * v[px + 2];
    }
    ulonglong2 t; t.x = pk2(a[0], a[1]); t.y = pk2(a[2], a[3]);
    *(ulonglong2*)(out + idx4) = t;
}

// ---------------- attention-coefficient mixer ----------------
__global__ __launch_bounds__(128) void attmix_k(const float* __restrict__ xn,
        const float* __restrict__ wA, const float* __restrict__ bA,
        const float* __restrict__ wB, const float* __restrict__ bB,
        const float* __restrict__ gam, float* __restrict__ att)
{
    __shared__ float swA[INTERC * 18], sbA[INTERC], swB[NSET * 12], sbB[NSET], sgam[NSET];
    int tid = threadIdx.x;
    for (int i = tid; i < INTERC * 18; i += 128) swA[i] = wA[i];
    for (int i = tid; i < INTERC; i += 128) sbA[i] = bA[i];
    for (int i = tid; i < NSET * 12; i += 128) swB[i] = wB[i];
    for (int i = tid; i < NSET; i += 128) { sbB[i] = bB[i]; sgam[i] = gam[i]; }
    __syncthreads();
    int pg = blockIdx.x * 128 + tid;
    int b = pg >> 12, p = pg & 4095;
    int h = p >> 6, w = p & 63;
    const float* xb = xn + (size_t)b * CCH * HW;
    float av[INTERC];
#pragma unroll
    for (int o = 0; o < INTERC; o++) {
        float acc = sbA[o];
#pragma unroll
        for (int t = 0; t < 2; t++) {
            const float* ch = xb + (size_t)(o * 2 + t) * HW;
#pragma unroll
            for (int kk = 0; kk < 9; kk++) {
                int hh = h + kk / 3 - 1, ww = w + kk % 3 - 1;
                if (hh >= 0 && hh < 64 && ww >= 0 && ww < 64)
                    acc += swA[o * 18 + t * 9 + kk] * ch[hh * 64 + ww];
            }
        }
        av[o] = acc;
    }
    float sg[12];
#pragma unroll
    for (int i = 0; i < 12; i++) sg[i] = av[i] * av[i + 12];
    for (int n = 0; n < NSET; n++) {
        float s = sbB[n];
#pragma unroll
        for (int i = 0; i < 12; i++) s += swB[n * 12 + i] * sg[i];
        size_t oi = ((size_t)b * NSET + n) * HW + p;
        att[oi] = sgam[n] * s + att[oi];
    }
}

// ---------------- KBA core + fused gelu(x1)*x2 epilogue ----------------
extern __shared__ u64 kba_sm[];
__global__ __launch_bounds__(128) void kba_k(const float* __restrict__ uf,
        const float* __restrict__ att, const float* __restrict__ kw,
        const float* __restrict__ kb, const float* __restrict__ ga1,
        const float* __restrict__ x1, float* __restrict__ mout)
{
    u64* kwsh = kba_sm;
    u64* ush  = kba_sm + 32 * 144;
    u64* kbsh = kba_sm + 32 * 144 + 36 * 128;
    float* ushf = (float*)ush;
    int tid = threadIdx.x;
    int p2 = blockIdx.x * 256 + tid * 2;
    int b = p2 >> 12, pp = p2 & 4095;
    int h = pp >> 6, w = pp & 63;
    const float* attb = att + (size_t)b * NSET * HW + pp;
    u64 a2[32];
#pragma unroll
    for (int n = 0; n < 32; n++) a2[n] = *(const u64*)(attb + (size_t)n * HW);

    for (int gi = 0; gi < 4; gi++) {
        int g = blockIdx.y * 4 + gi;
        const float* ufb = uf + ((size_t)b * HID + g * 4) * HW;
#pragma unroll
        for (int ci = 0; ci < 4; ci++) {
#pragma unroll
            for (int kk = 0; kk < 9; kk++) {
                int dh = kk / 3 - 1, dw = kk % 3 - 1;
                int j = ci * 9 + kk;
                int hh = h + dh;
                float v0 = 0.f, v1 = 0.f;
                if (hh >= 0 && hh < 64) {
                    const float* row = ufb + (size_t)ci * HW + hh * 64;
                    int wa = w + dw;
                    if (wa >= 0 && wa < 64) v0 = row[wa];
                    int wb = w + 1 + dw;
                    if (wb >= 0 && wb < 64) v1 = row[wb];
                }
                ush[j * 128 + tid] = pk2(v0, v1);
            }
        }
        for (int idx = tid; idx < 32 * 144; idx += 128) {
            int n = idx / 144, m2 = idx % 144;
            kwsh[idx] = dup2(kw[(size_t)n * 3456 + g * 144 + m2]);
        }
        kbsh[tid] = dup2(kb[(tid >> 2) * HID + g * 4 + (tid & 3)]);
        __syncthreads();

#pragma unroll
        for (int c = 0; c < 4; c++) {
            u64 s0 = 0ULL, s1 = 0ULL, s2 = 0ULL, s3 = 0ULL;
#pragma unroll
            for (int n = 0; n < 32; n += 4) {
                s0 = fma2_(a2[n + 0], kbsh[(n + 0) * 4 + c], s0);
                s1 = fma2_(a2[n + 1], kbsh[(n + 1) * 4 + c], s1);
                s2 = fma2_(a2[n + 2], kbsh[(n + 2) * 4 + c], s2);
                s3 = fma2_(a2[n + 3], kbsh[(n + 3) * 4 + c], s3);
            }
            const u64* kwc = kwsh + c * 36;
            for (int j = 0; j < 36; j += 2) {
                u64 tA0 = 0ULL, tA1 = 0ULL, tB0 = 0ULL, tB1 = 0ULL;
#pragma unroll
                for (int n = 0; n < 32; n += 2) {
                    ulonglong2 kv0 = *(const ulonglong2*)(kwc + n * 144 + j);
                    ulonglong2 kv1 = *(const ulonglong2*)(kwc + (n + 1) * 144 + j);
                    tA0 = fma2_(a2[n],     kv0.x, tA0);
                    tB0 = fma2_(a2[n],     kv0.y, tB0);
                    tA1 = fma2_(a2[n + 1], kv1.x, tA1);
                    tB1 = fma2_(a2[n + 1], kv1.y, tB1);
                }
                u64 tA = add2_(tA0, tA1), tB = add2_(tB0, tB1);
                s0 = fma2_(tA, ush[j * 128 + tid], s0);
                s1 = fma2_(tB, ush[(j + 1) * 128 + tid], s1);
            }
            u64 o = add2_(add2_(s0, s1), add2_(s2, s3));
            int ch = g * 4 + c;
            float ga = ga1[ch];
            float lo, hi; up2(o, lo, hi);
            float c0 = ushf[(c * 9 + 4) * 256 + 2 * tid];
            float c1 = ushf[(c * 9 + 4) * 256 + 2 * tid + 1];
            float x2lo = lo * ga + c0, x2hi = hi * ga + c1;
            // fused gelu(x1) * x2
            size_t xi = ((size_t)b * HID + ch) * HW + pp;
            float v0 = x1[xi], v1 = x1[xi + 1];
            float g0 = 0.5f * v0 * (1.f + erff(v0 * 0.70710678118654752f));
            float g1 = 0.5f * v1 * (1.f + erff(v1 * 0.70710678118654752f));
            *(u64*)(mout + xi) = pk2(g0 * x2lo, g1 * x2hi);
        }
        __syncthreads();
    }
}

// ---------------- MDTA: fused norms + 6x6 attention + softmax ----------------
__global__ __launch_bounds__(256) void attn_k(const float* __restrict__ qkv,
        const float* __restrict__ temp, float* __restrict__ attn)
{
    int bh = blockIdx.x; int b = bh >> 3, h = bh & 7;
    int warp = threadIdx.x >> 5, lane = threadIdx.x & 31;
    __shared__ float S[36], NQ[6], NK[6];
    const float* qb = qkv + ((size_t)b * 3 * CCH + h * DHEAD) * HW;
    const float* kb = qkv + ((size_t)b * 3 * CCH + CCH + h * DHEAD) * HW;
    for (int pi = warp; pi < 48; pi += 8) {
        const float* pa; const float* pb;
        if (pi < 36)      { pa = qb + (size_t)(pi / 6) * HW; pb = kb + (size_t)(pi % 6) * HW; }
        else if (pi < 42) { pa = qb + (size_t)(pi - 36) * HW; pb = pa; }
        else              { pa = kb + (size_t)(pi - 42) * HW; pb = pa; }
        float s = 0.f;
        for (int t = lane * 4; t < HW; t += 128) {
            float4 va = *(const float4*)(pa + t);
            float4 vb = *(const float4*)(pb + t);
            s += va.x * vb.x + va.y * vb.y + va.z * vb.z + va.w * vb.w;
        }
#pragma unroll
        for (int off = 16; off; off >>= 1) s += __shfl_down_sync(0xffffffffu, s, off);
        if (lane == 0) {
            if (pi < 36) S[pi] = s;
            else if (pi < 42) NQ[pi - 36] = sqrtf(s);
            else NK[pi - 42] = sqrtf(s);
        }
    }
    __syncthreads();
    if (threadIdx.x < 6) {
        int i = threadIdx.x;
        float nq = fmaxf(NQ[i], 1e-12f);
        float tv = temp[h];
        float row[6]; float mx = -1e30f;
#pragma unroll
        for (int j = 0; j < 6; j++) {
            float nk = fmaxf(NK[j], 1e-12f);
            row[j] = tv * S[i * 6 + j] / (nq * nk);
            mx = fmaxf(mx, row[j]);
        }
        float sum = 0.f;
#pragma unroll
        for (int j = 0; j < 6; j++) { row[j] = expf(row[j] - mx); sum += row[j]; }
        float inv = 1.f / sum;
#pragma unroll
        for (int j = 0; j < 6; j++)
            attn[((size_t)(b * 8 + h) * 6 + i) * 6 + j] = row[j] * inv;
    }
}

// ---------------- MDTA: fused (attn @ v) + mproj, 4px, OSPL=4 ----------------
__global__ __launch_bounds__(128) void mdta_k(const float* __restrict__ qkv,
        const float* __restrict__ attn, const float* __restrict__ mproj,
        float* __restrict__ out)
{
    __shared__ float scoef[288];
    __shared__ u64 ws2[4 * CCH];
    int tid = threadIdx.x;
    int o0 = blockIdx.y * 4;
    int p4 = (blockIdx.x * 128 + tid) * 4;
    int b = p4 >> 12, pp = p4 & 4095;
    int bblk = (blockIdx.x * 512) >> 12;
    for (int i = tid; i < 288; i += 128) scoef[i] = attn[bblk * 288 + i];
    for (int i = tid; i < 4 * CCH; i += 128)
        ws2[i] = dup2(mproj[(o0 + i / CCH) * CCH + i % CCH]);
    __syncthreads();
    u64 acc[4][2];
#pragma unroll
    for (int o = 0; o < 4; o++) { acc[o][0] = 0ULL; acc[o][1] = 0ULL; }
    const float* vb = qkv + ((size_t)b * 3 * CCH + 2 * CCH) * HW + pp;
#pragma unroll
    for (int h = 0; h < 8; h++) {
        u64 v[6][2];
#pragma unroll
        for (int j = 0; j < 6; j++) {
            ulonglong2 t = *(const ulonglong2*)(vb + (size_t)(h * 6 + j) * HW);
            v[j][0] = t.x; v[j][1] = t.y;
        }
#pragma unroll
        for (int i = 0; i < 6; i++) {
            int c = h * 6 + i;
            u64 md0 = 0ULL, md1 = 0ULL;
#pragma unroll
            for (int j = 0; j < 6; j++) {
                u64 cf = dup2(scoef[c * 6 + j]);
                md0 = fma2_(cf, v[j][0], md0);
                md1 = fma2_(cf, v[j][1], md1);
            }
#pragma unroll
            for (int o = 0; o < 4; o++) {
                u64 wv = ws2[o * CCH + c];
                acc[o][0] = fma2_(wv, md0, acc[o][0]);
                acc[o][1] = fma2_(wv, md1, acc[o][1]);
            }
        }
    }
    float* outb = out + ((size_t)b * CCH + o0) * HW + pp;
#pragma unroll
    for (int o = 0; o < 4; o++) {
        ulonglong2 t; t.x = acc[o][0]; t.y = acc[o][1];
        *(ulonglong2*)(outb + (size_t)o * HW) = t;
    }
}

// ---------------- final: kproj + residual combine, 4px, OSPL=4 ----------------
__global__ __launch_bounds__(128) void final_k(const float* __restrict__ x,
        const float* __restrict__ m, const float* __restrict__ mdta,
        const float* __restrict__ kproj,
        const float* __restrict__ ca1, const float* __restrict__ ca2,
        float* __restrict__ out)
{
    __shared__ __align__(16) u64 wp2[4 * HID];
    int tid = threadIdx.x;
    int o0 = blockIdx.y * 4;
    for (int i = tid; i < 4 * HID; i += 128)
        wp2[i] = dup2(kproj[(o0 + i / HID) * HID + i % HID]);
    __syncthreads();
    int p4 = (blockIdx.x * 128 + tid) * 4;
    int b = p4 >> 12, pp = p4 & 4095;
    const float* mb = m + (size_t)b * HID * HW + pp;
    u64 acc[4][2];
#pragma unroll
    for (int o = 0; o < 4; o++) { acc[o][0] = 0ULL; acc[o][1] = 0ULL; }
    for (int cc = 0; cc < HID; cc += 8) {
        u64 xv[8][2];
#pragma unroll
        for (int c = 0; c < 8; c++) {
            ulonglong2 t = *(const ulonglong2*)(mb + (size_t)(cc + c) * HW);
            xv[c][0] = t.x; xv[c][1] = t.y;
        }
#pragma unroll
        for (int o = 0; o < 4; o++) {
#pragma unroll
            for (int c = 0; c < 8; c += 2) {
                ulonglong2 wv = *(const ulonglong2*)&wp2[o * HID + cc + c];
                acc[o][0] = fma2_(wv.x, xv[c][0], acc[o][0]);
                acc[o][1] = fma2_(wv.x, xv[c][1], acc[o][1]);
                acc[o][0] = fma2_(wv.y, xv[c + 1][0], acc[o][0]);
                acc[o][1] = fma2_(wv.y, xv[c + 1][1], acc[o][1]);
            }
        }
    }
#pragma unroll
    for (int o = 0; o < 4; o++) {
        int oc = o0 + o;
        size_t oi = ((size_t)b * CCH + oc) * HW + pp;
        u64 a1 = dup2(ca1[b * CCH + oc]), a2 = dup2(ca2[b * CCH + oc]);
        ulonglong2 xv = *(const ulonglong2*)(x + oi);
        ulonglong2 dv = *(const ulonglong2*)(mdta + oi);
        ulonglong2 r;
        r.x = fma2_(a1, acc[o][0], fma2_(a2, dv.x, xv.x));
        r.y = fma2_(a1, acc[o][1], fma2_(a2, dv.y, xv.y));
        *(ulonglong2*)(out + oi) = r;
    }
}

// ---------------- host launcher ----------------
extern "C" void kernel_launch(void* const* d_in, const int* in_sizes, int n_in,
                              void* d_out, int out_size)
{
    const float* x       = (const float*)d_in[0];
    const float* n1w     = (const float*)d_in[1];
    const float* n1b     = (const float*)d_in[2];
    const float* n2w     = (const float*)d_in[3];
    const float* n2b     = (const float*)d_in[4];
    const float* kdw1    = (const float*)d_in[5];
    const float* kdw2    = (const float*)d_in[6];
    const float* kc1a    = (const float*)d_in[7];
    const float* kc1b    = (const float*)d_in[8];
    const float* kproj   = (const float*)d_in[9];
    const float* c2a_w   = (const float*)d_in[10];
    const float* c2a_b   = (const float*)d_in[11];
    const float* c2b_w   = (const float*)d_in[12];
    const float* c2b_b   = (const float*)d_in[13];
    const float* c211_w  = (const float*)d_in[14];
    const float* c211_b  = (const float*)d_in[15];
    const float* kw      = (const float*)d_in[16];
    const float* kb      = (const float*)d_in[17];
    const float* attg    = (const float*)d_in[18];
    const float* ga1     = (const float*)d_in[19];
    const float* temp    = (const float*)d_in[20];
    const float* qkv_w   = (const float*)d_in[21];
    const float* qkv_dww = (const float*)d_in[22];
    const float* mproj_w = (const float*)d_in[23];
    const float* ca1_w   = (const float*)d_in[24];
    const float* ca1_b   = (const float*)d_in[25];
    const float* ca2_w   = (const float*)d_in[26];
    const float* ca2_b   = (const float*)d_in[27];
    float* out = (float*)d_out;

    float* S = nullptr;
    cudaGetSymbolAddress((void**)&S, g_scratch);
    float* xn   = S + OFF_XN;
    float* xm   = S + OFF_XM;
    float* t1   = S + OFF_T1;
    float* t2   = S + OFF_T2;
    float* x1   = S + OFF_X1;
    float* uf   = S + OFF_UF;
    float* att  = S + OFF_ATT;
    float* qkvt = S + OFF_QKVT;
    float* qkv  = S + OFF_QKV;
    float* m    = S + OFF_M;
    float* gap  = S + OFF_GAP;
    float* ca1  = S + OFF_CA1;
    float* ca2  = S + OFF_CA2;
    float* attn = S + OFF_ATTN;
    float* mdta = qkvt;                     // reuse qkvt after consumed

    const int PIX = BATCH * HW;             // 16384
    const int XB4 = PIX / 512;              // 32

    const int KBA_SMEM = (32 * 144 + 36 * 128 + 32 * 4) * sizeof(u64);
    cudaFuncSetAttribute(kba_k, cudaFuncAttributeMaxDynamicSharedMemorySize, KBA_SMEM);

    gap_k<<<BATCH * CCH, 256>>>(x, gap);
    ca_k<<<1, 256>>>(gap, ca1_w, ca1_b, ca2_w, ca2_b, ca1, ca2);

    ln_k<<<PIX / 128, 128>>>(x, n1w, n1b, n2w, n2b, xn, xm);

    // KBA branch
    fused3q_k<<<dim3(XB4, 28), 128>>>(xn, kdw1, kc1a, c211_w, c211_b, t1, t2, att);
    dw3x3q_k<<<BATCH * HID * HW / 1024, 256>>>(t1, kdw2, x1, HID);
    dw3x3q_k<<<BATCH * HID * HW / 1024, 256>>>(t2, kc1b, uf, HID);
    attmix_k<<<PIX / 128, 128>>>(xn, c2a_w, c2a_b, c2b_w, c2b_b, attg, att);

    // MDTA branch
    conv1x1q_k<CCH, 3 * CCH, 8, false><<<dim3(XB4, 18), 128>>>(xm, qkv_w, nullptr, qkvt);
    dw3x3q_k<<<BATCH * 3 * CCH * HW / 1024, 256>>>(qkvt, qkv_dww, qkv, 3 * CCH);
    attn_k<<<BATCH * HEADS, 256>>>(qkv, temp, attn);
    mdta_k<<<dim3(XB4, 12), 128>>>(qkv, attn, mproj_w, mdta);

    // KBA core (+ fused gelu*x2 -> m)
    kba_k<<<dim3(PIX / 256, 6), 128, KBA_SMEM>>>(uf, att, kw, kb, ga1, x1, m);

    // projection + residual
    final_k<<<dim3(XB4, 12), 128>>>(x, m, mdta, kproj, ca1, ca2, out);
}

// round 7
// speedup vs baseline: 1.6664x; 1.1597x over previous
#include <cuda_runtime.h>
#include <cuda_bf16.h>
#include <math.h>
#include <cstdint>

// ---------------- problem constants ----------------
#define BATCH 4
#define CCH   48
#define HW    4096
#define HID   96
#define NSET  32
#define HEADS 8
#define DHEAD 6
#define INTERC 24

typedef unsigned long long u64;
__device__ __forceinline__ u64 pk2(float lo, float hi){ u64 r; asm("mov.b64 %0,{%1,%2};":"=l"(r):"f"(lo),"f"(hi)); return r; }
__device__ __forceinline__ u64 dup2(float v){ return pk2(v, v); }
__device__ __forceinline__ u64 fma2_(u64 a, u64 b, u64 c){ u64 d; asm("fma.rn.f32x2 %0,%1,%2,%3;":"=l"(d):"l"(a),"l"(b),"l"(c)); return d; }

__device__ __forceinline__ void mma_bf16(float* d, const uint32_t* a, const uint32_t* b){
    asm volatile("mma.sync.aligned.m16n8k16.row.col.f32.bf16.bf16.f32 "
        "{%0,%1,%2,%3}, {%4,%5,%6,%7}, {%8,%9}, {%0,%1,%2,%3};"
        : "+f"(d[0]),"+f"(d[1]),"+f"(d[2]),"+f"(d[3])
        : "r"(a[0]),"r"(a[1]),"r"(a[2]),"r"(a[3]), "r"(b[0]),"r"(b[1]));
}

// ---------------- scratch layout ----------------
#define OFF_XN    0LL
#define OFF_XM    (OFF_XN   + (long long)BATCH*CCH*HW)
#define OFF_T1    (OFF_XM   + (long long)BATCH*CCH*HW)
#define OFF_T2    (OFF_T1   + (long long)BATCH*HID*HW)
#define OFF_X1    (OFF_T2   + (long long)BATCH*HID*HW)
#define OFF_UF    (OFF_X1   + (long long)BATCH*HID*HW)
#define OFF_ATT   (OFF_UF   + (long long)BATCH*HID*HW)
#define OFF_QKVT  (OFF_ATT  + (long long)BATCH*NSET*HW)
#define OFF_QKV   (OFF_QKVT + (long long)BATCH*3*CCH*HW)
#define OFF_M     (OFF_QKV  + (long long)BATCH*3*CCH*HW)
#define OFF_GAP   (OFF_M    + (long long)BATCH*HID*HW)
#define OFF_CA1   (OFF_GAP  + BATCH*CCH)
#define OFF_CA2   (OFF_CA1  + BATCH*CCH)
#define OFF_ATTN  (OFF_CA2  + BATCH*CCH)
#define OFF_KWB   (OFF_ATTN + BATCH*HEADS*DHEAD*DHEAD)
#define SCRATCH_TOTAL (OFF_KWB + 24*160*32/2 + 64)

__device__ float g_scratch[SCRATCH_TOTAL];

// ---------------- gap ----------------
__global__ void gap_k(const float* __restrict__ x, float* __restrict__ gap)
{
    int bc = blockIdx.x;
    const float* xb = x + (size_t)bc * HW;
    __shared__ float red[256];
    float s = 0.f;
    for (int i = threadIdx.x; i < HW; i += 256) s += xb[i];
    red[threadIdx.x] = s; __syncthreads();
    for (int st = 128; st; st >>= 1) {
        if (threadIdx.x < st) red[threadIdx.x] += red[threadIdx.x + st];
        __syncthreads();
    }
    if (threadIdx.x == 0) gap[bc] = red[0] * (1.f / HW);
}

// ---------------- channel attention ----------------
__global__ void ca_k(const float* __restrict__ gap,
                     const float* __restrict__ w1, const float* __restrict__ b1,
                     const float* __restrict__ w2, const float* __restrict__ b2,
                     float* __restrict__ ca1, float* __restrict__ ca2)
{
    int t = threadIdx.x;
    if (t >= BATCH * CCH) return;
    int b = t / CCH, o = t % CCH;
    float s1 = b1[o], s2 = b2[o];
    for (int c = 0; c < CCH; c++) {
        float g = gap[b * CCH + c];
        s1 += w1[o * CCH + c] * g;
        s2 += w2[o * CCH + c] * g;
    }
    ca1[t] = s1; ca2[t] = s2;
}

// ---------------- LayerNorm2d ----------------
__global__ __launch_bounds__(128) void ln_k(const float* __restrict__ x,
        const float* __restrict__ n1w, const float* __restrict__ n1b,
        const float* __restrict__ n2w, const float* __restrict__ n2b,
        float* __restrict__ xn, float* __restrict__ xm)
{
    int pg = blockIdx.x * 128 + threadIdx.x;
    int b = pg >> 12, p = pg & 4095;
    const float* xb = x + (size_t)b * CCH * HW + p;
    float v[CCH];
    float s = 0.f, s2 = 0.f;
#pragma unroll
    for (int c = 0; c < CCH; c++) { float t = xb[(size_t)c * HW]; v[c] = t; s += t; s2 += t * t; }
    float mu = s * (1.f / CCH);
    float var = s2 * (1.f / CCH) - mu * mu;
    float r = rsqrtf(var + 1e-6f);
    float* xnb = xn + (size_t)b * CCH * HW + p;
    float* xmb = xm + (size_t)b * CCH * HW + p;
#pragma unroll
    for (int c = 0; c < CCH; c++) {
        float y = (v[c] - mu) * r;
        xnb[(size_t)c * HW] = n1w[c] * y + n1b[c];
        xmb[(size_t)c * HW] = n2w[c] * y + n2b[c];
    }
}

// ---------------- 4px packed 1x1 conv ----------------
template <int INC, int OUTC, int OSPL, bool HASB>
__global__ __launch_bounds__(128) void conv1x1q_k(const float* __restrict__ in,
        const float* __restrict__ w, const float* __restrict__ bias,
        float* __restrict__ out)
{
    __shared__ __align__(16) u64 ws2[OSPL * INC];
    __shared__ u64 bs2[OSPL];
    int tid = threadIdx.x;
    int o0 = blockIdx.y * OSPL;
    for (int i = tid; i < OSPL * INC; i += 128)
        ws2[i] = dup2(w[(o0 + i / INC) * INC + i % INC]);
    if (HASB) for (int i = tid; i < OSPL; i += 128) bs2[i] = dup2(bias[o0 + i]);
    __syncthreads();
    int p4 = (blockIdx.x * 128 + tid) * 4;
    int b = p4 >> 12, pp = p4 & 4095;
    const float* inb = in + (size_t)b * INC * HW + pp;
    u64 acc[OSPL][2];
#pragma unroll
    for (int o = 0; o < OSPL; o++) { acc[o][0] = HASB ? bs2[o] : 0ULL; acc[o][1] = acc[o][0]; }
    for (int cc = 0; cc < INC; cc += 8) {
        u64 xv[8][2];
#pragma unroll
        for (int c = 0; c < 8; c++) {
            ulonglong2 t = *(const ulonglong2*)(inb + (size_t)(cc + c) * HW);
            xv[c][0] = t.x; xv[c][1] = t.y;
        }
#pragma unroll
        for (int o = 0; o < OSPL; o++) {
#pragma unroll
            for (int c = 0; c < 8; c += 2) {
                ulonglong2 wv = *(const ulonglong2*)&ws2[o * INC + cc + c];
                acc[o][0] = fma2_(wv.x, xv[c][0], acc[o][0]);
                acc[o][1] = fma2_(wv.x, xv[c][1], acc[o][1]);
                acc[o][0] = fma2_(wv.y, xv[c + 1][0], acc[o][0]);
                acc[o][1] = fma2_(wv.y, xv[c + 1][1], acc[o][1]);
            }
        }
    }
    float* outb = out + ((size_t)b * OUTC + o0) * HW + pp;
#pragma unroll
    for (int o = 0; o < OSPL; o++) {
        ulonglong2 t; t.x = acc[o][0]; t.y = acc[o][1];
        *(ulonglong2*)(outb + (size_t)o * HW) = t;
    }
}

// ---------------- fused 3x conv1x1 from xn ----------------
__global__ __launch_bounds__(128) void fused3q_k(const float* __restrict__ xn,
        const float* __restrict__ w1, const float* __restrict__ w2,
        const float* __restrict__ w3, const float* __restrict__ b3,
        float* __restrict__ t1, float* __restrict__ t2, float* __restrict__ att)
{
    __shared__ __align__(16) u64 ws2[8 * CCH];
    __shared__ u64 bs2[8];
    int tid = threadIdx.x;
    int y = blockIdx.y;
    const float* w; float* outp; int ol; int outc; bool hasb;
    if (y < 12)      { w = w1; outp = t1;  ol = y * 8;         outc = HID;  hasb = false; }
    else if (y < 24) { w = w2; outp = t2;  ol = (y - 12) * 8;  outc = HID;  hasb = false; }
    else             { w = w3; outp = att; ol = (y - 24) * 8;  outc = NSET; hasb = true;  }
    for (int i = tid; i < 8 * CCH; i += 128)
        ws2[i] = dup2(w[(ol + i / CCH) * CCH + i % CCH]);
    if (hasb) { if (tid < 8) bs2[tid] = dup2(b3[ol + tid]); }
    __syncthreads();
    int p4 = (blockIdx.x * 128 + tid) * 4;
    int b = p4 >> 12, pp = p4 & 4095;
    const float* inb = xn + (size_t)b * CCH * HW + pp;
    u64 acc[8][2];
#pragma unroll
    for (int o = 0; o < 8; o++) { acc[o][0] = hasb ? bs2[o] : 0ULL; acc[o][1] = acc[o][0]; }
    for (int cc = 0; cc < CCH; cc += 8) {
        u64 xv[8][2];
#pragma unroll
        for (int c = 0; c < 8; c++) {
            ulonglong2 t = *(const ulonglong2*)(inb + (size_t)(cc + c) * HW);
            xv[c][0] = t.x; xv[c][1] = t.y;
        }
#pragma unroll
        for (int o = 0; o < 8; o++) {
#pragma unroll
            for (int c = 0; c < 8; c += 2) {
                ulonglong2 wv = *(const ulonglong2*)&ws2[o * CCH + cc + c];
                acc[o][0] = fma2_(wv.x, xv[c][0], acc[o][0]);
                acc[o][1] = fma2_(wv.x, xv[c][1], acc[o][1]);
                acc[o][0] = fma2_(wv.y, xv[c + 1][0], acc[o][0]);
                acc[o][1] = fma2_(wv.y, xv[c + 1][1], acc[o][1]);
            }
        }
    }
    float* outb = outp + ((size_t)b * outc + ol) * HW + pp;
#pragma unroll
    for (int o = 0; o < 8; o++) {
        ulonglong2 t; t.x = acc[o][0]; t.y = acc[o][1];
        *(ulonglong2*)(outb + (size_t)o * HW) = t;
    }
}

// ---------------- depthwise 3x3, 4px/thread ----------------
__global__ void dw3x3q_k(const float* __restrict__ in, const float* __restrict__ w,
                         float* __restrict__ out, int CH)
{
    int idx4 = (blockIdx.x * 256 + threadIdx.x) * 4;
    int p = idx4 & 4095; int bc = idx4 >> 12; int c = bc % CH;
    int h = p >> 6, w0 = p & 63;
    const float* inp = in + (size_t)bc * HW;
    const float* wc = w + c * 9;
    float wk[9];
#pragma unroll
    for (int i = 0; i < 9; i++) wk[i] = __ldg(wc + i);
    float a[4] = {0.f, 0.f, 0.f, 0.f};
#pragma unroll
    for (int kh = 0; kh < 3; kh++) {
        int hh = h + kh - 1;
        if (hh < 0 || hh > 63) continue;
        const float* r = inp + hh * 64;
        float4 v14 = *(const float4*)(r + w0);
        float vm1 = (w0 > 0)  ? r[w0 - 1] : 0.f;
        float v5  = (w0 < 60) ? r[w0 + 4] : 0.f;
        float v[6] = {vm1, v14.x, v14.y, v14.z, v14.w, v5};
        float k0 = wk[kh * 3], k1 = wk[kh * 3 + 1], k2 = wk[kh * 3 + 2];
#pragma unroll
        for (int px = 0; px < 4; px++)
            a[px] += k0 * v[px] + k1 * v[px + 1] + k2 * v[px + 2];
    }
    ulonglong2 t; t.x = pk2(a[0], a[1]); t.y = pk2(a[2], a[3]);
    *(ulonglong2*)(out + idx4) = t;
}

// ---------------- attention-coefficient mixer ----------------
__global__ __launch_bounds__(128) void attmix_k(const float* __restrict__ xn,
        const float* __restrict__ wA, const float* __restrict__ bA,
        const float* __restrict__ wB, const float* __restrict__ bB,
        const float* __restrict__ gam, float* __restrict__ att)
{
    __shared__ float swA[INTERC * 18], sbA[INTERC], swB[NSET * 12], sbB[NSET], sgam[NSET];
    int tid = threadIdx.x;
    for (int i = tid; i < INTERC * 18; i += 128) swA[i] = wA[i];
    for (int i = tid; i < INTERC; i += 128) sbA[i] = bA[i];
    for (int i = tid; i < NSET * 12; i += 128) swB[i] = wB[i];
    for (int i = tid; i < NSET; i += 128) { sbB[i] = bB[i]; sgam[i] = gam[i]; }
    __syncthreads();
    int pg = blockIdx.x * 128 + tid;
    int b = pg >> 12, p = pg & 4095;
    int h = p >> 6, w = p & 63;
    const float* xb = xn + (size_t)b * CCH * HW;
    float av[INTERC];
#pragma unroll
    for (int o = 0; o < INTERC; o++) {
        float acc = sbA[o];
#pragma unroll
        for (int t = 0; t < 2; t++) {
            const float* ch = xb + (size_t)(o * 2 + t) * HW;
#pragma unroll
            for (int kk = 0; kk < 9; kk++) {
                int hh = h + kk / 3 - 1, ww = w + kk % 3 - 1;
                if (hh >= 0 && hh < 64 && ww >= 0 && ww < 64)
                    acc += swA[o * 18 + t * 9 + kk] * ch[hh * 64 + ww];
            }
        }
        av[o] = acc;
    }
    float sg[12];
#pragma unroll
    for (int i = 0; i < 12; i++) sg[i] = av[i] * av[i + 12];
    for (int n = 0; n < NSET; n++) {
        float s = sbB[n];
#pragma unroll
        for (int i = 0; i < 12; i++) s += swB[n * 12 + i] * sg[i];
        size_t oi = ((size_t)b * NSET + n) * HW + p;
        att[oi] = sgam[n] * s + att[oi];
    }
}

// ---------------- kw/kb -> bf16 prepack: kwb[g][row160][n32] ----------------
__global__ void kwprep_k(const float* __restrict__ kw, const float* __restrict__ kb,
                         __nv_bfloat16* __restrict__ kwb)
{
    int g = blockIdx.x;
    for (int i = threadIdx.x; i < 160 * 32; i += 256) {
        int row = i >> 5, n = i & 31;
        int c = row / 40, rr = row - c * 40;
        float v;
        if (rr < 36)       v = kw[(size_t)n * 3456 + g * 144 + c * 36 + rr];
        else if (rr == 36) v = kb[n * HID + g * 4 + c];
        else               v = 0.f;
        kwb[((size_t)g * 160 + row) * 32 + n] = __float2bfloat16_rn(v);
    }
}

// ================= KBA core via warp-level bf16 MMA =================
// 128 px/block, 256 threads (8 warps, 1 m16-tile each).
// A(128x32 bf16) = att tile; per group B(160x32 bf16) from kwb.
// D = A@B^T (128x160 f32 frags). Epilogue: contract with patches + bias,
// x2 = .*ga1 + center, m = gelu(x1)*x2.
#define KT_A 0
#define KT_B 18432
#define KT_P 41472
#define KT_TOTAL 61952

__global__ __launch_bounds__(256) void kba_mma_k(
        const float* __restrict__ uf, const float* __restrict__ att,
        const __nv_bfloat16* __restrict__ kwb, const float* __restrict__ ga1,
        const float* __restrict__ x1, float* __restrict__ mout)
{
    extern __shared__ __align__(16) char smraw[];
    uint32_t* A32 = (uint32_t*)(smraw + KT_A);   // word-stride 36/row, 128 rows
    uint32_t* B32 = (uint32_t*)(smraw + KT_B);   // word-stride 36/row, 160 rows
    float*    P   = (float*)(smraw + KT_P);      // stride 40/row, 128 rows

    int tid = threadIdx.x, wid = tid >> 5, lane = tid & 31;
    int c0 = lane & 3, rq = lane >> 2;
    int pb = blockIdx.x * 128;
    int b = pb >> 12, pp0 = pb & 4095;

    int px = tid & 127, half = tid >> 7;
    int pp = pp0 + px;
    int h = pp >> 6, w = pp & 63;

    // stage A (bf16), each thread: row px, words half*8..+7
    {
        const float* attb = att + (size_t)b * NSET * HW + pp;
#pragma unroll
        for (int q = 0; q < 8; q++) {
            int n = (half * 8 + q) * 2;
            __nv_bfloat162 v;
            v.x = __float2bfloat16_rn(attb[(size_t)n * HW]);
            v.y = __float2bfloat16_rn(attb[(size_t)(n + 1) * HW]);
            A32[px * 36 + half * 8 + q] = *(uint32_t*)&v;
        }
    }
    // per-pixel patch geometry
    int offs[9]; bool val[9];
#pragma unroll
    for (int kk = 0; kk < 9; kk++) {
        int dh = kk / 3 - 1, dw = kk % 3 - 1;
        int hh = h + dh, ww = w + dw;
        val[kk] = (hh >= 0 && hh < 64 && ww >= 0 && ww < 64);
        offs[kk] = hh * 64 + ww;
    }
    __syncthreads();

    // hoisted A fragments (2 k-steps x 4 regs)
    int arow = 16 * wid + rq;
    uint32_t aF[2][4];
#pragma unroll
    for (int ks = 0; ks < 2; ks++) {
        int base = ks * 8;
        aF[ks][0] = A32[arow * 36 + base + c0];
        aF[ks][1] = A32[(arow + 8) * 36 + base + c0];
        aF[ks][2] = A32[arow * 36 + base + c0 + 4];
        aF[ks][3] = A32[(arow + 8) * 36 + base + c0 + 4];
    }

    for (int g = 0; g < 24; g++) {
        __syncthreads();
        // stage B
        const uint32_t* kwb32 = (const uint32_t*)(kwb + (size_t)g * 160 * 32);
        for (int i = tid; i < 2560; i += 256) {
            int row = i >> 4, np = i & 15;
            B32[row * 36 + np] = kwb32[i];
        }
        // stage patches (18 j per thread)
        const float* ufg = uf + ((size_t)b * HID + g * 4) * HW;
#pragma unroll
        for (int jj = 0; jj < 18; jj++) {
            int j = half * 18 + jj;
            int ci = j / 9, kk = j % 9;
            P[px * 40 + j] = val[kk] ? ufg[(size_t)ci * HW + offs[kk]] : 0.f;
        }
        __syncthreads();

#pragma unroll
        for (int cc = 0; cc < 4; cc++) {
            uint32_t bF[5][2][2];
            int nb = cc * 40;
#pragma unroll
            for (int t = 0; t < 5; t++) {
                int rowb = (nb + t * 8 + rq) * 36;
#pragma unroll
                for (int ks = 0; ks < 2; ks++) {
                    bF[t][ks][0] = B32[rowb + ks * 8 + c0];
                    bF[t][ks][1] = B32[rowb + ks * 8 + c0 + 4];
                }
            }
            float d[5][4];
#pragma unroll
            for (int t = 0; t < 5; t++) { d[t][0]=0.f; d[t][1]=0.f; d[t][2]=0.f; d[t][3]=0.f; }
#pragma unroll
            for (int t = 0; t < 5; t++) {
                mma_bf16(d[t], aF[0], bF[t][0]);
                mma_bf16(d[t], aF[1], bF[t][1]);
            }
            // epilogue: contract with patches
            int rlo = 16 * wid + rq, rhi = rlo + 8;
            float s0 = 0.f, s1 = 0.f;
#pragma unroll
            for (int t = 0; t < 5; t++) {
                int j0 = t * 8 + 2 * c0, j1 = j0 + 1;
                float w00, w01, w10, w11;
                if (j0 < 36)      { w00 = P[rlo * 40 + j0]; w10 = P[rhi * 40 + j0]; }
                else if (j0 == 36){ w00 = 1.f; w10 = 1.f; }
                else              { w00 = 0.f; w10 = 0.f; }
                if (j1 < 36)      { w01 = P[rlo * 40 + j1]; w11 = P[rhi * 40 + j1]; }
                else              { w01 = 0.f; w11 = 0.f; }
                s0 += d[t][0] * w00 + d[t][1] * w01;
                s1 += d[t][2] * w10 + d[t][3] * w11;
            }
            s0 += __shfl_xor_sync(0xffffffffu, s0, 1);
            s0 += __shfl_xor_sync(0xffffffffu, s0, 2);
            s1 += __shfl_xor_sync(0xffffffffu, s1, 1);
            s1 += __shfl_xor_sync(0xffffffffu, s1, 2);
            if (c0 == 0) {
                int ch = g * 4 + cc;
                float ga = ga1[ch];
                float cen0 = P[rlo * 40 + cc * 9 + 4];
                float cen1 = P[rhi * 40 + cc * 9 + 4];
                float x2a = s0 * ga + cen0;
                float x2b = s1 * ga + cen1;
                size_t xlo = ((size_t)b * HID + ch) * HW + pp0 + rlo;
                size_t xhi = xlo + 8;
                float v0 = x1[xlo], v1 = x1[xhi];
                mout[xlo] = 0.5f * v0 * (1.f + erff(v0 * 0.70710678118654752f)) * x2a;
                mout[xhi] = 0.5f * v1 * (1.f + erff(v1 * 0.70710678118654752f)) * x2b;
            }
        }
    }
}

// ---------------- MDTA: fused norms + 6x6 attention + softmax ----------------
__global__ __launch_bounds__(256) void attn_k(const float* __restrict__ qkv,
        const float* __restrict__ temp, float* __restrict__ attn)
{
    int bh = blockIdx.x; int b = bh >> 3, h = bh & 7;
    int warp = threadIdx.x >> 5, lane = threadIdx.x & 31;
    __shared__ float S[36], NQ[6], NK[6];
    const float* qb = qkv + ((size_t)b * 3 * CCH + h * DHEAD) * HW;
    const float* kb = qkv + ((size_t)b * 3 * CCH + CCH + h * DHEAD) * HW;
    for (int pi = warp; pi < 48; pi += 8) {
        const float* pa; const float* pb;
        if (pi < 36)      { pa = qb + (size_t)(pi / 6) * HW; pb = kb + (size_t)(pi % 6) * HW; }
        else if (pi < 42) { pa = qb + (size_t)(pi - 36) * HW; pb = pa; }
        else              { pa = kb + (size_t)(pi - 42) * HW; pb = pa; }
        float s = 0.f;
        for (int t = lane * 4; t < HW; t += 128) {
            float4 va = *(const float4*)(pa + t);
            float4 vb = *(const float4*)(pb + t);
            s += va.x * vb.x + va.y * vb.y + va.z * vb.z + va.w * vb.w;
        }
#pragma unroll
        for (int off = 16; off; off >>= 1) s += __shfl_down_sync(0xffffffffu, s, off);
        if (lane == 0) {
            if (pi < 36) S[pi] = s;
            else if (pi < 42) NQ[pi - 36] = sqrtf(s);
            else NK[pi - 42] = sqrtf(s);
        }
    }
    __syncthreads();
    if (threadIdx.x < 6) {
        int i = threadIdx.x;
        float nq = fmaxf(NQ[i], 1e-12f);
        float tv = temp[h];
        float row[6]; float mx = -1e30f;
#pragma unroll
        for (int j = 0; j < 6; j++) {
            float nk = fmaxf(NK[j], 1e-12f);
            row[j] = tv * S[i * 6 + j] / (nq * nk);
            mx = fmaxf(mx, row[j]);
        }
        float sum = 0.f;
#pragma unroll
        for (int j = 0; j < 6; j++) { row[j] = expf(row[j] - mx); sum += row[j]; }
        float inv = 1.f / sum;
#pragma unroll
        for (int j = 0; j < 6; j++)
            attn[((size_t)(b * 8 + h) * 6 + i) * 6 + j] = row[j] * inv;
    }
}

// ---------------- MDTA: fused (attn @ v) + mproj ----------------
__global__ __launch_bounds__(128) void mdta_k(const float* __restrict__ qkv,
        const float* __restrict__ attn, const float* __restrict__ mproj,
        float* __restrict__ out)
{
    __shared__ float scoef[288];
    __shared__ u64 ws2[4 * CCH];
    int tid = threadIdx.x;
    int o0 = blockIdx.y * 4;
    int p4 = (blockIdx.x * 128 + tid) * 4;
    int b = p4 >> 12, pp = p4 & 4095;
    int bblk = (blockIdx.x * 512) >> 12;
    for (int i = tid; i < 288; i += 128) scoef[i] = attn[bblk * 288 + i];
    for (int i = tid; i < 4 * CCH; i += 128)
        ws2[i] = dup2(mproj[(o0 + i / CCH) * CCH + i % CCH]);
    __syncthreads();
    u64 acc[4][2];
#pragma unroll
    for (int o = 0; o < 4; o++) { acc[o][0] = 0ULL; acc[o][1] = 0ULL; }
    const float* vb = qkv + ((size_t)b * 3 * CCH + 2 * CCH) * HW + pp;
#pragma unroll
    for (int h = 0; h < 8; h++) {
        u64 v[6][2];
#pragma unroll
        for (int j = 0; j < 6; j++) {
            ulonglong2 t = *(const ulonglong2*)(vb + (size_t)(h * 6 + j) * HW);
            v[j][0] = t.x; v[j][1] = t.y;
        }
#pragma unroll
        for (int i = 0; i < 6; i++) {
            int c = h * 6 + i;
            u64 md0 = 0ULL, md1 = 0ULL;
#pragma unroll
            for (int j = 0; j < 6; j++) {
                u64 cf = dup2(scoef[c * 6 + j]);
                md0 = fma2_(cf, v[j][0], md0);
                md1 = fma2_(cf, v[j][1], md1);
            }
#pragma unroll
            for (int o = 0; o < 4; o++) {
                u64 wv = ws2[o * CCH + c];
                acc[o][0] = fma2_(wv, md0, acc[o][0]);
                acc[o][1] = fma2_(wv, md1, acc[o][1]);
            }
        }
    }
    float* outb = out + ((size_t)b * CCH + o0) * HW + pp;
#pragma unroll
    for (int o = 0; o < 4; o++) {
        ulonglong2 t; t.x = acc[o][0]; t.y = acc[o][1];
        *(ulonglong2*)(outb + (size_t)o * HW) = t;
    }
}

// ---------------- final: kproj + residual combine ----------------
__global__ __launch_bounds__(128) void final_k(const float* __restrict__ x,
        const float* __restrict__ m, const float* __restrict__ mdta,
        const float* __restrict__ kproj,
        const float* __restrict__ ca1, const float* __restrict__ ca2,
        float* __restrict__ out)
{
    __shared__ __align__(16) u64 wp2[4 * HID];
    int tid = threadIdx.x;
    int o0 = blockIdx.y * 4;
    for (int i = tid; i < 4 * HID; i += 128)
        wp2[i] = dup2(kproj[(o0 + i / HID) * HID + i % HID]);
    __syncthreads();
    int p4 = (blockIdx.x * 128 + tid) * 4;
    int b = p4 >> 12, pp = p4 & 4095;
    const float* mb = m + (size_t)b * HID * HW + pp;
    u64 acc[4][2];
#pragma unroll
    for (int o = 0; o < 4; o++) { acc[o][0] = 0ULL; acc[o][1] = 0ULL; }
    for (int cc = 0; cc < HID; cc += 8) {
        u64 xv[8][2];
#pragma unroll
        for (int c = 0; c < 8; c++) {
            ulonglong2 t = *(const ulonglong2*)(mb + (size_t)(cc + c) * HW);
            xv[c][0] = t.x; xv[c][1] = t.y;
        }
#pragma unroll
        for (int o = 0; o < 4; o++) {
#pragma unroll
            for (int c = 0; c < 8; c += 2) {
                ulonglong2 wv = *(const ulonglong2*)&wp2[o * HID + cc + c];
                acc[o][0] = fma2_(wv.x, xv[c][0], acc[o][0]);
                acc[o][1] = fma2_(wv.x, xv[c][1], acc[o][1]);
                acc[o][0] = fma2_(wv.y, xv[c + 1][0], acc[o][0]);
                acc[o][1] = fma2_(wv.y, xv[c + 1][1], acc[o][1]);
            }
        }
    }
#pragma unroll
    for (int o = 0; o < 4; o++) {
        int oc = o0 + o;
        size_t oi = ((size_t)b * CCH + oc) * HW + pp;
        u64 a1 = dup2(ca1[b * CCH + oc]), a2 = dup2(ca2[b * CCH + oc]);
        ulonglong2 xv = *(const ulonglong2*)(x + oi);
        ulonglong2 dv = *(const ulonglong2*)(mdta + oi);
        ulonglong2 r;
        r.x = fma2_(a1, acc[o][0], fma2_(a2, dv.x, xv.x));
        r.y = fma2_(a1, acc[o][1], fma2_(a2, dv.y, xv.y));
        *(ulonglong2*)(out + oi) = r;
    }
}

// ---------------- host launcher ----------------
extern "C" void kernel_launch(void* const* d_in, const int* in_sizes, int n_in,
                              void* d_out, int out_size)
{
    const float* x       = (const float*)d_in[0];
    const float* n1w     = (const float*)d_in[1];
    const float* n1b     = (const float*)d_in[2];
    const float* n2w     = (const float*)d_in[3];
    const float* n2b     = (const float*)d_in[4];
    const float* kdw1    = (const float*)d_in[5];
    const float* kdw2    = (const float*)d_in[6];
    const float* kc1a    = (const float*)d_in[7];
    const float* kc1b    = (const float*)d_in[8];
    const float* kproj   = (const float*)d_in[9];
    const float* c2a_w   = (const float*)d_in[10];
    const float* c2a_b   = (const float*)d_in[11];
    const float* c2b_w   = (const float*)d_in[12];
    const float* c2b_b   = (const float*)d_in[13];
    const float* c211_w  = (const float*)d_in[14];
    const float* c211_b  = (const float*)d_in[15];
    const float* kw      = (const float*)d_in[16];
    const float* kb      = (const float*)d_in[17];
    const float* attg    = (const float*)d_in[18];
    const float* ga1     = (const float*)d_in[19];
    const float* temp    = (const float*)d_in[20];
    const float* qkv_w   = (const float*)d_in[21];
    const float* qkv_dww = (const float*)d_in[22];
    const float* mproj_w = (const float*)d_in[23];
    const float* ca1_w   = (const float*)d_in[24];
    const float* ca1_b   = (const float*)d_in[25];
    const float* ca2_w   = (const float*)d_in[26];
    const float* ca2_b   = (const float*)d_in[27];
    float* out = (float*)d_out;

    float* S = nullptr;
    cudaGetSymbolAddress((void**)&S, g_scratch);
    float* xn   = S + OFF_XN;
    float* xm   = S + OFF_XM;
    float* t1   = S + OFF_T1;
    float* t2   = S + OFF_T2;
    float* x1   = S + OFF_X1;
    float* uf   = S + OFF_UF;
    float* att  = S + OFF_ATT;
    float* qkvt = S + OFF_QKVT;
    float* qkv  = S + OFF_QKV;
    float* m    = S + OFF_M;
    float* gap  = S + OFF_GAP;
    float* ca1  = S + OFF_CA1;
    float* ca2  = S + OFF_CA2;
    float* attn = S + OFF_ATTN;
    __nv_bfloat16* kwb = (__nv_bfloat16*)(S + OFF_KWB);
    float* mdta = qkvt;                     // reuse

    const int PIX = BATCH * HW;             // 16384
    const int XB4 = PIX / 512;              // 32

    cudaFuncSetAttribute(kba_mma_k, cudaFuncAttributeMaxDynamicSharedMemorySize, KT_TOTAL);

    // prepack kw/kb (independent)
    kwprep_k<<<24, 256>>>(kw, kb, kwb);

    gap_k<<<BATCH * CCH, 256>>>(x, gap);
    ca_k<<<1, 256>>>(gap, ca1_w, ca1_b, ca2_w, ca2_b, ca1, ca2);

    ln_k<<<PIX / 128, 128>>>(x, n1w, n1b, n2w, n2b, xn, xm);

    // KBA branch
    fused3q_k<<<dim3(XB4, 28), 128>>>(xn, kdw1, kc1a, c211_w, c211_b, t1, t2, att);
    dw3x3q_k<<<BATCH * HID * HW / 1024, 256>>>(t1, kdw2, x1, HID);
    dw3x3q_k<<<BATCH * HID * HW / 1024, 256>>>(t2, kc1b, uf, HID);
    attmix_k<<<PIX / 128, 128>>>(xn, c2a_w, c2a_b, c2b_w, c2b_b, attg, att);

    // MDTA branch
    conv1x1q_k<CCH, 3 * CCH, 8, false><<<dim3(XB4, 18), 128>>>(xm, qkv_w, nullptr, qkvt);
    dw3x3q_k<<<BATCH * 3 * CCH * HW / 1024, 256>>>(qkvt, qkv_dww, qkv, 3 * CCH);
    attn_k<<<BATCH * HEADS, 256>>>(qkv, temp, attn);
    mdta_k<<<dim3(XB4, 12), 128>>>(qkv, attn, mproj_w, mdta);

    // KBA core via warp MMA (+ fused gelu*x2 -> m)
    kba_mma_k<<<PIX / 128, 256, KT_TOTAL>>>(uf, att, kwb, ga1, x1, m);

    // projection + residual
    final_k<<<dim3(XB4, 12), 128>>>(x, m, mdta, kproj, ca1, ca2, out);
}

// round 8
// speedup vs baseline: 1.7257x; 1.0356x over previous
#include <cuda_runtime.h>
#include <cuda_bf16.h>
#include <math.h>
#include <cstdint>

// ---------------- problem constants ----------------
#define BATCH 4
#define CCH   48
#define HW    4096
#define HID   96
#define NSET  32
#define HEADS 8
#define DHEAD 6
#define INTERC 24

typedef unsigned long long u64;
__device__ __forceinline__ u64 pk2(float lo, float hi){ u64 r; asm("mov.b64 %0,{%1,%2};":"=l"(r):"f"(lo),"f"(hi)); return r; }
__device__ __forceinline__ u64 dup2(float v){ return pk2(v, v); }
__device__ __forceinline__ u64 fma2_(u64 a, u64 b, u64 c){ u64 d; asm("fma.rn.f32x2 %0,%1,%2,%3;":"=l"(d):"l"(a),"l"(b),"l"(c)); return d; }

__device__ __forceinline__ void mma_bf16(float* d, const uint32_t* a, const uint32_t* b){
    asm volatile("mma.sync.aligned.m16n8k16.row.col.f32.bf16.bf16.f32 "
        "{%0,%1,%2,%3}, {%4,%5,%6,%7}, {%8,%9}, {%0,%1,%2,%3};"
        : "+f"(d[0]),"+f"(d[1]),"+f"(d[2]),"+f"(d[3])
        : "r"(a[0]),"r"(a[1]),"r"(a[2]),"r"(a[3]), "r"(b[0]),"r"(b[1]));
}

// ---------------- scratch layout ----------------
#define OFF_XN    0LL
#define OFF_XM    (OFF_XN   + (long long)BATCH*CCH*HW)
#define OFF_T1    (OFF_XM   + (long long)BATCH*CCH*HW)
#define OFF_T2    (OFF_T1   + (long long)BATCH*HID*HW)
#define OFF_X1    (OFF_T2   + (long long)BATCH*HID*HW)
#define OFF_UF    (OFF_X1   + (long long)BATCH*HID*HW)
#define OFF_ATT   (OFF_UF   + (long long)BATCH*HID*HW)
#define OFF_QKVT  (OFF_ATT  + (long long)BATCH*NSET*HW)
#define OFF_QKV   (OFF_QKVT + (long long)BATCH*3*CCH*HW)
#define OFF_M     (OFF_QKV  + (long long)BATCH*3*CCH*HW)
#define OFF_GAP   (OFF_M    + (long long)BATCH*HID*HW)
#define OFF_CA1   (OFF_GAP  + BATCH*CCH)
#define OFF_CA2   (OFF_CA1  + BATCH*CCH)
#define OFF_ATTN  (OFF_CA2  + BATCH*CCH)
#define OFF_KWB   (OFF_ATTN + BATCH*HEADS*DHEAD*DHEAD)
#define OFF_WB    (OFF_KWB + 24*160*32/2 + 64)
#define OFF_WQ    (OFF_WB  + 224*48/2 + 32)
#define SCRATCH_TOTAL (OFF_WQ + 144*48/2 + 32)

__device__ float g_scratch[SCRATCH_TOTAL];

// ---------------- gap ----------------
__global__ void gap_k(const float* __restrict__ x, float* __restrict__ gap)
{
    int bc = blockIdx.x;
    const float* xb = x + (size_t)bc * HW;
    __shared__ float red[256];
    float s = 0.f;
    for (int i = threadIdx.x; i < HW; i += 256) s += xb[i];
    red[threadIdx.x] = s; __syncthreads();
    for (int st = 128; st; st >>= 1) {
        if (threadIdx.x < st) red[threadIdx.x] += red[threadIdx.x + st];
        __syncthreads();
    }
    if (threadIdx.x == 0) gap[bc] = red[0] * (1.f / HW);
}

// ---------------- channel attention ----------------
__global__ void ca_k(const float* __restrict__ gap,
                     const float* __restrict__ w1, const float* __restrict__ b1,
                     const float* __restrict__ w2, const float* __restrict__ b2,
                     float* __restrict__ ca1, float* __restrict__ ca2)
{
    int t = threadIdx.x;
    if (t >= BATCH * CCH) return;
    int b = t / CCH, o = t % CCH;
    float s1 = b1[o], s2 = b2[o];
    for (int c = 0; c < CCH; c++) {
        float g = gap[b * CCH + c];
        s1 += w1[o * CCH + c] * g;
        s2 += w2[o * CCH + c] * g;
    }
    ca1[t] = s1; ca2[t] = s2;
}

// ---------------- LayerNorm2d, channel-split x4 ----------------
__global__ __launch_bounds__(512) void ln_k(const float* __restrict__ x,
        const float* __restrict__ n1w, const float* __restrict__ n1b,
        const float* __restrict__ n2w, const float* __restrict__ n2b,
        float* __restrict__ xn, float* __restrict__ xm)
{
    __shared__ float S1[512], S2[512];
    int tid = threadIdx.x;
    int px = tid & 127, grp = tid >> 7;
    int pg = blockIdx.x * 128 + px;
    int b = pg >> 12, p = pg & 4095;
    const float* xb = x + (size_t)b * CCH * HW + p + (size_t)grp * 12 * HW;
    float v[12]; float s = 0.f, s2 = 0.f;
#pragma unroll
    for (int c = 0; c < 12; c++) { float t = xb[(size_t)c * HW]; v[c] = t; s += t; s2 += t * t; }
    S1[tid] = s; S2[tid] = s2;
    __syncthreads();
    float st  = S1[px] + S1[px + 128] + S1[px + 256] + S1[px + 384];
    float st2 = S2[px] + S2[px + 128] + S2[px + 256] + S2[px + 384];
    float mu = st * (1.f / CCH);
    float var = st2 * (1.f / CCH) - mu * mu;
    float r = rsqrtf(var + 1e-6f);
    float* xnb = xn + (size_t)b * CCH * HW + p + (size_t)grp * 12 * HW;
    float* xmb = xm + (size_t)b * CCH * HW + p + (size_t)grp * 12 * HW;
#pragma unroll
    for (int c = 0; c < 12; c++) {
        int cg = grp * 12 + c;
        float y = (v[c] - mu) * r;
        xnb[(size_t)c * HW] = n1w[cg] * y + n1b[cg];
        xmb[(size_t)c * HW] = n2w[cg] * y + n2b[cg];
    }
}

// ---------------- weight prepack to bf16 ----------------
__global__ void wprep_k(const float* __restrict__ w1, const float* __restrict__ w2,
                        const float* __restrict__ w3, const float* __restrict__ qw,
                        __nv_bfloat16* __restrict__ wb, __nv_bfloat16* __restrict__ wq)
{
    int i = blockIdx.x * 256 + threadIdx.x;
    if (i < 224 * 48) {
        int o = i / 48, c = i % 48;
        float v = (o < 96) ? w1[o * 48 + c] : (o < 192) ? w2[(o - 96) * 48 + c]
                                                        : w3[(o - 192) * 48 + c];
        wb[i] = __float2bfloat16_rn(v);
    } else if (i < 224 * 48 + 144 * 48) {
        int j = i - 224 * 48;
        wq[j] = __float2bfloat16_rn(qw[j]);
    }
}

// ---------------- kw/kb -> bf16 prepack: kwb[g][row160][n32] ----------------
__global__ void kwprep_k(const float* __restrict__ kw, const float* __restrict__ kb,
                         __nv_bfloat16* __restrict__ kwb)
{
    int g = blockIdx.x;
    for (int i = threadIdx.x; i < 160 * 32; i += 256) {
        int row = i >> 5, n = i & 31;
        int c = row / 40, rr = row - c * 40;
        float v;
        if (rr < 36)       v = kw[(size_t)n * 3456 + g * 144 + c * 36 + rr];
        else if (rr == 36) v = kb[n * HID + g * 4 + c];
        else               v = 0.f;
        kwb[((size_t)g * 160 + row) * 32 + n] = __float2bfloat16_rn(v);
    }
}

// ---------------- fused3 via warp MMA: xn(48) -> t1(96), t2(96), att(32)+bias ----------------
__global__ __launch_bounds__(256) void fused3m_k(const float* __restrict__ xn,
        const __nv_bfloat16* __restrict__ wb, const float* __restrict__ b3,
        float* __restrict__ t1, float* __restrict__ t2, float* __restrict__ att)
{
    __shared__ uint32_t A32[128 * 28];
    __shared__ uint32_t WB32[224 * 28];
    __shared__ float sbias[224];
    int tid = threadIdx.x, wid = tid >> 5, lane = tid & 31;
    int c0 = lane & 3, rq = lane >> 2;
    int pb = blockIdx.x * 128;
    int b = pb >> 12, pp0 = pb & 4095;
    int px = tid & 127, half = tid >> 7;
    int pp = pp0 + px;

    const float* xb = xn + (size_t)b * CCH * HW + pp;
#pragma unroll
    for (int w = 0; w < 12; w++) {
        int wd = half * 12 + w; int c = wd * 2;
        __nv_bfloat162 v;
        v.x = __float2bfloat16_rn(xb[(size_t)c * HW]);
        v.y = __float2bfloat16_rn(xb[(size_t)(c + 1) * HW]);
        A32[px * 28 + wd] = *(uint32_t*)&v;
    }
    const uint32_t* wbg = (const uint32_t*)wb;
    for (int i = tid; i < 224 * 24; i += 256) { int o = i / 24, w = i % 24; WB32[o * 28 + w] = wbg[i]; }
    for (int i = tid; i < 224; i += 256) sbias[i] = (i < 192) ? 0.f : b3[i - 192];
    __syncthreads();

    int arow = wid * 16;
    uint32_t aF[3][4];
#pragma unroll
    for (int ks = 0; ks < 3; ks++) {
        aF[ks][0] = A32[(arow + rq) * 28 + ks * 8 + c0];
        aF[ks][1] = A32[(arow + rq + 8) * 28 + ks * 8 + c0];
        aF[ks][2] = A32[(arow + rq) * 28 + ks * 8 + c0 + 4];
        aF[ks][3] = A32[(arow + rq + 8) * 28 + ks * 8 + c0 + 4];
    }
    for (int nt = 0; nt < 28; nt++) {
        uint32_t bF[3][2];
        int rowb = (nt * 8 + rq) * 28;
#pragma unroll
        for (int ks = 0; ks < 3; ks++) { bF[ks][0] = WB32[rowb + ks * 8 + c0]; bF[ks][1] = WB32[rowb + ks * 8 + c0 + 4]; }
        float d[4] = {0.f, 0.f, 0.f, 0.f};
        mma_bf16(d, aF[0], bF[0]);
        mma_bf16(d, aF[1], bF[1]);
        mma_bf16(d, aF[2], bF[2]);
#pragma unroll
        for (int e = 0; e < 2; e++) {
            int oc = nt * 8 + 2 * c0 + e;
            float bia = sbias[oc];
            float* base; int ol; int outc;
            if (oc < 96)       { base = t1;  ol = oc;        outc = HID; }
            else if (oc < 192) { base = t2;  ol = oc - 96;   outc = HID; }
            else               { base = att; ol = oc - 192;  outc = NSET; }
            size_t o0 = ((size_t)b * outc + ol) * HW + pp0;
            base[o0 + arow + rq]     = d[e]     + bia;
            base[o0 + arow + rq + 8] = d[e + 2] + bia;
        }
    }
}

// ---------------- qkv 1x1 via warp MMA: xm(48) -> qkvt(144) ----------------
__global__ __launch_bounds__(256) void qkvm_k(const float* __restrict__ xm,
        const __nv_bfloat16* __restrict__ wq, float* __restrict__ out)
{
    __shared__ uint32_t A32[128 * 28];
    __shared__ uint32_t WB32[144 * 28];
    int tid = threadIdx.x, wid = tid >> 5, lane = tid & 31;
    int c0 = lane & 3, rq = lane >> 2;
    int pb = blockIdx.x * 128;
    int b = pb >> 12, pp0 = pb & 4095;
    int px = tid & 127, half = tid >> 7;
    int pp = pp0 + px;

    const float* xb = xm + (size_t)b * CCH * HW + pp;
#pragma unroll
    for (int w = 0; w < 12; w++) {
        int wd = half * 12 + w; int c = wd * 2;
        __nv_bfloat162 v;
        v.x = __float2bfloat16_rn(xb[(size_t)c * HW]);
        v.y = __float2bfloat16_rn(xb[(size_t)(c + 1) * HW]);
        A32[px * 28 + wd] = *(uint32_t*)&v;
    }
    const uint32_t* wbg = (const uint32_t*)wq;
    for (int i = tid; i < 144 * 24; i += 256) { int o = i / 24, w = i % 24; WB32[o * 28 + w] = wbg[i]; }
    __syncthreads();

    int arow = wid * 16;
    uint32_t aF[3][4];
#pragma unroll
    for (int ks = 0; ks < 3; ks++) {
        aF[ks][0] = A32[(arow + rq) * 28 + ks * 8 + c0];
        aF[ks][1] = A32[(arow + rq + 8) * 28 + ks * 8 + c0];
        aF[ks][2] = A32[(arow + rq) * 28 + ks * 8 + c0 + 4];
        aF[ks][3] = A32[(arow + rq + 8) * 28 + ks * 8 + c0 + 4];
    }
    for (int nt = 0; nt < 18; nt++) {
        uint32_t bF[3][2];
        int rowb = (nt * 8 + rq) * 28;
#pragma unroll
        for (int ks = 0; ks < 3; ks++) { bF[ks][0] = WB32[rowb + ks * 8 + c0]; bF[ks][1] = WB32[rowb + ks * 8 + c0 + 4]; }
        float d[4] = {0.f, 0.f, 0.f, 0.f};
        mma_bf16(d, aF[0], bF[0]);
        mma_bf16(d, aF[1], bF[1]);
        mma_bf16(d, aF[2], bF[2]);
#pragma unroll
        for (int e = 0; e < 2; e++) {
            int oc = nt * 8 + 2 * c0 + e;
            size_t o0 = ((size_t)b * (3 * CCH) + oc) * HW + pp0;
            out[o0 + arow + rq]     = d[e];
            out[o0 + arow + rq + 8] = d[e + 2];
        }
    }
}

// ---------------- depthwise 3x3, 4px/thread ----------------
__global__ void dw3x3q_k(const float* __restrict__ in, const float* __restrict__ w,
                         float* __restrict__ out, int CH)
{
    int idx4 = (blockIdx.x * 256 + threadIdx.x) * 4;
    int p = idx4 & 4095; int bc = idx4 >> 12; int c = bc % CH;
    int h = p >> 6, w0 = p & 63;
    const float* inp = in + (size_t)bc * HW;
    const float* wc = w + c * 9;
    float wk[9];
#pragma unroll
    for (int i = 0; i < 9; i++) wk[i] = __ldg(wc + i);
    float a[4] = {0.f, 0.f, 0.f, 0.f};
#pragma unroll
    for (int kh = 0; kh < 3; kh++) {
        int hh = h + kh - 1;
        if (hh < 0 || hh > 63) continue;
        const float* r = inp + hh * 64;
        float4 v14 = *(const float4*)(r + w0);
        float vm1 = (w0 > 0)  ? r[w0 - 1] : 0.f;
        float v5  = (w0 < 60) ? r[w0 + 4] : 0.f;
        float v[6] = {vm1, v14.x, v14.y, v14.z, v14.w, v5};
        float k0 = wk[kh * 3], k1 = wk[kh * 3 + 1], k2 = wk[kh * 3 + 2];
#pragma unroll
        for (int px = 0; px < 4; px++)
            a[px] += k0 * v[px] + k1 * v[px + 1] + k2 * v[px + 2];
    }
    ulonglong2 t; t.x = pk2(a[0], a[1]); t.y = pk2(a[2], a[3]);
    *(ulonglong2*)(out + idx4) = t;
}

// ---------------- attention-coefficient mixer ----------------
__global__ __launch_bounds__(128) void attmix_k(const float* __restrict__ xn,
        const float* __restrict__ wA, const float* __restrict__ bA,
        const float* __restrict__ wB, const float* __restrict__ bB,
        const float* __restrict__ gam, float* __restrict__ att)
{
    __shared__ float swA[INTERC * 18], sbA[INTERC], swB[NSET * 12], sbB[NSET], sgam[NSET];
    int tid = threadIdx.x;
    for (int i = tid; i < INTERC * 18; i += 128) swA[i] = wA[i];
    for (int i = tid; i < INTERC; i += 128) sbA[i] = bA[i];
    for (int i = tid; i < NSET * 12; i += 128) swB[i] = wB[i];
    for (int i = tid; i < NSET; i += 128) { sbB[i] = bB[i]; sgam[i] = gam[i]; }
    __syncthreads();
    int pg = blockIdx.x * 128 + tid;
    int b = pg >> 12, p = pg & 4095;
    int h = p >> 6, w = p & 63;
    const float* xb = xn + (size_t)b * CCH * HW;
    float av[INTERC];
#pragma unroll
    for (int o = 0; o < INTERC; o++) {
        float acc = sbA[o];
#pragma unroll
        for (int t = 0; t < 2; t++) {
            const float* ch = xb + (size_t)(o * 2 + t) * HW;
#pragma unroll
            for (int kk = 0; kk < 9; kk++) {
                int hh = h + kk / 3 - 1, ww = w + kk % 3 - 1;
                if (hh >= 0 && hh < 64 && ww >= 0 && ww < 64)
                    acc += swA[o * 18 + t * 9 + kk] * ch[hh * 64 + ww];
            }
        }
        av[o] = acc;
    }
    float sg[12];
#pragma unroll
    for (int i = 0; i < 12; i++) sg[i] = av[i] * av[i + 12];
    for (int n = 0; n < NSET; n++) {
        float s = sbB[n];
#pragma unroll
        for (int i = 0; i < 12; i++) s += swB[n * 12 + i] * sg[i];
        size_t oi = ((size_t)b * NSET + n) * HW + p;
        att[oi] = sgam[n] * s + att[oi];
    }
}

// ================= KBA core via warp-level bf16 MMA =================
#define KT_A 0
#define KT_B 18432
#define KT_P 41472
#define KT_TOTAL 61952

__global__ __launch_bounds__(256) void kba_mma_k(
        const float* __restrict__ uf, const float* __restrict__ att,
        const __nv_bfloat16* __restrict__ kwb, const float* __restrict__ ga1,
        const float* __restrict__ x1, float* __restrict__ mout)
{
    extern __shared__ __align__(16) char smraw[];
    uint32_t* A32 = (uint32_t*)(smraw + KT_A);
    uint32_t* B32 = (uint32_t*)(smraw + KT_B);
    float*    P   = (float*)(smraw + KT_P);

    int tid = threadIdx.x, wid = tid >> 5, lane = tid & 31;
    int c0 = lane & 3, rq = lane >> 2;
    int pb = blockIdx.x * 128;
    int b = pb >> 12, pp0 = pb & 4095;

    int px = tid & 127, half = tid >> 7;
    int pp = pp0 + px;
    int h = pp >> 6, w = pp & 63;

    {
        const float* attb = att + (size_t)b * NSET * HW + pp;
#pragma unroll
        for (int q = 0; q < 8; q++) {
            int n = (half * 8 + q) * 2;
            __nv_bfloat162 v;
            v.x = __float2bfloat16_rn(attb[(size_t)n * HW]);
            v.y = __float2bfloat16_rn(attb[(size_t)(n + 1) * HW]);
            A32[px * 36 + half * 8 + q] = *(uint32_t*)&v;
        }
    }
    int offs[9]; bool val[9];
#pragma unroll
    for (int kk = 0; kk < 9; kk++) {
        int dh = kk / 3 - 1, dw = kk % 3 - 1;
        int hh = h + dh, ww = w + dw;
        val[kk] = (hh >= 0 && hh < 64 && ww >= 0 && ww < 64);
        offs[kk] = hh * 64 + ww;
    }
    __syncthreads();

    int arow = 16 * wid + rq;
    uint32_t aF[2][4];
#pragma unroll
    for (int ks = 0; ks < 2; ks++) {
        int base = ks * 8;
        aF[ks][0] = A32[arow * 36 + base + c0];
        aF[ks][1] = A32[(arow + 8) * 36 + base + c0];
        aF[ks][2] = A32[arow * 36 + base + c0 + 4];
        aF[ks][3] = A32[(arow + 8) * 36 + base + c0 + 4];
    }

    for (int g = 0; g < 24; g++) {
        __syncthreads();
        const uint32_t* kwb32 = (const uint32_t*)(kwb + (size_t)g * 160 * 32);
        for (int i = tid; i < 2560; i += 256) {
            int row = i >> 4, np = i & 15;
            B32[row * 36 + np] = kwb32[i];
        }
        const float* ufg = uf + ((size_t)b * HID + g * 4) * HW;
#pragma unroll
        for (int jj = 0; jj < 18; jj++) {
            int j = half * 18 + jj;
            int ci = j / 9, kk = j % 9;
            P[px * 40 + j] = val[kk] ? ufg[(size_t)ci * HW + offs[kk]] : 0.f;
        }
        __syncthreads();

#pragma unroll
        for (int cc = 0; cc < 4; cc++) {
            uint32_t bF[5][2][2];
            int nb = cc * 40;
#pragma unroll
            for (int t = 0; t < 5; t++) {
                int rowb = (nb + t * 8 + rq) * 36;
#pragma unroll
                for (int ks = 0; ks < 2; ks++) {
                    bF[t][ks][0] = B32[rowb + ks * 8 + c0];
                    bF[t][ks][1] = B32[rowb + ks * 8 + c0 + 4];
                }
            }
            float d[5][4];
#pragma unroll
            for (int t = 0; t < 5; t++) { d[t][0]=0.f; d[t][1]=0.f; d[t][2]=0.f; d[t][3]=0.f; }
#pragma unroll
            for (int t = 0; t < 5; t++) {
                mma_bf16(d[t], aF[0], bF[t][0]);
                mma_bf16(d[t], aF[1], bF[t][1]);
            }
            int rlo = 16 * wid + rq, rhi = rlo + 8;
            float s0 = 0.f, s1 = 0.f;
#pragma unroll
            for (int t = 0; t < 5; t++) {
                int j0 = t * 8 + 2 * c0, j1 = j0 + 1;
                float w00, w01, w10, w11;
                if (j0 < 36)      { w00 = P[rlo * 40 + j0]; w10 = P[rhi * 40 + j0]; }
                else if (j0 == 36){ w00 = 1.f; w10 = 1.f; }
                else              { w00 = 0.f; w10 = 0.f; }
                if (j1 < 36)      { w01 = P[rlo * 40 + j1]; w11 = P[rhi * 40 + j1]; }
                else              { w01 = 0.f; w11 = 0.f; }
                s0 += d[t][0] * w00 + d[t][1] * w01;
                s1 += d[t][2] * w10 + d[t][3] * w11;
            }
            s0 += __shfl_xor_sync(0xffffffffu, s0, 1);
            s0 += __shfl_xor_sync(0xffffffffu, s0, 2);
            s1 += __shfl_xor_sync(0xffffffffu, s1, 1);
            s1 += __shfl_xor_sync(0xffffffffu, s1, 2);
            if (c0 == 0) {
                int ch = g * 4 + cc;
                float ga = ga1[ch];
                float cen0 = P[rlo * 40 + cc * 9 + 4];
                float cen1 = P[rhi * 40 + cc * 9 + 4];
                float x2a = s0 * ga + cen0;
                float x2b = s1 * ga + cen1;
                size_t xlo = ((size_t)b * HID + ch) * HW + pp0 + rlo;
                size_t xhi = xlo + 8;
                float v0 = x1[xlo], v1 = x1[xhi];
                mout[xlo] = 0.5f * v0 * (1.f + erff(v0 * 0.70710678118654752f)) * x2a;
                mout[xhi] = 0.5f * v1 * (1.f + erff(v1 * 0.70710678118654752f)) * x2b;
            }
        }
    }
}

// ---------------- MDTA: fused norms + 6x6 attention + softmax ----------------
__global__ __launch_bounds__(256) void attn_k(const float* __restrict__ qkv,
        const float* __restrict__ temp, float* __restrict__ attn)
{
    int bh = blockIdx.x; int b = bh >> 3, h = bh & 7;
    int warp = threadIdx.x >> 5, lane = threadIdx.x & 31;
    __shared__ float S[36], NQ[6], NK[6];
    const float* qb = qkv + ((size_t)b * 3 * CCH + h * DHEAD) * HW;
    const float* kb = qkv + ((size_t)b * 3 * CCH + CCH + h * DHEAD) * HW;
    for (int pi = warp; pi < 48; pi += 8) {
        const float* pa; const float* pb;
        if (pi < 36)      { pa = qb + (size_t)(pi / 6) * HW; pb = kb + (size_t)(pi % 6) * HW; }
        else if (pi < 42) { pa = qb + (size_t)(pi - 36) * HW; pb = pa; }
        else              { pa = kb + (size_t)(pi - 42) * HW; pb = pa; }
        float s = 0.f;
        for (int t = lane * 4; t < HW; t += 128) {
            float4 va = *(const float4*)(pa + t);
            float4 vb = *(const float4*)(pb + t);
            s += va.x * vb.x + va.y * vb.y + va.z * vb.z + va.w * vb.w;
        }
#pragma unroll
        for (int off = 16; off; off >>= 1) s += __shfl_down_sync(0xffffffffu, s, off);
        if (lane == 0) {
            if (pi < 36) S[pi] = s;
            else if (pi < 42) NQ[pi - 36] = sqrtf(s);
            else NK[pi - 42] = sqrtf(s);
        }
    }
    __syncthreads();
    if (threadIdx.x < 6) {
        int i = threadIdx.x;
        float nq = fmaxf(NQ[i], 1e-12f);
        float tv = temp[h];
        float row[6]; float mx = -1e30f;
#pragma unroll
        for (int j = 0; j < 6; j++) {
            float nk = fmaxf(NK[j], 1e-12f);
            row[j] = tv * S[i * 6 + j] / (nq * nk);
            mx = fmaxf(mx, row[j]);
        }
        float sum = 0.f;
#pragma unroll
        for (int j = 0; j < 6; j++) { row[j] = expf(row[j] - mx); sum += row[j]; }
        float inv = 1.f / sum;
#pragma unroll
        for (int j = 0; j < 6; j++)
            attn[((size_t)(b * 8 + h) * 6 + i) * 6 + j] = row[j] * inv;
    }
}

// ---------------- MDTA: fused (attn @ v) + mproj ----------------
__global__ __launch_bounds__(128) void mdta_k(const float* __restrict__ qkv,
        const float* __restrict__ attn, const float* __restrict__ mproj,
        float* __restrict__ out)
{
    __shared__ float scoef[288];
    __shared__ u64 ws2[4 * CCH];
    int tid = threadIdx.x;
    int o0 = blockIdx.y * 4;
    int p4 = (blockIdx.x * 128 + tid) * 4;
    int b = p4 >> 12, pp = p4 & 4095;
    int bblk = (blockIdx.x * 512) >> 12;
    for (int i = tid; i < 288; i += 128) scoef[i] = attn[bblk * 288 + i];
    for (int i = tid; i < 4 * CCH; i += 128)
        ws2[i] = dup2(mproj[(o0 + i / CCH) * CCH + i % CCH]);
    __syncthreads();
    u64 acc[4][2];
#pragma unroll
    for (int o = 0; o < 4; o++) { acc[o][0] = 0ULL; acc[o][1] = 0ULL; }
    const float* vb = qkv + ((size_t)b * 3 * CCH + 2 * CCH) * HW + pp;
#pragma unroll
    for (int h = 0; h < 8; h++) {
        u64 v[6][2];
#pragma unroll
        for (int j = 0; j < 6; j++) {
            ulonglong2 t = *(const ulonglong2*)(vb + (size_t)(h * 6 + j) * HW);
            v[j][0] = t.x; v[j][1] = t.y;
        }
#pragma unroll
        for (int i = 0; i < 6; i++) {
            int c = h * 6 + i;
            u64 md0 = 0ULL, md1 = 0ULL;
#pragma unroll
            for (int j = 0; j < 6; j++) {
                u64 cf = dup2(scoef[c * 6 + j]);
                md0 = fma2_(cf, v[j][0], md0);
                md1 = fma2_(cf, v[j][1], md1);
            }
#pragma unroll
            for (int o = 0; o < 4; o++) {
                u64 wv = ws2[o * CCH + c];
                acc[o][0] = fma2_(wv, md0, acc[o][0]);
                acc[o][1] = fma2_(wv, md1, acc[o][1]);
            }
        }
    }
    float* outb = out + ((size_t)b * CCH + o0) * HW + pp;
#pragma unroll
    for (int o = 0; o < 4; o++) {
        ulonglong2 t; t.x = acc[o][0]; t.y = acc[o][1];
        *(ulonglong2*)(outb + (size_t)o * HW) = t;
    }
}

// ---------------- final: kproj + residual combine ----------------
__global__ __launch_bounds__(128) void final_k(const float* __restrict__ x,
        const float* __restrict__ m, const float* __restrict__ mdta,
        const float* __restrict__ kproj,
        const float* __restrict__ ca1, const float* __restrict__ ca2,
        float* __restrict__ out)
{
    __shared__ __align__(16) u64 wp2[4 * HID];
    int tid = threadIdx.x;
    int o0 = blockIdx.y * 4;
    for (int i = tid; i < 4 * HID; i += 128)
        wp2[i] = dup2(kproj[(o0 + i / HID) * HID + i % HID]);
    __syncthreads();
    int p4 = (blockIdx.x * 128 + tid) * 4;
    int b = p4 >> 12, pp = p4 & 4095;
    const float* mb = m + (size_t)b * HID * HW + pp;
    u64 acc[4][2];
#pragma unroll
    for (int o = 0; o < 4; o++) { acc[o][0] = 0ULL; acc[o][1] = 0ULL; }
    for (int cc = 0; cc < HID; cc += 8) {
        u64 xv[8][2];
#pragma unroll
        for (int c = 0; c < 8; c++) {
            ulonglong2 t = *(const ulonglong2*)(mb + (size_t)(cc + c) * HW);
            xv[c][0] = t.x; xv[c][1] = t.y;
        }
#pragma unroll
        for (int o = 0; o < 4; o++) {
#pragma unroll
            for (int c = 0; c < 8; c += 2) {
                ulonglong2 wv = *(const ulonglong2*)&wp2[o * HID + cc + c];
                acc[o][0] = fma2_(wv.x, xv[c][0], acc[o][0]);
                acc[o][1] = fma2_(wv.x, xv[c][1], acc[o][1]);
                acc[o][0] = fma2_(wv.y, xv[c + 1][0], acc[o][0]);
                acc[o][1] = fma2_(wv.y, xv[c + 1][1], acc[o][1]);
            }
        }
    }
#pragma unroll
    for (int o = 0; o < 4; o++) {
        int oc = o0 + o;
        size_t oi = ((size_t)b * CCH + oc) * HW + pp;
        u64 a1 = dup2(ca1[b * CCH + oc]), a2 = dup2(ca2[b * CCH + oc]);
        ulonglong2 xv = *(const ulonglong2*)(x + oi);
        ulonglong2 dv = *(const ulonglong2*)(mdta + oi);
        ulonglong2 r;
        r.x = fma2_(a1, acc[o][0], fma2_(a2, dv.x, xv.x));
        r.y = fma2_(a1, acc[o][1], fma2_(a2, dv.y, xv.y));
        *(ulonglong2*)(out + oi) = r;
    }
}

// ---------------- host launcher ----------------
extern "C" void kernel_launch(void* const* d_in, const int* in_sizes, int n_in,
                              void* d_out, int out_size)
{
    const float* x       = (const float*)d_in[0];
    const float* n1w     = (const float*)d_in[1];
    const float* n1b     = (const float*)d_in[2];
    const float* n2w     = (const float*)d_in[3];
    const float* n2b     = (const float*)d_in[4];
    const float* kdw1    = (const float*)d_in[5];
    const float* kdw2    = (const float*)d_in[6];
    const float* kc1a    = (const float*)d_in[7];
    const float* kc1b    = (const float*)d_in[8];
    const float* kproj   = (const float*)d_in[9];
    const float* c2a_w   = (const float*)d_in[10];
    const float* c2a_b   = (const float*)d_in[11];
    const float* c2b_w   = (const float*)d_in[12];
    const float* c2b_b   = (const float*)d_in[13];
    const float* c211_w  = (const float*)d_in[14];
    const float* c211_b  = (const float*)d_in[15];
    const float* kw      = (const float*)d_in[16];
    const float* kb      = (const float*)d_in[17];
    const float* attg    = (const float*)d_in[18];
    const float* ga1     = (const float*)d_in[19];
    const float* temp    = (const float*)d_in[20];
    const float* qkv_w   = (const float*)d_in[21];
    const float* qkv_dww = (const float*)d_in[22];
    const float* mproj_w = (const float*)d_in[23];
    const float* ca1_w   = (const float*)d_in[24];
    const float* ca1_b   = (const float*)d_in[25];
    const float* ca2_w   = (const float*)d_in[26];
    const float* ca2_b   = (const float*)d_in[27];
    float* out = (float*)d_out;

    float* S = nullptr;
    cudaGetSymbolAddress((void**)&S, g_scratch);
    float* xn   = S + OFF_XN;
    float* xm   = S + OFF_XM;
    float* t1   = S + OFF_T1;
    float* t2   = S + OFF_T2;
    float* x1   = S + OFF_X1;
    float* uf   = S + OFF_UF;
    float* att  = S + OFF_ATT;
    float* qkvt = S + OFF_QKVT;
    float* qkv  = S + OFF_QKV;
    float* m    = S + OFF_M;
    float* gap  = S + OFF_GAP;
    float* ca1  = S + OFF_CA1;
    float* ca2  = S + OFF_CA2;
    float* attn = S + OFF_ATTN;
    __nv_bfloat16* kwb = (__nv_bfloat16*)(S + OFF_KWB);
    __nv_bfloat16* wb  = (__nv_bfloat16*)(S + OFF_WB);
    __nv_bfloat16* wq  = (__nv_bfloat16*)(S + OFF_WQ);
    float* mdta = qkvt;                     // reuse

    const int PIX = BATCH * HW;             // 16384
    const int XB4 = PIX / 512;              // 32

    cudaFuncSetAttribute(kba_mma_k, cudaFuncAttributeMaxDynamicSharedMemorySize, KT_TOTAL);

    // weight prepacks (independent)
    kwprep_k<<<24, 256>>>(kw, kb, kwb);
    wprep_k<<<(224 * 48 + 144 * 48 + 255) / 256, 256>>>(kdw1, kc1a, c211_w, qkv_w, wb, wq);

    gap_k<<<BATCH * CCH, 256>>>(x, gap);
    ca_k<<<1, 256>>>(gap, ca1_w, ca1_b, ca2_w, ca2_b, ca1, ca2);

    ln_k<<<PIX / 128, 512>>>(x, n1w, n1b, n2w, n2b, xn, xm);

    // KBA branch
    fused3m_k<<<PIX / 128, 256>>>(xn, wb, c211_b, t1, t2, att);
    dw3x3q_k<<<BATCH * HID * HW / 1024, 256>>>(t1, kdw2, x1, HID);
    dw3x3q_k<<<BATCH * HID * HW / 1024, 256>>>(t2, kc1b, uf, HID);
    attmix_k<<<PIX / 128, 128>>>(xn, c2a_w, c2a_b, c2b_w, c2b_b, attg, att);

    // MDTA branch
    qkvm_k<<<PIX / 128, 256>>>(xm, wq, qkvt);
    dw3x3q_k<<<BATCH * 3 * CCH * HW / 1024, 256>>>(qkvt, qkv_dww, qkv, 3 * CCH);
    attn_k<<<BATCH * HEADS, 256>>>(qkv, temp, attn);
    mdta_k<<<dim3(XB4, 12), 128>>>(qkv, attn, mproj_w, mdta);

    // KBA core via warp MMA (+ fused gelu*x2 -> m)
    kba_mma_k<<<PIX / 128, 256, KT_TOTAL>>>(uf, att, kwb, ga1, x1, m);

    // projection + residual
    final_k<<<dim3(XB4, 12), 128>>>(x, m, mdta, kproj, ca1, ca2, out);
}

// round 9
// speedup vs baseline: 1.8761x; 1.0872x over previous
#include <cuda_runtime.h>
#include <cuda_bf16.h>
#include <math.h>
#include <cstdint>

// ---------------- problem constants ----------------
#define BATCH 4
#define CCH   48
#define HW    4096
#define HID   96
#define NSET  32
#define HEADS 8
#define DHEAD 6
#define INTERC 24

typedef unsigned long long u64;
__device__ __forceinline__ u64 pk2(float lo, float hi){ u64 r; asm("mov.b64 %0,{%1,%2};":"=l"(r):"f"(lo),"f"(hi)); return r; }
__device__ __forceinline__ u64 dup2(float v){ return pk2(v, v); }
__device__ __forceinline__ u64 fma2_(u64 a, u64 b, u64 c){ u64 d; asm("fma.rn.f32x2 %0,%1,%2,%3;":"=l"(d):"l"(a),"l"(b),"l"(c)); return d; }

__device__ __forceinline__ void mma_bf16(float* d, const uint32_t* a, const uint32_t* b){
    asm volatile("mma.sync.aligned.m16n8k16.row.col.f32.bf16.bf16.f32 "
        "{%0,%1,%2,%3}, {%4,%5,%6,%7}, {%8,%9}, {%0,%1,%2,%3};"
        : "+f"(d[0]),"+f"(d[1]),"+f"(d[2]),"+f"(d[3])
        : "r"(a[0]),"r"(a[1]),"r"(a[2]),"r"(a[3]), "r"(b[0]),"r"(b[1]));
}

// ---------------- scratch layout ----------------
#define OFF_XN    0LL
#define OFF_XM    (OFF_XN   + (long long)BATCH*CCH*HW)
#define OFF_T1    (OFF_XM   + (long long)BATCH*CCH*HW)
#define OFF_T2    (OFF_T1   + (long long)BATCH*HID*HW)
#define OFF_X1    (OFF_T2   + (long long)BATCH*HID*HW)
#define OFF_UF    (OFF_X1   + (long long)BATCH*HID*HW)
#define OFF_ATT   (OFF_UF   + (long long)BATCH*HID*HW)
#define OFF_QKVT  (OFF_ATT  + (long long)BATCH*NSET*HW)
#define OFF_QKV   (OFF_QKVT + (long long)BATCH*3*CCH*HW)
#define OFF_M     (OFF_QKV  + (long long)BATCH*3*CCH*HW)
#define OFF_GAP   (OFF_M    + (long long)BATCH*HID*HW)
#define OFF_CA1   (OFF_GAP  + BATCH*CCH)
#define OFF_CA2   (OFF_CA1  + BATCH*CCH)
#define OFF_ATTN  (OFF_CA2  + BATCH*CCH)
#define OFF_KWB   (OFF_ATTN + BATCH*HEADS*DHEAD*DHEAD)
#define OFF_WB    (OFF_KWB + 24*160*32/2 + 64)
#define OFF_WQ    (OFF_WB  + 224*48/2 + 32)
#define SCRATCH_TOTAL (OFF_WQ + 144*48/2 + 32)

__device__ float g_scratch[SCRATCH_TOTAL];

// ---------------- gap ----------------
__global__ void gap_k(const float* __restrict__ x, float* __restrict__ gap)
{
    int bc = blockIdx.x;
    const float* xb = x + (size_t)bc * HW;
    __shared__ float red[256];
    float s = 0.f;
    for (int i = threadIdx.x; i < HW; i += 256) s += xb[i];
    red[threadIdx.x] = s; __syncthreads();
    for (int st = 128; st; st >>= 1) {
        if (threadIdx.x < st) red[threadIdx.x] += red[threadIdx.x + st];
        __syncthreads();
    }
    if (threadIdx.x == 0) gap[bc] = red[0] * (1.f / HW);
}

// ---------------- channel attention: one block per (b,o), parallel dot ----------------
__global__ __launch_bounds__(64) void ca_k(const float* __restrict__ gap,
                     const float* __restrict__ w1, const float* __restrict__ b1,
                     const float* __restrict__ w2, const float* __restrict__ b2,
                     float* __restrict__ ca1, float* __restrict__ ca2)
{
    int bo = blockIdx.x;                 // 0..191
    int b = bo / CCH, o = bo % CCH;
    int t = threadIdx.x;
    __shared__ float R1[64], R2[64];
    float s1 = 0.f, s2 = 0.f;
    if (t < CCH) {
        float g = gap[b * CCH + t];
        s1 = w1[o * CCH + t] * g;
        s2 = w2[o * CCH + t] * g;
    }
    R1[t] = s1; R2[t] = s2;
    __syncthreads();
    for (int st = 32; st; st >>= 1) {
        if (t < st) { R1[t] += R1[t + st]; R2[t] += R2[t + st]; }
        __syncthreads();
    }
    if (t == 0) { ca1[bo] = R1[0] + b1[o]; ca2[bo] = R2[0] + b2[o]; }
}

// ---------------- LayerNorm2d, channel-split x4 ----------------
__global__ __launch_bounds__(512) void ln_k(const float* __restrict__ x,
        const float* __restrict__ n1w, const float* __restrict__ n1b,
        const float* __restrict__ n2w, const float* __restrict__ n2b,
        float* __restrict__ xn, float* __restrict__ xm)
{
    __shared__ float S1[512], S2[512];
    int tid = threadIdx.x;
    int px = tid & 127, grp = tid >> 7;
    int pg = blockIdx.x * 128 + px;
    int b = pg >> 12, p = pg & 4095;
    const float* xb = x + (size_t)b * CCH * HW + p + (size_t)grp * 12 * HW;
    float v[12]; float s = 0.f, s2 = 0.f;
#pragma unroll
    for (int c = 0; c < 12; c++) { float t = xb[(size_t)c * HW]; v[c] = t; s += t; s2 += t * t; }
    S1[tid] = s; S2[tid] = s2;
    __syncthreads();
    float st  = S1[px] + S1[px + 128] + S1[px + 256] + S1[px + 384];
    float st2 = S2[px] + S2[px + 128] + S2[px + 256] + S2[px + 384];
    float mu = st * (1.f / CCH);
    float var = st2 * (1.f / CCH) - mu * mu;
    float r = rsqrtf(var + 1e-6f);
    float* xnb = xn + (size_t)b * CCH * HW + p + (size_t)grp * 12 * HW;
    float* xmb = xm + (size_t)b * CCH * HW + p + (size_t)grp * 12 * HW;
#pragma unroll
    for (int c = 0; c < 12; c++) {
        int cg = grp * 12 + c;
        float y = (v[c] - mu) * r;
        xnb[(size_t)c * HW] = n1w[cg] * y + n1b[cg];
        xmb[(size_t)c * HW] = n2w[cg] * y + n2b[cg];
    }
}

// ---------------- merged weight prepack to bf16 ----------------
__global__ void prep_k(const float* __restrict__ kw, const float* __restrict__ kb,
                       const float* __restrict__ w1, const float* __restrict__ w2,
                       const float* __restrict__ w3, const float* __restrict__ qw,
                       __nv_bfloat16* __restrict__ kwb,
                       __nv_bfloat16* __restrict__ wb, __nv_bfloat16* __restrict__ wq)
{
    int i = blockIdx.x * 256 + threadIdx.x;
    if (i < 24 * 160 * 32) {
        int g = i / (160 * 32);
        int rem = i % (160 * 32);
        int row = rem >> 5, n = rem & 31;
        int c = row / 40, rr = row - c * 40;
        float v;
        if (rr < 36)       v = kw[(size_t)n * 3456 + g * 144 + c * 36 + rr];
        else if (rr == 36) v = kb[n * HID + g * 4 + c];
        else               v = 0.f;
        kwb[i] = __float2bfloat16_rn(v);
    } else if (i < 24 * 160 * 32 + 224 * 48) {
        int j = i - 24 * 160 * 32;
        int o = j / 48, c = j % 48;
        float v = (o < 96) ? w1[o * 48 + c] : (o < 192) ? w2[(o - 96) * 48 + c]
                                                        : w3[(o - 192) * 48 + c];
        wb[j] = __float2bfloat16_rn(v);
    } else if (i < 24 * 160 * 32 + 224 * 48 + 144 * 48) {
        int j = i - 24 * 160 * 32 - 224 * 48;
        wq[j] = __float2bfloat16_rn(qw[j]);
    }
}

// ---------------- fused3 via warp MMA ----------------
__global__ __launch_bounds__(256) void fused3m_k(const float* __restrict__ xn,
        const __nv_bfloat16* __restrict__ wb, const float* __restrict__ b3,
        float* __restrict__ t1, float* __restrict__ t2, float* __restrict__ att)
{
    __shared__ uint32_t A32[128 * 28];
    __shared__ uint32_t WB32[224 * 28];
    __shared__ float sbias[224];
    int tid = threadIdx.x, wid = tid >> 5, lane = tid & 31;
    int c0 = lane & 3, rq = lane >> 2;
    int pb = blockIdx.x * 128;
    int b = pb >> 12, pp0 = pb & 4095;
    int px = tid & 127, half = tid >> 7;
    int pp = pp0 + px;

    const float* xb = xn + (size_t)b * CCH * HW + pp;
#pragma unroll
    for (int w = 0; w < 12; w++) {
        int wd = half * 12 + w; int c = wd * 2;
        __nv_bfloat162 v;
        v.x = __float2bfloat16_rn(xb[(size_t)c * HW]);
        v.y = __float2bfloat16_rn(xb[(size_t)(c + 1) * HW]);
        A32[px * 28 + wd] = *(uint32_t*)&v;
    }
    const uint32_t* wbg = (const uint32_t*)wb;
    for (int i = tid; i < 224 * 24; i += 256) { int o = i / 24, w = i % 24; WB32[o * 28 + w] = wbg[i]; }
    for (int i = tid; i < 224; i += 256) sbias[i] = (i < 192) ? 0.f : b3[i - 192];
    __syncthreads();

    int arow = wid * 16;
    uint32_t aF[3][4];
#pragma unroll
    for (int ks = 0; ks < 3; ks++) {
        aF[ks][0] = A32[(arow + rq) * 28 + ks * 8 + c0];
        aF[ks][1] = A32[(arow + rq + 8) * 28 + ks * 8 + c0];
        aF[ks][2] = A32[(arow + rq) * 28 + ks * 8 + c0 + 4];
        aF[ks][3] = A32[(arow + rq + 8) * 28 + ks * 8 + c0 + 4];
    }
    for (int nt = 0; nt < 28; nt++) {
        uint32_t bF[3][2];
        int rowb = (nt * 8 + rq) * 28;
#pragma unroll
        for (int ks = 0; ks < 3; ks++) { bF[ks][0] = WB32[rowb + ks * 8 + c0]; bF[ks][1] = WB32[rowb + ks * 8 + c0 + 4]; }
        float d[4] = {0.f, 0.f, 0.f, 0.f};
        mma_bf16(d, aF[0], bF[0]);
        mma_bf16(d, aF[1], bF[1]);
        mma_bf16(d, aF[2], bF[2]);
#pragma unroll
        for (int e = 0; e < 2; e++) {
            int oc = nt * 8 + 2 * c0 + e;
            float bia = sbias[oc];
            float* base; int ol; int outc;
            if (oc < 96)       { base = t1;  ol = oc;        outc = HID; }
            else if (oc < 192) { base = t2;  ol = oc - 96;   outc = HID; }
            else               { base = att; ol = oc - 192;  outc = NSET; }
            size_t o0 = ((size_t)b * outc + ol) * HW + pp0;
            base[o0 + arow + rq]     = d[e]     + bia;
            base[o0 + arow + rq + 8] = d[e + 2] + bia;
        }
    }
}

// ---------------- qkv 1x1 via warp MMA ----------------
__global__ __launch_bounds__(256) void qkvm_k(const float* __restrict__ xm,
        const __nv_bfloat16* __restrict__ wq, float* __restrict__ out)
{
    __shared__ uint32_t A32[128 * 28];
    __shared__ uint32_t WB32[144 * 28];
    int tid = threadIdx.x, wid = tid >> 5, lane = tid & 31;
    int c0 = lane & 3, rq = lane >> 2;
    int pb = blockIdx.x * 128;
    int b = pb >> 12, pp0 = pb & 4095;
    int px = tid & 127, half = tid >> 7;
    int pp = pp0 + px;

    const float* xb = xm + (size_t)b * CCH * HW + pp;
#pragma unroll
    for (int w = 0; w < 12; w++) {
        int wd = half * 12 + w; int c = wd * 2;
        __nv_bfloat162 v;
        v.x = __float2bfloat16_rn(xb[(size_t)c * HW]);
        v.y = __float2bfloat16_rn(xb[(size_t)(c + 1) * HW]);
        A32[px * 28 + wd] = *(uint32_t*)&v;
    }
    const uint32_t* wbg = (const uint32_t*)wq;
    for (int i = tid; i < 144 * 24; i += 256) { int o = i / 24, w = i % 24; WB32[o * 28 + w] = wbg[i]; }
    __syncthreads();

    int arow = wid * 16;
    uint32_t aF[3][4];
#pragma unroll
    for (int ks = 0; ks < 3; ks++) {
        aF[ks][0] = A32[(arow + rq) * 28 + ks * 8 + c0];
        aF[ks][1] = A32[(arow + rq + 8) * 28 + ks * 8 + c0];
        aF[ks][2] = A32[(arow + rq) * 28 + ks * 8 + c0 + 4];
        aF[ks][3] = A32[(arow + rq + 8) * 28 + ks * 8 + c0 + 4];
    }
    for (int nt = 0; nt < 18; nt++) {
        uint32_t bF[3][2];
        int rowb = (nt * 8 + rq) * 28;
#pragma unroll
        for (int ks = 0; ks < 3; ks++) { bF[ks][0] = WB32[rowb + ks * 8 + c0]; bF[ks][1] = WB32[rowb + ks * 8 + c0 + 4]; }
        float d[4] = {0.f, 0.f, 0.f, 0.f};
        mma_bf16(d, aF[0], bF[0]);
        mma_bf16(d, aF[1], bF[1]);
        mma_bf16(d, aF[2], bF[2]);
#pragma unroll
        for (int e = 0; e < 2; e++) {
            int oc = nt * 8 + 2 * c0 + e;
            size_t o0 = ((size_t)b * (3 * CCH) + oc) * HW + pp0;
            out[o0 + arow + rq]     = d[e];
            out[o0 + arow + rq + 8] = d[e + 2];
        }
    }
}

// ---------------- merged depthwise 3x3: t1->x1(96), t2->uf(96), qkvt->qkv(144) ----------------
__global__ void dwall_k(const float* __restrict__ t1, const float* __restrict__ kdw2,
                        const float* __restrict__ t2, const float* __restrict__ kc1b,
                        const float* __restrict__ qkvt, const float* __restrict__ qkvw,
                        float* __restrict__ x1, float* __restrict__ uf,
                        float* __restrict__ qkv)
{
    int gidx4 = (blockIdx.x * 256 + threadIdx.x);      // over B*336*HW/4
    int p = (gidx4 * 4) & 4095;
    int plane = (gidx4 * 4) >> 12;                     // 0 .. B*336-1
    int b = plane / 336, cg = plane % 336;
    const float* in; const float* wsrc; float* outp; int c; int CH;
    if (cg < 96)       { in = t1;   wsrc = kdw2; outp = x1;  c = cg;       CH = 96; }
    else if (cg < 192) { in = t2;   wsrc = kc1b; outp = uf;  c = cg - 96;  CH = 96; }
    else               { in = qkvt; wsrc = qkvw; outp = qkv; c = cg - 192; CH = 144; }
    int h = p >> 6, w0 = p & 63;
    const float* inp = in + ((size_t)b * CH + c) * HW;
    const float* wc = wsrc + c * 9;
    float wk[9];
#pragma unroll
    for (int i = 0; i < 9; i++) wk[i] = __ldg(wc + i);
    float a[4] = {0.f, 0.f, 0.f, 0.f};
#pragma unroll
    for (int kh = 0; kh < 3; kh++) {
        int hh = h + kh - 1;
        if (hh < 0 || hh > 63) continue;
        const float* r = inp + hh * 64;
        float4 v14 = *(const float4*)(r + w0);
        float vm1 = (w0 > 0)  ? r[w0 - 1] : 0.f;
        float v5  = (w0 < 60) ? r[w0 + 4] : 0.f;
        float v[6] = {vm1, v14.x, v14.y, v14.z, v14.w, v5};
        float k0 = wk[kh * 3], k1 = wk[kh * 3 + 1], k2 = wk[kh * 3 + 2];
#pragma unroll
        for (int px = 0; px < 4; px++)
            a[px] += k0 * v[px] + k1 * v[px + 1] + k2 * v[px + 2];
    }
    ulonglong2 t; t.x = pk2(a[0], a[1]); t.y = pk2(a[2], a[3]);
    *(ulonglong2*)(outp + ((size_t)b * CH + c) * HW + p) = t;
}

// ---------------- attention-coefficient mixer ----------------
__global__ __launch_bounds__(128) void attmix_k(const float* __restrict__ xn,
        const float* __restrict__ wA, const float* __restrict__ bA,
        const float* __restrict__ wB, const float* __restrict__ bB,
        const float* __restrict__ gam, float* __restrict__ att)
{
    __shared__ float swA[INTERC * 18], sbA[INTERC], swB[NSET * 12], sbB[NSET], sgam[NSET];
    int tid = threadIdx.x;
    for (int i = tid; i < INTERC * 18; i += 128) swA[i] = wA[i];
    for (int i = tid; i < INTERC; i += 128) sbA[i] = bA[i];
    for (int i = tid; i < NSET * 12; i += 128) swB[i] = wB[i];
    for (int i = tid; i < NSET; i += 128) { sbB[i] = bB[i]; sgam[i] = gam[i]; }
    __syncthreads();
    int pg = blockIdx.x * 128 + tid;
    int b = pg >> 12, p = pg & 4095;
    int h = p >> 6, w = p & 63;
    const float* xb = xn + (size_t)b * CCH * HW;
    float av[INTERC];
#pragma unroll
    for (int o = 0; o < INTERC; o++) {
        float acc = sbA[o];
#pragma unroll
        for (int t = 0; t < 2; t++) {
            const float* ch = xb + (size_t)(o * 2 + t) * HW;
#pragma unroll
            for (int kk = 0; kk < 9; kk++) {
                int hh = h + kk / 3 - 1, ww = w + kk % 3 - 1;
                if (hh >= 0 && hh < 64 && ww >= 0 && ww < 64)
                    acc += swA[o * 18 + t * 9 + kk] * ch[hh * 64 + ww];
            }
        }
        av[o] = acc;
    }
    float sg[12];
#pragma unroll
    for (int i = 0; i < 12; i++) sg[i] = av[i] * av[i + 12];
    for (int n = 0; n < NSET; n++) {
        float s = sbB[n];
#pragma unroll
        for (int i = 0; i < 12; i++) s += swB[n * 12 + i] * sg[i];
        size_t oi = ((size_t)b * NSET + n) * HW + p;
        att[oi] = sgam[n] * s + att[oi];
    }
}

// ================= KBA core via warp-level bf16 MMA =================
#define KT_A 0
#define KT_B 18432
#define KT_P 41472
#define KT_TOTAL 61952

__global__ __launch_bounds__(256) void kba_mma_k(
        const float* __restrict__ uf, const float* __restrict__ att,
        const __nv_bfloat16* __restrict__ kwb, const float* __restrict__ ga1,
        const float* __restrict__ x1, float* __restrict__ mout)
{
    extern __shared__ __align__(16) char smraw[];
    uint32_t* A32 = (uint32_t*)(smraw + KT_A);
    uint32_t* B32 = (uint32_t*)(smraw + KT_B);
    float*    P   = (float*)(smraw + KT_P);

    int tid = threadIdx.x, wid = tid >> 5, lane = tid & 31;
    int c0 = lane & 3, rq = lane >> 2;
    int pb = blockIdx.x * 128;
    int b = pb >> 12, pp0 = pb & 4095;

    int px = tid & 127, half = tid >> 7;
    int pp = pp0 + px;
    int h = pp >> 6, w = pp & 63;

    {
        const float* attb = att + (size_t)b * NSET * HW + pp;
#pragma unroll
        for (int q = 0; q < 8; q++) {
            int n = (half * 8 + q) * 2;
            __nv_bfloat162 v;
            v.x = __float2bfloat16_rn(attb[(size_t)n * HW]);
            v.y = __float2bfloat16_rn(attb[(size_t)(n + 1) * HW]);
            A32[px * 36 + half * 8 + q] = *(uint32_t*)&v;
        }
    }
    int offs[9]; bool val[9];
#pragma unroll
    for (int kk = 0; kk < 9; kk++) {
        int dh = kk / 3 - 1, dw = kk % 3 - 1;
        int hh = h + dh, ww = w + dw;
        val[kk] = (hh >= 0 && hh < 64 && ww >= 0 && ww < 64);
        offs[kk] = hh * 64 + ww;
    }
    __syncthreads();

    int arow = 16 * wid + rq;
    uint32_t aF[2][4];
#pragma unroll
    for (int ks = 0; ks < 2; ks++) {
        int base = ks * 8;
        aF[ks][0] = A32[arow * 36 + base + c0];
        aF[ks][1] = A32[(arow + 8) * 36 + base + c0];
        aF[ks][2] = A32[arow * 36 + base + c0 + 4];
        aF[ks][3] = A32[(arow + 8) * 36 + base + c0 + 4];
    }

    for (int g = 0; g < 24; g++) {
        __syncthreads();
        const uint32_t* kwb32 = (const uint32_t*)(kwb + (size_t)g * 160 * 32);
        for (int i = tid; i < 2560; i += 256) {
            int row = i >> 4, np = i & 15;
            B32[row * 36 + np] = kwb32[i];
        }
        const float* ufg = uf + ((size_t)b * HID + g * 4) * HW;
#pragma unroll
        for (int jj = 0; jj < 18; jj++) {
            int j = half * 18 + jj;
            int ci = j / 9, kk = j % 9;
            P[px * 40 + j] = val[kk] ? ufg[(size_t)ci * HW + offs[kk]] : 0.f;
        }
        __syncthreads();

#pragma unroll
        for (int cc = 0; cc < 4; cc++) {
            uint32_t bF[5][2][2];
            int nb = cc * 40;
#pragma unroll
            for (int t = 0; t < 5; t++) {
                int rowb = (nb + t * 8 + rq) * 36;
#pragma unroll
                for (int ks = 0; ks < 2; ks++) {
                    bF[t][ks][0] = B32[rowb + ks * 8 + c0];
                    bF[t][ks][1] = B32[rowb + ks * 8 + c0 + 4];
                }
            }
            float d[5][4];
#pragma unroll
            for (int t = 0; t < 5; t++) { d[t][0]=0.f; d[t][1]=0.f; d[t][2]=0.f; d[t][3]=0.f; }
#pragma unroll
            for (int t = 0; t < 5; t++) {
                mma_bf16(d[t], aF[0], bF[t][0]);
                mma_bf16(d[t], aF[1], bF[t][1]);
            }
            int rlo = 16 * wid + rq, rhi = rlo + 8;
            float s0 = 0.f, s1 = 0.f;
#pragma unroll
            for (int t = 0; t < 5; t++) {
                int j0 = t * 8 + 2 * c0, j1 = j0 + 1;
                float w00, w01, w10, w11;
                if (j0 < 36)      { w00 = P[rlo * 40 + j0]; w10 = P[rhi * 40 + j0]; }
                else if (j0 == 36){ w00 = 1.f; w10 = 1.f; }
                else              { w00 = 0.f; w10 = 0.f; }
                if (j1 < 36)      { w01 = P[rlo * 40 + j1]; w11 = P[rhi * 40 + j1]; }
                else              { w01 = 0.f; w11 = 0.f; }
                s0 += d[t][0] * w00 + d[t][1] * w01;
                s1 += d[t][2] * w10 + d[t][3] * w11;
            }
            s0 += __shfl_xor_sync(0xffffffffu, s0, 1);
            s0 += __shfl_xor_sync(0xffffffffu, s0, 2);
            s1 += __shfl_xor_sync(0xffffffffu, s1, 1);
            s1 += __shfl_xor_sync(0xffffffffu, s1, 2);
            if (c0 == 0) {
                int ch = g * 4 + cc;
                float ga = ga1[ch];
                float cen0 = P[rlo * 40 + cc * 9 + 4];
                float cen1 = P[rhi * 40 + cc * 9 + 4];
                float x2a = s0 * ga + cen0;
                float x2b = s1 * ga + cen1;
                size_t xlo = ((size_t)b * HID + ch) * HW + pp0 + rlo;
                size_t xhi = xlo + 8;
                float v0 = x1[xlo], v1 = x1[xhi];
                mout[xlo] = 0.5f * v0 * (1.f + erff(v0 * 0.70710678118654752f)) * x2a;
                mout[xhi] = 0.5f * v1 * (1.f + erff(v1 * 0.70710678118654752f)) * x2b;
            }
        }
    }
}

// ---------------- MDTA: fused norms + 6x6 attention + softmax ----------------
__global__ __launch_bounds__(256) void attn_k(const float* __restrict__ qkv,
        const float* __restrict__ temp, float* __restrict__ attn)
{
    int bh = blockIdx.x; int b = bh >> 3, h = bh & 7;
    int warp = threadIdx.x >> 5, lane = threadIdx.x & 31;
    __shared__ float S[36], NQ[6], NK[6];
    const float* qb = qkv + ((size_t)b * 3 * CCH + h * DHEAD) * HW;
    const float* kb = qkv + ((size_t)b * 3 * CCH + CCH + h * DHEAD) * HW;
    for (int pi = warp; pi < 48; pi += 8) {
        const float* pa; const float* pb;
        if (pi < 36)      { pa = qb + (size_t)(pi / 6) * HW; pb = kb + (size_t)(pi % 6) * HW; }
        else if (pi < 42) { pa = qb + (size_t)(pi - 36) * HW; pb = pa; }
        else              { pa = kb + (size_t)(pi - 42) * HW; pb = pa; }
        float s = 0.f;
        for (int t = lane * 4; t < HW; t += 128) {
            float4 va = *(const float4*)(pa + t);
            float4 vb = *(const float4*)(pb + t);
            s += va.x * vb.x + va.y * vb.y + va.z * vb.z + va.w * vb.w;
        }
#pragma unroll
        for (int off = 16; off; off >>= 1) s += __shfl_down_sync(0xffffffffu, s, off);
        if (lane == 0) {
            if (pi < 36) S[pi] = s;
            else if (pi < 42) NQ[pi - 36] = sqrtf(s);
            else NK[pi - 42] = sqrtf(s);
        }
    }
    __syncthreads();
    if (threadIdx.x < 6) {
        int i = threadIdx.x;
        float nq = fmaxf(NQ[i], 1e-12f);
        float tv = temp[h];
        float row[6]; float mx = -1e30f;
#pragma unroll
        for (int j = 0; j < 6; j++) {
            float nk = fmaxf(NK[j], 1e-12f);
            row[j] = tv * S[i * 6 + j] / (nq * nk);
            mx = fmaxf(mx, row[j]);
        }
        float sum = 0.f;
#pragma unroll
        for (int j = 0; j < 6; j++) { row[j] = expf(row[j] - mx); sum += row[j]; }
        float inv = 1.f / sum;
#pragma unroll
        for (int j = 0; j < 6; j++)
            attn[((size_t)(b * 8 + h) * 6 + i) * 6 + j] = row[j] * inv;
    }
}

// ---------------- MDTA: fused (attn @ v) + mproj ----------------
__global__ __launch_bounds__(128) void mdta_k(const float* __restrict__ qkv,
        const float* __restrict__ attn, const float* __restrict__ mproj,
        float* __restrict__ out)
{
    __shared__ float scoef[288];
    __shared__ u64 ws2[4 * CCH];
    int tid = threadIdx.x;
    int o0 = blockIdx.y * 4;
    int p4 = (blockIdx.x * 128 + tid) * 4;
    int b = p4 >> 12, pp = p4 & 4095;
    int bblk = (blockIdx.x * 512) >> 12;
    for (int i = tid; i < 288; i += 128) scoef[i] = attn[bblk * 288 + i];
    for (int i = tid; i < 4 * CCH; i += 128)
        ws2[i] = dup2(mproj[(o0 + i / CCH) * CCH + i % CCH]);
    __syncthreads();
    u64 acc[4][2];
#pragma unroll
    for (int o = 0; o < 4; o++) { acc[o][0] = 0ULL; acc[o][1] = 0ULL; }
    const float* vb = qkv + ((size_t)b * 3 * CCH + 2 * CCH) * HW + pp;
#pragma unroll
    for (int h = 0; h < 8; h++) {
        u64 v[6][2];
#pragma unroll
        for (int j = 0; j < 6; j++) {
            ulonglong2 t = *(const ulonglong2*)(vb + (size_t)(h * 6 + j) * HW);
            v[j][0] = t.x; v[j][1] = t.y;
        }
#pragma unroll
        for (int i = 0; i < 6; i++) {
            int c = h * 6 + i;
            u64 md0 = 0ULL, md1 = 0ULL;
#pragma unroll
            for (int j = 0; j < 6; j++) {
                u64 cf = dup2(scoef[c * 6 + j]);
                md0 = fma2_(cf, v[j][0], md0);
                md1 = fma2_(cf, v[j][1], md1);
            }
#pragma unroll
            for (int o = 0; o < 4; o++) {
                u64 wv = ws2[o * CCH + c];
                acc[o][0] = fma2_(wv, md0, acc[o][0]);
                acc[o][1] = fma2_(wv, md1, acc[o][1]);
            }
        }
    }
    float* outb = out + ((size_t)b * CCH + o0) * HW + pp;
#pragma unroll
    for (int o = 0; o < 4; o++) {
        ulonglong2 t; t.x = acc[o][0]; t.y = acc[o][1];
        *(ulonglong2*)(outb + (size_t)o * HW) = t;
    }
}

// ---------------- final: kproj + residual combine ----------------
__global__ __launch_bounds__(128) void final_k(const float* __restrict__ x,
        const float* __restrict__ m, const float* __restrict__ mdta,
        const float* __restrict__ kproj,
        const float* __restrict__ ca1, const float* __restrict__ ca2,
        float* __restrict__ out)
{
    __shared__ __align__(16) u64 wp2[4 * HID];
    int tid = threadIdx.x;
    int o0 = blockIdx.y * 4;
    for (int i = tid; i < 4 * HID; i += 128)
        wp2[i] = dup2(kproj[(o0 + i / HID) * HID + i % HID]);
    __syncthreads();
    int p4 = (blockIdx.x * 128 + tid) * 4;
    int b = p4 >> 12, pp = p4 & 4095;
    const float* mb = m + (size_t)b * HID * HW + pp;
    u64 acc[4][2];
#pragma unroll
    for (int o = 0; o < 4; o++) { acc[o][0] = 0ULL; acc[o][1] = 0ULL; }
    for (int cc = 0; cc < HID; cc += 8) {
        u64 xv[8][2];
#pragma unroll
        for (int c = 0; c < 8; c++) {
            ulonglong2 t = *(const ulonglong2*)(mb + (size_t)(cc + c) * HW);
            xv[c][0] = t.x; xv[c][1] = t.y;
        }
#pragma unroll
        for (int o = 0; o < 4; o++) {
#pragma unroll
            for (int c = 0; c < 8; c += 2) {
                ulonglong2 wv = *(const ulonglong2*)&wp2[o * HID + cc + c];
                acc[o][0] = fma2_(wv.x, xv[c][0], acc[o][0]);
                acc[o][1] = fma2_(wv.x, xv[c][1], acc[o][1]);
                acc[o][0] = fma2_(wv.y, xv[c + 1][0], acc[o][0]);
                acc[o][1] = fma2_(wv.y, xv[c + 1][1], acc[o][1]);
            }
        }
    }
#pragma unroll
    for (int o = 0; o < 4; o++) {
        int oc = o0 + o;
        size_t oi = ((size_t)b * CCH + oc) * HW + pp;
        u64 a1 = dup2(ca1[b * CCH + oc]), a2 = dup2(ca2[b * CCH + oc]);
        ulonglong2 xv = *(const ulonglong2*)(x + oi);
        ulonglong2 dv = *(const ulonglong2*)(mdta + oi);
        ulonglong2 r;
        r.x = fma2_(a1, acc[o][0], fma2_(a2, dv.x, xv.x));
        r.y = fma2_(a1, acc[o][1], fma2_(a2, dv.y, xv.y));
        *(ulonglong2*)(out + oi) = r;
    }
}

// ---------------- host launcher ----------------
extern "C" void kernel_launch(void* const* d_in, const int* in_sizes, int n_in,
                              void* d_out, int out_size)
{
    const float* x       = (const float*)d_in[0];
    const float* n1w     = (const float*)d_in[1];
    const float* n1b     = (const float*)d_in[2];
    const float* n2w     = (const float*)d_in[3];
    const float* n2b     = (const float*)d_in[4];
    const float* kdw1    = (const float*)d_in[5];
    const float* kdw2    = (const float*)d_in[6];
    const float* kc1a    = (const float*)d_in[7];
    const float* kc1b    = (const float*)d_in[8];
    const float* kproj   = (const float*)d_in[9];
    const float* c2a_w   = (const float*)d_in[10];
    const float* c2a_b   = (const float*)d_in[11];
    const float* c2b_w   = (const float*)d_in[12];
    const float* c2b_b   = (const float*)d_in[13];
    const float* c211_w  = (const float*)d_in[14];
    const float* c211_b  = (const float*)d_in[15];
    const float* kw      = (const float*)d_in[16];
    const float* kb      = (const float*)d_in[17];
    const float* attg    = (const float*)d_in[18];
    const float* ga1     = (const float*)d_in[19];
    const float* temp    = (const float*)d_in[20];
    const float* qkv_w   = (const float*)d_in[21];
    const float* qkv_dww = (const float*)d_in[22];
    const float* mproj_w = (const float*)d_in[23];
    const float* ca1_w   = (const float*)d_in[24];
    const float* ca1_b   = (const float*)d_in[25];
    const float* ca2_w   = (const float*)d_in[26];
    const float* ca2_b   = (const float*)d_in[27];
    float* out = (float*)d_out;

    float* S = nullptr;
    cudaGetSymbolAddress((void**)&S, g_scratch);
    float* xn   = S + OFF_XN;
    float* xm   = S + OFF_XM;
    float* t1   = S + OFF_T1;
    float* t2   = S + OFF_T2;
    float* x1   = S + OFF_X1;
    float* uf   = S + OFF_UF;
    float* att  = S + OFF_ATT;
    float* qkvt = S + OFF_QKVT;
    float* qkv  = S + OFF_QKV;
    float* m    = S + OFF_M;
    float* gap  = S + OFF_GAP;
    float* ca1  = S + OFF_CA1;
    float* ca2  = S + OFF_CA2;
    float* attn = S + OFF_ATTN;
    __nv_bfloat16* kwb = (__nv_bfloat16*)(S + OFF_KWB);
    __nv_bfloat16* wb  = (__nv_bfloat16*)(S + OFF_WB);
    __nv_bfloat16* wq  = (__nv_bfloat16*)(S + OFF_WQ);
    float* mdta = qkvt;                     // reuse

    const int PIX = BATCH * HW;             // 16384
    const int XB4 = PIX / 512;              // 32

    cudaFuncSetAttribute(kba_mma_k, cudaFuncAttributeMaxDynamicSharedMemorySize, KT_TOTAL);

    // merged weight prepack
    const int PREP_N = 24 * 160 * 32 + 224 * 48 + 144 * 48;
    prep_k<<<(PREP_N + 255) / 256, 256>>>(kw, kb, kdw1, kc1a, c211_w, qkv_w, kwb, wb, wq);

    gap_k<<<BATCH * CCH, 256>>>(x, gap);
    ca_k<<<BATCH * CCH, 64>>>(gap, ca1_w, ca1_b, ca2_w, ca2_b, ca1, ca2);

    ln_k<<<PIX / 128, 512>>>(x, n1w, n1b, n2w, n2b, xn, xm);

    // branch GEMMs
    fused3m_k<<<PIX / 128, 256>>>(xn, wb, c211_b, t1, t2, att);
    qkvm_k<<<PIX / 128, 256>>>(xm, wq, qkvt);

    // merged depthwise conv (t1->x1, t2->uf, qkvt->qkv)
    dwall_k<<<BATCH * 336 * HW / 1024, 256>>>(t1, kdw2, t2, kc1b, qkvt, qkv_dww,
                                              x1, uf, qkv);

    attmix_k<<<PIX / 128, 128>>>(xn, c2a_w, c2a_b, c2b_w, c2b_b, attg, att);

    // MDTA
    attn_k<<<BATCH * HEADS, 256>>>(qkv, temp, attn);
    mdta_k<<<dim3(XB4, 12), 128>>>(qkv, attn, mproj_w, mdta);

    // KBA core via warp MMA (+ fused gelu*x2 -> m)
    kba_mma_k<<<PIX / 128, 256, KT_TOTAL>>>(uf, att, kwb, ga1, x1, m);

    // projection + residual
    final_k<<<dim3(XB4, 12), 128>>>(x, m, mdta, kproj, ca1, ca2, out);
}

// round 10
// speedup vs baseline: 2.3164x; 1.2347x over previous
#include <cuda_runtime.h>
#include <cuda_bf16.h>
#include <math.h>
#include <cstdint>

// ---------------- problem constants ----------------
#define BATCH 4
#define CCH   48
#define HW    4096
#define HID   96
#define NSET  32
#define HEADS 8
#define DHEAD 6
#define INTERC 24

typedef unsigned long long u64;
__device__ __forceinline__ u64 pk2(float lo, float hi){ u64 r; asm("mov.b64 %0,{%1,%2};":"=l"(r):"f"(lo),"f"(hi)); return r; }
__device__ __forceinline__ u64 dup2(float v){ return pk2(v, v); }
__device__ __forceinline__ u64 fma2_(u64 a, u64 b, u64 c){ u64 d; asm("fma.rn.f32x2 %0,%1,%2,%3;":"=l"(d):"l"(a),"l"(b),"l"(c)); return d; }

__device__ __forceinline__ void mma_bf16(float* d, const uint32_t* a, const uint32_t* b){
    asm volatile("mma.sync.aligned.m16n8k16.row.col.f32.bf16.bf16.f32 "
        "{%0,%1,%2,%3}, {%4,%5,%6,%7}, {%8,%9}, {%0,%1,%2,%3};"
        : "+f"(d[0]),"+f"(d[1]),"+f"(d[2]),"+f"(d[3])
        : "r"(a[0]),"r"(a[1]),"r"(a[2]),"r"(a[3]), "r"(b[0]),"r"(b[1]));
}

// ---------------- scratch layout ----------------
#define OFF_XN    0LL
#define OFF_XM    (OFF_XN   + (long long)BATCH*CCH*HW)
#define OFF_T1    (OFF_XM   + (long long)BATCH*CCH*HW)
#define OFF_T2    (OFF_T1   + (long long)BATCH*HID*HW)
#define OFF_X1    (OFF_T2   + (long long)BATCH*HID*HW)
#define OFF_UF    (OFF_X1   + (long long)BATCH*HID*HW)
#define OFF_ATT   (OFF_UF   + (long long)BATCH*HID*HW)
#define OFF_QKVT  (OFF_ATT  + (long long)BATCH*NSET*HW)
#define OFF_QKV   (OFF_QKVT + (long long)BATCH*3*CCH*HW)
#define OFF_M     (OFF_QKV  + (long long)BATCH*3*CCH*HW)
#define OFF_GAP   (OFF_M    + (long long)BATCH*HID*HW)
#define OFF_CA1   (OFF_GAP  + BATCH*CCH)
#define OFF_CA2   (OFF_CA1  + BATCH*CCH)
#define OFF_ATTN  (OFF_CA2  + BATCH*CCH)
#define OFF_KWB   (OFF_ATTN + BATCH*HEADS*DHEAD*DHEAD)
#define OFF_WB    (OFF_KWB + 24*160*32/2 + 64)
#define OFF_WQ    (OFF_WB  + 224*48/2 + 32)
#define SCRATCH_TOTAL (OFF_WQ + 144*48/2 + 32)

__device__ float g_scratch[SCRATCH_TOTAL];

// ---------------- gap ----------------
__global__ void gap_k(const float* __restrict__ x, float* __restrict__ gap)
{
    int bc = blockIdx.x;
    const float* xb = x + (size_t)bc * HW;
    __shared__ float red[256];
    float s = 0.f;
    for (int i = threadIdx.x; i < HW; i += 256) s += xb[i];
    red[threadIdx.x] = s; __syncthreads();
    for (int st = 128; st; st >>= 1) {
        if (threadIdx.x < st) red[threadIdx.x] += red[threadIdx.x + st];
        __syncthreads();
    }
    if (threadIdx.x == 0) gap[bc] = red[0] * (1.f / HW);
}

// ---------------- channel attention: one block per (b,o) ----------------
__global__ __launch_bounds__(64) void ca_k(const float* __restrict__ gap,
                     const float* __restrict__ w1, const float* __restrict__ b1,
                     const float* __restrict__ w2, const float* __restrict__ b2,
                     float* __restrict__ ca1, float* __restrict__ ca2)
{
    int bo = blockIdx.x;
    int b = bo / CCH, o = bo % CCH;
    int t = threadIdx.x;
    __shared__ float R1[64], R2[64];
    float s1 = 0.f, s2 = 0.f;
    if (t < CCH) {
        float g = gap[b * CCH + t];
        s1 = w1[o * CCH + t] * g;
        s2 = w2[o * CCH + t] * g;
    }
    R1[t] = s1; R2[t] = s2;
    __syncthreads();
    for (int st = 32; st; st >>= 1) {
        if (t < st) { R1[t] += R1[t + st]; R2[t] += R2[t + st]; }
        __syncthreads();
    }
    if (t == 0) { ca1[bo] = R1[0] + b1[o]; ca2[bo] = R2[0] + b2[o]; }
}

// ---------------- LayerNorm2d: 64 px x 4 channel groups, 256 blocks ----------------
__global__ __launch_bounds__(256) void ln_k(const float* __restrict__ x,
        const float* __restrict__ n1w, const float* __restrict__ n1b,
        const float* __restrict__ n2w, const float* __restrict__ n2b,
        float* __restrict__ xn, float* __restrict__ xm)
{
    __shared__ float S1[256], S2[256];
    int tid = threadIdx.x;
    int px = tid & 63, grp = tid >> 6;
    int pg = blockIdx.x * 64 + px;
    int b = pg >> 12, p = pg & 4095;
    const float* xb = x + (size_t)b * CCH * HW + p + (size_t)grp * 12 * HW;
    float v[12]; float s = 0.f, s2 = 0.f;
#pragma unroll
    for (int c = 0; c < 12; c++) { float t = xb[(size_t)c * HW]; v[c] = t; s += t; s2 += t * t; }
    S1[tid] = s; S2[tid] = s2;
    __syncthreads();
    float st  = S1[px] + S1[px + 64] + S1[px + 128] + S1[px + 192];
    float st2 = S2[px] + S2[px + 64] + S2[px + 128] + S2[px + 192];
    float mu = st * (1.f / CCH);
    float var = st2 * (1.f / CCH) - mu * mu;
    float r = rsqrtf(var + 1e-6f);
    float* xnb = xn + (size_t)b * CCH * HW + p + (size_t)grp * 12 * HW;
    float* xmb = xm + (size_t)b * CCH * HW + p + (size_t)grp * 12 * HW;
#pragma unroll
    for (int c = 0; c < 12; c++) {
        int cg = grp * 12 + c;
        float y = (v[c] - mu) * r;
        xnb[(size_t)c * HW] = n1w[cg] * y + n1b[cg];
        xmb[(size_t)c * HW] = n2w[cg] * y + n2b[cg];
    }
}

// ---------------- merged weight prepack to bf16 ----------------
__global__ void prep_k(const float* __restrict__ kw, const float* __restrict__ kb,
                       const float* __restrict__ w1, const float* __restrict__ w2,
                       const float* __restrict__ w3, const float* __restrict__ qw,
                       __nv_bfloat16* __restrict__ kwb,
                       __nv_bfloat16* __restrict__ wb, __nv_bfloat16* __restrict__ wq)
{
    int i = blockIdx.x * 256 + threadIdx.x;
    if (i < 24 * 160 * 32) {
        int g = i / (160 * 32);
        int rem = i % (160 * 32);
        int row = rem >> 5, n = rem & 31;
        int c = row / 40, rr = row - c * 40;
        float v;
        if (rr < 36)       v = kw[(size_t)n * 3456 + g * 144 + c * 36 + rr];
        else if (rr == 36) v = kb[n * HID + g * 4 + c];
        else               v = 0.f;
        kwb[i] = __float2bfloat16_rn(v);
    } else if (i < 24 * 160 * 32 + 224 * 48) {
        int j = i - 24 * 160 * 32;
        int o = j / 48, c = j % 48;
        float v = (o < 96) ? w1[o * 48 + c] : (o < 192) ? w2[(o - 96) * 48 + c]
                                                        : w3[(o - 192) * 48 + c];
        wb[j] = __float2bfloat16_rn(v);
    } else if (i < 24 * 160 * 32 + 224 * 48 + 144 * 48) {
        int j = i - 24 * 160 * 32 - 224 * 48;
        wq[j] = __float2bfloat16_rn(qw[j]);
    }
}

// ---------------- fused3 via warp MMA, y-split x2 (112 out-ch each) ----------------
__global__ __launch_bounds__(256) void fused3m_k(const float* __restrict__ xn,
        const __nv_bfloat16* __restrict__ wb, const float* __restrict__ b3,
        float* __restrict__ t1, float* __restrict__ t2, float* __restrict__ att)
{
    __shared__ uint32_t A32[128 * 28];
    __shared__ uint32_t WB32[112 * 28];
    __shared__ float sbias[112];
    int tid = threadIdx.x, wid = tid >> 5, lane = tid & 31;
    int c0 = lane & 3, rq = lane >> 2;
    int y = blockIdx.y;                      // 0 or 1
    int ob = y * 112;
    int pb = blockIdx.x * 128;
    int b = pb >> 12, pp0 = pb & 4095;
    int px = tid & 127, half = tid >> 7;
    int pp = pp0 + px;

    const float* xb = xn + (size_t)b * CCH * HW + pp;
#pragma unroll
    for (int w = 0; w < 12; w++) {
        int wd = half * 12 + w; int c = wd * 2;
        __nv_bfloat162 v;
        v.x = __float2bfloat16_rn(xb[(size_t)c * HW]);
        v.y = __float2bfloat16_rn(xb[(size_t)(c + 1) * HW]);
        A32[px * 28 + wd] = *(uint32_t*)&v;
    }
    const uint32_t* wbg = (const uint32_t*)wb;
    for (int i = tid; i < 112 * 24; i += 256) {
        int o = i / 24, w = i % 24;
        WB32[o * 28 + w] = wbg[(ob + o) * 24 + w];
    }
    for (int i = tid; i < 112; i += 256) {
        int oc = ob + i;
        sbias[i] = (oc < 192) ? 0.f : b3[oc - 192];
    }
    __syncthreads();

    int arow = wid * 16;
    uint32_t aF[3][4];
#pragma unroll
    for (int ks = 0; ks < 3; ks++) {
        aF[ks][0] = A32[(arow + rq) * 28 + ks * 8 + c0];
        aF[ks][1] = A32[(arow + rq + 8) * 28 + ks * 8 + c0];
        aF[ks][2] = A32[(arow + rq) * 28 + ks * 8 + c0 + 4];
        aF[ks][3] = A32[(arow + rq + 8) * 28 + ks * 8 + c0 + 4];
    }
    for (int nt = 0; nt < 14; nt++) {
        uint32_t bF[3][2];
        int rowb = (nt * 8 + rq) * 28;
#pragma unroll
        for (int ks = 0; ks < 3; ks++) { bF[ks][0] = WB32[rowb + ks * 8 + c0]; bF[ks][1] = WB32[rowb + ks * 8 + c0 + 4]; }
        float d[4] = {0.f, 0.f, 0.f, 0.f};
        mma_bf16(d, aF[0], bF[0]);
        mma_bf16(d, aF[1], bF[1]);
        mma_bf16(d, aF[2], bF[2]);
#pragma unroll
        for (int e = 0; e < 2; e++) {
            int ol = nt * 8 + 2 * c0 + e;
            int oc = ob + ol;
            float bia = sbias[ol];
            float* base; int oo; int outc;
            if (oc < 96)       { base = t1;  oo = oc;        outc = HID; }
            else if (oc < 192) { base = t2;  oo = oc - 96;   outc = HID; }
            else               { base = att; oo = oc - 192;  outc = NSET; }
            size_t o0 = ((size_t)b * outc + oo) * HW + pp0;
            base[o0 + arow + rq]     = d[e]     + bia;
            base[o0 + arow + rq + 8] = d[e + 2] + bia;
        }
    }
}

// ---------------- qkv 1x1 via warp MMA, y-split x2 (72 out-ch each) ----------------
__global__ __launch_bounds__(256) void qkvm_k(const float* __restrict__ xm,
        const __nv_bfloat16* __restrict__ wq, float* __restrict__ out)
{
    __shared__ uint32_t A32[128 * 28];
    __shared__ uint32_t WB32[72 * 28];
    int tid = threadIdx.x, wid = tid >> 5, lane = tid & 31;
    int c0 = lane & 3, rq = lane >> 2;
    int y = blockIdx.y;
    int ob = y * 72;
    int pb = blockIdx.x * 128;
    int b = pb >> 12, pp0 = pb & 4095;
    int px = tid & 127, half = tid >> 7;
    int pp = pp0 + px;

    const float* xb = xm + (size_t)b * CCH * HW + pp;
#pragma unroll
    for (int w = 0; w < 12; w++) {
        int wd = half * 12 + w; int c = wd * 2;
        __nv_bfloat162 v;
        v.x = __float2bfloat16_rn(xb[(size_t)c * HW]);
        v.y = __float2bfloat16_rn(xb[(size_t)(c + 1) * HW]);
        A32[px * 28 + wd] = *(uint32_t*)&v;
    }
    const uint32_t* wbg = (const uint32_t*)wq;
    for (int i = tid; i < 72 * 24; i += 256) {
        int o = i / 24, w = i % 24;
        WB32[o * 28 + w] = wbg[(ob + o) * 24 + w];
    }
    __syncthreads();

    int arow = wid * 16;
    uint32_t aF[3][4];
#pragma unroll
    for (int ks = 0; ks < 3; ks++) {
        aF[ks][0] = A32[(arow + rq) * 28 + ks * 8 + c0];
        aF[ks][1] = A32[(arow + rq + 8) * 28 + ks * 8 + c0];
        aF[ks][2] = A32[(arow + rq) * 28 + ks * 8 + c0 + 4];
        aF[ks][3] = A32[(arow + rq + 8) * 28 + ks * 8 + c0 + 4];
    }
    for (int nt = 0; nt < 9; nt++) {
        uint32_t bF[3][2];
        int rowb = (nt * 8 + rq) * 28;
#pragma unroll
        for (int ks = 0; ks < 3; ks++) { bF[ks][0] = WB32[rowb + ks * 8 + c0]; bF[ks][1] = WB32[rowb + ks * 8 + c0 + 4]; }
        float d[4] = {0.f, 0.f, 0.f, 0.f};
        mma_bf16(d, aF[0], bF[0]);
        mma_bf16(d, aF[1], bF[1]);
        mma_bf16(d, aF[2], bF[2]);
#pragma unroll
        for (int e = 0; e < 2; e++) {
            int oc = ob + nt * 8 + 2 * c0 + e;
            size_t o0 = ((size_t)b * (3 * CCH) + oc) * HW + pp0;
            out[o0 + arow + rq]     = d[e];
            out[o0 + arow + rq + 8] = d[e + 2];
        }
    }
}

// ---------------- merged depthwise 3x3 ----------------
__global__ void dwall_k(const float* __restrict__ t1, const float* __restrict__ kdw2,
                        const float* __restrict__ t2, const float* __restrict__ kc1b,
                        const float* __restrict__ qkvt, const float* __restrict__ qkvw,
                        float* __restrict__ x1, float* __restrict__ uf,
                        float* __restrict__ qkv)
{
    int gidx4 = (blockIdx.x * 256 + threadIdx.x);
    int p = (gidx4 * 4) & 4095;
    int plane = (gidx4 * 4) >> 12;
    int b = plane / 336, cg = plane % 336;
    const float* in; const float* wsrc; float* outp; int c; int CH;
    if (cg < 96)       { in = t1;   wsrc = kdw2; outp = x1;  c = cg;       CH = 96; }
    else if (cg < 192) { in = t2;   wsrc = kc1b; outp = uf;  c = cg - 96;  CH = 96; }
    else               { in = qkvt; wsrc = qkvw; outp = qkv; c = cg - 192; CH = 144; }
    int h = p >> 6, w0 = p & 63;
    const float* inp = in + ((size_t)b * CH + c) * HW;
    const float* wc = wsrc + c * 9;
    float wk[9];
#pragma unroll
    for (int i = 0; i < 9; i++) wk[i] = __ldg(wc + i);
    float a[4] = {0.f, 0.f, 0.f, 0.f};
#pragma unroll
    for (int kh = 0; kh < 3; kh++) {
        int hh = h + kh - 1;
        if (hh < 0 || hh > 63) continue;
        const float* r = inp + hh * 64;
        float4 v14 = *(const float4*)(r + w0);
        float vm1 = (w0 > 0)  ? r[w0 - 1] : 0.f;
        float v5  = (w0 < 60) ? r[w0 + 4] : 0.f;
        float v[6] = {vm1, v14.x, v14.y, v14.z, v14.w, v5};
        float k0 = wk[kh * 3], k1 = wk[kh * 3 + 1], k2 = wk[kh * 3 + 2];
#pragma unroll
        for (int px = 0; px < 4; px++)
            a[px] += k0 * v[px] + k1 * v[px + 1] + k2 * v[px + 2];
    }
    ulonglong2 t; t.x = pk2(a[0], a[1]); t.y = pk2(a[2], a[3]);
    *(ulonglong2*)(outp + ((size_t)b * CH + c) * HW + p) = t;
}

// ---------------- attention-coefficient mixer: 64px x 2 halves ----------------
__global__ __launch_bounds__(128) void attmix_k(const float* __restrict__ xn,
        const float* __restrict__ wA, const float* __restrict__ bA,
        const float* __restrict__ wB, const float* __restrict__ bB,
        const float* __restrict__ gam, float* __restrict__ att)
{
    __shared__ float swA[INTERC * 18], sbA[INTERC], swB[NSET * 12], sbB[NSET], sgam[NSET];
    __shared__ float sav[64 * 24];
    int tid = threadIdx.x;
    for (int i = tid; i < INTERC * 18; i += 128) swA[i] = wA[i];
    if (tid < INTERC) sbA[tid] = bA[tid];
    for (int i = tid; i < NSET * 12; i += 128) swB[i] = wB[i];
    if (tid < NSET) { sbB[tid] = bB[tid]; sgam[tid] = gam[tid]; }
    __syncthreads();
    int px = tid & 63, half = tid >> 6;
    int pg = blockIdx.x * 64 + px;
    int b = pg >> 12, p = pg & 4095;
    int h = p >> 6, w = p & 63;
    const float* xb = xn + (size_t)b * CCH * HW;
#pragma unroll
    for (int oo = 0; oo < 12; oo++) {
        int o = half * 12 + oo;
        float acc = sbA[o];
#pragma unroll
        for (int t = 0; t < 2; t++) {
            const float* ch = xb + (size_t)(o * 2 + t) * HW;
#pragma unroll
            for (int kk = 0; kk < 9; kk++) {
                int hh = h + kk / 3 - 1, ww = w + kk % 3 - 1;
                if (hh >= 0 && hh < 64 && ww >= 0 && ww < 64)
                    acc += swA[o * 18 + t * 9 + kk] * ch[hh * 64 + ww];
            }
        }
        sav[px * 24 + o] = acc;
    }
    __syncthreads();
    float sg[12];
#pragma unroll
    for (int i = 0; i < 12; i++) sg[i] = sav[px * 24 + i] * sav[px * 24 + 12 + i];
#pragma unroll
    for (int nn = 0; nn < 16; nn++) {
        int n = half * 16 + nn;
        float s = sbB[n];
#pragma unroll
        for (int i = 0; i < 12; i++) s += swB[n * 12 + i] * sg[i];
        size_t oi = ((size_t)b * NSET + n) * HW + p;
        att[oi] = sgam[n] * s + att[oi];
    }
}

// ================= KBA core via warp MMA, y-split x2 (12 groups each) =================
#define KT_A 0
#define KT_B 18432
#define KT_P 41472
#define KT_TOTAL 61952

__global__ __launch_bounds__(256) void kba_mma_k(
        const float* __restrict__ uf, const float* __restrict__ att,
        const __nv_bfloat16* __restrict__ kwb, const float* __restrict__ ga1,
        const float* __restrict__ x1, float* __restrict__ mout)
{
    extern __shared__ __align__(16) char smraw[];
    uint32_t* A32 = (uint32_t*)(smraw + KT_A);
    uint32_t* B32 = (uint32_t*)(smraw + KT_B);
    float*    P   = (float*)(smraw + KT_P);

    int tid = threadIdx.x, wid = tid >> 5, lane = tid & 31;
    int c0 = lane & 3, rq = lane >> 2;
    int pb = blockIdx.x * 128;
    int b = pb >> 12, pp0 = pb & 4095;
    int g0 = blockIdx.y * 12;

    int px = tid & 127, half = tid >> 7;
    int pp = pp0 + px;
    int h = pp >> 6, w = pp & 63;

    {
        const float* attb = att + (size_t)b * NSET * HW + pp;
#pragma unroll
        for (int q = 0; q < 8; q++) {
            int n = (half * 8 + q) * 2;
            __nv_bfloat162 v;
            v.x = __float2bfloat16_rn(attb[(size_t)n * HW]);
            v.y = __float2bfloat16_rn(attb[(size_t)(n + 1) * HW]);
            A32[px * 36 + half * 8 + q] = *(uint32_t*)&v;
        }
    }
    int offs[9]; bool val[9];
#pragma unroll
    for (int kk = 0; kk < 9; kk++) {
        int dh = kk / 3 - 1, dw = kk % 3 - 1;
        int hh = h + dh, ww = w + dw;
        val[kk] = (hh >= 0 && hh < 64 && ww >= 0 && ww < 64);
        offs[kk] = hh * 64 + ww;
    }
    __syncthreads();

    int arow = 16 * wid + rq;
    uint32_t aF[2][4];
#pragma unroll
    for (int ks = 0; ks < 2; ks++) {
        int base = ks * 8;
        aF[ks][0] = A32[arow * 36 + base + c0];
        aF[ks][1] = A32[(arow + 8) * 36 + base + c0];
        aF[ks][2] = A32[arow * 36 + base + c0 + 4];
        aF[ks][3] = A32[(arow + 8) * 36 + base + c0 + 4];
    }

    for (int gi = 0; gi < 12; gi++) {
        int g = g0 + gi;
        __syncthreads();
        const uint32_t* kwb32 = (const uint32_t*)(kwb + (size_t)g * 160 * 32);
        for (int i = tid; i < 2560; i += 256) {
            int row = i >> 4, np = i & 15;
            B32[row * 36 + np] = kwb32[i];
        }
        const float* ufg = uf + ((size_t)b * HID + g * 4) * HW;
#pragma unroll
        for (int jj = 0; jj < 18; jj++) {
            int j = half * 18 + jj;
            int ci = j / 9, kk = j % 9;
            P[px * 40 + j] = val[kk] ? ufg[(size_t)ci * HW + offs[kk]] : 0.f;
        }
        __syncthreads();

#pragma unroll
        for (int cc = 0; cc < 4; cc++) {
            uint32_t bF[5][2][2];
            int nb = cc * 40;
#pragma unroll
            for (int t = 0; t < 5; t++) {
                int rowb = (nb + t * 8 + rq) * 36;
#pragma unroll
                for (int ks = 0; ks < 2; ks++) {
                    bF[t][ks][0] = B32[rowb + ks * 8 + c0];
                    bF[t][ks][1] = B32[rowb + ks * 8 + c0 + 4];
                }
            }
            float d[5][4];
#pragma unroll
            for (int t = 0; t < 5; t++) { d[t][0]=0.f; d[t][1]=0.f; d[t][2]=0.f; d[t][3]=0.f; }
#pragma unroll
            for (int t = 0; t < 5; t++) {
                mma_bf16(d[t], aF[0], bF[t][0]);
                mma_bf16(d[t], aF[1], bF[t][1]);
            }
            int rlo = 16 * wid + rq, rhi = rlo + 8;
            float s0 = 0.f, s1 = 0.f;
#pragma unroll
            for (int t = 0; t < 5; t++) {
                int j0 = t * 8 + 2 * c0, j1 = j0 + 1;
                float w00, w01, w10, w11;
                if (j0 < 36)      { w00 = P[rlo * 40 + j0]; w10 = P[rhi * 40 + j0]; }
                else if (j0 == 36){ w00 = 1.f; w10 = 1.f; }
                else              { w00 = 0.f; w10 = 0.f; }
                if (j1 < 36)      { w01 = P[rlo * 40 + j1]; w11 = P[rhi * 40 + j1]; }
                else              { w01 = 0.f; w11 = 0.f; }
                s0 += d[t][0] * w00 + d[t][1] * w01;
                s1 += d[t][2] * w10 + d[t][3] * w11;
            }
            s0 += __shfl_xor_sync(0xffffffffu, s0, 1);
            s0 += __shfl_xor_sync(0xffffffffu, s0, 2);
            s1 += __shfl_xor_sync(0xffffffffu, s1, 1);
            s1 += __shfl_xor_sync(0xffffffffu, s1, 2);
            if (c0 == 0) {
                int ch = g * 4 + cc;
                float ga = ga1[ch];
                float cen0 = P[rlo * 40 + cc * 9 + 4];
                float cen1 = P[rhi * 40 + cc * 9 + 4];
                float x2a = s0 * ga + cen0;
                float x2b = s1 * ga + cen1;
                size_t xlo = ((size_t)b * HID + ch) * HW + pp0 + rlo;
                size_t xhi = xlo + 8;
                float v0 = x1[xlo], v1 = x1[xhi];
                mout[xlo] = 0.5f * v0 * (1.f + erff(v0 * 0.70710678118654752f)) * x2a;
                mout[xhi] = 0.5f * v1 * (1.f + erff(v1 * 0.70710678118654752f)) * x2b;
            }
        }
    }
}

// ---------------- MDTA: fused norms + 6x6 attention + softmax ----------------
__global__ __launch_bounds__(256) void attn_k(const float* __restrict__ qkv,
        const float* __restrict__ temp, float* __restrict__ attn)
{
    int bh = blockIdx.x; int b = bh >> 3, h = bh & 7;
    int warp = threadIdx.x >> 5, lane = threadIdx.x & 31;
    __shared__ float S[36], NQ[6], NK[6];
    const float* qb = qkv + ((size_t)b * 3 * CCH + h * DHEAD) * HW;
    const float* kb = qkv + ((size_t)b * 3 * CCH + CCH + h * DHEAD) * HW;
    for (int pi = warp; pi < 48; pi += 8) {
        const float* pa; const float* pb;
        if (pi < 36)      { pa = qb + (size_t)(pi / 6) * HW; pb = kb + (size_t)(pi % 6) * HW; }
        else if (pi < 42) { pa = qb + (size_t)(pi - 36) * HW; pb = pa; }
        else              { pa = kb + (size_t)(pi - 42) * HW; pb = pa; }
        float s = 0.f;
        for (int t = lane * 4; t < HW; t += 128) {
            float4 va = *(const float4*)(pa + t);
            float4 vb = *(const float4*)(pb + t);
            s += va.x * vb.x + va.y * vb.y + va.z * vb.z + va.w * vb.w;
        }
#pragma unroll
        for (int off = 16; off; off >>= 1) s += __shfl_down_sync(0xffffffffu, s, off);
        if (lane == 0) {
            if (pi < 36) S[pi] = s;
            else if (pi < 42) NQ[pi - 36] = sqrtf(s);
            else NK[pi - 42] = sqrtf(s);
        }
    }
    __syncthreads();
    if (threadIdx.x < 6) {
        int i = threadIdx.x;
        float nq = fmaxf(NQ[i], 1e-12f);
        float tv = temp[h];
        float row[6]; float mx = -1e30f;
#pragma unroll
        for (int j = 0; j < 6; j++) {
            float nk = fmaxf(NK[j], 1e-12f);
            row[j] = tv * S[i * 6 + j] / (nq * nk);
            mx = fmaxf(mx, row[j]);
        }
        float sum = 0.f;
#pragma unroll
        for (int j = 0; j < 6; j++) { row[j] = expf(row[j] - mx); sum += row[j]; }
        float inv = 1.f / sum;
#pragma unroll
        for (int j = 0; j < 6; j++)
            attn[((size_t)(b * 8 + h) * 6 + i) * 6 + j] = row[j] * inv;
    }
}

// ---------------- MDTA: fused (attn @ v) + mproj ----------------
__global__ __launch_bounds__(128) void mdta_k(const float* __restrict__ qkv,
        const float* __restrict__ attn, const float* __restrict__ mproj,
        float* __restrict__ out)
{
    __shared__ float scoef[288];
    __shared__ u64 ws2[4 * CCH];
    int tid = threadIdx.x;
    int o0 = blockIdx.y * 4;
    int p4 = (blockIdx.x * 128 + tid) * 4;
    int b = p4 >> 12, pp = p4 & 4095;
    int bblk = (blockIdx.x * 512) >> 12;
    for (int i = tid; i < 288; i += 128) scoef[i] = attn[bblk * 288 + i];
    for (int i = tid; i < 4 * CCH; i += 128)
        ws2[i] = dup2(mproj[(o0 + i / CCH) * CCH + i % CCH]);
    __syncthreads();
    u64 acc[4][2];
#pragma unroll
    for (int o = 0; o < 4; o++) { acc[o][0] = 0ULL; acc[o][1] = 0ULL; }
    const float* vb = qkv + ((size_t)b * 3 * CCH + 2 * CCH) * HW + pp;
#pragma unroll
    for (int h = 0; h < 8; h++) {
        u64 v[6][2];
#pragma unroll
        for (int j = 0; j < 6; j++) {
            ulonglong2 t = *(const ulonglong2*)(vb + (size_t)(h * 6 + j) * HW);
            v[j][0] = t.x; v[j][1] = t.y;
        }
#pragma unroll
        for (int i = 0; i < 6; i++) {
            int c = h * 6 + i;
            u64 md0 = 0ULL, md1 = 0ULL;
#pragma unroll
            for (int j = 0; j < 6; j++) {
                u64 cf = dup2(scoef[c * 6 + j]);
                md0 = fma2_(cf, v[j][0], md0);
                md1 = fma2_(cf, v[j][1], md1);
            }
#pragma unroll
            for (int o = 0; o < 4; o++) {
                u64 wv = ws2[o * CCH + c];
                acc[o][0] = fma2_(wv, md0, acc[o][0]);
                acc[o][1] = fma2_(wv, md1, acc[o][1]);
            }
        }
    }
    float* outb = out + ((size_t)b * CCH + o0) * HW + pp;
#pragma unroll
    for (int o = 0; o < 4; o++) {
        ulonglong2 t; t.x = acc[o][0]; t.y = acc[o][1];
        *(ulonglong2*)(outb + (size_t)o * HW) = t;
    }
}

// ---------------- final: kproj + residual combine ----------------
__global__ __launch_bounds__(128) void final_k(const float* __restrict__ x,
        const float* __restrict__ m, const float* __restrict__ mdta,
        const float* __restrict__ kproj,
        const float* __restrict__ ca1, const float* __restrict__ ca2,
        float* __restrict__ out)
{
    __shared__ __align__(16) u64 wp2[4 * HID];
    int tid = threadIdx.x;
    int o0 = blockIdx.y * 4;
    for (int i = tid; i < 4 * HID; i += 128)
        wp2[i] = dup2(kproj[(o0 + i / HID) * HID + i % HID]);
    __syncthreads();
    int p4 = (blockIdx.x * 128 + tid) * 4;
    int b = p4 >> 12, pp = p4 & 4095;
    const float* mb = m + (size_t)b * HID * HW + pp;
    u64 acc[4][2];
#pragma unroll
    for (int o = 0; o < 4; o++) { acc[o][0] = 0ULL; acc[o][1] = 0ULL; }
    for (int cc = 0; cc < HID; cc += 8) {
        u64 xv[8][2];
#pragma unroll
        for (int c = 0; c < 8; c++) {
            ulonglong2 t = *(const ulonglong2*)(mb + (size_t)(cc + c) * HW);
            xv[c][0] = t.x; xv[c][1] = t.y;
        }
#pragma unroll
        for (int o = 0; o < 4; o++) {
#pragma unroll
            for (int c = 0; c < 8; c += 2) {
                ulonglong2 wv = *(const ulonglong2*)&wp2[o * HID + cc + c];
                acc[o][0] = fma2_(wv.x, xv[c][0], acc[o][0]);
                acc[o][1] = fma2_(wv.x, xv[c][1], acc[o][1]);
                acc[o][0] = fma2_(wv.y, xv[c + 1][0], acc[o][0]);
                acc[o][1] = fma2_(wv.y, xv[c + 1][1], acc[o][1]);
            }
        }
    }
#pragma unroll
    for (int o = 0; o < 4; o++) {
        int oc = o0 + o;
        size_t oi = ((size_t)b * CCH + oc) * HW + pp;
        u64 a1 = dup2(ca1[b * CCH + oc]), a2 = dup2(ca2[b * CCH + oc]);
        ulonglong2 xv = *(const ulonglong2*)(x + oi);
        ulonglong2 dv = *(const ulonglong2*)(mdta + oi);
        ulonglong2 r;
        r.x = fma2_(a1, acc[o][0], fma2_(a2, dv.x, xv.x));
        r.y = fma2_(a1, acc[o][1], fma2_(a2, dv.y, xv.y));
        *(ulonglong2*)(out + oi) = r;
    }
}

// ---------------- host launcher ----------------
extern "C" void kernel_launch(void* const* d_in, const int* in_sizes, int n_in,
                              void* d_out, int out_size)
{
    const float* x       = (const float*)d_in[0];
    const float* n1w     = (const float*)d_in[1];
    const float* n1b     = (const float*)d_in[2];
    const float* n2w     = (const float*)d_in[3];
    const float* n2b     = (const float*)d_in[4];
    const float* kdw1    = (const float*)d_in[5];
    const float* kdw2    = (const float*)d_in[6];
    const float* kc1a    = (const float*)d_in[7];
    const float* kc1b    = (const float*)d_in[8];
    const float* kproj   = (const float*)d_in[9];
    const float* c2a_w   = (const float*)d_in[10];
    const float* c2a_b   = (const float*)d_in[11];
    const float* c2b_w   = (const float*)d_in[12];
    const float* c2b_b   = (const float*)d_in[13];
    const float* c211_w  = (const float*)d_in[14];
    const float* c211_b  = (const float*)d_in[15];
    const float* kw      = (const float*)d_in[16];
    const float* kb      = (const float*)d_in[17];
    const float* attg    = (const float*)d_in[18];
    const float* ga1     = (const float*)d_in[19];
    const float* temp    = (const float*)d_in[20];
    const float* qkv_w   = (const float*)d_in[21];
    const float* qkv_dww = (const float*)d_in[22];
    const float* mproj_w = (const float*)d_in[23];
    const float* ca1_w   = (const float*)d_in[24];
    const float* ca1_b   = (const float*)d_in[25];
    const float* ca2_w   = (const float*)d_in[26];
    const float* ca2_b   = (const float*)d_in[27];
    float* out = (float*)d_out;

    float* S = nullptr;
    cudaGetSymbolAddress((void**)&S, g_scratch);
    float* xn   = S + OFF_XN;
    float* xm   = S + OFF_XM;
    float* t1   = S + OFF_T1;
    float* t2   = S + OFF_T2;
    float* x1   = S + OFF_X1;
    float* uf   = S + OFF_UF;
    float* att  = S + OFF_ATT;
    float* qkvt = S + OFF_QKVT;
    float* qkv  = S + OFF_QKV;
    float* m    = S + OFF_M;
    float* gap  = S + OFF_GAP;
    float* ca1  = S + OFF_CA1;
    float* ca2  = S + OFF_CA2;
    float* attn = S + OFF_ATTN;
    __nv_bfloat16* kwb = (__nv_bfloat16*)(S + OFF_KWB);
    __nv_bfloat16* wb  = (__nv_bfloat16*)(S + OFF_WB);
    __nv_bfloat16* wq  = (__nv_bfloat16*)(S + OFF_WQ);
    float* mdta = qkvt;                     // reuse

    const int PIX = BATCH * HW;             // 16384
    const int XB4 = PIX / 512;              // 32

    cudaFuncSetAttribute(kba_mma_k, cudaFuncAttributeMaxDynamicSharedMemorySize, KT_TOTAL);

    const int PREP_N = 24 * 160 * 32 + 224 * 48 + 144 * 48;
    prep_k<<<(PREP_N + 255) / 256, 256>>>(kw, kb, kdw1, kc1a, c211_w, qkv_w, kwb, wb, wq);

    gap_k<<<BATCH * CCH, 256>>>(x, gap);
    ca_k<<<BATCH * CCH, 64>>>(gap, ca1_w, ca1_b, ca2_w, ca2_b, ca1, ca2);

    ln_k<<<PIX / 64, 256>>>(x, n1w, n1b, n2w, n2b, xn, xm);

    // branch GEMMs (y-split for occupancy)
    fused3m_k<<<dim3(PIX / 128, 2), 256>>>(xn, wb, c211_b, t1, t2, att);
    qkvm_k<<<dim3(PIX / 128, 2), 256>>>(xm, wq, qkvt);

    // merged depthwise conv
    dwall_k<<<BATCH * 336 * HW / 1024, 256>>>(t1, kdw2, t2, kc1b, qkvt, qkv_dww,
                                              x1, uf, qkv);

    attmix_k<<<PIX / 64, 128>>>(xn, c2a_w, c2a_b, c2b_w, c2b_b, attg, att);

    // MDTA
    attn_k<<<BATCH * HEADS, 256>>>(qkv, temp, attn);
    mdta_k<<<dim3(XB4, 12), 128>>>(qkv, attn, mproj_w, mdta);

    // KBA core (y-split over group halves)
    kba_mma_k<<<dim3(PIX / 128, 2), 256, KT_TOTAL>>>(uf, att, kwb, ga1, x1, m);

    // projection + residual
    final_k<<<dim3(XB4, 12), 128>>>(x, m, mdta, kproj, ca1, ca2, out);
}

// round 11
// speedup vs baseline: 2.7011x; 1.1661x over previous
#include <cuda_runtime.h>
#include <cuda_bf16.h>
#include <math.h>
#include <cstdint>

// ---------------- problem constants ----------------
#define BATCH 4
#define CCH   48
#define HW    4096
#define HID   96
#define NSET  32
#define HEADS 8
#define DHEAD 6
#define INTERC 24

typedef unsigned long long u64;
__device__ __forceinline__ u64 pk2(float lo, float hi){ u64 r; asm("mov.b64 %0,{%1,%2};":"=l"(r):"f"(lo),"f"(hi)); return r; }
__device__ __forceinline__ u64 dup2(float v){ return pk2(v, v); }
__device__ __forceinline__ u64 fma2_(u64 a, u64 b, u64 c){ u64 d; asm("fma.rn.f32x2 %0,%1,%2,%3;":"=l"(d):"l"(a),"l"(b),"l"(c)); return d; }

__device__ __forceinline__ void mma_bf16(float* d, const uint32_t* a, const uint32_t* b){
    asm volatile("mma.sync.aligned.m16n8k16.row.col.f32.bf16.bf16.f32 "
        "{%0,%1,%2,%3}, {%4,%5,%6,%7}, {%8,%9}, {%0,%1,%2,%3};"
        : "+f"(d[0]),"+f"(d[1]),"+f"(d[2]),"+f"(d[3])
        : "r"(a[0]),"r"(a[1]),"r"(a[2]),"r"(a[3]), "r"(b[0]),"r"(b[1]));
}

// ---------------- scratch layout ----------------
#define OFF_XN    0LL
#define OFF_XM    (OFF_XN   + (long long)BATCH*CCH*HW)
#define OFF_T1    (OFF_XM   + (long long)BATCH*CCH*HW)
#define OFF_T2    (OFF_T1   + (long long)BATCH*HID*HW)
#define OFF_X1    (OFF_T2   + (long long)BATCH*HID*HW)
#define OFF_UF    (OFF_X1   + (long long)BATCH*HID*HW)
#define OFF_ATT   (OFF_UF   + (long long)BATCH*HID*HW)
#define OFF_QKVT  (OFF_ATT  + (long long)BATCH*NSET*HW)
#define OFF_QKV   (OFF_QKVT + (long long)BATCH*3*CCH*HW)
#define OFF_M     (OFF_QKV  + (long long)BATCH*3*CCH*HW)
#define OFF_GAP   (OFF_M    + (long long)BATCH*HID*HW)
#define OFF_ATTN  (OFF_GAP  + BATCH*CCH)
#define OFF_KWB   (OFF_ATTN + BATCH*HEADS*DHEAD*DHEAD)
#define OFF_WB    (OFF_KWB + 24*160*32/2 + 64)
#define OFF_WQ    (OFF_WB  + 192*48/2 + 32)
#define SCRATCH_TOTAL (OFF_WQ + 144*48/2 + 32)

__device__ float g_scratch[SCRATCH_TOTAL];

// ---------------- gap ----------------
__global__ void gap_k(const float* __restrict__ x, float* __restrict__ gap)
{
    int bc = blockIdx.x;
    const float* xb = x + (size_t)bc * HW;
    __shared__ float red[256];
    float s = 0.f;
    for (int i = threadIdx.x; i < HW; i += 256) s += xb[i];
    red[threadIdx.x] = s; __syncthreads();
    for (int st = 128; st; st >>= 1) {
        if (threadIdx.x < st) red[threadIdx.x] += red[threadIdx.x + st];
        __syncthreads();
    }
    if (threadIdx.x == 0) gap[bc] = red[0] * (1.f / HW);
}

// ---------------- LayerNorm2d: 64 px x 4 channel groups ----------------
__global__ __launch_bounds__(256) void ln_k(const float* __restrict__ x,
        const float* __restrict__ n1w, const float* __restrict__ n1b,
        const float* __restrict__ n2w, const float* __restrict__ n2b,
        float* __restrict__ xn, float* __restrict__ xm)
{
    __shared__ float S1[256], S2[256];
    int tid = threadIdx.x;
    int px = tid & 63, grp = tid >> 6;
    int pg = blockIdx.x * 64 + px;
    int b = pg >> 12, p = pg & 4095;
    const float* xb = x + (size_t)b * CCH * HW + p + (size_t)grp * 12 * HW;
    float v[12]; float s = 0.f, s2 = 0.f;
#pragma unroll
    for (int c = 0; c < 12; c++) { float t = xb[(size_t)c * HW]; v[c] = t; s += t; s2 += t * t; }
    S1[tid] = s; S2[tid] = s2;
    __syncthreads();
    float st  = S1[px] + S1[px + 64] + S1[px + 128] + S1[px + 192];
    float st2 = S2[px] + S2[px + 64] + S2[px + 128] + S2[px + 192];
    float mu = st * (1.f / CCH);
    float var = st2 * (1.f / CCH) - mu * mu;
    float r = rsqrtf(var + 1e-6f);
    float* xnb = xn + (size_t)b * CCH * HW + p + (size_t)grp * 12 * HW;
    float* xmb = xm + (size_t)b * CCH * HW + p + (size_t)grp * 12 * HW;
#pragma unroll
    for (int c = 0; c < 12; c++) {
        int cg = grp * 12 + c;
        float y = (v[c] - mu) * r;
        xnb[(size_t)c * HW] = n1w[cg] * y + n1b[cg];
        xmb[(size_t)c * HW] = n2w[cg] * y + n2b[cg];
    }
}

// ---------------- merged weight prepack to bf16 ----------------
__global__ void prep_k(const float* __restrict__ kw, const float* __restrict__ kb,
                       const float* __restrict__ w1, const float* __restrict__ w2,
                       const float* __restrict__ qw,
                       __nv_bfloat16* __restrict__ kwb,
                       __nv_bfloat16* __restrict__ wb, __nv_bfloat16* __restrict__ wq)
{
    int i = blockIdx.x * 256 + threadIdx.x;
    if (i < 24 * 160 * 32) {
        int g = i / (160 * 32);
        int rem = i % (160 * 32);
        int row = rem >> 5, n = rem & 31;
        int c = row / 40, rr = row - c * 40;
        float v;
        if (rr < 36)       v = kw[(size_t)n * 3456 + g * 144 + c * 36 + rr];
        else if (rr == 36) v = kb[n * HID + g * 4 + c];
        else               v = 0.f;
        kwb[i] = __float2bfloat16_rn(v);
    } else if (i < 24 * 160 * 32 + 192 * 48) {
        int j = i - 24 * 160 * 32;
        int o = j / 48, c = j % 48;
        float v = (o < 96) ? w1[o * 48 + c] : w2[(o - 96) * 48 + c];
        wb[j] = __float2bfloat16_rn(v);
    } else if (i < 24 * 160 * 32 + 192 * 48 + 144 * 48) {
        int j = i - 24 * 160 * 32 - 192 * 48;
        wq[j] = __float2bfloat16_rn(qw[j]);
    }
}

// ---------------- fused2 via warp MMA: xn -> t1(96), t2(96), y-split x2 ----------------
__global__ __launch_bounds__(256) void fused3m_k(const float* __restrict__ xn,
        const __nv_bfloat16* __restrict__ wb,
        float* __restrict__ t1, float* __restrict__ t2)
{
    __shared__ uint32_t A32[128 * 28];
    __shared__ uint32_t WB32[96 * 28];
    int tid = threadIdx.x, wid = tid >> 5, lane = tid & 31;
    int c0 = lane & 3, rq = lane >> 2;
    int y = blockIdx.y;
    int ob = y * 96;
    int pb = blockIdx.x * 128;
    int b = pb >> 12, pp0 = pb & 4095;
    int px = tid & 127, half = tid >> 7;
    int pp = pp0 + px;

    const float* xb = xn + (size_t)b * CCH * HW + pp;
#pragma unroll
    for (int w = 0; w < 12; w++) {
        int wd = half * 12 + w; int c = wd * 2;
        __nv_bfloat162 v;
        v.x = __float2bfloat16_rn(xb[(size_t)c * HW]);
        v.y = __float2bfloat16_rn(xb[(size_t)(c + 1) * HW]);
        A32[px * 28 + wd] = *(uint32_t*)&v;
    }
    const uint32_t* wbg = (const uint32_t*)wb;
    for (int i = tid; i < 96 * 24; i += 256) {
        int o = i / 24, w = i % 24;
        WB32[o * 28 + w] = wbg[(ob + o) * 24 + w];
    }
    __syncthreads();

    int arow = wid * 16;
    uint32_t aF[3][4];
#pragma unroll
    for (int ks = 0; ks < 3; ks++) {
        aF[ks][0] = A32[(arow + rq) * 28 + ks * 8 + c0];
        aF[ks][1] = A32[(arow + rq + 8) * 28 + ks * 8 + c0];
        aF[ks][2] = A32[(arow + rq) * 28 + ks * 8 + c0 + 4];
        aF[ks][3] = A32[(arow + rq + 8) * 28 + ks * 8 + c0 + 4];
    }
    for (int nt = 0; nt < 12; nt++) {
        uint32_t bF[3][2];
        int rowb = (nt * 8 + rq) * 28;
#pragma unroll
        for (int ks = 0; ks < 3; ks++) { bF[ks][0] = WB32[rowb + ks * 8 + c0]; bF[ks][1] = WB32[rowb + ks * 8 + c0 + 4]; }
        float d[4] = {0.f, 0.f, 0.f, 0.f};
        mma_bf16(d, aF[0], bF[0]);
        mma_bf16(d, aF[1], bF[1]);
        mma_bf16(d, aF[2], bF[2]);
#pragma unroll
        for (int e = 0; e < 2; e++) {
            int oc = ob + nt * 8 + 2 * c0 + e;
            float* base = (oc < 96) ? t1 : t2;
            int oo = (oc < 96) ? oc : oc - 96;
            size_t o0 = ((size_t)b * HID + oo) * HW + pp0;
            base[o0 + arow + rq]     = d[e];
            base[o0 + arow + rq + 8] = d[e + 2];
        }
    }
}

// ---------------- qkv 1x1 via warp MMA, y-split x2 ----------------
__global__ __launch_bounds__(256) void qkvm_k(const float* __restrict__ xm,
        const __nv_bfloat16* __restrict__ wq, float* __restrict__ out)
{
    __shared__ uint32_t A32[128 * 28];
    __shared__ uint32_t WB32[72 * 28];
    int tid = threadIdx.x, wid = tid >> 5, lane = tid & 31;
    int c0 = lane & 3, rq = lane >> 2;
    int y = blockIdx.y;
    int ob = y * 72;
    int pb = blockIdx.x * 128;
    int b = pb >> 12, pp0 = pb & 4095;
    int px = tid & 127, half = tid >> 7;
    int pp = pp0 + px;

    const float* xb = xm + (size_t)b * CCH * HW + pp;
#pragma unroll
    for (int w = 0; w < 12; w++) {
        int wd = half * 12 + w; int c = wd * 2;
        __nv_bfloat162 v;
        v.x = __float2bfloat16_rn(xb[(size_t)c * HW]);
        v.y = __float2bfloat16_rn(xb[(size_t)(c + 1) * HW]);
        A32[px * 28 + wd] = *(uint32_t*)&v;
    }
    const uint32_t* wbg = (const uint32_t*)wq;
    for (int i = tid; i < 72 * 24; i += 256) {
        int o = i / 24, w = i % 24;
        WB32[o * 28 + w] = wbg[(ob + o) * 24 + w];
    }
    __syncthreads();

    int arow = wid * 16;
    uint32_t aF[3][4];
#pragma unroll
    for (int ks = 0; ks < 3; ks++) {
        aF[ks][0] = A32[(arow + rq) * 28 + ks * 8 + c0];
        aF[ks][1] = A32[(arow + rq + 8) * 28 + ks * 8 + c0];
        aF[ks][2] = A32[(arow + rq) * 28 + ks * 8 + c0 + 4];
        aF[ks][3] = A32[(arow + rq + 8) * 28 + ks * 8 + c0 + 4];
    }
    for (int nt = 0; nt < 9; nt++) {
        uint32_t bF[3][2];
        int rowb = (nt * 8 + rq) * 28;
#pragma unroll
        for (int ks = 0; ks < 3; ks++) { bF[ks][0] = WB32[rowb + ks * 8 + c0]; bF[ks][1] = WB32[rowb + ks * 8 + c0 + 4]; }
        float d[4] = {0.f, 0.f, 0.f, 0.f};
        mma_bf16(d, aF[0], bF[0]);
        mma_bf16(d, aF[1], bF[1]);
        mma_bf16(d, aF[2], bF[2]);
#pragma unroll
        for (int e = 0; e < 2; e++) {
            int oc = ob + nt * 8 + 2 * c0 + e;
            size_t o0 = ((size_t)b * (3 * CCH) + oc) * HW + pp0;
            out[o0 + arow + rq]     = d[e];
            out[o0 + arow + rq + 8] = d[e + 2];
        }
    }
}

// ---------------- depthwise 3x3 for t1/t2 (192 planes) ----------------
__global__ void dw12_k(const float* __restrict__ t1, const float* __restrict__ kdw2,
                       const float* __restrict__ t2, const float* __restrict__ kc1b,
                       float* __restrict__ x1, float* __restrict__ uf)
{
    int gidx4 = (blockIdx.x * 256 + threadIdx.x);
    int p = (gidx4 * 4) & 4095;
    int plane = (gidx4 * 4) >> 12;
    int b = plane / 192, cg = plane % 192;
    const float* in; const float* wsrc; float* outp; int c;
    if (cg < 96) { in = t1; wsrc = kdw2; outp = x1; c = cg; }
    else         { in = t2; wsrc = kc1b; outp = uf; c = cg - 96; }
    int h = p >> 6, w0 = p & 63;
    const float* inp = in + ((size_t)b * 96 + c) * HW;
    const float* wc = wsrc + c * 9;
    float wk[9];
#pragma unroll
    for (int i = 0; i < 9; i++) wk[i] = __ldg(wc + i);
    float a[4] = {0.f, 0.f, 0.f, 0.f};
#pragma unroll
    for (int kh = 0; kh < 3; kh++) {
        int hh = h + kh - 1;
        if (hh < 0 || hh > 63) continue;
        const float* r = inp + hh * 64;
        float4 v14 = *(const float4*)(r + w0);
        float vm1 = (w0 > 0)  ? r[w0 - 1] : 0.f;
        float v5  = (w0 < 60) ? r[w0 + 4] : 0.f;
        float v[6] = {vm1, v14.x, v14.y, v14.z, v14.w, v5};
        float k0 = wk[kh * 3], k1 = wk[kh * 3 + 1], k2 = wk[kh * 3 + 2];
#pragma unroll
        for (int px = 0; px < 4; px++)
            a[px] += k0 * v[px] + k1 * v[px + 1] + k2 * v[px + 2];
    }
    ulonglong2 t; t.x = pk2(a[0], a[1]); t.y = pk2(a[2], a[3]);
    *(ulonglong2*)(outp + ((size_t)b * 96 + c) * HW + p) = t;
}

// ---------------- depthwise 3x3 for qkv (144 planes) ----------------
__global__ void dwq_k(const float* __restrict__ qkvt, const float* __restrict__ qkvw,
                      float* __restrict__ qkv)
{
    int gidx4 = (blockIdx.x * 256 + threadIdx.x);
    int p = (gidx4 * 4) & 4095;
    int plane = (gidx4 * 4) >> 12;
    int b = plane / 144, c = plane % 144;
    int h = p >> 6, w0 = p & 63;
    const float* inp = qkvt + ((size_t)b * 144 + c) * HW;
    const float* wc = qkvw + c * 9;
    float wk[9];
#pragma unroll
    for (int i = 0; i < 9; i++) wk[i] = __ldg(wc + i);
    float a[4] = {0.f, 0.f, 0.f, 0.f};
#pragma unroll
    for (int kh = 0; kh < 3; kh++) {
        int hh = h + kh - 1;
        if (hh < 0 || hh > 63) continue;
        const float* r = inp + hh * 64;
        float4 v14 = *(const float4*)(r + w0);
        float vm1 = (w0 > 0)  ? r[w0 - 1] : 0.f;
        float v5  = (w0 < 60) ? r[w0 + 4] : 0.f;
        float v[6] = {vm1, v14.x, v14.y, v14.z, v14.w, v5};
        float k0 = wk[kh * 3], k1 = wk[kh * 3 + 1], k2 = wk[kh * 3 + 2];
#pragma unroll
        for (int px = 0; px < 4; px++)
            a[px] += k0 * v[px] + k1 * v[px + 1] + k2 * v[px + 2];
    }
    ulonglong2 t; t.x = pk2(a[0], a[1]); t.y = pk2(a[2], a[3]);
    *(ulonglong2*)(qkv + ((size_t)b * 144 + c) * HW + p) = t;
}

// ---------------- attmix: grouped3x3+gate+1x1 AND c211 1x1, att written once ----------------
__global__ __launch_bounds__(128) void attmix_k(const float* __restrict__ xn,
        const float* __restrict__ wA, const float* __restrict__ bA,
        const float* __restrict__ wB, const float* __restrict__ bB,
        const float* __restrict__ gam,
        const float* __restrict__ c211w, const float* __restrict__ c211b,
        float* __restrict__ att)
{
    __shared__ float swA[INTERC * 18], sbA[INTERC], swB[NSET * 12], sbB[NSET], sgam[NSET];
    __shared__ float sw3[NSET * CCH], sb3[NSET];
    __shared__ float scen[64 * 48];
    __shared__ float sav[64 * 24];
    int tid = threadIdx.x;
    for (int i = tid; i < INTERC * 18; i += 128) swA[i] = wA[i];
    if (tid < INTERC) sbA[tid] = bA[tid];
    for (int i = tid; i < NSET * 12; i += 128) swB[i] = wB[i];
    if (tid < NSET) { sbB[tid] = bB[tid]; sgam[tid] = gam[tid]; sb3[tid] = c211b[tid]; }
    for (int i = tid; i < NSET * CCH; i += 128) sw3[i] = c211w[i];
    __syncthreads();
    int px = tid & 63, half = tid >> 6;
    int pg = blockIdx.x * 64 + px;
    int b = pg >> 12, p = pg & 4095;
    int h = p >> 6, w = p & 63;
    const float* xb = xn + (size_t)b * CCH * HW;
#pragma unroll
    for (int oo = 0; oo < 12; oo++) {
        int o = half * 12 + oo;
        float acc = sbA[o];
#pragma unroll
        for (int t = 0; t < 2; t++) {
            int c = o * 2 + t;
            const float* ch = xb + (size_t)c * HW;
            float cen = 0.f;
#pragma unroll
            for (int kk = 0; kk < 9; kk++) {
                int hh = h + kk / 3 - 1, ww = w + kk % 3 - 1;
                if (hh >= 0 && hh < 64 && ww >= 0 && ww < 64) {
                    float vv = ch[hh * 64 + ww];
                    acc += swA[o * 18 + t * 9 + kk] * vv;
                    if (kk == 4) cen = vv;
                }
            }
            scen[px * 48 + c] = cen;
        }
        sav[px * 24 + o] = acc;
    }
    __syncthreads();
    float sg[12];
#pragma unroll
    for (int i = 0; i < 12; i++) sg[i] = sav[px * 24 + i] * sav[px * 24 + 12 + i];
#pragma unroll
    for (int nn = 0; nn < 16; nn++) {
        int n = half * 16 + nn;
        float s = sbB[n];
#pragma unroll
        for (int i = 0; i < 12; i++) s += swB[n * 12 + i] * sg[i];
        float c2 = sb3[n];
#pragma unroll
        for (int c = 0; c < 48; c++) c2 += sw3[n * 48 + c] * scen[px * 48 + c];
        att[((size_t)b * NSET + n) * HW + p] = sgam[n] * s + c2;
    }
}

// ================= KBA core via warp MMA, y-split x2 =================
#define KT_A 0
#define KT_B 18432
#define KT_P 41472
#define KT_TOTAL 61952

__global__ __launch_bounds__(256) void kba_mma_k(
        const float* __restrict__ uf, const float* __restrict__ att,
        const __nv_bfloat16* __restrict__ kwb, const float* __restrict__ ga1,
        const float* __restrict__ x1, float* __restrict__ mout)
{
    extern __shared__ __align__(16) char smraw[];
    uint32_t* A32 = (uint32_t*)(smraw + KT_A);
    uint32_t* B32 = (uint32_t*)(smraw + KT_B);
    float*    P   = (float*)(smraw + KT_P);

    int tid = threadIdx.x, wid = tid >> 5, lane = tid & 31;
    int c0 = lane & 3, rq = lane >> 2;
    int pb = blockIdx.x * 128;
    int b = pb >> 12, pp0 = pb & 4095;
    int g0 = blockIdx.y * 12;

    int px = tid & 127, half = tid >> 7;
    int pp = pp0 + px;
    int h = pp >> 6, w = pp & 63;

    {
        const float* attb = att + (size_t)b * NSET * HW + pp;
#pragma unroll
        for (int q = 0; q < 8; q++) {
            int n = (half * 8 + q) * 2;
            __nv_bfloat162 v;
            v.x = __float2bfloat16_rn(attb[(size_t)n * HW]);
            v.y = __float2bfloat16_rn(attb[(size_t)(n + 1) * HW]);
            A32[px * 36 + half * 8 + q] = *(uint32_t*)&v;
        }
    }
    int offs[9]; bool val[9];
#pragma unroll
    for (int kk = 0; kk < 9; kk++) {
        int dh = kk / 3 - 1, dw = kk % 3 - 1;
        int hh = h + dh, ww = w + dw;
        val[kk] = (hh >= 0 && hh < 64 && ww >= 0 && ww < 64);
        offs[kk] = hh * 64 + ww;
    }
    __syncthreads();

    int arow = 16 * wid + rq;
    uint32_t aF[2][4];
#pragma unroll
    for (int ks = 0; ks < 2; ks++) {
        int base = ks * 8;
        aF[ks][0] = A32[arow * 36 + base + c0];
        aF[ks][1] = A32[(arow + 8) * 36 + base + c0];
        aF[ks][2] = A32[arow * 36 + base + c0 + 4];
        aF[ks][3] = A32[(arow + 8) * 36 + base + c0 + 4];
    }

    for (int gi = 0; gi < 12; gi++) {
        int g = g0 + gi;
        __syncthreads();
        const uint32_t* kwb32 = (const uint32_t*)(kwb + (size_t)g * 160 * 32);
        for (int i = tid; i < 2560; i += 256) {
            int row = i >> 4, np = i & 15;
            B32[row * 36 + np] = kwb32[i];
        }
        const float* ufg = uf + ((size_t)b * HID + g * 4) * HW;
#pragma unroll
        for (int jj = 0; jj < 18; jj++) {
            int j = half * 18 + jj;
            int ci = j / 9, kk = j % 9;
            P[px * 40 + j] = val[kk] ? ufg[(size_t)ci * HW + offs[kk]] : 0.f;
        }
        __syncthreads();

#pragma unroll
        for (int cc = 0; cc < 4; cc++) {
            uint32_t bF[5][2][2];
            int nb = cc * 40;
#pragma unroll
            for (int t = 0; t < 5; t++) {
                int rowb = (nb + t * 8 + rq) * 36;
#pragma unroll
                for (int ks = 0; ks < 2; ks++) {
                    bF[t][ks][0] = B32[rowb + ks * 8 + c0];
                    bF[t][ks][1] = B32[rowb + ks * 8 + c0 + 4];
                }
            }
            float d[5][4];
#pragma unroll
            for (int t = 0; t < 5; t++) { d[t][0]=0.f; d[t][1]=0.f; d[t][2]=0.f; d[t][3]=0.f; }
#pragma unroll
            for (int t = 0; t < 5; t++) {
                mma_bf16(d[t], aF[0], bF[t][0]);
                mma_bf16(d[t], aF[1], bF[t][1]);
            }
            int rlo = 16 * wid + rq, rhi = rlo + 8;
            float s0 = 0.f, s1 = 0.f;
#pragma unroll
            for (int t = 0; t < 5; t++) {
                int j0 = t * 8 + 2 * c0, j1 = j0 + 1;
                float w00, w01, w10, w11;
                if (j0 < 36)      { w00 = P[rlo * 40 + j0]; w10 = P[rhi * 40 + j0]; }
                else if (j0 == 36){ w00 = 1.f; w10 = 1.f; }
                else              { w00 = 0.f; w10 = 0.f; }
                if (j1 < 36)      { w01 = P[rlo * 40 + j1]; w11 = P[rhi * 40 + j1]; }
                else              { w01 = 0.f; w11 = 0.f; }
                s0 += d[t][0] * w00 + d[t][1] * w01;
                s1 += d[t][2] * w10 + d[t][3] * w11;
            }
            s0 += __shfl_xor_sync(0xffffffffu, s0, 1);
            s0 += __shfl_xor_sync(0xffffffffu, s0, 2);
            s1 += __shfl_xor_sync(0xffffffffu, s1, 1);
            s1 += __shfl_xor_sync(0xffffffffu, s1, 2);
            if (c0 == 0) {
                int ch = g * 4 + cc;
                float ga = ga1[ch];
                float cen0 = P[rlo * 40 + cc * 9 + 4];
                float cen1 = P[rhi * 40 + cc * 9 + 4];
                float x2a = s0 * ga + cen0;
                float x2b = s1 * ga + cen1;
                size_t xlo = ((size_t)b * HID + ch) * HW + pp0 + rlo;
                size_t xhi = xlo + 8;
                float v0 = x1[xlo], v1 = x1[xhi];
                mout[xlo] = 0.5f * v0 * (1.f + erff(v0 * 0.70710678118654752f)) * x2a;
                mout[xhi] = 0.5f * v1 * (1.f + erff(v1 * 0.70710678118654752f)) * x2b;
            }
        }
    }
}

// ---------------- MDTA: fused norms + 6x6 attention + softmax ----------------
__global__ __launch_bounds__(256) void attn_k(const float* __restrict__ qkv,
        const float* __restrict__ temp, float* __restrict__ attn)
{
    int bh = blockIdx.x; int b = bh >> 3, h = bh & 7;
    int warp = threadIdx.x >> 5, lane = threadIdx.x & 31;
    __shared__ float S[36], NQ[6], NK[6];
    const float* qb = qkv + ((size_t)b * 3 * CCH + h * DHEAD) * HW;
    const float* kb = qkv + ((size_t)b * 3 * CCH + CCH + h * DHEAD) * HW;
    for (int pi = warp; pi < 48; pi += 8) {
        const float* pa; const float* pb;
        if (pi < 36)      { pa = qb + (size_t)(pi / 6) * HW; pb = kb + (size_t)(pi % 6) * HW; }
        else if (pi < 42) { pa = qb + (size_t)(pi - 36) * HW; pb = pa; }
        else              { pa = kb + (size_t)(pi - 42) * HW; pb = pa; }
        float s = 0.f;
        for (int t = lane * 4; t < HW; t += 128) {
            float4 va = *(const float4*)(pa + t);
            float4 vb = *(const float4*)(pb + t);
            s += va.x * vb.x + va.y * vb.y + va.z * vb.z + va.w * vb.w;
        }
#pragma unroll
        for (int off = 16; off; off >>= 1) s += __shfl_down_sync(0xffffffffu, s, off);
        if (lane == 0) {
            if (pi < 36) S[pi] = s;
            else if (pi < 42) NQ[pi - 36] = sqrtf(s);
            else NK[pi - 42] = sqrtf(s);
        }
    }
    __syncthreads();
    if (threadIdx.x < 6) {
        int i = threadIdx.x;
        float nq = fmaxf(NQ[i], 1e-12f);
        float tv = temp[h];
        float row[6]; float mx = -1e30f;
#pragma unroll
        for (int j = 0; j < 6; j++) {
            float nk = fmaxf(NK[j], 1e-12f);
            row[j] = tv * S[i * 6 + j] / (nq * nk);
            mx = fmaxf(mx, row[j]);
        }
        float sum = 0.f;
#pragma unroll
        for (int j = 0; j < 6; j++) { row[j] = expf(row[j] - mx); sum += row[j]; }
        float inv = 1.f / sum;
#pragma unroll
        for (int j = 0; j < 6; j++)
            attn[((size_t)(b * 8 + h) * 6 + i) * 6 + j] = row[j] * inv;
    }
}

// ---------------- MDTA: fused (attn @ v) + mproj ----------------
__global__ __launch_bounds__(128) void mdta_k(const float* __restrict__ qkv,
        const float* __restrict__ attn, const float* __restrict__ mproj,
        float* __restrict__ out)
{
    __shared__ float scoef[288];
    __shared__ u64 ws2[4 * CCH];
    int tid = threadIdx.x;
    int o0 = blockIdx.y * 4;
    int p4 = (blockIdx.x * 128 + tid) * 4;
    int b = p4 >> 12, pp = p4 & 4095;
    int bblk = (blockIdx.x * 512) >> 12;
    for (int i = tid; i < 288; i += 128) scoef[i] = attn[bblk * 288 + i];
    for (int i = tid; i < 4 * CCH; i += 128)
        ws2[i] = dup2(mproj[(o0 + i / CCH) * CCH + i % CCH]);
    __syncthreads();
    u64 acc[4][2];
#pragma unroll
    for (int o = 0; o < 4; o++) { acc[o][0] = 0ULL; acc[o][1] = 0ULL; }
    const float* vb = qkv + ((size_t)b * 3 * CCH + 2 * CCH) * HW + pp;
#pragma unroll
    for (int h = 0; h < 8; h++) {
        u64 v[6][2];
#pragma unroll
        for (int j = 0; j < 6; j++) {
            ulonglong2 t = *(const ulonglong2*)(vb + (size_t)(h * 6 + j) * HW);
            v[j][0] = t.x; v[j][1] = t.y;
        }
#pragma unroll
        for (int i = 0; i < 6; i++) {
            int c = h * 6 + i;
            u64 md0 = 0ULL, md1 = 0ULL;
#pragma unroll
            for (int j = 0; j < 6; j++) {
                u64 cf = dup2(scoef[c * 6 + j]);
                md0 = fma2_(cf, v[j][0], md0);
                md1 = fma2_(cf, v[j][1], md1);
            }
#pragma unroll
            for (int o = 0; o < 4; o++) {
                u64 wv = ws2[o * CCH + c];
                acc[o][0] = fma2_(wv, md0, acc[o][0]);
                acc[o][1] = fma2_(wv, md1, acc[o][1]);
            }
        }
    }
    float* outb = out + ((size_t)b * CCH + o0) * HW + pp;
#pragma unroll
    for (int o = 0; o < 4; o++) {
        ulonglong2 t; t.x = acc[o][0]; t.y = acc[o][1];
        *(ulonglong2*)(outb + (size_t)o * HW) = t;
    }
}

// ---------------- final: kproj + residual combine + inline channel-attention ----------------
__global__ __launch_bounds__(128) void final_k(const float* __restrict__ x,
        const float* __restrict__ m, const float* __restrict__ mdta,
        const float* __restrict__ kproj, const float* __restrict__ gap,
        const float* __restrict__ ca1w, const float* __restrict__ ca1b,
        const float* __restrict__ ca2w, const float* __restrict__ ca2b,
        float* __restrict__ out)
{
    __shared__ __align__(16) u64 wp2[4 * HID];
    __shared__ float sca1[4], sca2[4];
    int tid = threadIdx.x, wid = tid >> 5, lane = tid & 31;
    int o0 = blockIdx.y * 4;
    int bblk = (blockIdx.x * 512) >> 12;
    for (int i = tid; i < 4 * HID; i += 128)
        wp2[i] = dup2(kproj[(o0 + i / HID) * HID + i % HID]);
    // warp wid computes ca for channel o0+wid
    {
        int oc = o0 + wid;
        float s1 = 0.f, s2 = 0.f;
        for (int c = lane; c < CCH; c += 32) {
            float g = gap[bblk * CCH + c];
            s1 += ca1w[oc * CCH + c] * g;
            s2 += ca2w[oc * CCH + c] * g;
        }
#pragma unroll
        for (int off = 16; off; off >>= 1) {
            s1 += __shfl_down_sync(0xffffffffu, s1, off);
            s2 += __shfl_down_sync(0xffffffffu, s2, off);
        }
        if (lane == 0) { sca1[wid] = s1 + ca1b[oc]; sca2[wid] = s2 + ca2b[oc]; }
    }
    __syncthreads();
    int p4 = (blockIdx.x * 128 + tid) * 4;
    int b = p4 >> 12, pp = p4 & 4095;
    const float* mb = m + (size_t)b * HID * HW + pp;
    u64 acc[4][2];
#pragma unroll
    for (int o = 0; o < 4; o++) { acc[o][0] = 0ULL; acc[o][1] = 0ULL; }
    for (int cc = 0; cc < HID; cc += 8) {
        u64 xv[8][2];
#pragma unroll
        for (int c = 0; c < 8; c++) {
            ulonglong2 t = *(const ulonglong2*)(mb + (size_t)(cc + c) * HW);
            xv[c][0] = t.x; xv[c][1] = t.y;
        }
#pragma unroll
        for (int o = 0; o < 4; o++) {
#pragma unroll
            for (int c = 0; c < 8; c += 2) {
                ulonglong2 wv = *(const ulonglong2*)&wp2[o * HID + cc + c];
                acc[o][0] = fma2_(wv.x, xv[c][0], acc[o][0]);
                acc[o][1] = fma2_(wv.x, xv[c][1], acc[o][1]);
                acc[o][0] = fma2_(wv.y, xv[c + 1][0], acc[o][0]);
                acc[o][1] = fma2_(wv.y, xv[c + 1][1], acc[o][1]);
            }
        }
    }
#pragma unroll
    for (int o = 0; o < 4; o++) {
        int oc = o0 + o;
        size_t oi = ((size_t)b * CCH + oc) * HW + pp;
        u64 a1 = dup2(sca1[o]), a2 = dup2(sca2[o]);
        ulonglong2 xv = *(const ulonglong2*)(x + oi);
        ulonglong2 dv = *(const ulonglong2*)(mdta + oi);
        ulonglong2 r;
        r.x = fma2_(a1, acc[o][0], fma2_(a2, dv.x, xv.x));
        r.y = fma2_(a1, acc[o][1], fma2_(a2, dv.y, xv.y));
        *(ulonglong2*)(out + oi) = r;
    }
}

// ---------------- host launcher ----------------
extern "C" void kernel_launch(void* const* d_in, const int* in_sizes, int n_in,
                              void* d_out, int out_size)
{
    const float* x       = (const float*)d_in[0];
    const float* n1w     = (const float*)d_in[1];
    const float* n1b     = (const float*)d_in[2];
    const float* n2w     = (const float*)d_in[3];
    const float* n2b     = (const float*)d_in[4];
    const float* kdw1    = (const float*)d_in[5];
    const float* kdw2    = (const float*)d_in[6];
    const float* kc1a    = (const float*)d_in[7];
    const float* kc1b    = (const float*)d_in[8];
    const float* kproj   = (const float*)d_in[9];
    const float* c2a_w   = (const float*)d_in[10];
    const float* c2a_b   = (const float*)d_in[11];
    const float* c2b_w   = (const float*)d_in[12];
    const float* c2b_b   = (const float*)d_in[13];
    const float* c211_w  = (const float*)d_in[14];
    const float* c211_b  = (const float*)d_in[15];
    const float* kw      = (const float*)d_in[16];
    const float* kb      = (const float*)d_in[17];
    const float* attg    = (const float*)d_in[18];
    const float* ga1     = (const float*)d_in[19];
    const float* temp    = (const float*)d_in[20];
    const float* qkv_w   = (const float*)d_in[21];
    const float* qkv_dww = (const float*)d_in[22];
    const float* mproj_w = (const float*)d_in[23];
    const float* ca1_w   = (const float*)d_in[24];
    const float* ca1_b   = (const float*)d_in[25];
    const float* ca2_w   = (const float*)d_in[26];
    const float* ca2_b   = (const float*)d_in[27];
    float* out = (float*)d_out;

    float* S = nullptr;
    cudaGetSymbolAddress((void**)&S, g_scratch);
    float* xn   = S + OFF_XN;
    float* xm   = S + OFF_XM;
    float* t1   = S + OFF_T1;
    float* t2   = S + OFF_T2;
    float* x1   = S + OFF_X1;
    float* uf   = S + OFF_UF;
    float* att  = S + OFF_ATT;
    float* qkvt = S + OFF_QKVT;
    float* qkv  = S + OFF_QKV;
    float* m    = S + OFF_M;
    float* gap  = S + OFF_GAP;
    float* attn = S + OFF_ATTN;
    __nv_bfloat16* kwb = (__nv_bfloat16*)(S + OFF_KWB);
    __nv_bfloat16* wb  = (__nv_bfloat16*)(S + OFF_WB);
    __nv_bfloat16* wq  = (__nv_bfloat16*)(S + OFF_WQ);
    float* mdta = qkvt;                     // reuse

    const int PIX = BATCH * HW;             // 16384
    const int XB4 = PIX / 512;              // 32

    // lazy one-time stream/event setup (side streams for graph fork-join)
    static cudaStream_t sB = nullptr, sC = nullptr;
    static cudaEvent_t evLN = nullptr, evB = nullptr, evC = nullptr;
    if (sB == nullptr) {
        cudaStreamCreateWithFlags(&sB, cudaStreamNonBlocking);
        cudaStreamCreateWithFlags(&sC, cudaStreamNonBlocking);
        cudaEventCreateWithFlags(&evLN, cudaEventDisableTiming);
        cudaEventCreateWithFlags(&evB, cudaEventDisableTiming);
        cudaEventCreateWithFlags(&evC, cudaEventDisableTiming);
        cudaFuncSetAttribute(kba_mma_k, cudaFuncAttributeMaxDynamicSharedMemorySize, KT_TOTAL);
    }

    const int PREP_N = 24 * 160 * 32 + 192 * 48 + 144 * 48;
    prep_k<<<(PREP_N + 255) / 256, 256>>>(kw, kb, kdw1, kc1a, qkv_w, kwb, wb, wq);
    gap_k<<<BATCH * CCH, 256>>>(x, gap);
    ln_k<<<PIX / 64, 256>>>(x, n1w, n1b, n2w, n2b, xn, xm);
    cudaEventRecord(evLN, 0);

    // ---- stream B: MDTA chain ----
    cudaStreamWaitEvent(sB, evLN, 0);
    qkvm_k<<<dim3(PIX / 128, 2), 256, 0, sB>>>(xm, wq, qkvt);
    dwq_k<<<BATCH * 144 * HW / 1024, 256, 0, sB>>>(qkvt, qkv_dww, qkv);
    attn_k<<<BATCH * HEADS, 256, 0, sB>>>(qkv, temp, attn);
    mdta_k<<<dim3(XB4, 12), 128, 0, sB>>>(qkv, attn, mproj_w, mdta);
    cudaEventRecord(evB, sB);

    // ---- stream C: attmix (incl c211) ----
    cudaStreamWaitEvent(sC, evLN, 0);
    attmix_k<<<PIX / 64, 128, 0, sC>>>(xn, c2a_w, c2a_b, c2b_w, c2b_b, attg,
                                       c211_w, c211_b, att);
    cudaEventRecord(evC, sC);

    // ---- main stream: KBA critical path ----
    fused3m_k<<<dim3(PIX / 128, 2), 256>>>(xn, wb, t1, t2);
    dw12_k<<<BATCH * 192 * HW / 1024, 256>>>(t1, kdw2, t2, kc1b, x1, uf);
    cudaStreamWaitEvent(0, evC, 0);
    kba_mma_k<<<dim3(PIX / 128, 2), 256, KT_TOTAL>>>(uf, att, kwb, ga1, x1, m);
    cudaStreamWaitEvent(0, evB, 0);
    final_k<<<dim3(XB4, 12), 128>>>(x, m, mdta, kproj, gap,
                                    ca1_w, ca1_b, ca2_w, ca2_b, out);
}

// round 13
// speedup vs baseline: 2.8841x; 1.0678x over previous
#include <cuda_runtime.h>
#include <cuda_bf16.h>
#include <math.h>
#include <cstdint>

// ---------------- problem constants ----------------
#define BATCH 4
#define CCH   48
#define HW    4096
#define HID   96
#define NSET  32
#define HEADS 8
#define DHEAD 6
#define INTERC 24

typedef unsigned long long u64;
__device__ __forceinline__ u64 pk2(float lo, float hi){ u64 r; asm("mov.b64 %0,{%1,%2};":"=l"(r):"f"(lo),"f"(hi)); return r; }
__device__ __forceinline__ u64 dup2(float v){ return pk2(v, v); }
__device__ __forceinline__ u64 fma2_(u64 a, u64 b, u64 c){ u64 d; asm("fma.rn.f32x2 %0,%1,%2,%3;":"=l"(d):"l"(a),"l"(b),"l"(c)); return d; }

__device__ __forceinline__ void mma_bf16(float* d, const uint32_t* a, const uint32_t* b){
    asm volatile("mma.sync.aligned.m16n8k16.row.col.f32.bf16.bf16.f32 "
        "{%0,%1,%2,%3}, {%4,%5,%6,%7}, {%8,%9}, {%0,%1,%2,%3};"
        : "+f"(d[0]),"+f"(d[1]),"+f"(d[2]),"+f"(d[3])
        : "r"(a[0]),"r"(a[1]),"r"(a[2]),"r"(a[3]), "r"(b[0]),"r"(b[1]));
}

// ---------------- scratch layout ----------------
#define OFF_XN    0LL
#define OFF_T1    (OFF_XN   + (long long)BATCH*CCH*HW)
#define OFF_T2    (OFF_T1   + (long long)BATCH*HID*HW)
#define OFF_X1    (OFF_T2   + (long long)BATCH*HID*HW)
#define OFF_UF    (OFF_X1   + (long long)BATCH*HID*HW)
#define OFF_ATT   (OFF_UF   + (long long)BATCH*HID*HW)
#define OFF_QKVT  (OFF_ATT  + (long long)BATCH*NSET*HW)
#define OFF_QKV   (OFF_QKVT + (long long)BATCH*3*CCH*HW)
#define OFF_M     (OFF_QKV  + (long long)BATCH*3*CCH*HW)
#define OFF_GAP   (OFF_M    + (long long)BATCH*HID*HW)
#define OFF_ATTN  (OFF_GAP  + BATCH*CCH)
#define OFF_KWB   (OFF_ATTN + BATCH*HEADS*DHEAD*DHEAD)
#define OFF_WB    (OFF_KWB + 24*160*32/2 + 64)
#define OFF_WQ    (OFF_WB  + 192*48/2 + 32)
#define SCRATCH_TOTAL (OFF_WQ + 144*48/2 + 32)

__device__ float g_scratch[SCRATCH_TOTAL];

// ---------------- merged prep + gap ----------------
#define GAPB (BATCH * CCH)
__global__ void prepgap_k(const float* __restrict__ x,
                          const float* __restrict__ kw, const float* __restrict__ kb,
                          const float* __restrict__ w1, const float* __restrict__ w2,
                          const float* __restrict__ qw,
                          float* __restrict__ gap,
                          __nv_bfloat16* __restrict__ kwb,
                          __nv_bfloat16* __restrict__ wb, __nv_bfloat16* __restrict__ wq)
{
    if (blockIdx.x < GAPB) {
        int bc = blockIdx.x;
        const float* xb = x + (size_t)bc * HW;
        __shared__ float red[256];
        float s = 0.f;
        for (int i = threadIdx.x; i < HW; i += 256) s += xb[i];
        red[threadIdx.x] = s; __syncthreads();
        for (int st = 128; st; st >>= 1) {
            if (threadIdx.x < st) red[threadIdx.x] += red[threadIdx.x + st];
            __syncthreads();
        }
        if (threadIdx.x == 0) gap[bc] = red[0] * (1.f / HW);
        return;
    }
    int i = (blockIdx.x - GAPB) * 256 + threadIdx.x;
    if (i < 24 * 160 * 32) {
        int g = i / (160 * 32);
        int rem = i % (160 * 32);
        int row = rem >> 5, n = rem & 31;
        int c = row / 40, rr = row - c * 40;
        float v;
        if (rr < 36)       v = kw[(size_t)n * 3456 + g * 144 + c * 36 + rr];
        else if (rr == 36) v = kb[n * HID + g * 4 + c];
        else               v = 0.f;
        kwb[i] = __float2bfloat16_rn(v);
    } else if (i < 24 * 160 * 32 + 192 * 48) {
        int j = i - 24 * 160 * 32;
        int o = j / 48, c = j % 48;
        float v = (o < 96) ? w1[o * 48 + c] : w2[(o - 96) * 48 + c];
        wb[j] = __float2bfloat16_rn(v);
    } else if (i < 24 * 160 * 32 + 192 * 48 + 144 * 48) {
        int j = i - 24 * 160 * 32 - 192 * 48;
        wq[j] = __float2bfloat16_rn(qw[j]);
    }
}

// ---------------- LayerNorm (xn only, feeds attmix) ----------------
__global__ __launch_bounds__(256) void ln_k(const float* __restrict__ x,
        const float* __restrict__ n1w, const float* __restrict__ n1b,
        float* __restrict__ xn)
{
    __shared__ float S1[256], S2[256];
    int tid = threadIdx.x;
    int px = tid & 63, grp = tid >> 6;
    int pg = blockIdx.x * 64 + px;
    int b = pg >> 12, p = pg & 4095;
    const float* xb = x + (size_t)b * CCH * HW + p + (size_t)grp * 12 * HW;
    float v[12]; float s = 0.f, s2 = 0.f;
#pragma unroll
    for (int c = 0; c < 12; c++) { float t = xb[(size_t)c * HW]; v[c] = t; s += t; s2 += t * t; }
    S1[tid] = s; S2[tid] = s2;
    __syncthreads();
    float st  = S1[px] + S1[px + 64] + S1[px + 128] + S1[px + 192];
    float st2 = S2[px] + S2[px + 64] + S2[px + 128] + S2[px + 192];
    float mu = st * (1.f / CCH);
    float var = st2 * (1.f / CCH) - mu * mu;
    float r = rsqrtf(var + 1e-6f);
    float* xnb = xn + (size_t)b * CCH * HW + p + (size_t)grp * 12 * HW;
#pragma unroll
    for (int c = 0; c < 12; c++) {
        int cg = grp * 12 + c;
        xnb[(size_t)c * HW] = n1w[cg] * (v[c] - mu) * r + n1b[cg];
    }
}

// ---------------- fused2 via warp MMA with inline LN: x -> t1(96), t2(96) ----------------
__global__ __launch_bounds__(256) void fused3m_k(const float* __restrict__ x,
        const float* __restrict__ n1w, const float* __restrict__ n1b,
        const __nv_bfloat16* __restrict__ wb,
        float* __restrict__ t1, float* __restrict__ t2)
{
    __shared__ uint32_t A32[128 * 28];
    __shared__ uint32_t WB32[96 * 28];
    __shared__ float SS1[256], SS2[256];
    __shared__ float sw1[CCH], sb1[CCH];
    int tid = threadIdx.x, wid = tid >> 5, lane = tid & 31;
    int c0 = lane & 3, rq = lane >> 2;
    int y = blockIdx.y;
    int ob = y * 96;
    int pb = blockIdx.x * 128;
    int b = pb >> 12, pp0 = pb & 4095;
    int px = tid & 127, half = tid >> 7;
    int pp = pp0 + px;

    if (tid < CCH) { sw1[tid] = n1w[tid]; sb1[tid] = n1b[tid]; }
    const float* xb = x + (size_t)b * CCH * HW + pp;
    float v[24];
    float s = 0.f, s2 = 0.f;
#pragma unroll
    for (int w = 0; w < 12; w++) {
        int c = (half * 12 + w) * 2;
        float a0 = xb[(size_t)c * HW], a1 = xb[(size_t)(c + 1) * HW];
        v[2 * w] = a0; v[2 * w + 1] = a1;
        s += a0 + a1; s2 += a0 * a0 + a1 * a1;
    }
    SS1[tid] = s; SS2[tid] = s2;
    const uint32_t* wbg = (const uint32_t*)wb;
    for (int i = tid; i < 96 * 24; i += 256) {
        int o = i / 24, w = i % 24;
        WB32[o * 28 + w] = wbg[(ob + o) * 24 + w];
    }
    __syncthreads();
    {
        float st  = SS1[px] + SS1[px + 128];
        float st2 = SS2[px] + SS2[px + 128];
        float mu = st * (1.f / CCH);
        float var = st2 * (1.f / CCH) - mu * mu;
        float r = rsqrtf(var + 1e-6f);
#pragma unroll
        for (int w = 0; w < 12; w++) {
            int c = (half * 12 + w) * 2;
            __nv_bfloat162 bv;
            bv.x = __float2bfloat16_rn(sw1[c] * (v[2 * w] - mu) * r + sb1[c]);
            bv.y = __float2bfloat16_rn(sw1[c + 1] * (v[2 * w + 1] - mu) * r + sb1[c + 1]);
            A32[px * 28 + half * 12 + w] = *(uint32_t*)&bv;
        }
    }
    __syncthreads();

    int arow = wid * 16;
    uint32_t aF[3][4];
#pragma unroll
    for (int ks = 0; ks < 3; ks++) {
        aF[ks][0] = A32[(arow + rq) * 28 + ks * 8 + c0];
        aF[ks][1] = A32[(arow + rq + 8) * 28 + ks * 8 + c0];
        aF[ks][2] = A32[(arow + rq) * 28 + ks * 8 + c0 + 4];
        aF[ks][3] = A32[(arow + rq + 8) * 28 + ks * 8 + c0 + 4];
    }
    for (int nt = 0; nt < 12; nt++) {
        uint32_t bF[3][2];
        int rowb = (nt * 8 + rq) * 28;
#pragma unroll
        for (int ks = 0; ks < 3; ks++) { bF[ks][0] = WB32[rowb + ks * 8 + c0]; bF[ks][1] = WB32[rowb + ks * 8 + c0 + 4]; }
        float d[4] = {0.f, 0.f, 0.f, 0.f};
        mma_bf16(d, aF[0], bF[0]);
        mma_bf16(d, aF[1], bF[1]);
        mma_bf16(d, aF[2], bF[2]);
#pragma unroll
        for (int e = 0; e < 2; e++) {
            int oc = ob + nt * 8 + 2 * c0 + e;
            float* base = (oc < 96) ? t1 : t2;
            int oo = (oc < 96) ? oc : oc - 96;
            size_t o0 = ((size_t)b * HID + oo) * HW + pp0;
            base[o0 + arow + rq]     = d[e];
            base[o0 + arow + rq + 8] = d[e + 2];
        }
    }
}

// ---------------- qkv 1x1 via warp MMA with inline LN ----------------
__global__ __launch_bounds__(256) void qkvm_k(const float* __restrict__ x,
        const float* __restrict__ n2w, const float* __restrict__ n2b,
        const __nv_bfloat16* __restrict__ wq, float* __restrict__ out)
{
    __shared__ uint32_t A32[128 * 28];
    __shared__ uint32_t WB32[72 * 28];
    __shared__ float SS1[256], SS2[256];
    __shared__ float sw1[CCH], sb1[CCH];
    int tid = threadIdx.x, wid = tid >> 5, lane = tid & 31;
    int c0 = lane & 3, rq = lane >> 2;
    int y = blockIdx.y;
    int ob = y * 72;
    int pb = blockIdx.x * 128;
    int b = pb >> 12, pp0 = pb & 4095;
    int px = tid & 127, half = tid >> 7;
    int pp = pp0 + px;

    if (tid < CCH) { sw1[tid] = n2w[tid]; sb1[tid] = n2b[tid]; }
    const float* xb = x + (size_t)b * CCH * HW + pp;
    float v[24];
    float s = 0.f, s2 = 0.f;
#pragma unroll
    for (int w = 0; w < 12; w++) {
        int c = (half * 12 + w) * 2;
        float a0 = xb[(size_t)c * HW], a1 = xb[(size_t)(c + 1) * HW];
        v[2 * w] = a0; v[2 * w + 1] = a1;
        s += a0 + a1; s2 += a0 * a0 + a1 * a1;
    }
    SS1[tid] = s; SS2[tid] = s2;
    const uint32_t* wbg = (const uint32_t*)wq;
    for (int i = tid; i < 72 * 24; i += 256) {
        int o = i / 24, w = i % 24;
        WB32[o * 28 + w] = wbg[(ob + o) * 24 + w];
    }
    __syncthreads();
    {
        float st  = SS1[px] + SS1[px + 128];
        float st2 = SS2[px] + SS2[px + 128];
        float mu = st * (1.f / CCH);
        float var = st2 * (1.f / CCH) - mu * mu;
        float r = rsqrtf(var + 1e-6f);
#pragma unroll
        for (int w = 0; w < 12; w++) {
            int c = (half * 12 + w) * 2;
            __nv_bfloat162 bv;
            bv.x = __float2bfloat16_rn(sw1[c] * (v[2 * w] - mu) * r + sb1[c]);
            bv.y = __float2bfloat16_rn(sw1[c + 1] * (v[2 * w + 1] - mu) * r + sb1[c + 1]);
            A32[px * 28 + half * 12 + w] = *(uint32_t*)&bv;
        }
    }
    __syncthreads();

    int arow = wid * 16;
    uint32_t aF[3][4];
#pragma unroll
    for (int ks = 0; ks < 3; ks++) {
        aF[ks][0] = A32[(arow + rq) * 28 + ks * 8 + c0];
        aF[ks][1] = A32[(arow + rq + 8) * 28 + ks * 8 + c0];
        aF[ks][2] = A32[(arow + rq) * 28 + ks * 8 + c0 + 4];
        aF[ks][3] = A32[(arow + rq + 8) * 28 + ks * 8 + c0 + 4];
    }
    for (int nt = 0; nt < 9; nt++) {
        uint32_t bF[3][2];
        int rowb = (nt * 8 + rq) * 28;
#pragma unroll
        for (int ks = 0; ks < 3; ks++) { bF[ks][0] = WB32[rowb + ks * 8 + c0]; bF[ks][1] = WB32[rowb + ks * 8 + c0 + 4]; }
        float d[4] = {0.f, 0.f, 0.f, 0.f};
        mma_bf16(d, aF[0], bF[0]);
        mma_bf16(d, aF[1], bF[1]);
        mma_bf16(d, aF[2], bF[2]);
#pragma unroll
        for (int e = 0; e < 2; e++) {
            int oc = ob + nt * 8 + 2 * c0 + e;
            size_t o0 = ((size_t)b * (3 * CCH) + oc) * HW + pp0;
            out[o0 + arow + rq]     = d[e];
            out[o0 + arow + rq + 8] = d[e + 2];
        }
    }
}

// ---------------- depthwise 3x3 for t1/t2 ----------------
__global__ void dw12_k(const float* __restrict__ t1, const float* __restrict__ kdw2,
                       const float* __restrict__ t2, const float* __restrict__ kc1b,
                       float* __restrict__ x1, float* __restrict__ uf)
{
    int gidx4 = (blockIdx.x * 256 + threadIdx.x);
    int p = (gidx4 * 4) & 4095;
    int plane = (gidx4 * 4) >> 12;
    int b = plane / 192, cg = plane % 192;
    const float* in; const float* wsrc; float* outp; int c;
    if (cg < 96) { in = t1; wsrc = kdw2; outp = x1; c = cg; }
    else         { in = t2; wsrc = kc1b; outp = uf; c = cg - 96; }
    int h = p >> 6, w0 = p & 63;
    const float* inp = in + ((size_t)b * 96 + c) * HW;
    const float* wc = wsrc + c * 9;
    float wk[9];
#pragma unroll
    for (int i = 0; i < 9; i++) wk[i] = __ldg(wc + i);
    float a[4] = {0.f, 0.f, 0.f, 0.f};
#pragma unroll
    for (int kh = 0; kh < 3; kh++) {
        int hh = h + kh - 1;
        if (hh < 0 || hh > 63) continue;
        const float* r = inp + hh * 64;
        float4 v14 = *(const float4*)(r + w0);
        float vm1 = (w0 > 0)  ? r[w0 - 1] : 0.f;
        float v5  = (w0 < 60) ? r[w0 + 4] : 0.f;
        float v[6] = {vm1, v14.x, v14.y, v14.z, v14.w, v5};
        float k0 = wk[kh * 3], k1 = wk[kh * 3 + 1], k2 = wk[kh * 3 + 2];
#pragma unroll
        for (int px = 0; px < 4; px++)
            a[px] += k0 * v[px] + k1 * v[px + 1] + k2 * v[px + 2];
    }
    ulonglong2 t; t.x = pk2(a[0], a[1]); t.y = pk2(a[2], a[3]);
    *(ulonglong2*)(outp + ((size_t)b * 96 + c) * HW + p) = t;
}

// ---------------- depthwise 3x3 for qkv ----------------
__global__ void dwq_k(const float* __restrict__ qkvt, const float* __restrict__ qkvw,
                      float* __restrict__ qkv)
{
    int gidx4 = (blockIdx.x * 256 + threadIdx.x);
    int p = (gidx4 * 4) & 4095;
    int plane = (gidx4 * 4) >> 12;
    int b = plane / 144, c = plane % 144;
    int h = p >> 6, w0 = p & 63;
    const float* inp = qkvt + ((size_t)b * 144 + c) * HW;
    const float* wc = qkvw + c * 9;
    float wk[9];
#pragma unroll
    for (int i = 0; i < 9; i++) wk[i] = __ldg(wc + i);
    float a[4] = {0.f, 0.f, 0.f, 0.f};
#pragma unroll
    for (int kh = 0; kh < 3; kh++) {
        int hh = h + kh - 1;
        if (hh < 0 || hh > 63) continue;
        const float* r = inp + hh * 64;
        float4 v14 = *(const float4*)(r + w0);
        float vm1 = (w0 > 0)  ? r[w0 - 1] : 0.f;
        float v5  = (w0 < 60) ? r[w0 + 4] : 0.f;
        float v[6] = {vm1, v14.x, v14.y, v14.z, v14.w, v5};
        float k0 = wk[kh * 3], k1 = wk[kh * 3 + 1], k2 = wk[kh * 3 + 2];
#pragma unroll
        for (int px = 0; px < 4; px++)
            a[px] += k0 * v[px] + k1 * v[px + 1] + k2 * v[px + 2];
    }
    ulonglong2 t; t.x = pk2(a[0], a[1]); t.y = pk2(a[2], a[3]);
    *(ulonglong2*)(qkv + ((size_t)b * 144 + c) * HW + p) = t;
}

// ---------------- attmix: grouped3x3+gate+1x1 AND c211, att written once ----------------
__global__ __launch_bounds__(128) void attmix_k(const float* __restrict__ xn,
        const float* __restrict__ wA, const float* __restrict__ bA,
        const float* __restrict__ wB, const float* __restrict__ bB,
        const float* __restrict__ gam,
        const float* __restrict__ c211w, const float* __restrict__ c211b,
        float* __restrict__ att)
{
    __shared__ float swA[INTERC * 18], sbA[INTERC], swB[NSET * 12], sbB[NSET], sgam[NSET];
    __shared__ float sw3[NSET * CCH], sb3[NSET];
    __shared__ float scen[64 * 48];
    __shared__ float sav[64 * 24];
    int tid = threadIdx.x;
    for (int i = tid; i < INTERC * 18; i += 128) swA[i] = wA[i];
    if (tid < INTERC) sbA[tid] = bA[tid];
    for (int i = tid; i < NSET * 12; i += 128) swB[i] = wB[i];
    if (tid < NSET) { sbB[tid] = bB[tid]; sgam[tid] = gam[tid]; sb3[tid] = c211b[tid]; }
    for (int i = tid; i < NSET * CCH; i += 128) sw3[i] = c211w[i];
    __syncthreads();
    int px = tid & 63, half = tid >> 6;
    int pg = blockIdx.x * 64 + px;
    int b = pg >> 12, p = pg & 4095;
    int h = p >> 6, w = p & 63;
    const float* xb = xn + (size_t)b * CCH * HW;
#pragma unroll
    for (int oo = 0; oo < 12; oo++) {
        int o = half * 12 + oo;
        float acc = sbA[o];
#pragma unroll
        for (int t = 0; t < 2; t++) {
            int c = o * 2 + t;
            const float* ch = xb + (size_t)c * HW;
            float cen = 0.f;
#pragma unroll
            for (int kk = 0; kk < 9; kk++) {
                int hh = h + kk / 3 - 1, ww = w + kk % 3 - 1;
                if (hh >= 0 && hh < 64 && ww >= 0 && ww < 64) {
                    float vv = ch[hh * 64 + ww];
                    acc += swA[o * 18 + t * 9 + kk] * vv;
                    if (kk == 4) cen = vv;
                }
            }
            scen[px * 48 + c] = cen;
        }
        sav[px * 24 + o] = acc;
    }
    __syncthreads();
    float sg[12];
#pragma unroll
    for (int i = 0; i < 12; i++) sg[i] = sav[px * 24 + i] * sav[px * 24 + 12 + i];
#pragma unroll
    for (int nn = 0; nn < 16; nn++) {
        int n = half * 16 + nn;
        float s = sbB[n];
#pragma unroll
        for (int i = 0; i < 12; i++) s += swB[n * 12 + i] * sg[i];
        float c2 = sb3[n];
#pragma unroll
        for (int c = 0; c < 48; c++) c2 += sw3[n * 48 + c] * scen[px * 48 + c];
        att[((size_t)b * NSET + n) * HW + p] = sgam[n] * s + c2;
    }
}

// ================= KBA core via warp MMA, y-split x2 =================
#define KT_A 0
#define KT_B 18432
#define KT_P 41472
#define KT_TOTAL 61952

__global__ __launch_bounds__(256) void kba_mma_k(
        const float* __restrict__ uf, const float* __restrict__ att,
        const __nv_bfloat16* __restrict__ kwb, const float* __restrict__ ga1,
        const float* __restrict__ x1, float* __restrict__ mout)
{
    extern __shared__ __align__(16) char smraw[];
    uint32_t* A32 = (uint32_t*)(smraw + KT_A);
    uint32_t* B32 = (uint32_t*)(smraw + KT_B);
    float*    P   = (float*)(smraw + KT_P);

    int tid = threadIdx.x, wid = tid >> 5, lane = tid & 31;
    int c0 = lane & 3, rq = lane >> 2;
    int pb = blockIdx.x * 128;
    int b = pb >> 12, pp0 = pb & 4095;
    int g0 = blockIdx.y * 12;

    int px = tid & 127, half = tid >> 7;
    int pp = pp0 + px;
    int h = pp >> 6, w = pp & 63;

    {
        const float* attb = att + (size_t)b * NSET * HW + pp;
#pragma unroll
        for (int q = 0; q < 8; q++) {
            int n = (half * 8 + q) * 2;
            __nv_bfloat162 v;
            v.x = __float2bfloat16_rn(attb[(size_t)n * HW]);
            v.y = __float2bfloat16_rn(attb[(size_t)(n + 1) * HW]);
            A32[px * 36 + half * 8 + q] = *(uint32_t*)&v;
        }
    }
    int offs[9]; bool val[9];
#pragma unroll
    for (int kk = 0; kk < 9; kk++) {
        int dh = kk / 3 - 1, dw = kk % 3 - 1;
        int hh = h + dh, ww = w + dw;
        val[kk] = (hh >= 0 && hh < 64 && ww >= 0 && ww < 64);
        offs[kk] = hh * 64 + ww;
    }
    __syncthreads();

    int arow = 16 * wid + rq;
    uint32_t aF[2][4];
#pragma unroll
    for (int ks = 0; ks < 2; ks++) {
        int base = ks * 8;
        aF[ks][0] = A32[arow * 36 + base + c0];
        aF[ks][1] = A32[(arow + 8) * 36 + base + c0];
        aF[ks][2] = A32[arow * 36 + base + c0 + 4];
        aF[ks][3] = A32[(arow + 8) * 36 + base + c0 + 4];
    }

    for (int gi = 0; gi < 12; gi++) {
        int g = g0 + gi;
        __syncthreads();
        const uint32_t* kwb32 = (const uint32_t*)(kwb + (size_t)g * 160 * 32);
        for (int i = tid; i < 2560; i += 256) {
            int row = i >> 4, np = i & 15;
            B32[row * 36 + np] = kwb32[i];
        }
        const float* ufg = uf + ((size_t)b * HID + g * 4) * HW;
#pragma unroll
        for (int jj = 0; jj < 18; jj++) {
            int j = half * 18 + jj;
            int ci = j / 9, kk = j % 9;
            P[px * 40 + j] = val[kk] ? ufg[(size_t)ci * HW + offs[kk]] : 0.f;
        }
        __syncthreads();

#pragma unroll
        for (int cc = 0; cc < 4; cc++) {
            uint32_t bF[5][2][2];
            int nb = cc * 40;
#pragma unroll
            for (int t = 0; t < 5; t++) {
                int rowb = (nb + t * 8 + rq) * 36;
#pragma unroll
                for (int ks = 0; ks < 2; ks++) {
                    bF[t][ks][0] = B32[rowb + ks * 8 + c0];
                    bF[t][ks][1] = B32[rowb + ks * 8 + c0 + 4];
                }
            }
            float d[5][4];
#pragma unroll
            for (int t = 0; t < 5; t++) { d[t][0]=0.f; d[t][1]=0.f; d[t][2]=0.f; d[t][3]=0.f; }
#pragma unroll
            for (int t = 0; t < 5; t++) {
                mma_bf16(d[t], aF[0], bF[t][0]);
                mma_bf16(d[t], aF[1], bF[t][1]);
            }
            int rlo = 16 * wid + rq, rhi = rlo + 8;
            float s0 = 0.f, s1 = 0.f;
#pragma unroll
            for (int t = 0; t < 5; t++) {
                int j0 = t * 8 + 2 * c0, j1 = j0 + 1;
                float w00, w01, w10, w11;
                if (j0 < 36)      { w00 = P[rlo * 40 + j0]; w10 = P[rhi * 40 + j0]; }
                else if (j0 == 36){ w00 = 1.f; w10 = 1.f; }
                else              { w00 = 0.f; w10 = 0.f; }
                if (j1 < 36)      { w01 = P[rlo * 40 + j1]; w11 = P[rhi * 40 + j1]; }
                else              { w01 = 0.f; w11 = 0.f; }
                s0 += d[t][0] * w00 + d[t][1] * w01;
                s1 += d[t][2] * w10 + d[t][3] * w11;
            }
            s0 += __shfl_xor_sync(0xffffffffu, s0, 1);
            s0 += __shfl_xor_sync(0xffffffffu, s0, 2);
            s1 += __shfl_xor_sync(0xffffffffu, s1, 1);
            s1 += __shfl_xor_sync(0xffffffffu, s1, 2);
            if (c0 == 0) {
                int ch = g * 4 + cc;
                float ga = ga1[ch];
                float cen0 = P[rlo * 40 + cc * 9 + 4];
                float cen1 = P[rhi * 40 + cc * 9 + 4];
                float x2a = s0 * ga + cen0;
                float x2b = s1 * ga + cen1;
                size_t xlo = ((size_t)b * HID + ch) * HW + pp0 + rlo;
                size_t xhi = xlo + 8;
                float v0 = x1[xlo], v1 = x1[xhi];
                mout[xlo] = 0.5f * v0 * (1.f + erff(v0 * 0.70710678118654752f)) * x2a;
                mout[xhi] = 0.5f * v1 * (1.f + erff(v1 * 0.70710678118654752f)) * x2b;
            }
        }
    }
}

// ---------------- MDTA: fused norms + 6x6 attention + softmax ----------------
__global__ __launch_bounds__(256) void attn_k(const float* __restrict__ qkv,
        const float* __restrict__ temp, float* __restrict__ attn)
{
    int bh = blockIdx.x; int b = bh >> 3, h = bh & 7;
    int warp = threadIdx.x >> 5, lane = threadIdx.x & 31;
    __shared__ float S[36], NQ[6], NK[6];
    const float* qb = qkv + ((size_t)b * 3 * CCH + h * DHEAD) * HW;
    const float* kb = qkv + ((size_t)b * 3 * CCH + CCH + h * DHEAD) * HW;
    for (int pi = warp; pi < 48; pi += 8) {
        const float* pa; const float* pb;
        if (pi < 36)      { pa = qb + (size_t)(pi / 6) * HW; pb = kb + (size_t)(pi % 6) * HW; }
        else if (pi < 42) { pa = qb + (size_t)(pi - 36) * HW; pb = pa; }
        else              { pa = kb + (size_t)(pi - 42) * HW; pb = pa; }
        float s = 0.f;
        for (int t = lane * 4; t < HW; t += 128) {
            float4 va = *(const float4*)(pa + t);
            float4 vb = *(const float4*)(pb + t);
            s += va.x * vb.x + va.y * vb.y + va.z * vb.z + va.w * vb.w;
        }
#pragma unroll
        for (int off = 16; off; off >>= 1) s += __shfl_down_sync(0xffffffffu, s, off);
        if (lane == 0) {
            if (pi < 36) S[pi] = s;
            else if (pi < 42) NQ[pi - 36] = sqrtf(s);
            else NK[pi - 42] = sqrtf(s);
        }
    }
    __syncthreads();
    if (threadIdx.x < 6) {
        int i = threadIdx.x;
        float nq = fmaxf(NQ[i], 1e-12f);
        float tv = temp[h];
        float row[6]; float mx = -1e30f;
#pragma unroll
        for (int j = 0; j < 6; j++) {
            float nk = fmaxf(NK[j], 1e-12f);
            row[j] = tv * S[i * 6 + j] / (nq * nk);
            mx = fmaxf(mx, row[j]);
        }
        float sum = 0.f;
#pragma unroll
        for (int j = 0; j < 6; j++) { row[j] = expf(row[j] - mx); sum += row[j]; }
        float inv = 1.f / sum;
#pragma unroll
        for (int j = 0; j < 6; j++)
            attn[((size_t)(b * 8 + h) * 6 + i) * 6 + j] = row[j] * inv;
    }
}

// ---------------- MDTA: fused (attn @ v) + mproj ----------------
__global__ __launch_bounds__(128) void mdta_k(const float* __restrict__ qkv,
        const float* __restrict__ attn, const float* __restrict__ mproj,
        float* __restrict__ out)
{
    __shared__ float scoef[288];
    __shared__ u64 ws2[4 * CCH];
    int tid = threadIdx.x;
    int o0 = blockIdx.y * 4;
    int p4 = (blockIdx.x * 128 + tid) * 4;
    int b = p4 >> 12, pp = p4 & 4095;
    int bblk = (blockIdx.x * 512) >> 12;
    for (int i = tid; i < 288; i += 128) scoef[i] = attn[bblk * 288 + i];
    for (int i = tid; i < 4 * CCH; i += 128)
        ws2[i] = dup2(mproj[(o0 + i / CCH) * CCH + i % CCH]);
    __syncthreads();
    u64 acc[4][2];
#pragma unroll
    for (int o = 0; o < 4; o++) { acc[o][0] = 0ULL; acc[o][1] = 0ULL; }
    const float* vb = qkv + ((size_t)b * 3 * CCH + 2 * CCH) * HW + pp;
#pragma unroll
    for (int h = 0; h < 8; h++) {
        u64 v[6][2];
#pragma unroll
        for (int j = 0; j < 6; j++) {
            ulonglong2 t = *(const ulonglong2*)(vb + (size_t)(h * 6 + j) * HW);
            v[j][0] = t.x; v[j][1] = t.y;
        }
#pragma unroll
        for (int i = 0; i < 6; i++) {
            int c = h * 6 + i;
            u64 md0 = 0ULL, md1 = 0ULL;
#pragma unroll
            for (int j = 0; j < 6; j++) {
                u64 cf = dup2(scoef[c * 6 + j]);
                md0 = fma2_(cf, v[j][0], md0);
                md1 = fma2_(cf, v[j][1], md1);
            }
#pragma unroll
            for (int o = 0; o < 4; o++) {
                u64 wv = ws2[o * CCH + c];
                acc[o][0] = fma2_(wv, md0, acc[o][0]);
                acc[o][1] = fma2_(wv, md1, acc[o][1]);
            }
        }
    }
    float* outb = out + ((size_t)b * CCH + o0) * HW + pp;
#pragma unroll
    for (int o = 0; o < 4; o++) {
        ulonglong2 t; t.x = acc[o][0]; t.y = acc[o][1];
        *(ulonglong2*)(outb + (size_t)o * HW) = t;
    }
}

// ---------------- final: kproj + residual + inline channel-attention ----------------
__global__ __launch_bounds__(128) void final_k(const float* __restrict__ x,
        const float* __restrict__ m, const float* __restrict__ mdta,
        const float* __restrict__ kproj, const float* __restrict__ gap,
        const float* __restrict__ ca1w, const float* __restrict__ ca1b,
        const float* __restrict__ ca2w, const float* __restrict__ ca2b,
        float* __restrict__ out)
{
    __shared__ __align__(16) u64 wp2[4 * HID];
    __shared__ float sca1[4], sca2[4];
    int tid = threadIdx.x, wid = tid >> 5, lane = tid & 31;
    int o0 = blockIdx.y * 4;
    int bblk = (blockIdx.x * 512) >> 12;
    for (int i = tid; i < 4 * HID; i += 128)
        wp2[i] = dup2(kproj[(o0 + i / HID) * HID + i % HID]);
    {
        int oc = o0 + wid;
        float s1 = 0.f, s2 = 0.f;
        for (int c = lane; c < CCH; c += 32) {
            float g = gap[bblk * CCH + c];
            s1 += ca1w[oc * CCH + c] * g;
            s2 += ca2w[oc * CCH + c] * g;
        }
#pragma unroll
        for (int off = 16; off; off >>= 1) {
            s1 += __shfl_down_sync(0xffffffffu, s1, off);
            s2 += __shfl_down_sync(0xffffffffu, s2, off);
        }
        if (lane == 0) { sca1[wid] = s1 + ca1b[oc]; sca2[wid] = s2 + ca2b[oc]; }
    }
    __syncthreads();
    int p4 = (blockIdx.x * 128 + tid) * 4;
    int b = p4 >> 12, pp = p4 & 4095;
    const float* mb = m + (size_t)b * HID * HW + pp;
    u64 acc[4][2];
#pragma unroll
    for (int o = 0; o < 4; o++) { acc[o][0] = 0ULL; acc[o][1] = 0ULL; }
    for (int cc = 0; cc < HID; cc += 8) {
        u64 xv[8][2];
#pragma unroll
        for (int c = 0; c < 8; c++) {
            ulonglong2 t = *(const ulonglong2*)(mb + (size_t)(cc + c) * HW);
            xv[c][0] = t.x; xv[c][1] = t.y;
        }
#pragma unroll
        for (int o = 0; o < 4; o++) {
#pragma unroll
            for (int c = 0; c < 8; c += 2) {
                ulonglong2 wv = *(const ulonglong2*)&wp2[o * HID + cc + c];
                acc[o][0] = fma2_(wv.x, xv[c][0], acc[o][0]);
                acc[o][1] = fma2_(wv.x, xv[c][1], acc[o][1]);
                acc[o][0] = fma2_(wv.y, xv[c + 1][0], acc[o][0]);
                acc[o][1] = fma2_(wv.y, xv[c + 1][1], acc[o][1]);
            }
        }
    }
#pragma unroll
    for (int o = 0; o < 4; o++) {
        int oc = o0 + o;
        size_t oi = ((size_t)b * CCH + oc) * HW + pp;
        u64 a1 = dup2(sca1[o]), a2 = dup2(sca2[o]);
        ulonglong2 xv = *(const ulonglong2*)(x + oi);
        ulonglong2 dv = *(const ulonglong2*)(mdta + oi);
        ulonglong2 r;
        r.x = fma2_(a1, acc[o][0], fma2_(a2, dv.x, xv.x));
        r.y = fma2_(a1, acc[o][1], fma2_(a2, dv.y, xv.y));
        *(ulonglong2*)(out + oi) = r;
    }
}

// ---------------- host launcher ----------------
extern "C" void kernel_launch(void* const* d_in, const int* in_sizes, int n_in,
                              void* d_out, int out_size)
{
    const float* x       = (const float*)d_in[0];
    const float* n1w     = (const float*)d_in[1];
    const float* n1b     = (const float*)d_in[2];
    const float* n2w     = (const float*)d_in[3];
    const float* n2b     = (const float*)d_in[4];
    const float* kdw1    = (const float*)d_in[5];
    const float* kdw2    = (const float*)d_in[6];
    const float* kc1a    = (const float*)d_in[7];
    const float* kc1b    = (const float*)d_in[8];
    const float* kproj   = (const float*)d_in[9];
    const float* c2a_w   = (const float*)d_in[10];
    const float* c2a_b   = (const float*)d_in[11];
    const float* c2b_w   = (const float*)d_in[12];
    const float* c2b_b   = (const float*)d_in[13];
    const float* c211_w  = (const float*)d_in[14];
    const float* c211_b  = (const float*)d_in[15];
    const float* kw      = (const float*)d_in[16];
    const float* kb      = (const float*)d_in[17];
    const float* attg    = (const float*)d_in[18];
    const float* ga1     = (const float*)d_in[19];
    const float* temp    = (const float*)d_in[20];
    const float* qkv_w   = (const float*)d_in[21];
    const float* qkv_dww = (const float*)d_in[22];
    const float* mproj_w = (const float*)d_in[23];
    const float* ca1_w   = (const float*)d_in[24];
    const float* ca1_b   = (const float*)d_in[25];
    const float* ca2_w   = (const float*)d_in[26];
    const float* ca2_b   = (const float*)d_in[27];
    float* out = (float*)d_out;

    float* S = nullptr;
    cudaGetSymbolAddress((void**)&S, g_scratch);
    float* xn   = S + OFF_XN;
    float* t1   = S + OFF_T1;
    float* t2   = S + OFF_T2;
    float* x1   = S + OFF_X1;
    float* uf   = S + OFF_UF;
    float* att  = S + OFF_ATT;
    float* qkvt = S + OFF_QKVT;
    float* qkv  = S + OFF_QKV;
    float* m    = S + OFF_M;
    float* gap  = S + OFF_GAP;
    float* attn = S + OFF_ATTN;
    __nv_bfloat16* kwb = (__nv_bfloat16*)(S + OFF_KWB);
    __nv_bfloat16* wb  = (__nv_bfloat16*)(S + OFF_WB);
    __nv_bfloat16* wq  = (__nv_bfloat16*)(S + OFF_WQ);
    float* mdta = qkvt;                     // reuse

    const int PIX = BATCH * HW;             // 16384
    const int XB4 = PIX / 512;              // 32

    static cudaStream_t sB = nullptr, sC = nullptr;
    static cudaEvent_t evRoot = nullptr, evP = nullptr, evB = nullptr, evC = nullptr;
    if (sB == nullptr) {
        cudaStreamCreateWithFlags(&sB, cudaStreamNonBlocking);
        cudaStreamCreateWithFlags(&sC, cudaStreamNonBlocking);
        cudaEventCreateWithFlags(&evRoot, cudaEventDisableTiming);
        cudaEventCreateWithFlags(&evP, cudaEventDisableTiming);
        cudaEventCreateWithFlags(&evB, cudaEventDisableTiming);
        cudaEventCreateWithFlags(&evC, cudaEventDisableTiming);
        cudaFuncSetAttribute(kba_mma_k, cudaFuncAttributeMaxDynamicSharedMemorySize, KT_TOTAL);
    }

    // root: fork side streams FROM the origin stream (capture-legal ordering)
    cudaEventRecord(evRoot, 0);
    cudaStreamWaitEvent(sC, evRoot, 0);
    cudaStreamWaitEvent(sB, evRoot, 0);

    // ---- stream C: ln(xn) -> attmix ----
    ln_k<<<PIX / 64, 256, 0, sC>>>(x, n1w, n1b, xn);
    attmix_k<<<PIX / 64, 128, 0, sC>>>(xn, c2a_w, c2a_b, c2b_w, c2b_b, attg,
                                       c211_w, c211_b, att);
    cudaEventRecord(evC, sC);

    // ---- main: prep+gap ----
    const int PREP_N = 24 * 160 * 32 + 192 * 48 + 144 * 48;
    prepgap_k<<<GAPB + (PREP_N + 255) / 256, 256>>>(x, kw, kb, kdw1, kc1a, qkv_w,
                                                    gap, kwb, wb, wq);
    cudaEventRecord(evP, 0);

    // ---- stream B: MDTA chain (needs wq from prep) ----
    cudaStreamWaitEvent(sB, evP, 0);
    qkvm_k<<<dim3(PIX / 128, 2), 256, 0, sB>>>(x, n2w, n2b, wq, qkvt);
    dwq_k<<<BATCH * 144 * HW / 1024, 256, 0, sB>>>(qkvt, qkv_dww, qkv);
    attn_k<<<BATCH * HEADS, 256, 0, sB>>>(qkv, temp, attn);
    mdta_k<<<dim3(XB4, 12), 128, 0, sB>>>(qkv, attn, mproj_w, mdta);
    cudaEventRecord(evB, sB);

    // ---- main: KBA critical path ----
    fused3m_k<<<dim3(PIX / 128, 2), 256>>>(x, n1w, n1b, wb, t1, t2);
    dw12_k<<<BATCH * 192 * HW / 1024, 256>>>(t1, kdw2, t2, kc1b, x1, uf);
    cudaStreamWaitEvent(0, evC, 0);
    kba_mma_k<<<dim3(PIX / 128, 2), 256, KT_TOTAL>>>(uf, att, kwb, ga1, x1, m);
    cudaStreamWaitEvent(0, evB, 0);
    final_k<<<dim3(XB4, 12), 128>>>(x, m, mdta, kproj, gap,
                                    ca1_w, ca1_b, ca2_w, ca2_b, out);
}

// round 14
// speedup vs baseline: 3.1930x; 1.1071x over previous
#include <cuda_runtime.h>
#include <cuda_bf16.h>
#include <math.h>
#include <cstdint>

// ---------------- problem constants ----------------
#define BATCH 4
#define CCH   48
#define HW    4096
#define HID   96
#define NSET  32
#define HEADS 8
#define DHEAD 6
#define INTERC 24

typedef unsigned long long u64;
__device__ __forceinline__ u64 pk2(float lo, float hi){ u64 r; asm("mov.b64 %0,{%1,%2};":"=l"(r):"f"(lo),"f"(hi)); return r; }
__device__ __forceinline__ u64 dup2(float v){ return pk2(v, v); }
__device__ __forceinline__ u64 fma2_(u64 a, u64 b, u64 c){ u64 d; asm("fma.rn.f32x2 %0,%1,%2,%3;":"=l"(d):"l"(a),"l"(b),"l"(c)); return d; }

__device__ __forceinline__ void mma_bf16(float* d, const uint32_t* a, const uint32_t* b){
    asm volatile("mma.sync.aligned.m16n8k16.row.col.f32.bf16.bf16.f32 "
        "{%0,%1,%2,%3}, {%4,%5,%6,%7}, {%8,%9}, {%0,%1,%2,%3};"
        : "+f"(d[0]),"+f"(d[1]),"+f"(d[2]),"+f"(d[3])
        : "r"(a[0]),"r"(a[1]),"r"(a[2]),"r"(a[3]), "r"(b[0]),"r"(b[1]));
}

// ---------------- scratch layout ----------------
#define OFF_XN    0LL
#define OFF_T1    (OFF_XN   + (long long)BATCH*CCH*HW)
#define OFF_T2    (OFF_T1   + (long long)BATCH*HID*HW)
#define OFF_X1    (OFF_T2   + (long long)BATCH*HID*HW)
#define OFF_UF    (OFF_X1   + (long long)BATCH*HID*HW)
#define OFF_ATT   (OFF_UF   + (long long)BATCH*HID*HW)
#define OFF_QKVT  (OFF_ATT  + (long long)BATCH*NSET*HW)
#define OFF_QKV   (OFF_QKVT + (long long)BATCH*3*CCH*HW)
#define OFF_M     (OFF_QKV  + (long long)BATCH*3*CCH*HW)
#define OFF_GAP   (OFF_M    + (long long)BATCH*HID*HW)
#define OFF_ATTN  (OFF_GAP  + BATCH*CCH)
#define OFF_KWB   (OFF_ATTN + BATCH*HEADS*DHEAD*DHEAD)
#define OFF_WB    (OFF_KWB + 24*160*32/2 + 64)
#define OFF_WQ    (OFF_WB  + 192*48/2 + 32)
#define SCRATCH_TOTAL (OFF_WQ + 144*48/2 + 32)

__device__ float g_scratch[SCRATCH_TOTAL];

// ---------------- merged prep + gap ----------------
#define GAPB (BATCH * CCH)
__global__ void prepgap_k(const float* __restrict__ x,
                          const float* __restrict__ kw, const float* __restrict__ kb,
                          const float* __restrict__ w1, const float* __restrict__ w2,
                          const float* __restrict__ qw,
                          float* __restrict__ gap,
                          __nv_bfloat16* __restrict__ kwb,
                          __nv_bfloat16* __restrict__ wb, __nv_bfloat16* __restrict__ wq)
{
    if (blockIdx.x < GAPB) {
        int bc = blockIdx.x;
        const float* xb = x + (size_t)bc * HW;
        __shared__ float red[256];
        float s = 0.f;
        for (int i = threadIdx.x; i < HW; i += 256) s += xb[i];
        red[threadIdx.x] = s; __syncthreads();
        for (int st = 128; st; st >>= 1) {
            if (threadIdx.x < st) red[threadIdx.x] += red[threadIdx.x + st];
            __syncthreads();
        }
        if (threadIdx.x == 0) gap[bc] = red[0] * (1.f / HW);
        return;
    }
    int i = (blockIdx.x - GAPB) * 256 + threadIdx.x;
    if (i < 24 * 160 * 32) {
        int g = i / (160 * 32);
        int rem = i % (160 * 32);
        int row = rem >> 5, n = rem & 31;
        int c = row / 40, rr = row - c * 40;
        float v;
        if (rr < 36)       v = kw[(size_t)n * 3456 + g * 144 + c * 36 + rr];
        else if (rr == 36) v = kb[n * HID + g * 4 + c];
        else               v = 0.f;
        kwb[i] = __float2bfloat16_rn(v);
    } else if (i < 24 * 160 * 32 + 192 * 48) {
        int j = i - 24 * 160 * 32;
        int o = j / 48, c = j % 48;
        float v = (o < 96) ? w1[o * 48 + c] : w2[(o - 96) * 48 + c];
        wb[j] = __float2bfloat16_rn(v);
    } else if (i < 24 * 160 * 32 + 192 * 48 + 144 * 48) {
        int j = i - 24 * 160 * 32 - 192 * 48;
        wq[j] = __float2bfloat16_rn(qw[j]);
    }
}

// ---------------- LayerNorm (xn only, feeds attmix) ----------------
__global__ __launch_bounds__(256) void ln_k(const float* __restrict__ x,
        const float* __restrict__ n1w, const float* __restrict__ n1b,
        float* __restrict__ xn)
{
    __shared__ float S1[256], S2[256];
    int tid = threadIdx.x;
    int px = tid & 63, grp = tid >> 6;
    int pg = blockIdx.x * 64 + px;
    int b = pg >> 12, p = pg & 4095;
    const float* xb = x + (size_t)b * CCH * HW + p + (size_t)grp * 12 * HW;
    float v[12]; float s = 0.f, s2 = 0.f;
#pragma unroll
    for (int c = 0; c < 12; c++) { float t = xb[(size_t)c * HW]; v[c] = t; s += t; s2 += t * t; }
    S1[tid] = s; S2[tid] = s2;
    __syncthreads();
    float st  = S1[px] + S1[px + 64] + S1[px + 128] + S1[px + 192];
    float st2 = S2[px] + S2[px + 64] + S2[px + 128] + S2[px + 192];
    float mu = st * (1.f / CCH);
    float var = st2 * (1.f / CCH) - mu * mu;
    float r = rsqrtf(var + 1e-6f);
    float* xnb = xn + (size_t)b * CCH * HW + p + (size_t)grp * 12 * HW;
#pragma unroll
    for (int c = 0; c < 12; c++) {
        int cg = grp * 12 + c;
        xnb[(size_t)c * HW] = n1w[cg] * (v[c] - mu) * r + n1b[cg];
    }
}

// ---------------- fused2 via warp MMA with inline LN: x -> t1(96), t2(96) ----------------
__global__ __launch_bounds__(256) void fused3m_k(const float* __restrict__ x,
        const float* __restrict__ n1w, const float* __restrict__ n1b,
        const __nv_bfloat16* __restrict__ wb,
        float* __restrict__ t1, float* __restrict__ t2)
{
    __shared__ uint32_t A32[128 * 28];
    __shared__ uint32_t WB32[96 * 28];
    __shared__ float SS1[256], SS2[256];
    __shared__ float sw1[CCH], sb1[CCH];
    int tid = threadIdx.x, wid = tid >> 5, lane = tid & 31;
    int c0 = lane & 3, rq = lane >> 2;
    int y = blockIdx.y;
    int ob = y * 96;
    int pb = blockIdx.x * 128;
    int b = pb >> 12, pp0 = pb & 4095;
    int px = tid & 127, half = tid >> 7;
    int pp = pp0 + px;

    if (tid < CCH) { sw1[tid] = n1w[tid]; sb1[tid] = n1b[tid]; }
    const float* xb = x + (size_t)b * CCH * HW + pp;
    float v[24];
    float s = 0.f, s2 = 0.f;
#pragma unroll
    for (int w = 0; w < 12; w++) {
        int c = (half * 12 + w) * 2;
        float a0 = xb[(size_t)c * HW], a1 = xb[(size_t)(c + 1) * HW];
        v[2 * w] = a0; v[2 * w + 1] = a1;
        s += a0 + a1; s2 += a0 * a0 + a1 * a1;
    }
    SS1[tid] = s; SS2[tid] = s2;
    const uint32_t* wbg = (const uint32_t*)wb;
    for (int i = tid; i < 96 * 24; i += 256) {
        int o = i / 24, w = i % 24;
        WB32[o * 28 + w] = wbg[(ob + o) * 24 + w];
    }
    __syncthreads();
    {
        float st  = SS1[px] + SS1[px + 128];
        float st2 = SS2[px] + SS2[px + 128];
        float mu = st * (1.f / CCH);
        float var = st2 * (1.f / CCH) - mu * mu;
        float r = rsqrtf(var + 1e-6f);
#pragma unroll
        for (int w = 0; w < 12; w++) {
            int c = (half * 12 + w) * 2;
            __nv_bfloat162 bv;
            bv.x = __float2bfloat16_rn(sw1[c] * (v[2 * w] - mu) * r + sb1[c]);
            bv.y = __float2bfloat16_rn(sw1[c + 1] * (v[2 * w + 1] - mu) * r + sb1[c + 1]);
            A32[px * 28 + half * 12 + w] = *(uint32_t*)&bv;
        }
    }
    __syncthreads();

    int arow = wid * 16;
    uint32_t aF[3][4];
#pragma unroll
    for (int ks = 0; ks < 3; ks++) {
        aF[ks][0] = A32[(arow + rq) * 28 + ks * 8 + c0];
        aF[ks][1] = A32[(arow + rq + 8) * 28 + ks * 8 + c0];
        aF[ks][2] = A32[(arow + rq) * 28 + ks * 8 + c0 + 4];
        aF[ks][3] = A32[(arow + rq + 8) * 28 + ks * 8 + c0 + 4];
    }
    for (int nt = 0; nt < 12; nt++) {
        uint32_t bF[3][2];
        int rowb = (nt * 8 + rq) * 28;
#pragma unroll
        for (int ks = 0; ks < 3; ks++) { bF[ks][0] = WB32[rowb + ks * 8 + c0]; bF[ks][1] = WB32[rowb + ks * 8 + c0 + 4]; }
        float d[4] = {0.f, 0.f, 0.f, 0.f};
        mma_bf16(d, aF[0], bF[0]);
        mma_bf16(d, aF[1], bF[1]);
        mma_bf16(d, aF[2], bF[2]);
#pragma unroll
        for (int e = 0; e < 2; e++) {
            int oc = ob + nt * 8 + 2 * c0 + e;
            float* base = (oc < 96) ? t1 : t2;
            int oo = (oc < 96) ? oc : oc - 96;
            size_t o0 = ((size_t)b * HID + oo) * HW + pp0;
            base[o0 + arow + rq]     = d[e];
            base[o0 + arow + rq + 8] = d[e + 2];
        }
    }
}

// ---------------- qkv 1x1 via warp MMA with inline LN ----------------
__global__ __launch_bounds__(256) void qkvm_k(const float* __restrict__ x,
        const float* __restrict__ n2w, const float* __restrict__ n2b,
        const __nv_bfloat16* __restrict__ wq, float* __restrict__ out)
{
    __shared__ uint32_t A32[128 * 28];
    __shared__ uint32_t WB32[72 * 28];
    __shared__ float SS1[256], SS2[256];
    __shared__ float sw1[CCH], sb1[CCH];
    int tid = threadIdx.x, wid = tid >> 5, lane = tid & 31;
    int c0 = lane & 3, rq = lane >> 2;
    int y = blockIdx.y;
    int ob = y * 72;
    int pb = blockIdx.x * 128;
    int b = pb >> 12, pp0 = pb & 4095;
    int px = tid & 127, half = tid >> 7;
    int pp = pp0 + px;

    if (tid < CCH) { sw1[tid] = n2w[tid]; sb1[tid] = n2b[tid]; }
    const float* xb = x + (size_t)b * CCH * HW + pp;
    float v[24];
    float s = 0.f, s2 = 0.f;
#pragma unroll
    for (int w = 0; w < 12; w++) {
        int c = (half * 12 + w) * 2;
        float a0 = xb[(size_t)c * HW], a1 = xb[(size_t)(c + 1) * HW];
        v[2 * w] = a0; v[2 * w + 1] = a1;
        s += a0 + a1; s2 += a0 * a0 + a1 * a1;
    }
    SS1[tid] = s; SS2[tid] = s2;
    const uint32_t* wbg = (const uint32_t*)wq;
    for (int i = tid; i < 72 * 24; i += 256) {
        int o = i / 24, w = i % 24;
        WB32[o * 28 + w] = wbg[(ob + o) * 24 + w];
    }
    __syncthreads();
    {
        float st  = SS1[px] + SS1[px + 128];
        float st2 = SS2[px] + SS2[px + 128];
        float mu = st * (1.f / CCH);
        float var = st2 * (1.f / CCH) - mu * mu;
        float r = rsqrtf(var + 1e-6f);
#pragma unroll
        for (int w = 0; w < 12; w++) {
            int c = (half * 12 + w) * 2;
            __nv_bfloat162 bv;
            bv.x = __float2bfloat16_rn(sw1[c] * (v[2 * w] - mu) * r + sb1[c]);
            bv.y = __float2bfloat16_rn(sw1[c + 1] * (v[2 * w + 1] - mu) * r + sb1[c + 1]);
            A32[px * 28 + half * 12 + w] = *(uint32_t*)&bv;
        }
    }
    __syncthreads();

    int arow = wid * 16;
    uint32_t aF[3][4];
#pragma unroll
    for (int ks = 0; ks < 3; ks++) {
        aF[ks][0] = A32[(arow + rq) * 28 + ks * 8 + c0];
        aF[ks][1] = A32[(arow + rq + 8) * 28 + ks * 8 + c0];
        aF[ks][2] = A32[(arow + rq) * 28 + ks * 8 + c0 + 4];
        aF[ks][3] = A32[(arow + rq + 8) * 28 + ks * 8 + c0 + 4];
    }
    for (int nt = 0; nt < 9; nt++) {
        uint32_t bF[3][2];
        int rowb = (nt * 8 + rq) * 28;
#pragma unroll
        for (int ks = 0; ks < 3; ks++) { bF[ks][0] = WB32[rowb + ks * 8 + c0]; bF[ks][1] = WB32[rowb + ks * 8 + c0 + 4]; }
        float d[4] = {0.f, 0.f, 0.f, 0.f};
        mma_bf16(d, aF[0], bF[0]);
        mma_bf16(d, aF[1], bF[1]);
        mma_bf16(d, aF[2], bF[2]);
#pragma unroll
        for (int e = 0; e < 2; e++) {
            int oc = ob + nt * 8 + 2 * c0 + e;
            size_t o0 = ((size_t)b * (3 * CCH) + oc) * HW + pp0;
            out[o0 + arow + rq]     = d[e];
            out[o0 + arow + rq + 8] = d[e + 2];
        }
    }
}

// ---------------- depthwise 3x3 for t1/t2 ----------------
__global__ void dw12_k(const float* __restrict__ t1, const float* __restrict__ kdw2,
                       const float* __restrict__ t2, const float* __restrict__ kc1b,
                       float* __restrict__ x1, float* __restrict__ uf)
{
    int gidx4 = (blockIdx.x * 256 + threadIdx.x);
    int p = (gidx4 * 4) & 4095;
    int plane = (gidx4 * 4) >> 12;
    int b = plane / 192, cg = plane % 192;
    const float* in; const float* wsrc; float* outp; int c;
    if (cg < 96) { in = t1; wsrc = kdw2; outp = x1; c = cg; }
    else         { in = t2; wsrc = kc1b; outp = uf; c = cg - 96; }
    int h = p >> 6, w0 = p & 63;
    const float* inp = in + ((size_t)b * 96 + c) * HW;
    const float* wc = wsrc + c * 9;
    float wk[9];
#pragma unroll
    for (int i = 0; i < 9; i++) wk[i] = __ldg(wc + i);
    float a[4] = {0.f, 0.f, 0.f, 0.f};
#pragma unroll
    for (int kh = 0; kh < 3; kh++) {
        int hh = h + kh - 1;
        if (hh < 0 || hh > 63) continue;
        const float* r = inp + hh * 64;
        float4 v14 = *(const float4*)(r + w0);
        float vm1 = (w0 > 0)  ? r[w0 - 1] : 0.f;
        float v5  = (w0 < 60) ? r[w0 + 4] : 0.f;
        float v[6] = {vm1, v14.x, v14.y, v14.z, v14.w, v5};
        float k0 = wk[kh * 3], k1 = wk[kh * 3 + 1], k2 = wk[kh * 3 + 2];
#pragma unroll
        for (int px = 0; px < 4; px++)
            a[px] += k0 * v[px] + k1 * v[px + 1] + k2 * v[px + 2];
    }
    ulonglong2 t; t.x = pk2(a[0], a[1]); t.y = pk2(a[2], a[3]);
    *(ulonglong2*)(outp + ((size_t)b * 96 + c) * HW + p) = t;
}

// ---------------- depthwise 3x3 for qkv ----------------
__global__ void dwq_k(const float* __restrict__ qkvt, const float* __restrict__ qkvw,
                      float* __restrict__ qkv)
{
    int gidx4 = (blockIdx.x * 256 + threadIdx.x);
    int p = (gidx4 * 4) & 4095;
    int plane = (gidx4 * 4) >> 12;
    int b = plane / 144, c = plane % 144;
    int h = p >> 6, w0 = p & 63;
    const float* inp = qkvt + ((size_t)b * 144 + c) * HW;
    const float* wc = qkvw + c * 9;
    float wk[9];
#pragma unroll
    for (int i = 0; i < 9; i++) wk[i] = __ldg(wc + i);
    float a[4] = {0.f, 0.f, 0.f, 0.f};
#pragma unroll
    for (int kh = 0; kh < 3; kh++) {
        int hh = h + kh - 1;
        if (hh < 0 || hh > 63) continue;
        const float* r = inp + hh * 64;
        float4 v14 = *(const float4*)(r + w0);
        float vm1 = (w0 > 0)  ? r[w0 - 1] : 0.f;
        float v5  = (w0 < 60) ? r[w0 + 4] : 0.f;
        float v[6] = {vm1, v14.x, v14.y, v14.z, v14.w, v5};
        float k0 = wk[kh * 3], k1 = wk[kh * 3 + 1], k2 = wk[kh * 3 + 2];
#pragma unroll
        for (int px = 0; px < 4; px++)
            a[px] += k0 * v[px] + k1 * v[px + 1] + k2 * v[px + 2];
    }
    ulonglong2 t; t.x = pk2(a[0], a[1]); t.y = pk2(a[2], a[3]);
    *(ulonglong2*)(qkv + ((size_t)b * 144 + c) * HW + p) = t;
}

// ---------------- attmix ----------------
__global__ __launch_bounds__(128) void attmix_k(const float* __restrict__ xn,
        const float* __restrict__ wA, const float* __restrict__ bA,
        const float* __restrict__ wB, const float* __restrict__ bB,
        const float* __restrict__ gam,
        const float* __restrict__ c211w, const float* __restrict__ c211b,
        float* __restrict__ att)
{
    __shared__ float swA[INTERC * 18], sbA[INTERC], swB[NSET * 12], sbB[NSET], sgam[NSET];
    __shared__ float sw3[NSET * CCH], sb3[NSET];
    __shared__ float scen[64 * 48];
    __shared__ float sav[64 * 24];
    int tid = threadIdx.x;
    for (int i = tid; i < INTERC * 18; i += 128) swA[i] = wA[i];
    if (tid < INTERC) sbA[tid] = bA[tid];
    for (int i = tid; i < NSET * 12; i += 128) swB[i] = wB[i];
    if (tid < NSET) { sbB[tid] = bB[tid]; sgam[tid] = gam[tid]; sb3[tid] = c211b[tid]; }
    for (int i = tid; i < NSET * CCH; i += 128) sw3[i] = c211w[i];
    __syncthreads();
    int px = tid & 63, half = tid >> 6;
    int pg = blockIdx.x * 64 + px;
    int b = pg >> 12, p = pg & 4095;
    int h = p >> 6, w = p & 63;
    const float* xb = xn + (size_t)b * CCH * HW;
#pragma unroll
    for (int oo = 0; oo < 12; oo++) {
        int o = half * 12 + oo;
        float acc = sbA[o];
#pragma unroll
        for (int t = 0; t < 2; t++) {
            int c = o * 2 + t;
            const float* ch = xb + (size_t)c * HW;
            float cen = 0.f;
#pragma unroll
            for (int kk = 0; kk < 9; kk++) {
                int hh = h + kk / 3 - 1, ww = w + kk % 3 - 1;
                if (hh >= 0 && hh < 64 && ww >= 0 && ww < 64) {
                    float vv = ch[hh * 64 + ww];
                    acc += swA[o * 18 + t * 9 + kk] * vv;
                    if (kk == 4) cen = vv;
                }
            }
            scen[px * 48 + c] = cen;
        }
        sav[px * 24 + o] = acc;
    }
    __syncthreads();
    float sg[12];
#pragma unroll
    for (int i = 0; i < 12; i++) sg[i] = sav[px * 24 + i] * sav[px * 24 + 12 + i];
#pragma unroll
    for (int nn = 0; nn < 16; nn++) {
        int n = half * 16 + nn;
        float s = sbB[n];
#pragma unroll
        for (int i = 0; i < 12; i++) s += swB[n * 12 + i] * sg[i];
        float c2 = sb3[n];
#pragma unroll
        for (int c = 0; c < 48; c++) c2 += sw3[n * 48 + c] * scen[px * 48 + c];
        att[((size_t)b * NSET + n) * HW + p] = sgam[n] * s + c2;
    }
}

// ================= KBA core via warp MMA, y-split x4 (6 groups each) =================
#define KT_A 0
#define KT_B 18432
#define KT_P 41472
#define KT_TOTAL 61952

__global__ __launch_bounds__(256) void kba_mma_k(
        const float* __restrict__ uf, const float* __restrict__ att,
        const __nv_bfloat16* __restrict__ kwb, const float* __restrict__ ga1,
        const float* __restrict__ x1, float* __restrict__ mout)
{
    extern __shared__ __align__(16) char smraw[];
    uint32_t* A32 = (uint32_t*)(smraw + KT_A);
    uint32_t* B32 = (uint32_t*)(smraw + KT_B);
    float*    P   = (float*)(smraw + KT_P);

    int tid = threadIdx.x, wid = tid >> 5, lane = tid & 31;
    int c0 = lane & 3, rq = lane >> 2;
    int pb = blockIdx.x * 128;
    int b = pb >> 12, pp0 = pb & 4095;
    int g0 = blockIdx.y * 6;

    int px = tid & 127, half = tid >> 7;
    int pp = pp0 + px;
    int h = pp >> 6, w = pp & 63;

    {
        const float* attb = att + (size_t)b * NSET * HW + pp;
#pragma unroll
        for (int q = 0; q < 8; q++) {
            int n = (half * 8 + q) * 2;
            __nv_bfloat162 v;
            v.x = __float2bfloat16_rn(attb[(size_t)n * HW]);
            v.y = __float2bfloat16_rn(attb[(size_t)(n + 1) * HW]);
            A32[px * 36 + half * 8 + q] = *(uint32_t*)&v;
        }
    }
    int offs[9]; bool val[9];
#pragma unroll
    for (int kk = 0; kk < 9; kk++) {
        int dh = kk / 3 - 1, dw = kk % 3 - 1;
        int hh = h + dh, ww = w + dw;
        val[kk] = (hh >= 0 && hh < 64 && ww >= 0 && ww < 64);
        offs[kk] = hh * 64 + ww;
    }
    __syncthreads();

    int arow = 16 * wid + rq;
    uint32_t aF[2][4];
#pragma unroll
    for (int ks = 0; ks < 2; ks++) {
        int base = ks * 8;
        aF[ks][0] = A32[arow * 36 + base + c0];
        aF[ks][1] = A32[(arow + 8) * 36 + base + c0];
        aF[ks][2] = A32[arow * 36 + base + c0 + 4];
        aF[ks][3] = A32[(arow + 8) * 36 + base + c0 + 4];
    }

    for (int gi = 0; gi < 6; gi++) {
        int g = g0 + gi;
        __syncthreads();
        const uint32_t* kwb32 = (const uint32_t*)(kwb + (size_t)g * 160 * 32);
        for (int i = tid; i < 2560; i += 256) {
            int row = i >> 4, np = i & 15;
            B32[row * 36 + np] = kwb32[i];
        }
        const float* ufg = uf + ((size_t)b * HID + g * 4) * HW;
#pragma unroll
        for (int jj = 0; jj < 18; jj++) {
            int j = half * 18 + jj;
            int ci = j / 9, kk = j % 9;
            P[px * 40 + j] = val[kk] ? ufg[(size_t)ci * HW + offs[kk]] : 0.f;
        }
        __syncthreads();

#pragma unroll
        for (int cc = 0; cc < 4; cc++) {
            uint32_t bF[5][2][2];
            int nb = cc * 40;
#pragma unroll
            for (int t = 0; t < 5; t++) {
                int rowb = (nb + t * 8 + rq) * 36;
#pragma unroll
                for (int ks = 0; ks < 2; ks++) {
                    bF[t][ks][0] = B32[rowb + ks * 8 + c0];
                    bF[t][ks][1] = B32[rowb + ks * 8 + c0 + 4];
                }
            }
            float d[5][4];
#pragma unroll
            for (int t = 0; t < 5; t++) { d[t][0]=0.f; d[t][1]=0.f; d[t][2]=0.f; d[t][3]=0.f; }
#pragma unroll
            for (int t = 0; t < 5; t++) {
                mma_bf16(d[t], aF[0], bF[t][0]);
                mma_bf16(d[t], aF[1], bF[t][1]);
            }
            int rlo = 16 * wid + rq, rhi = rlo + 8;
            float s0 = 0.f, s1 = 0.f;
#pragma unroll
            for (int t = 0; t < 5; t++) {
                int j0 = t * 8 + 2 * c0, j1 = j0 + 1;
                float w00, w01, w10, w11;
                if (j0 < 36)      { w00 = P[rlo * 40 + j0]; w10 = P[rhi * 40 + j0]; }
                else if (j0 == 36){ w00 = 1.f; w10 = 1.f; }
                else              { w00 = 0.f; w10 = 0.f; }
                if (j1 < 36)      { w01 = P[rlo * 40 + j1]; w11 = P[rhi * 40 + j1]; }
                else              { w01 = 0.f; w11 = 0.f; }
                s0 += d[t][0] * w00 + d[t][1] * w01;
                s1 += d[t][2] * w10 + d[t][3] * w11;
            }
            s0 += __shfl_xor_sync(0xffffffffu, s0, 1);
            s0 += __shfl_xor_sync(0xffffffffu, s0, 2);
            s1 += __shfl_xor_sync(0xffffffffu, s1, 1);
            s1 += __shfl_xor_sync(0xffffffffu, s1, 2);
            if (c0 == 0) {
                int ch = g * 4 + cc;
                float ga = ga1[ch];
                float cen0 = P[rlo * 40 + cc * 9 + 4];
                float cen1 = P[rhi * 40 + cc * 9 + 4];
                float x2a = s0 * ga + cen0;
                float x2b = s1 * ga + cen1;
                size_t xlo = ((size_t)b * HID + ch) * HW + pp0 + rlo;
                size_t xhi = xlo + 8;
                float v0 = x1[xlo], v1 = x1[xhi];
                mout[xlo] = 0.5f * v0 * (1.f + erff(v0 * 0.70710678118654752f)) * x2a;
                mout[xhi] = 0.5f * v1 * (1.f + erff(v1 * 0.70710678118654752f)) * x2b;
            }
        }
    }
}

// ---------------- MDTA: fused norms + 6x6 attention + softmax ----------------
__global__ __launch_bounds__(256) void attn_k(const float* __restrict__ qkv,
        const float* __restrict__ temp, float* __restrict__ attn)
{
    int bh = blockIdx.x; int b = bh >> 3, h = bh & 7;
    int warp = threadIdx.x >> 5, lane = threadIdx.x & 31;
    __shared__ float S[36], NQ[6], NK[6];
    const float* qb = qkv + ((size_t)b * 3 * CCH + h * DHEAD) * HW;
    const float* kb = qkv + ((size_t)b * 3 * CCH + CCH + h * DHEAD) * HW;
    for (int pi = warp; pi < 48; pi += 8) {
        const float* pa; const float* pb;
        if (pi < 36)      { pa = qb + (size_t)(pi / 6) * HW; pb = kb + (size_t)(pi % 6) * HW; }
        else if (pi < 42) { pa = qb + (size_t)(pi - 36) * HW; pb = pa; }
        else              { pa = kb + (size_t)(pi - 42) * HW; pb = pa; }
        float s = 0.f;
        for (int t = lane * 4; t < HW; t += 128) {
            float4 va = *(const float4*)(pa + t);
            float4 vb = *(const float4*)(pb + t);
            s += va.x * vb.x + va.y * vb.y + va.z * vb.z + va.w * vb.w;
        }
#pragma unroll
        for (int off = 16; off; off >>= 1) s += __shfl_down_sync(0xffffffffu, s, off);
        if (lane == 0) {
            if (pi < 36) S[pi] = s;
            else if (pi < 42) NQ[pi - 36] = sqrtf(s);
            else NK[pi - 42] = sqrtf(s);
        }
    }
    __syncthreads();
    if (threadIdx.x < 6) {
        int i = threadIdx.x;
        float nq = fmaxf(NQ[i], 1e-12f);
        float tv = temp[h];
        float row[6]; float mx = -1e30f;
#pragma unroll
        for (int j = 0; j < 6; j++) {
            float nk = fmaxf(NK[j], 1e-12f);
            row[j] = tv * S[i * 6 + j] / (nq * nk);
            mx = fmaxf(mx, row[j]);
        }
        float sum = 0.f;
#pragma unroll
        for (int j = 0; j < 6; j++) { row[j] = expf(row[j] - mx); sum += row[j]; }
        float inv = 1.f / sum;
#pragma unroll
        for (int j = 0; j < 6; j++)
            attn[((size_t)(b * 8 + h) * 6 + i) * 6 + j] = row[j] * inv;
    }
}

// ---------------- MDTA: fused (attn @ v) + mproj ----------------
__global__ __launch_bounds__(128) void mdta_k(const float* __restrict__ qkv,
        const float* __restrict__ attn, const float* __restrict__ mproj,
        float* __restrict__ out)
{
    __shared__ float scoef[288];
    __shared__ u64 ws2[4 * CCH];
    int tid = threadIdx.x;
    int o0 = blockIdx.y * 4;
    int p4 = (blockIdx.x * 128 + tid) * 4;
    int b = p4 >> 12, pp = p4 & 4095;
    int bblk = (blockIdx.x * 512) >> 12;
    for (int i = tid; i < 288; i += 128) scoef[i] = attn[bblk * 288 + i];
    for (int i = tid; i < 4 * CCH; i += 128)
        ws2[i] = dup2(mproj[(o0 + i / CCH) * CCH + i % CCH]);
    __syncthreads();
    u64 acc[4][2];
#pragma unroll
    for (int o = 0; o < 4; o++) { acc[o][0] = 0ULL; acc[o][1] = 0ULL; }
    const float* vb = qkv + ((size_t)b * 3 * CCH + 2 * CCH) * HW + pp;
#pragma unroll
    for (int h = 0; h < 8; h++) {
        u64 v[6][2];
#pragma unroll
        for (int j = 0; j < 6; j++) {
            ulonglong2 t = *(const ulonglong2*)(vb + (size_t)(h * 6 + j) * HW);
            v[j][0] = t.x; v[j][1] = t.y;
        }
#pragma unroll
        for (int i = 0; i < 6; i++) {
            int c = h * 6 + i;
            u64 md0 = 0ULL, md1 = 0ULL;
#pragma unroll
            for (int j = 0; j < 6; j++) {
                u64 cf = dup2(scoef[c * 6 + j]);
                md0 = fma2_(cf, v[j][0], md0);
                md1 = fma2_(cf, v[j][1], md1);
            }
#pragma unroll
            for (int o = 0; o < 4; o++) {
                u64 wv = ws2[o * CCH + c];
                acc[o][0] = fma2_(wv, md0, acc[o][0]);
                acc[o][1] = fma2_(wv, md1, acc[o][1]);
            }
        }
    }
    float* outb = out + ((size_t)b * CCH + o0) * HW + pp;
#pragma unroll
    for (int o = 0; o < 4; o++) {
        ulonglong2 t; t.x = acc[o][0]; t.y = acc[o][1];
        *(ulonglong2*)(outb + (size_t)o * HW) = t;
    }
}

// ---------------- final via warp MMA: m(96)->48 + residual + mdta + inline ca ----------------
__global__ __launch_bounds__(256) void finalm_k(const float* __restrict__ x,
        const float* __restrict__ m, const float* __restrict__ mdta,
        const float* __restrict__ kproj, const float* __restrict__ gap,
        const float* __restrict__ ca1w, const float* __restrict__ ca1b,
        const float* __restrict__ ca2w, const float* __restrict__ ca2b,
        float* __restrict__ out)
{
    __shared__ uint32_t A32[128 * 52];
    __shared__ uint32_t WB32[48 * 52];
    __shared__ float sca1[48], sca2[48];
    int tid = threadIdx.x, wid = tid >> 5, lane = tid & 31;
    int c0 = lane & 3, rq = lane >> 2;
    int pb = blockIdx.x * 128;
    int b = pb >> 12, pp0 = pb & 4095;
    int px = tid & 127, half = tid >> 7;
    int pp = pp0 + px;

    // stage A = m tile (bf16), 48 ch per half-thread
    const float* mb = m + (size_t)b * HID * HW + pp;
#pragma unroll
    for (int w = 0; w < 24; w++) {
        int c = (half * 24 + w) * 2;
        __nv_bfloat162 bv;
        bv.x = __float2bfloat16_rn(mb[(size_t)c * HW]);
        bv.y = __float2bfloat16_rn(mb[(size_t)(c + 1) * HW]);
        A32[px * 52 + half * 24 + w] = *(uint32_t*)&bv;
    }
    // stage B = kproj (convert to bf16 pairs)
    for (int i = tid; i < 48 * 48; i += 256) {
        int o = i / 48, w = i % 48;
        __nv_bfloat162 bv;
        bv.x = __float2bfloat16_rn(kproj[o * HID + 2 * w]);
        bv.y = __float2bfloat16_rn(kproj[o * HID + 2 * w + 1]);
        WB32[o * 52 + w] = *(uint32_t*)&bv;
    }
    // inline channel attention (48 channels, one thread each)
    if (tid < 48) {
        float s1 = ca1b[tid], s2 = ca2b[tid];
        for (int c = 0; c < CCH; c++) {
            float g = gap[b * CCH + c];
            s1 += ca1w[tid * CCH + c] * g;
            s2 += ca2w[tid * CCH + c] * g;
        }
        sca1[tid] = s1; sca2[tid] = s2;
    }
    __syncthreads();

    int arow = wid * 16;
    uint32_t aF[6][4];
#pragma unroll
    for (int ks = 0; ks < 6; ks++) {
        aF[ks][0] = A32[(arow + rq) * 52 + ks * 8 + c0];
        aF[ks][1] = A32[(arow + rq + 8) * 52 + ks * 8 + c0];
        aF[ks][2] = A32[(arow + rq) * 52 + ks * 8 + c0 + 4];
        aF[ks][3] = A32[(arow + rq + 8) * 52 + ks * 8 + c0 + 4];
    }
#pragma unroll
    for (int nt = 0; nt < 6; nt++) {
        uint32_t bF[6][2];
        int rowb = (nt * 8 + rq) * 52;
#pragma unroll
        for (int ks = 0; ks < 6; ks++) { bF[ks][0] = WB32[rowb + ks * 8 + c0]; bF[ks][1] = WB32[rowb + ks * 8 + c0 + 4]; }
        float d[4] = {0.f, 0.f, 0.f, 0.f};
#pragma unroll
        for (int ks = 0; ks < 6; ks++) mma_bf16(d, aF[ks], bF[ks]);
#pragma unroll
        for (int e = 0; e < 2; e++) {
            int oc = nt * 8 + 2 * c0 + e;
            float a1 = sca1[oc], a2 = sca2[oc];
            size_t o0 = ((size_t)b * CCH + oc) * HW + pp0;
            size_t i0 = o0 + arow + rq, i1 = i0 + 8;
            out[i0] = x[i0] + a1 * d[e]     + a2 * mdta[i0];
            out[i1] = x[i1] + a1 * d[e + 2] + a2 * mdta[i1];
        }
    }
}

// ---------------- host launcher ----------------
extern "C" void kernel_launch(void* const* d_in, const int* in_sizes, int n_in,
                              void* d_out, int out_size)
{
    const float* x       = (const float*)d_in[0];
    const float* n1w     = (const float*)d_in[1];
    const float* n1b     = (const float*)d_in[2];
    const float* n2w     = (const float*)d_in[3];
    const float* n2b     = (const float*)d_in[4];
    const float* kdw1    = (const float*)d_in[5];
    const float* kdw2    = (const float*)d_in[6];
    const float* kc1a    = (const float*)d_in[7];
    const float* kc1b    = (const float*)d_in[8];
    const float* kproj   = (const float*)d_in[9];
    const float* c2a_w   = (const float*)d_in[10];
    const float* c2a_b   = (const float*)d_in[11];
    const float* c2b_w   = (const float*)d_in[12];
    const float* c2b_b   = (const float*)d_in[13];
    const float* c211_w  = (const float*)d_in[14];
    const float* c211_b  = (const float*)d_in[15];
    const float* kw      = (const float*)d_in[16];
    const float* kb      = (const float*)d_in[17];
    const float* attg    = (const float*)d_in[18];
    const float* ga1     = (const float*)d_in[19];
    const float* temp    = (const float*)d_in[20];
    const float* qkv_w   = (const float*)d_in[21];
    const float* qkv_dww = (const float*)d_in[22];
    const float* mproj_w = (const float*)d_in[23];
    const float* ca1_w   = (const float*)d_in[24];
    const float* ca1_b   = (const float*)d_in[25];
    const float* ca2_w   = (const float*)d_in[26];
    const float* ca2_b   = (const float*)d_in[27];
    float* out = (float*)d_out;

    float* S = nullptr;
    cudaGetSymbolAddress((void**)&S, g_scratch);
    float* xn   = S + OFF_XN;
    float* t1   = S + OFF_T1;
    float* t2   = S + OFF_T2;
    float* x1   = S + OFF_X1;
    float* uf   = S + OFF_UF;
    float* att  = S + OFF_ATT;
    float* qkvt = S + OFF_QKVT;
    float* qkv  = S + OFF_QKV;
    float* m    = S + OFF_M;
    float* gap  = S + OFF_GAP;
    float* attn = S + OFF_ATTN;
    __nv_bfloat16* kwb = (__nv_bfloat16*)(S + OFF_KWB);
    __nv_bfloat16* wb  = (__nv_bfloat16*)(S + OFF_WB);
    __nv_bfloat16* wq  = (__nv_bfloat16*)(S + OFF_WQ);
    float* mdta = qkvt;                     // reuse

    const int PIX = BATCH * HW;             // 16384
    const int XB4 = PIX / 512;              // 32

    static cudaStream_t sB = nullptr, sC = nullptr;
    static cudaEvent_t evRoot = nullptr, evP = nullptr, evB = nullptr, evC = nullptr;
    if (sB == nullptr) {
        cudaStreamCreateWithFlags(&sB, cudaStreamNonBlocking);
        cudaStreamCreateWithFlags(&sC, cudaStreamNonBlocking);
        cudaEventCreateWithFlags(&evRoot, cudaEventDisableTiming);
        cudaEventCreateWithFlags(&evP, cudaEventDisableTiming);
        cudaEventCreateWithFlags(&evB, cudaEventDisableTiming);
        cudaEventCreateWithFlags(&evC, cudaEventDisableTiming);
        cudaFuncSetAttribute(kba_mma_k, cudaFuncAttributeMaxDynamicSharedMemorySize, KT_TOTAL);
    }

    cudaEventRecord(evRoot, 0);
    cudaStreamWaitEvent(sC, evRoot, 0);
    cudaStreamWaitEvent(sB, evRoot, 0);

    // ---- stream C: ln(xn) -> attmix ----
    ln_k<<<PIX / 64, 256, 0, sC>>>(x, n1w, n1b, xn);
    attmix_k<<<PIX / 64, 128, 0, sC>>>(xn, c2a_w, c2a_b, c2b_w, c2b_b, attg,
                                       c211_w, c211_b, att);
    cudaEventRecord(evC, sC);

    // ---- main: prep+gap ----
    const int PREP_N = 24 * 160 * 32 + 192 * 48 + 144 * 48;
    prepgap_k<<<GAPB + (PREP_N + 255) / 256, 256>>>(x, kw, kb, kdw1, kc1a, qkv_w,
                                                    gap, kwb, wb, wq);
    cudaEventRecord(evP, 0);

    // ---- stream B: MDTA chain ----
    cudaStreamWaitEvent(sB, evP, 0);
    qkvm_k<<<dim3(PIX / 128, 2), 256, 0, sB>>>(x, n2w, n2b, wq, qkvt);
    dwq_k<<<BATCH * 144 * HW / 1024, 256, 0, sB>>>(qkvt, qkv_dww, qkv);
    attn_k<<<BATCH * HEADS, 256, 0, sB>>>(qkv, temp, attn);
    mdta_k<<<dim3(XB4, 12), 128, 0, sB>>>(qkv, attn, mproj_w, mdta);
    cudaEventRecord(evB, sB);

    // ---- main: KBA critical path ----
    fused3m_k<<<dim3(PIX / 128, 2), 256>>>(x, n1w, n1b, wb, t1, t2);
    dw12_k<<<BATCH * 192 * HW / 1024, 256>>>(t1, kdw2, t2, kc1b, x1, uf);
    cudaStreamWaitEvent(0, evC, 0);
    kba_mma_k<<<dim3(PIX / 128, 4), 256, KT_TOTAL>>>(uf, att, kwb, ga1, x1, m);
    cudaStreamWaitEvent(0, evB, 0);
    finalm_k<<<PIX / 128, 256>>>(x, m, mdta, kproj, gap,
                                 ca1_w, ca1_b, ca2_w, ca2_b, out);
}